// round 1
// baseline (speedup 1.0000x reference)
#include <cuda_runtime.h>
#include <math.h>

#define NPTS 100000
#define CDIM 96
#define GRES 32
#define G3   (GRES*GRES*GRES)

// ----------------------------- scratch (device globals; no runtime alloc) ---
__device__ int   g_vidx[NPTS];
__device__ float g_cnt[G3];
__device__ float g_inv[G3];
__device__ int   g_nbi[8*NPTS];
__device__ float g_nbw[8*NPTS];
__device__ float g_grid[G3*2*CDIM];     // voxel grid, up to 192 channels
__device__ float g_conv[G3*CDIM];       // conv output, 96 channels
__device__ float g_vout[G3];            // conv output, 1 channel
__device__ float g_q[NPTS*CDIM];
__device__ float g_h[NPTS*CDIM];
__device__ float g_energy[NPTS*CDIM];
__device__ float g_attn[NPTS];
// transposed weights
__device__ float g_wqT [27*CDIM*CDIM];
__device__ float g_whT [27*CDIM*CDIM];
__device__ float g_attT[27*2*CDIM*CDIM];
__device__ float g_updT[27*2*CDIM*CDIM];
__device__ float g_vT  [27*CDIM];
__device__ float g_wqlT [CDIM*CDIM];
__device__ float g_whlT [CDIM*CDIM];
__device__ float g_attlT[2*CDIM*CDIM];
__device__ float g_updlT[2*CDIM*CDIM];

// ----------------------------- utility kernels ------------------------------
__global__ void zero_k(float* __restrict__ p, int n) {
    int i = blockIdx.x * blockDim.x + threadIdx.x;
    if (i < n) p[i] = 0.f;
}

__global__ void vox_k(const float* __restrict__ coords) {
    int p = blockIdx.x * blockDim.x + threadIdx.x;
    if (p >= NPTS) return;
    float x = coords[3*p+0], y = coords[3*p+1], z = coords[3*p+2];
    int vx = min(max((int)floorf(x), 0), GRES-1);
    int vy = min(max((int)floorf(y), 0), GRES-1);
    int vz = min(max((int)floorf(z), 0), GRES-1);
    int flat = (vx*GRES + vy)*GRES + vz;
    g_vidx[p] = flat;
    atomicAdd(&g_cnt[flat], 1.0f);
}

__global__ void inv_k() {
    int v = blockIdx.x * blockDim.x + threadIdx.x;
    if (v < G3) g_inv[v] = (g_cnt[v] > 0.f) ? (1.f / g_cnt[v]) : 0.f;
}

__global__ void trilin_k(const float* __restrict__ coords) {
    int p = blockIdx.x * blockDim.x + threadIdx.x;
    if (p >= NPTS) return;
    float cx = coords[3*p+0], cy = coords[3*p+1], cz = coords[3*p+2];
    float bx = floorf(cx), by = floorf(cy), bz = floorf(cz);
    float fx = cx - bx, fy = cy - by, fz = cz - bz;
    int ix = (int)bx, iy = (int)by, iz = (int)bz;
    #pragma unroll
    for (int j = 0; j < 8; j++) {
        int dx = (j >> 2) & 1, dy = (j >> 1) & 1, dz = j & 1;
        int nx = ix + dx, ny = iy + dy, nz = iz + dz;
        bool valid = (nx >= 0 && nx < GRES && ny >= 0 && ny < GRES && nz >= 0 && nz < GRES);
        int cxc = min(max(nx,0),GRES-1), cyc = min(max(ny,0),GRES-1), czc = min(max(nz,0),GRES-1);
        int flc = (cxc*GRES + cyc)*GRES + czc;
        float w = (dx ? fx : 1.f-fx) * (dy ? fy : 1.f-fy) * (dz ? fz : 1.f-fz);
        if (!valid || !(g_cnt[flc] > 0.f)) w = 0.f;
        g_nbi[j*NPTS + p] = flc;
        g_nbw[j*NPTS + p] = w;
    }
}

// feats (NPTS x cin) scattered into g_grid (G3 x cdst) at channel offset coff,
// optionally scaled per-point.
__global__ void scatter_k(const float* __restrict__ feats, const float* __restrict__ scale,
                          int cin, int cdst, int coff) {
    int i = blockIdx.x * blockDim.x + threadIdx.x;
    if (i >= NPTS * cin) return;
    int p = i / cin;
    int c = i - p * cin;
    float v = feats[i];
    if (scale) v *= scale[p];
    atomicAdd(&g_grid[(size_t)g_vidx[p] * cdst + coff + c], v);
}

__global__ void gscale_k(int cdim) {
    int i = blockIdx.x * blockDim.x + threadIdx.x;
    if (i >= G3 * cdim) return;
    g_grid[i] *= g_inv[i / cdim];
}

// ----------------------------- weight transposes ----------------------------
// conv w: (cout, cin, 27) -> wT[(k*cin+ci)*cout + co]
__global__ void tconv_k(const float* __restrict__ w, float* __restrict__ wT, int cin, int cout) {
    int i = blockIdx.x * blockDim.x + threadIdx.x;
    int total = cout * cin * 27;
    if (i >= total) return;
    int k  = i % 27;
    int r  = i / 27;
    int ci = r % cin;
    int co = r / cin;
    wT[(k*cin + ci)*cout + co] = w[i];
}

// lin w: (cout, cin) -> wT[ci*cout + co]
__global__ void tlin_k(const float* __restrict__ w, float* __restrict__ wT, int cin, int cout) {
    int i = blockIdx.x * blockDim.x + threadIdx.x;
    if (i >= cout * cin) return;
    int co = i / cin, ci = i - co * cin;
    wT[ci*cout + co] = w[i];
}

// ----------------------------- 3x3x3 conv over 32^3 grid --------------------
// Block = one (x,y) pencil (all 32 z, all 96 cout). 768 threads: co = tid%96,
// z-group = tid/96 (4 z each). Input chunk (32 ci) staged in smem with halo.
template<int CIN>
__global__ void __launch_bounds__(768) conv3d_k(const float* __restrict__ wT) {
    constexpr int CH = 32;     // ci chunk
    constexpr int ZD = 37;     // padded z stride (conflict-free)
    __shared__ float s[9 * CH * ZD];

    int pix = blockIdx.x;            // x*32 + y
    int px = pix >> 5, py = pix & 31;
    int tid = threadIdx.x;
    int co = tid % 96;
    int zg = tid / 96;               // 0..7
    int z0 = zg * 4;

    float acc0 = 0.f, acc1 = 0.f, acc2 = 0.f, acc3 = 0.f;

    for (int cc = 0; cc < CIN; cc += CH) {
        // zero smem (covers z halo / invalid-neighbor padding)
        for (int i = tid; i < 9 * CH * ZD; i += 768) s[i] = 0.f;
        __syncthreads();
        // load 9 neighbor pencils x 32 z x 32 ci
        for (int i = tid; i < 9 * 32 * CH; i += 768) {
            int ci = i & 31;
            int z  = (i >> 5) & 31;
            int nb = i >> 10;
            int nx = px + nb / 3 - 1;
            int ny = py + nb % 3 - 1;
            if ((unsigned)nx < GRES && (unsigned)ny < GRES) {
                s[(nb*CH + ci)*ZD + z + 1] =
                    g_grid[(size_t)(((nx<<5) + ny)*32 + z) * CIN + cc + ci];
            }
        }
        __syncthreads();

        for (int ci = 0; ci < CH; ci++) {
            int cig = cc + ci;
            #pragma unroll
            for (int nb = 0; nb < 9; nb++) {
                const float* sp = &s[(nb*CH + ci)*ZD + z0];
                float r0 = sp[0], r1 = sp[1], r2 = sp[2];
                float r3 = sp[3], r4 = sp[4], r5 = sp[5];
                float w0 = wT[((nb*3 + 0)*CIN + cig)*96 + co];
                float w1 = wT[((nb*3 + 1)*CIN + cig)*96 + co];
                float w2 = wT[((nb*3 + 2)*CIN + cig)*96 + co];
                acc0 += r0*w0 + r1*w1 + r2*w2;
                acc1 += r1*w0 + r2*w1 + r3*w2;
                acc2 += r2*w0 + r3*w1 + r4*w2;
                acc3 += r3*w0 + r4*w1 + r5*w2;
            }
        }
        __syncthreads();
    }

    size_t base = ((size_t)pix*32 + z0)*96 + co;
    g_conv[base      ] = acc0;
    g_conv[base +  96] = acc1;
    g_conv[base + 192] = acc2;
    g_conv[base + 288] = acc3;
}

// 3x3x3 conv, cout = 1 (v_conv). One thread per voxel.
__global__ void conv1_k() {
    int v = blockIdx.x * blockDim.x + threadIdx.x;
    if (v >= G3) return;
    int px = v >> 10, py = (v >> 5) & 31, pz = v & 31;
    float acc = 0.f;
    for (int kx = 0; kx < 3; kx++) {
        int nx = px + kx - 1;
        if ((unsigned)nx >= GRES) continue;
        for (int ky = 0; ky < 3; ky++) {
            int ny = py + ky - 1;
            if ((unsigned)ny >= GRES) continue;
            for (int kz = 0; kz < 3; kz++) {
                int nz = pz + kz - 1;
                if ((unsigned)nz >= GRES) continue;
                const float* ip = &g_grid[(size_t)(((nx<<5) + ny)*32 + nz) * CDIM];
                const float* wp = &g_vT[((kx*3 + ky)*3 + kz) * CDIM];
                float a = 0.f;
                #pragma unroll 8
                for (int ci = 0; ci < CDIM; ci++) a += ip[ci] * wp[ci];
                acc += a;
            }
        }
    }
    g_vout[v] = acc;
}

// ----------------------------- devox + linear (fused) -----------------------
// out[p,co] = sum_j nbw[j,p]*g_conv[nbi[j,p],co] + x1[p,:]@WT1[:,co]
//             (+ s2(p) * x2[p,:]@WT2[:,co]) + bias[co]; optional tanh.
__global__ void devoxlin_k(const float* __restrict__ x1, const float* __restrict__ WT1,
                           const float* __restrict__ x2, const float* __restrict__ WT2,
                           const float* __restrict__ scale2,
                           const float* __restrict__ bias,
                           float* __restrict__ out, int do_tanh) {
    int i = blockIdx.x * blockDim.x + threadIdx.x;
    if (i >= NPTS * CDIM) return;
    int p = i / CDIM;
    int co = i - p * CDIM;
    float acc = bias[co];
    #pragma unroll
    for (int j = 0; j < 8; j++) {
        float w = g_nbw[j*NPTS + p];
        if (w != 0.f) acc += w * g_conv[(size_t)g_nbi[j*NPTS + p]*CDIM + co];
    }
    const float* xr = x1 + (size_t)p * CDIM;
    #pragma unroll 8
    for (int ci = 0; ci < CDIM; ci++) acc += xr[ci] * WT1[ci*CDIM + co];
    if (x2) {
        const float* x2r = x2 + (size_t)p * CDIM;
        float a2 = 0.f;
        #pragma unroll 8
        for (int ci = 0; ci < CDIM; ci++) a2 += x2r[ci] * WT2[ci*CDIM + co];
        acc += (scale2 ? scale2[p] : 1.f) * a2;
    }
    if (do_tanh) acc = tanhf(acc);
    out[i] = acc;
}

// attn devox (cout=1): attn[p] = sum_j nbw*g_vout[nbi] + energy[p,:]@v_lw + v_lb
__global__ void attn_k(const float* __restrict__ energy,
                       const float* __restrict__ v_lw, const float* __restrict__ v_lb) {
    int p = blockIdx.x * blockDim.x + threadIdx.x;
    if (p >= NPTS) return;
    float acc = v_lb[0];
    #pragma unroll
    for (int j = 0; j < 8; j++) {
        float w = g_nbw[j*NPTS + p];
        if (w != 0.f) acc += w * g_vout[g_nbi[j*NPTS + p]];
    }
    const float* er = energy + (size_t)p * CDIM;
    #pragma unroll 8
    for (int ci = 0; ci < CDIM; ci++) acc += er[ci] * v_lw[ci];
    g_attn[p] = acc;
}

// ----------------------------- host orchestration ---------------------------
extern "C" void kernel_launch(void* const* d_in, const int* in_sizes, int n_in,
                              void* d_out, int out_size) {
    const float* hidden   = (const float*)d_in[0];
    const float* query    = (const float*)d_in[1];
    const float* coords   = (const float*)d_in[2];
    const float* wq_conv  = (const float*)d_in[3];
    const float* wq_lw    = (const float*)d_in[4];
    const float* wq_lb    = (const float*)d_in[5];
    const float* wh_conv  = (const float*)d_in[6];
    const float* wh_lw    = (const float*)d_in[7];
    const float* wh_lb    = (const float*)d_in[8];
    const float* att_conv = (const float*)d_in[9];
    const float* att_lw   = (const float*)d_in[10];
    const float* att_lb   = (const float*)d_in[11];
    const float* v_conv   = (const float*)d_in[12];
    const float* v_lw     = (const float*)d_in[13];
    const float* v_lb     = (const float*)d_in[14];
    const float* upd_conv = (const float*)d_in[15];
    const float* upd_lw   = (const float*)d_in[16];
    const float* upd_lb   = (const float*)d_in[17];
    float* out = (float*)d_out;

    float *pcnt, *pgrid, *pq, *ph, *pe, *pattn;
    float *pwqT, *pwhT, *pattT, *pupdT, *pvT;
    float *pwqlT, *pwhlT, *pattlT, *pupdlT;
    cudaGetSymbolAddress((void**)&pcnt,   g_cnt);
    cudaGetSymbolAddress((void**)&pgrid,  g_grid);
    cudaGetSymbolAddress((void**)&pq,     g_q);
    cudaGetSymbolAddress((void**)&ph,     g_h);
    cudaGetSymbolAddress((void**)&pe,     g_energy);
    cudaGetSymbolAddress((void**)&pattn,  g_attn);
    cudaGetSymbolAddress((void**)&pwqT,   g_wqT);
    cudaGetSymbolAddress((void**)&pwhT,   g_whT);
    cudaGetSymbolAddress((void**)&pattT,  g_attT);
    cudaGetSymbolAddress((void**)&pupdT,  g_updT);
    cudaGetSymbolAddress((void**)&pvT,    g_vT);
    cudaGetSymbolAddress((void**)&pwqlT,  g_wqlT);
    cudaGetSymbolAddress((void**)&pwhlT,  g_whlT);
    cudaGetSymbolAddress((void**)&pattlT, g_attlT);
    cudaGetSymbolAddress((void**)&pupdlT, g_updlT);

    const int TB = 256;
    auto gs = [](int n, int tb){ return (n + tb - 1) / tb; };

    // --- shared precompute ---
    zero_k<<<gs(G3,TB), TB>>>(pcnt, G3);
    vox_k<<<gs(NPTS,TB), TB>>>(coords);
    inv_k<<<gs(G3,TB), TB>>>();
    trilin_k<<<gs(NPTS,TB), TB>>>(coords);

    // --- weight transposes ---
    tconv_k<<<gs(96*96*27,TB), TB>>>(wq_conv,  pwqT, 96, 96);
    tconv_k<<<gs(96*96*27,TB), TB>>>(wh_conv,  pwhT, 96, 96);
    tconv_k<<<gs(96*192*27,TB),TB>>>(att_conv, pattT, 192, 96);
    tconv_k<<<gs(96*192*27,TB),TB>>>(upd_conv, pupdT, 192, 96);
    tconv_k<<<gs(96*27,TB),   TB>>>(v_conv,   pvT, 96, 1);
    tlin_k<<<gs(96*96,TB),  TB>>>(wq_lw,  pwqlT, 96, 96);
    tlin_k<<<gs(96*96,TB),  TB>>>(wh_lw,  pwhlT, 96, 96);
    tlin_k<<<gs(96*192,TB), TB>>>(att_lw, pattlT, 192, 96);
    tlin_k<<<gs(96*192,TB), TB>>>(upd_lw, pupdlT, 192, 96);

    // --- sconv q ---
    zero_k<<<gs(G3*96,TB), TB>>>(pgrid, G3*96);
    scatter_k<<<gs(NPTS*96,TB), TB>>>(query, nullptr, 96, 96, 0);
    gscale_k<<<gs(G3*96,TB), TB>>>(96);
    conv3d_k<96><<<1024, 768>>>(pwqT);
    devoxlin_k<<<gs(NPTS*96,TB), TB>>>(query, pwqlT, nullptr, nullptr, nullptr, wq_lb, pq, 0);

    // --- sconv h ---
    zero_k<<<gs(G3*96,TB), TB>>>(pgrid, G3*96);
    scatter_k<<<gs(NPTS*96,TB), TB>>>(hidden, nullptr, 96, 96, 0);
    gscale_k<<<gs(G3*96,TB), TB>>>(96);
    conv3d_k<96><<<1024, 768>>>(pwhT);
    devoxlin_k<<<gs(NPTS*96,TB), TB>>>(hidden, pwhlT, nullptr, nullptr, nullptr, wh_lb, ph, 0);

    // --- energy = tanh(sconv([h, q])) ---
    zero_k<<<gs(G3*192,TB), TB>>>(pgrid, G3*192);
    scatter_k<<<gs(NPTS*96,TB), TB>>>(ph, nullptr, 96, 192, 0);
    scatter_k<<<gs(NPTS*96,TB), TB>>>(pq, nullptr, 96, 192, 96);
    gscale_k<<<gs(G3*192,TB), TB>>>(192);
    conv3d_k<192><<<1024, 768>>>(pattT);
    devoxlin_k<<<gs(NPTS*96,TB), TB>>>(ph, pattlT, pq, pattlT + 96*96, nullptr, att_lb, pe, 1);

    // --- attn = sconv(energy) (cout = 1) ---
    zero_k<<<gs(G3*96,TB), TB>>>(pgrid, G3*96);
    scatter_k<<<gs(NPTS*96,TB), TB>>>(pe, nullptr, 96, 96, 0);
    gscale_k<<<gs(G3*96,TB), TB>>>(96);
    conv1_k<<<gs(G3,TB), TB>>>();
    attn_k<<<gs(NPTS,TB), TB>>>(pe, v_lw, v_lb);

    // --- out = tanh(sconv([q, attn*h])) ---
    zero_k<<<gs(G3*192,TB), TB>>>(pgrid, G3*192);
    scatter_k<<<gs(NPTS*96,TB), TB>>>(pq, nullptr, 96, 192, 0);
    scatter_k<<<gs(NPTS*96,TB), TB>>>(ph, pattn, 96, 192, 96);
    gscale_k<<<gs(G3*192,TB), TB>>>(192);
    conv3d_k<192><<<1024, 768>>>(pupdT);
    devoxlin_k<<<gs(NPTS*96,TB), TB>>>(pq, pupdlT, ph, pupdlT + 96*96, pattn, upd_lb, out, 1);
}

// round 3
// speedup vs baseline: 2.0328x; 2.0328x over previous
#include <cuda_runtime.h>
#include <cuda_bf16.h>
#include <cstdint>
#include <math.h>

#define NPTS 100000
#define CDIM 96
#define GRES 32
#define G3   (GRES*GRES*GRES)
#define PAD  34
#define PP2  (PAD*PAD)
#define PGV  (PP2*PAD)

// ======================= scratch (device globals) ===========================
__device__ int   g_vidx[NPTS];
__device__ float g_cnt[G3];
__device__ float g_inv[G3];
__device__ int   g_nbi[8*NPTS];
__device__ float g_nbw[8*NPTS];
__device__ float g_grid[G3*2*CDIM];
__device__ float g_conv[G3*CDIM];
__device__ float g_vout[G3];
__device__ float g_q[NPTS*CDIM];
__device__ float g_h[NPTS*CDIM];
__device__ float g_energy[NPTS*CDIM];
__device__ float g_attn[NPTS];
// padded bf16 split grid [pp][zz][ci] (ci stride = KPAD)
__device__ __nv_bfloat16 g_pA_hi[PGV*192];
__device__ __nv_bfloat16 g_pA_lo[PGV*192];
// pre-swizzled split conv weights: [tap*nch+chunk][split(2)][6144 = 96 rows x 64 ci]
__device__ __nv_bfloat16 g_wqB [27*2*2*6144];
__device__ __nv_bfloat16 g_whB [27*2*2*6144];
__device__ __nv_bfloat16 g_attB[27*3*2*6144];
__device__ __nv_bfloat16 g_updB[27*3*2*6144];
__device__ float g_vT  [27*CDIM];
__device__ float g_wqlT [CDIM*CDIM];
__device__ float g_whlT [CDIM*CDIM];
__device__ float g_attlT[2*CDIM*CDIM];
__device__ float g_updlT[2*CDIM*CDIM];

// ======================= mma/ldmatrix helpers ================================
__device__ __forceinline__ uint32_t smem_u32(const void* p) {
    uint32_t a;
    asm("{ .reg .u64 t; cvta.to.shared.u64 t, %1; cvt.u32.u64 %0, t; }" : "=r"(a) : "l"(p));
    return a;
}
__device__ __forceinline__ void ldsm4(uint32_t* r, uint32_t addr) {
    asm volatile("ldmatrix.sync.aligned.m8n8.x4.shared.b16 {%0,%1,%2,%3}, [%4];"
        : "=r"(r[0]), "=r"(r[1]), "=r"(r[2]), "=r"(r[3]) : "r"(addr));
}
__device__ __forceinline__ void mma16816(float* c, const uint32_t* a, const uint32_t* b) {
    asm volatile("mma.sync.aligned.m16n8k16.row.col.f32.bf16.bf16.f32 "
        "{%0,%1,%2,%3}, {%4,%5,%6,%7}, {%8,%9}, {%0,%1,%2,%3};"
        : "+f"(c[0]), "+f"(c[1]), "+f"(c[2]), "+f"(c[3])
        : "r"(a[0]), "r"(a[1]), "r"(a[2]), "r"(a[3]), "r"(b[0]), "r"(b[1]));
}

// ======================= small utility kernels ==============================
__global__ void zero_k(float* __restrict__ p, int n) {
    int i = blockIdx.x * blockDim.x + threadIdx.x;
    if (i < n) p[i] = 0.f;
}

__global__ void vox_k(const float* __restrict__ coords) {
    int p = blockIdx.x * blockDim.x + threadIdx.x;
    if (p >= NPTS) return;
    int vx = min(max((int)floorf(coords[3*p+0]), 0), GRES-1);
    int vy = min(max((int)floorf(coords[3*p+1]), 0), GRES-1);
    int vz = min(max((int)floorf(coords[3*p+2]), 0), GRES-1);
    int flat = (vx*GRES + vy)*GRES + vz;
    g_vidx[p] = flat;
    atomicAdd(&g_cnt[flat], 1.0f);
}

__global__ void inv_k() {
    int v = blockIdx.x * blockDim.x + threadIdx.x;
    if (v < G3) g_inv[v] = (g_cnt[v] > 0.f) ? (1.f / g_cnt[v]) : 0.f;
}

__global__ void trilin_k(const float* __restrict__ coords) {
    int p = blockIdx.x * blockDim.x + threadIdx.x;
    if (p >= NPTS) return;
    float cx = coords[3*p+0], cy = coords[3*p+1], cz = coords[3*p+2];
    float bx = floorf(cx), by = floorf(cy), bz = floorf(cz);
    float fx = cx - bx, fy = cy - by, fz = cz - bz;
    int ix = (int)bx, iy = (int)by, iz = (int)bz;
    #pragma unroll
    for (int j = 0; j < 8; j++) {
        int dx = (j >> 2) & 1, dy = (j >> 1) & 1, dz = j & 1;
        int nx = ix + dx, ny = iy + dy, nz = iz + dz;
        bool valid = (nx >= 0 && nx < GRES && ny >= 0 && ny < GRES && nz >= 0 && nz < GRES);
        int cxc = min(max(nx,0),GRES-1), cyc = min(max(ny,0),GRES-1), czc = min(max(nz,0),GRES-1);
        int flc = (cxc*GRES + cyc)*GRES + czc;
        float w = (dx ? fx : 1.f-fx) * (dy ? fy : 1.f-fy) * (dz ? fz : 1.f-fz);
        if (!valid || !(g_cnt[flc] > 0.f)) w = 0.f;
        g_nbi[j*NPTS + p] = flc;
        g_nbw[j*NPTS + p] = w;
    }
}

__global__ void scatter_k(const float* __restrict__ feats, const float* __restrict__ scale,
                          int cin, int cdst, int coff) {
    int i = blockIdx.x * blockDim.x + threadIdx.x;
    if (i >= NPTS * cin) return;
    int p = i / cin;
    int c = i - p * cin;
    float v = feats[i];
    if (scale) v *= scale[p];
    atomicAdd(&g_grid[(size_t)g_vidx[p] * cdst + coff + c], v);
}

// mean-scale + pad + bf16 split
template<int CIN, int KPAD>
__global__ void convert_pad_k() {
    int i = blockIdx.x * blockDim.x + threadIdx.x;
    if (i >= PGV * KPAD) return;
    int ci = i % KPAD;
    int pv = i / KPAD;
    int zz = pv % PAD;
    int pp = pv / PAD;
    int py = pp % PAD;
    int px = pp / PAD;
    float val = 0.f;
    if (px >= 1 && px <= GRES && py >= 1 && py <= GRES && zz >= 1 && zz <= GRES && ci < CIN) {
        int v = (((px-1) * GRES) + (py-1)) * GRES + (zz-1);
        val = g_grid[(size_t)v * CIN + ci] * g_inv[v];
    }
    __nv_bfloat16 hi = __float2bfloat16(val);
    __nv_bfloat16 lo = __float2bfloat16(val - __bfloat162float(hi));
    g_pA_hi[i] = hi;
    g_pA_lo[i] = lo;
}

// conv w (cout=96, cin=CIN, 27) -> split + pre-swizzled B tiles
// layout per (tap,chunk,split): row co in [0,96), k cw in [0,64):
//   elem = co*64 + ((cw>>3) ^ (co&7))*8 + (cw&7)
template<int CIN, int KPAD, int NCH>
__global__ void prep_wB_k(const float* __restrict__ w, __nv_bfloat16* __restrict__ dst) {
    int i = blockIdx.x * blockDim.x + threadIdx.x;
    if (i >= 27 * KPAD * 96) return;
    int co  = i % 96;
    int r   = i / 96;
    int ci  = r % KPAD;
    int tap = r / KPAD;
    float val = (ci < CIN) ? w[((size_t)co * CIN + ci) * 27 + tap] : 0.f;
    __nv_bfloat16 hi = __float2bfloat16(val);
    __nv_bfloat16 lo = __float2bfloat16(val - __bfloat162float(hi));
    int chunk = ci >> 6;
    int cw = ci & 63;
    uint32_t elem = (uint32_t)co * 64 + (uint32_t)(((cw >> 3) ^ (co & 7)) * 8) + (cw & 7);
    size_t base = (size_t)(tap * NCH + chunk) * 2 * 6144;
    dst[base + elem] = hi;
    dst[base + 6144 + elem] = lo;
}

__global__ void tconv_k(const float* __restrict__ w, float* __restrict__ wT, int cin, int cout) {
    int i = blockIdx.x * blockDim.x + threadIdx.x;
    int total = cout * cin * 27;
    if (i >= total) return;
    int k  = i % 27;
    int r  = i / 27;
    int ci = r % cin;
    int co = r / cin;
    wT[(k*cin + ci)*cout + co] = w[i];
}
__global__ void tlin_k(const float* __restrict__ w, float* __restrict__ wT, int cin, int cout) {
    int i = blockIdx.x * blockDim.x + threadIdx.x;
    if (i >= cout * cin) return;
    int co = i / cin, ci = i - co * cin;
    wT[ci*cout + co] = w[i];
}

// ======================= HMMA 3x3x3 conv =====================================
// Block: M=128 voxels (x fixed, 4 y-pencils, 32 z) x N=96 couts, 8 warps,
// warp tile 32x48. K: 27 taps x NCH 64-ci chunks; split-bf16 3-mma.
#define SM_AHI  0
#define SM_ALO  16384
#define SM_BHI  32768
#define SM_BLO  45056
#define SM_TOT  57344

template<int KPAD, int NCH>
__global__ void __launch_bounds__(256, 1) conv_mma_k(const __nv_bfloat16* __restrict__ wB) {
    extern __shared__ char smem[];
    uint32_t sb = smem_u32(smem);
    int tid = threadIdx.x;
    int warp = tid >> 5, lane = tid & 31;
    int m_off = (warp & 3) * 32;
    int n_off = (warp >> 2) * 48;

    int x  = blockIdx.x >> 3;
    int y0 = (blockIdx.x & 7) * 4;

    float acc[2][6][4];
    #pragma unroll
    for (int mi = 0; mi < 2; mi++)
        #pragma unroll
        for (int nj = 0; nj < 6; nj++)
            #pragma unroll
            for (int e = 0; e < 4; e++) acc[mi][nj][e] = 0.f;

    // ldmatrix base offsets (per thread, byte offsets within a 128B-row tile)
    // A: row = m_off + mi*16 + (lane&7) + ((lane>>3)&1)*8 ; khalf = lane>>4
    int a_row_in = (lane & 7) + ((lane >> 3) & 1) * 8;   // 0..15 within m16
    int a_khalf  = lane >> 4;                            // 0/1
    // B: tq = lane>>3 ; row = n16 + (lane&7) + (tq>>1)*8 ; khalf = tq&1
    int b_row_in = (lane & 7) + ((lane >> 3) >> 1) * 8;  // 0..15 within n16
    int b_khalf  = (lane >> 3) & 1;

    for (int tap = 0; tap < 27; tap++) {
        int dx = tap / 9, dy = (tap / 3) % 3, dz = tap % 3;
        int ppb = (x + dx) * PAD + (y0 + dy);
        for (int ch = 0; ch < NCH; ch++) {
            __syncthreads();
            // ---- stage A (hi+lo): swizzled 16B copies ----
            #pragma unroll
            for (int t = tid; t < 2048; t += 256) {
                int split = t >> 10;
                int e = t & 1023;
                int r = e >> 3, c8 = e & 7;
                int j = r >> 5, z = r & 31;
                size_t src = ((size_t)((ppb + j) * PAD + (z + dz)) * KPAD) + ch * 64 + c8 * 8;
                uint4 v = *(const uint4*)((split ? g_pA_lo : g_pA_hi) + src);
                uint32_t off = (uint32_t)r * 128 + (uint32_t)((c8 ^ (r & 7)) * 16);
                *(uint4*)(smem + (split ? SM_ALO : SM_AHI) + off) = v;
            }
            // ---- stage B (hi+lo): straight copy (pre-swizzled) ----
            const __nv_bfloat16* bs = wB + (size_t)(tap * NCH + ch) * 2 * 6144;
            #pragma unroll
            for (int t = tid; t < 1536; t += 256) {
                uint4 v = *(const uint4*)(bs + t * 8);
                *(uint4*)(smem + SM_BHI + t * 16) = v;
            }
            __syncthreads();

            // ---- compute: 4 k16 steps ----
            #pragma unroll
            for (int kk = 0; kk < 4; kk++) {
                uint32_t ah[2][4], al[2][4], bh[3][4], bl[3][4];
                #pragma unroll
                for (int mi = 0; mi < 2; mi++) {
                    int row = m_off + mi * 16 + a_row_in;
                    int kc = kk * 2 + a_khalf;
                    uint32_t off = (uint32_t)row * 128 + (uint32_t)((kc ^ (row & 7)) * 16);
                    ldsm4(ah[mi], sb + SM_AHI + off);
                    ldsm4(al[mi], sb + SM_ALO + off);
                }
                #pragma unroll
                for (int ni = 0; ni < 3; ni++) {
                    int row = n_off + ni * 16 + b_row_in;
                    int kc = kk * 2 + b_khalf;
                    uint32_t off = (uint32_t)row * 128 + (uint32_t)((kc ^ (row & 7)) * 16);
                    ldsm4(bh[ni], sb + SM_BHI + off);
                    ldsm4(bl[ni], sb + SM_BLO + off);
                }
                #pragma unroll
                for (int mi = 0; mi < 2; mi++) {
                    #pragma unroll
                    for (int nj = 0; nj < 6; nj++) {
                        const uint32_t* bfh = &bh[nj >> 1][(nj & 1) * 2];
                        const uint32_t* bfl = &bl[nj >> 1][(nj & 1) * 2];
                        mma16816(acc[mi][nj], ah[mi], bfh);
                        mma16816(acc[mi][nj], ah[mi], bfl);
                        mma16816(acc[mi][nj], al[mi], bfh);
                    }
                }
            }
        }
    }

    // ---- epilogue ----
    #pragma unroll
    for (int mi = 0; mi < 2; mi++) {
        #pragma unroll
        for (int half = 0; half < 2; half++) {
            int r = m_off + mi * 16 + (lane >> 2) + half * 8;
            int j = r >> 5, z = r & 31;
            size_t vbase = ((size_t)(x * GRES + y0 + j) * GRES + z) * 96;
            #pragma unroll
            for (int nj = 0; nj < 6; nj++) {
                int co = n_off + nj * 8 + 2 * (lane & 3);
                float2 v = make_float2(acc[mi][nj][half * 2], acc[mi][nj][half * 2 + 1]);
                *(float2*)(&g_conv[vbase + co]) = v;
            }
        }
    }
}

// ======================= cout=1 conv (v_conv) ===============================
__global__ void conv1_k() {
    int v = blockIdx.x * blockDim.x + threadIdx.x;
    if (v >= G3) return;
    int px = v >> 10, py = (v >> 5) & 31, pz = v & 31;
    float acc = 0.f;
    for (int kx = 0; kx < 3; kx++) {
        int nx = px + kx - 1;
        if ((unsigned)nx >= GRES) continue;
        for (int ky = 0; ky < 3; ky++) {
            int ny = py + ky - 1;
            if ((unsigned)ny >= GRES) continue;
            for (int kz = 0; kz < 3; kz++) {
                int nz = pz + kz - 1;
                if ((unsigned)nz >= GRES) continue;
                int nf = ((nx<<5) + ny)*32 + nz;
                const float* ip = &g_grid[(size_t)nf * CDIM];
                const float* wp = &g_vT[((kx*3 + ky)*3 + kz) * CDIM];
                float a = 0.f;
                #pragma unroll 8
                for (int ci = 0; ci < CDIM; ci++) a += ip[ci] * wp[ci];
                acc += a * g_inv[nf];
            }
        }
    }
    g_vout[v] = acc;
}

// ======================= devox + linear (fused) =============================
__global__ void devoxlin_k(const float* __restrict__ x1, const float* __restrict__ WT1,
                           const float* __restrict__ x2, const float* __restrict__ WT2,
                           const float* __restrict__ scale2,
                           const float* __restrict__ bias,
                           float* __restrict__ out, int do_tanh) {
    int i = blockIdx.x * blockDim.x + threadIdx.x;
    if (i >= NPTS * CDIM) return;
    int p = i / CDIM;
    int co = i - p * CDIM;
    float acc = bias[co];
    #pragma unroll
    for (int j = 0; j < 8; j++) {
        float w = g_nbw[j*NPTS + p];
        if (w != 0.f) acc += w * g_conv[(size_t)g_nbi[j*NPTS + p]*CDIM + co];
    }
    const float* xr = x1 + (size_t)p * CDIM;
    #pragma unroll 8
    for (int ci = 0; ci < CDIM; ci++) acc += xr[ci] * WT1[ci*CDIM + co];
    if (x2) {
        const float* x2r = x2 + (size_t)p * CDIM;
        float a2 = 0.f;
        #pragma unroll 8
        for (int ci = 0; ci < CDIM; ci++) a2 += x2r[ci] * WT2[ci*CDIM + co];
        acc += (scale2 ? scale2[p] : 1.f) * a2;
    }
    if (do_tanh) acc = tanhf(acc);
    out[i] = acc;
}

__global__ void attn_k(const float* __restrict__ energy,
                       const float* __restrict__ v_lw, const float* __restrict__ v_lb) {
    int p = blockIdx.x * blockDim.x + threadIdx.x;
    if (p >= NPTS) return;
    float acc = v_lb[0];
    #pragma unroll
    for (int j = 0; j < 8; j++) {
        float w = g_nbw[j*NPTS + p];
        if (w != 0.f) acc += w * g_vout[g_nbi[j*NPTS + p]];
    }
    const float* er = energy + (size_t)p * CDIM;
    #pragma unroll 8
    for (int ci = 0; ci < CDIM; ci++) acc += er[ci] * v_lw[ci];
    g_attn[p] = acc;
}

// ======================= host orchestration =================================
extern "C" void kernel_launch(void* const* d_in, const int* in_sizes, int n_in,
                              void* d_out, int out_size) {
    const float* hidden   = (const float*)d_in[0];
    const float* query    = (const float*)d_in[1];
    const float* coords   = (const float*)d_in[2];
    const float* wq_conv  = (const float*)d_in[3];
    const float* wq_lw    = (const float*)d_in[4];
    const float* wq_lb    = (const float*)d_in[5];
    const float* wh_conv  = (const float*)d_in[6];
    const float* wh_lw    = (const float*)d_in[7];
    const float* wh_lb    = (const float*)d_in[8];
    const float* att_conv = (const float*)d_in[9];
    const float* att_lw   = (const float*)d_in[10];
    const float* att_lb   = (const float*)d_in[11];
    const float* v_conv   = (const float*)d_in[12];
    const float* v_lw     = (const float*)d_in[13];
    const float* v_lb     = (const float*)d_in[14];
    const float* upd_conv = (const float*)d_in[15];
    const float* upd_lw   = (const float*)d_in[16];
    const float* upd_lb   = (const float*)d_in[17];
    float* out = (float*)d_out;

    float *pcnt, *pgrid, *pq, *ph, *pe, *pattn, *pvT;
    float *pwqlT, *pwhlT, *pattlT, *pupdlT;
    __nv_bfloat16 *pwqB, *pwhB, *pattB, *pupdB;
    cudaGetSymbolAddress((void**)&pcnt,   g_cnt);
    cudaGetSymbolAddress((void**)&pgrid,  g_grid);
    cudaGetSymbolAddress((void**)&pq,     g_q);
    cudaGetSymbolAddress((void**)&ph,     g_h);
    cudaGetSymbolAddress((void**)&pe,     g_energy);
    cudaGetSymbolAddress((void**)&pattn,  g_attn);
    cudaGetSymbolAddress((void**)&pvT,    g_vT);
    cudaGetSymbolAddress((void**)&pwqlT,  g_wqlT);
    cudaGetSymbolAddress((void**)&pwhlT,  g_whlT);
    cudaGetSymbolAddress((void**)&pattlT, g_attlT);
    cudaGetSymbolAddress((void**)&pupdlT, g_updlT);
    cudaGetSymbolAddress((void**)&pwqB,  g_wqB);
    cudaGetSymbolAddress((void**)&pwhB,  g_whB);
    cudaGetSymbolAddress((void**)&pattB, g_attB);
    cudaGetSymbolAddress((void**)&pupdB, g_updB);

    cudaFuncSetAttribute(conv_mma_k<128,2>, cudaFuncAttributeMaxDynamicSharedMemorySize, SM_TOT);
    cudaFuncSetAttribute(conv_mma_k<192,3>, cudaFuncAttributeMaxDynamicSharedMemorySize, SM_TOT);

    const int TB = 256;
    auto gs = [](long long n, int tb){ return (int)((n + tb - 1) / tb); };

    // --- shared precompute ---
    zero_k<<<gs(G3,TB), TB>>>(pcnt, G3);
    vox_k<<<gs(NPTS,TB), TB>>>(coords);
    inv_k<<<gs(G3,TB), TB>>>();
    trilin_k<<<gs(NPTS,TB), TB>>>(coords);

    // --- weight prep ---
    prep_wB_k<96,128,2><<<gs(27LL*128*96,TB), TB>>>(wq_conv, pwqB);
    prep_wB_k<96,128,2><<<gs(27LL*128*96,TB), TB>>>(wh_conv, pwhB);
    prep_wB_k<192,192,3><<<gs(27LL*192*96,TB), TB>>>(att_conv, pattB);
    prep_wB_k<192,192,3><<<gs(27LL*192*96,TB), TB>>>(upd_conv, pupdB);
    tconv_k<<<gs(96*27,TB), TB>>>(v_conv, pvT, 96, 1);
    tlin_k<<<gs(96*96,TB),  TB>>>(wq_lw,  pwqlT, 96, 96);
    tlin_k<<<gs(96*96,TB),  TB>>>(wh_lw,  pwhlT, 96, 96);
    tlin_k<<<gs(96*192,TB), TB>>>(att_lw, pattlT, 192, 96);
    tlin_k<<<gs(96*192,TB), TB>>>(upd_lw, pupdlT, 192, 96);

    // --- sconv q ---
    zero_k<<<gs(G3*96,TB), TB>>>(pgrid, G3*96);
    scatter_k<<<gs((long long)NPTS*96,TB), TB>>>(query, nullptr, 96, 96, 0);
    convert_pad_k<96,128><<<gs((long long)PGV*128,TB), TB>>>();
    conv_mma_k<128,2><<<256, 256, SM_TOT>>>(pwqB);
    devoxlin_k<<<gs((long long)NPTS*96,TB), TB>>>(query, pwqlT, nullptr, nullptr, nullptr, wq_lb, pq, 0);

    // --- sconv h ---
    zero_k<<<gs(G3*96,TB), TB>>>(pgrid, G3*96);
    scatter_k<<<gs((long long)NPTS*96,TB), TB>>>(hidden, nullptr, 96, 96, 0);
    convert_pad_k<96,128><<<gs((long long)PGV*128,TB), TB>>>();
    conv_mma_k<128,2><<<256, 256, SM_TOT>>>(pwhB);
    devoxlin_k<<<gs((long long)NPTS*96,TB), TB>>>(hidden, pwhlT, nullptr, nullptr, nullptr, wh_lb, ph, 0);

    // --- energy = tanh(sconv([h, q])) ---
    zero_k<<<gs(G3*192,TB), TB>>>(pgrid, G3*192);
    scatter_k<<<gs((long long)NPTS*96,TB), TB>>>(ph, nullptr, 96, 192, 0);
    scatter_k<<<gs((long long)NPTS*96,TB), TB>>>(pq, nullptr, 96, 192, 96);
    convert_pad_k<192,192><<<gs((long long)PGV*192,TB), TB>>>();
    conv_mma_k<192,3><<<256, 256, SM_TOT>>>(pattB);
    devoxlin_k<<<gs((long long)NPTS*96,TB), TB>>>(ph, pattlT, pq, pattlT + 96*96, nullptr, att_lb, pe, 1);

    // --- attn = sconv(energy), cout=1 ---
    zero_k<<<gs(G3*96,TB), TB>>>(pgrid, G3*96);
    scatter_k<<<gs((long long)NPTS*96,TB), TB>>>(pe, nullptr, 96, 96, 0);
    conv1_k<<<gs(G3,TB), TB>>>();
    attn_k<<<gs(NPTS,TB), TB>>>(pe, v_lw, v_lb);

    // --- out = tanh(sconv([q, attn*h])) ---
    zero_k<<<gs(G3*192,TB), TB>>>(pgrid, G3*192);
    scatter_k<<<gs((long long)NPTS*96,TB), TB>>>(pq, nullptr, 96, 192, 0);
    scatter_k<<<gs((long long)NPTS*96,TB), TB>>>(ph, pattn, 96, 192, 96);
    convert_pad_k<192,192><<<gs((long long)PGV*192,TB), TB>>>();
    conv_mma_k<192,3><<<256, 256, SM_TOT>>>(pupdB);
    devoxlin_k<<<gs((long long)NPTS*96,TB), TB>>>(pq, pupdlT, ph, pupdlT + 96*96, pattn, upd_lb, out, 1);
}

// round 4
// speedup vs baseline: 2.2961x; 1.1295x over previous
#include <cuda_runtime.h>
#include <cuda_bf16.h>
#include <cstdint>
#include <math.h>

#define NPTS 100000
#define CDIM 96
#define GRES 32
#define G3   (GRES*GRES*GRES)
#define PAD  34
#define PP2  (PAD*PAD)
#define PGV  (PP2*PAD)

// ======================= scratch (device globals) ===========================
__device__ int   g_vidx[NPTS];
__device__ float g_cnt[G3];
__device__ float g_inv[G3];
__device__ int   g_nbi[8*NPTS];
__device__ float g_nbw[8*NPTS];
__device__ float g_grid[G3*2*CDIM];
__device__ float g_conv[G3*CDIM];
__device__ float g_vout[G3];
__device__ float g_q[NPTS*CDIM];
__device__ float g_h[NPTS*CDIM];
__device__ float g_energy[NPTS*CDIM];
__device__ float g_attn[NPTS];
// padded bf16 split grid [px][py][zz][ci] (ci stride = KPAD)
__device__ __nv_bfloat16 g_pA_hi[PGV*192];
__device__ __nv_bfloat16 g_pA_lo[PGV*192];
// pre-swizzled split conv weights: [tap*nch+chunk][split(2)][6144 = 96 rows x 64 ci]
__device__ __nv_bfloat16 g_wqB [27*2*2*6144];
__device__ __nv_bfloat16 g_whB [27*2*2*6144];
__device__ __nv_bfloat16 g_attB[27*3*2*6144];
__device__ __nv_bfloat16 g_updB[27*3*2*6144];
__device__ float g_vT  [27*CDIM];
__device__ float g_wqlT [CDIM*CDIM];
__device__ float g_whlT [CDIM*CDIM];
__device__ float g_attlT[2*CDIM*CDIM];
__device__ float g_updlT[2*CDIM*CDIM];

// ======================= mma/ldmatrix/cp.async helpers =======================
__device__ __forceinline__ uint32_t smem_u32(const void* p) {
    uint32_t a;
    asm("{ .reg .u64 t; cvta.to.shared.u64 t, %1; cvt.u32.u64 %0, t; }" : "=r"(a) : "l"(p));
    return a;
}
__device__ __forceinline__ void ldsm4(uint32_t* r, uint32_t addr) {
    asm volatile("ldmatrix.sync.aligned.m8n8.x4.shared.b16 {%0,%1,%2,%3}, [%4];"
        : "=r"(r[0]), "=r"(r[1]), "=r"(r[2]), "=r"(r[3]) : "r"(addr));
}
__device__ __forceinline__ void mma16816(float* c, const uint32_t* a, const uint32_t* b) {
    asm volatile("mma.sync.aligned.m16n8k16.row.col.f32.bf16.bf16.f32 "
        "{%0,%1,%2,%3}, {%4,%5,%6,%7}, {%8,%9}, {%0,%1,%2,%3};"
        : "+f"(c[0]), "+f"(c[1]), "+f"(c[2]), "+f"(c[3])
        : "r"(a[0]), "r"(a[1]), "r"(a[2]), "r"(a[3]), "r"(b[0]), "r"(b[1]));
}
__device__ __forceinline__ void cpa16(uint32_t dst, const void* src) {
    asm volatile("cp.async.cg.shared.global [%0], [%1], 16;" :: "r"(dst), "l"(src));
}
__device__ __forceinline__ void cpa_commit() { asm volatile("cp.async.commit_group;"); }
__device__ __forceinline__ void cpa_wait0()  { asm volatile("cp.async.wait_group 0;"); }

// ======================= small utility kernels ==============================
__global__ void zero_k(float* __restrict__ p, int n) {
    int i = blockIdx.x * blockDim.x + threadIdx.x;
    if (i < n) p[i] = 0.f;
}

__global__ void vox_k(const float* __restrict__ coords) {
    int p = blockIdx.x * blockDim.x + threadIdx.x;
    if (p >= NPTS) return;
    int vx = min(max((int)floorf(coords[3*p+0]), 0), GRES-1);
    int vy = min(max((int)floorf(coords[3*p+1]), 0), GRES-1);
    int vz = min(max((int)floorf(coords[3*p+2]), 0), GRES-1);
    int flat = (vx*GRES + vy)*GRES + vz;
    g_vidx[p] = flat;
    atomicAdd(&g_cnt[flat], 1.0f);
}

__global__ void inv_k() {
    int v = blockIdx.x * blockDim.x + threadIdx.x;
    if (v < G3) g_inv[v] = (g_cnt[v] > 0.f) ? (1.f / g_cnt[v]) : 0.f;
}

__global__ void trilin_k(const float* __restrict__ coords) {
    int p = blockIdx.x * blockDim.x + threadIdx.x;
    if (p >= NPTS) return;
    float cx = coords[3*p+0], cy = coords[3*p+1], cz = coords[3*p+2];
    float bx = floorf(cx), by = floorf(cy), bz = floorf(cz);
    float fx = cx - bx, fy = cy - by, fz = cz - bz;
    int ix = (int)bx, iy = (int)by, iz = (int)bz;
    #pragma unroll
    for (int j = 0; j < 8; j++) {
        int dx = (j >> 2) & 1, dy = (j >> 1) & 1, dz = j & 1;
        int nx = ix + dx, ny = iy + dy, nz = iz + dz;
        bool valid = (nx >= 0 && nx < GRES && ny >= 0 && ny < GRES && nz >= 0 && nz < GRES);
        int cxc = min(max(nx,0),GRES-1), cyc = min(max(ny,0),GRES-1), czc = min(max(nz,0),GRES-1);
        int flc = (cxc*GRES + cyc)*GRES + czc;
        float w = (dx ? fx : 1.f-fx) * (dy ? fy : 1.f-fy) * (dz ? fz : 1.f-fz);
        if (!valid || !(g_cnt[flc] > 0.f)) w = 0.f;
        g_nbi[j*NPTS + p] = flc;
        g_nbw[j*NPTS + p] = w;
    }
}

__global__ void scatter_k(const float* __restrict__ feats, const float* __restrict__ scale,
                          int cin, int cdst, int coff) {
    int i = blockIdx.x * blockDim.x + threadIdx.x;
    if (i >= NPTS * cin) return;
    int p = i / cin;
    int c = i - p * cin;
    float v = feats[i];
    if (scale) v *= scale[p];
    atomicAdd(&g_grid[(size_t)g_vidx[p] * cdst + coff + c], v);
}

// mean-scale + pad + bf16 split
template<int CIN, int KPAD>
__global__ void convert_pad_k() {
    int i = blockIdx.x * blockDim.x + threadIdx.x;
    if (i >= PGV * KPAD) return;
    int ci = i % KPAD;
    int pv = i / KPAD;
    int zz = pv % PAD;
    int pp = pv / PAD;
    int py = pp % PAD;
    int px = pp / PAD;
    float val = 0.f;
    if (px >= 1 && px <= GRES && py >= 1 && py <= GRES && zz >= 1 && zz <= GRES && ci < CIN) {
        int v = (((px-1) * GRES) + (py-1)) * GRES + (zz-1);
        val = g_grid[(size_t)v * CIN + ci] * g_inv[v];
    }
    __nv_bfloat16 hi = __float2bfloat16(val);
    __nv_bfloat16 lo = __float2bfloat16(val - __bfloat162float(hi));
    g_pA_hi[i] = hi;
    g_pA_lo[i] = lo;
}

// conv w (cout=96, cin=CIN, 27) -> split + pre-swizzled B tiles
template<int CIN, int KPAD, int NCH>
__global__ void prep_wB_k(const float* __restrict__ w, __nv_bfloat16* __restrict__ dst) {
    int i = blockIdx.x * blockDim.x + threadIdx.x;
    if (i >= 27 * KPAD * 96) return;
    int co  = i % 96;
    int r   = i / 96;
    int ci  = r % KPAD;
    int tap = r / KPAD;
    float val = (ci < CIN) ? w[((size_t)co * CIN + ci) * 27 + tap] : 0.f;
    __nv_bfloat16 hi = __float2bfloat16(val);
    __nv_bfloat16 lo = __float2bfloat16(val - __bfloat162float(hi));
    int chunk = ci >> 6;
    int cw = ci & 63;
    uint32_t elem = (uint32_t)co * 64 + (uint32_t)(((cw >> 3) ^ (co & 7)) * 8) + (cw & 7);
    size_t base = (size_t)(tap * NCH + chunk) * 2 * 6144;
    dst[base + elem] = hi;
    dst[base + 6144 + elem] = lo;
}

__global__ void tconv_k(const float* __restrict__ w, float* __restrict__ wT, int cin, int cout) {
    int i = blockIdx.x * blockDim.x + threadIdx.x;
    int total = cout * cin * 27;
    if (i >= total) return;
    int k  = i % 27;
    int r  = i / 27;
    int ci = r % cin;
    int co = r / cin;
    wT[(k*cin + ci)*cout + co] = w[i];
}
__global__ void tlin_k(const float* __restrict__ w, float* __restrict__ wT, int cin, int cout) {
    int i = blockIdx.x * blockDim.x + threadIdx.x;
    if (i >= cout * cin) return;
    int co = i / cin, ci = i - co * cin;
    wT[ci*cout + co] = w[i];
}

// ======================= HMMA 3x3x3 conv (slab-resident A) ==================
// Block: M=128 voxels (x fixed, 4 y-pencils, 32 z) x N=96, 8 warps (32x48 tiles).
// For each (chunk, dx): stage A slab [6y][34z][64ci] hi+lo once (52KB); then
// loop 9 (dy,dz) taps, B tile (24KB) cp.async double-buffered; tap = row shift.
#define A_SPLIT 26112            // 204 rows * 128B
#define SM_B0   52224
#define SM_B1   76800
#define SM_TOT  101376

template<int KPAD, int NCH>
__global__ void __launch_bounds__(256, 2) conv_mma_k(const __nv_bfloat16* __restrict__ wB) {
    extern __shared__ char smem[];
    uint32_t sb = smem_u32(smem);
    int tid = threadIdx.x;
    int warp = tid >> 5, lane = tid & 31;
    int m_off = (warp & 3) * 32;
    int n_off = (warp >> 2) * 48;

    int x  = blockIdx.x >> 3;
    int y0 = (blockIdx.x & 7) * 4;

    float acc[2][6][4];
    #pragma unroll
    for (int mi = 0; mi < 2; mi++)
        #pragma unroll
        for (int nj = 0; nj < 6; nj++)
            #pragma unroll
            for (int e = 0; e < 4; e++) acc[mi][nj][e] = 0.f;

    int a_row_in = (lane & 7) + ((lane >> 3) & 1) * 8;
    int a_khalf  = lane >> 4;
    int b_row_in = (lane & 7) + ((lane >> 3) >> 1) * 8;
    int b_khalf  = (lane >> 3) & 1;

    // slab row bases: m -> (j)*34 + z  (j = y index, z)
    int rb[2];
    #pragma unroll
    for (int mi = 0; mi < 2; mi++) {
        int m = m_off + mi * 16 + a_row_in;
        rb[mi] = (m >> 5) * 34 + (m & 31);
    }
    int brow[3];
    #pragma unroll
    for (int ni = 0; ni < 3; ni++) brow[ni] = n_off + ni * 16 + b_row_in;

    for (int cc = 0; cc < NCH; cc++) {
        for (int dx = 0; dx < 3; dx++) {
            __syncthreads();   // prior tap computes done: A slab + B buffers reusable

            // prefetch B[tap0] -> buf0
            {
                const __nv_bfloat16* bs = wB + (size_t)((dx * 9) * NCH + cc) * 12288;
                #pragma unroll
                for (int t = tid; t < 1536; t += 256)
                    cpa16(sb + SM_B0 + t * 16, bs + t * 8);
                cpa_commit();
            }
            // stage A slab: 204 rows (6y x 34z) x 8 c8-units x 2 splits
            {
                size_t pvbase = ((size_t)(x + dx) * PAD + y0) * PAD;
                #pragma unroll
                for (int t = tid; t < 3264; t += 256) {
                    int split = (t >= 1632);
                    int e = split ? t - 1632 : t;
                    int r = e >> 3, c8 = e & 7;
                    const __nv_bfloat16* src =
                        (split ? g_pA_lo : g_pA_hi) + (pvbase + r) * KPAD + cc * 64 + c8 * 8;
                    uint4 v = *(const uint4*)src;
                    *(uint4*)(smem + split * A_SPLIT + r * 128 + ((c8 ^ (r & 7)) << 4)) = v;
                }
            }

            for (int t9 = 0; t9 < 9; t9++) {
                cpa_wait0();
                __syncthreads();   // B[t9] + A slab visible; prev compute done
                if (t9 < 8) {      // prefetch B[t9+1] into the other buffer
                    const __nv_bfloat16* bs =
                        wB + (size_t)((dx * 9 + t9 + 1) * NCH + cc) * 12288;
                    uint32_t dst = sb + ((t9 & 1) ? SM_B0 : SM_B1);
                    #pragma unroll
                    for (int t = tid; t < 1536; t += 256)
                        cpa16(dst + t * 16, bs + t * 8);
                    cpa_commit();
                }
                uint32_t bbase = sb + ((t9 & 1) ? SM_B1 : SM_B0);
                int toff = (t9 / 3) * PAD + (t9 % 3);   // dy*34 + dz

                #pragma unroll
                for (int kk = 0; kk < 4; kk++) {
                    uint32_t ah[2][4], al[2][4], bh[3][4], bl[3][4];
                    #pragma unroll
                    for (int mi = 0; mi < 2; mi++) {
                        int r = rb[mi] + toff;
                        int kc = kk * 2 + a_khalf;
                        uint32_t off = (uint32_t)r * 128 + (uint32_t)((kc ^ (r & 7)) << 4);
                        ldsm4(ah[mi], sb + off);
                        ldsm4(al[mi], sb + A_SPLIT + off);
                    }
                    #pragma unroll
                    for (int ni = 0; ni < 3; ni++) {
                        int r = brow[ni];
                        int kc = kk * 2 + b_khalf;
                        uint32_t off = (uint32_t)r * 128 + (uint32_t)((kc ^ (r & 7)) << 4);
                        ldsm4(bh[ni], bbase + off);
                        ldsm4(bl[ni], bbase + 12288 + off);
                    }
                    #pragma unroll
                    for (int mi = 0; mi < 2; mi++) {
                        #pragma unroll
                        for (int nj = 0; nj < 6; nj++) {
                            const uint32_t* bfh = &bh[nj >> 1][(nj & 1) * 2];
                            const uint32_t* bfl = &bl[nj >> 1][(nj & 1) * 2];
                            mma16816(acc[mi][nj], ah[mi], bfh);
                            mma16816(acc[mi][nj], ah[mi], bfl);
                            mma16816(acc[mi][nj], al[mi], bfh);
                        }
                    }
                }
            }
        }
    }

    // ---- epilogue ----
    #pragma unroll
    for (int mi = 0; mi < 2; mi++) {
        #pragma unroll
        for (int half = 0; half < 2; half++) {
            int r = m_off + mi * 16 + (lane >> 2) + half * 8;
            int j = r >> 5, z = r & 31;
            size_t vbase = ((size_t)(x * GRES + y0 + j) * GRES + z) * 96;
            #pragma unroll
            for (int nj = 0; nj < 6; nj++) {
                int co = n_off + nj * 8 + 2 * (lane & 3);
                float2 v = make_float2(acc[mi][nj][half * 2], acc[mi][nj][half * 2 + 1]);
                *(float2*)(&g_conv[vbase + co]) = v;
            }
        }
    }
}

// ======================= cout=1 conv (v_conv) ===============================
__global__ void conv1_k() {
    int v = blockIdx.x * blockDim.x + threadIdx.x;
    if (v >= G3) return;
    int px = v >> 10, py = (v >> 5) & 31, pz = v & 31;
    float acc = 0.f;
    for (int kx = 0; kx < 3; kx++) {
        int nx = px + kx - 1;
        if ((unsigned)nx >= GRES) continue;
        for (int ky = 0; ky < 3; ky++) {
            int ny = py + ky - 1;
            if ((unsigned)ny >= GRES) continue;
            for (int kz = 0; kz < 3; kz++) {
                int nz = pz + kz - 1;
                if ((unsigned)nz >= GRES) continue;
                int nf = ((nx<<5) + ny)*32 + nz;
                const float* ip = &g_grid[(size_t)nf * CDIM];
                const float* wp = &g_vT[((kx*3 + ky)*3 + kz) * CDIM];
                float a = 0.f;
                #pragma unroll 8
                for (int ci = 0; ci < CDIM; ci++) a += ip[ci] * wp[ci];
                acc += a * g_inv[nf];
            }
        }
    }
    g_vout[v] = acc;
}

// ======================= devox + linear (fused) =============================
__global__ void devoxlin_k(const float* __restrict__ x1, const float* __restrict__ WT1,
                           const float* __restrict__ x2, const float* __restrict__ WT2,
                           const float* __restrict__ scale2,
                           const float* __restrict__ bias,
                           float* __restrict__ out, int do_tanh) {
    int i = blockIdx.x * blockDim.x + threadIdx.x;
    if (i >= NPTS * CDIM) return;
    int p = i / CDIM;
    int co = i - p * CDIM;
    float acc = bias[co];
    #pragma unroll
    for (int j = 0; j < 8; j++) {
        float w = g_nbw[j*NPTS + p];
        if (w != 0.f) acc += w * g_conv[(size_t)g_nbi[j*NPTS + p]*CDIM + co];
    }
    const float* xr = x1 + (size_t)p * CDIM;
    #pragma unroll 8
    for (int ci = 0; ci < CDIM; ci++) acc += xr[ci] * WT1[ci*CDIM + co];
    if (x2) {
        const float* x2r = x2 + (size_t)p * CDIM;
        float a2 = 0.f;
        #pragma unroll 8
        for (int ci = 0; ci < CDIM; ci++) a2 += x2r[ci] * WT2[ci*CDIM + co];
        acc += (scale2 ? scale2[p] : 1.f) * a2;
    }
    if (do_tanh) acc = tanhf(acc);
    out[i] = acc;
}

__global__ void attn_k(const float* __restrict__ energy,
                       const float* __restrict__ v_lw, const float* __restrict__ v_lb) {
    int p = blockIdx.x * blockDim.x + threadIdx.x;
    if (p >= NPTS) return;
    float acc = v_lb[0];
    #pragma unroll
    for (int j = 0; j < 8; j++) {
        float w = g_nbw[j*NPTS + p];
        if (w != 0.f) acc += w * g_vout[g_nbi[j*NPTS + p]];
    }
    const float* er = energy + (size_t)p * CDIM;
    #pragma unroll 8
    for (int ci = 0; ci < CDIM; ci++) acc += er[ci] * v_lw[ci];
    g_attn[p] = acc;
}

// ======================= host orchestration =================================
extern "C" void kernel_launch(void* const* d_in, const int* in_sizes, int n_in,
                              void* d_out, int out_size) {
    const float* hidden   = (const float*)d_in[0];
    const float* query    = (const float*)d_in[1];
    const float* coords   = (const float*)d_in[2];
    const float* wq_conv  = (const float*)d_in[3];
    const float* wq_lw    = (const float*)d_in[4];
    const float* wq_lb    = (const float*)d_in[5];
    const float* wh_conv  = (const float*)d_in[6];
    const float* wh_lw    = (const float*)d_in[7];
    const float* wh_lb    = (const float*)d_in[8];
    const float* att_conv = (const float*)d_in[9];
    const float* att_lw   = (const float*)d_in[10];
    const float* att_lb   = (const float*)d_in[11];
    const float* v_conv   = (const float*)d_in[12];
    const float* v_lw     = (const float*)d_in[13];
    const float* v_lb     = (const float*)d_in[14];
    const float* upd_conv = (const float*)d_in[15];
    const float* upd_lw   = (const float*)d_in[16];
    const float* upd_lb   = (const float*)d_in[17];
    float* out = (float*)d_out;

    float *pcnt, *pgrid, *pq, *ph, *pe, *pattn, *pvT;
    float *pwqlT, *pwhlT, *pattlT, *pupdlT;
    __nv_bfloat16 *pwqB, *pwhB, *pattB, *pupdB;
    cudaGetSymbolAddress((void**)&pcnt,   g_cnt);
    cudaGetSymbolAddress((void**)&pgrid,  g_grid);
    cudaGetSymbolAddress((void**)&pq,     g_q);
    cudaGetSymbolAddress((void**)&ph,     g_h);
    cudaGetSymbolAddress((void**)&pe,     g_energy);
    cudaGetSymbolAddress((void**)&pattn,  g_attn);
    cudaGetSymbolAddress((void**)&pvT,    g_vT);
    cudaGetSymbolAddress((void**)&pwqlT,  g_wqlT);
    cudaGetSymbolAddress((void**)&pwhlT,  g_whlT);
    cudaGetSymbolAddress((void**)&pattlT, g_attlT);
    cudaGetSymbolAddress((void**)&pupdlT, g_updlT);
    cudaGetSymbolAddress((void**)&pwqB,  g_wqB);
    cudaGetSymbolAddress((void**)&pwhB,  g_whB);
    cudaGetSymbolAddress((void**)&pattB, g_attB);
    cudaGetSymbolAddress((void**)&pupdB, g_updB);

    cudaFuncSetAttribute(conv_mma_k<128,2>, cudaFuncAttributeMaxDynamicSharedMemorySize, SM_TOT);
    cudaFuncSetAttribute(conv_mma_k<192,3>, cudaFuncAttributeMaxDynamicSharedMemorySize, SM_TOT);

    const int TB = 256;
    auto gs = [](long long n, int tb){ return (int)((n + tb - 1) / tb); };

    // --- shared precompute ---
    zero_k<<<gs(G3,TB), TB>>>(pcnt, G3);
    vox_k<<<gs(NPTS,TB), TB>>>(coords);
    inv_k<<<gs(G3,TB), TB>>>();
    trilin_k<<<gs(NPTS,TB), TB>>>(coords);

    // --- weight prep ---
    prep_wB_k<96,128,2><<<gs(27LL*128*96,TB), TB>>>(wq_conv, pwqB);
    prep_wB_k<96,128,2><<<gs(27LL*128*96,TB), TB>>>(wh_conv, pwhB);
    prep_wB_k<192,192,3><<<gs(27LL*192*96,TB), TB>>>(att_conv, pattB);
    prep_wB_k<192,192,3><<<gs(27LL*192*96,TB), TB>>>(upd_conv, pupdB);
    tconv_k<<<gs(96*27,TB), TB>>>(v_conv, pvT, 96, 1);
    tlin_k<<<gs(96*96,TB),  TB>>>(wq_lw,  pwqlT, 96, 96);
    tlin_k<<<gs(96*96,TB),  TB>>>(wh_lw,  pwhlT, 96, 96);
    tlin_k<<<gs(96*192,TB), TB>>>(att_lw, pattlT, 192, 96);
    tlin_k<<<gs(96*192,TB), TB>>>(upd_lw, pupdlT, 192, 96);

    // --- sconv q ---
    zero_k<<<gs(G3*96,TB), TB>>>(pgrid, G3*96);
    scatter_k<<<gs((long long)NPTS*96,TB), TB>>>(query, nullptr, 96, 96, 0);
    convert_pad_k<96,128><<<gs((long long)PGV*128,TB), TB>>>();
    conv_mma_k<128,2><<<256, 256, SM_TOT>>>(pwqB);
    devoxlin_k<<<gs((long long)NPTS*96,TB), TB>>>(query, pwqlT, nullptr, nullptr, nullptr, wq_lb, pq, 0);

    // --- sconv h ---
    zero_k<<<gs(G3*96,TB), TB>>>(pgrid, G3*96);
    scatter_k<<<gs((long long)NPTS*96,TB), TB>>>(hidden, nullptr, 96, 96, 0);
    convert_pad_k<96,128><<<gs((long long)PGV*128,TB), TB>>>();
    conv_mma_k<128,2><<<256, 256, SM_TOT>>>(pwhB);
    devoxlin_k<<<gs((long long)NPTS*96,TB), TB>>>(hidden, pwhlT, nullptr, nullptr, nullptr, wh_lb, ph, 0);

    // --- energy = tanh(sconv([h, q])) ---
    zero_k<<<gs(G3*192,TB), TB>>>(pgrid, G3*192);
    scatter_k<<<gs((long long)NPTS*96,TB), TB>>>(ph, nullptr, 96, 192, 0);
    scatter_k<<<gs((long long)NPTS*96,TB), TB>>>(pq, nullptr, 96, 192, 96);
    convert_pad_k<192,192><<<gs((long long)PGV*192,TB), TB>>>();
    conv_mma_k<192,3><<<256, 256, SM_TOT>>>(pattB);
    devoxlin_k<<<gs((long long)NPTS*96,TB), TB>>>(ph, pattlT, pq, pattlT + 96*96, nullptr, att_lb, pe, 1);

    // --- attn = sconv(energy), cout=1 ---
    zero_k<<<gs(G3*96,TB), TB>>>(pgrid, G3*96);
    scatter_k<<<gs((long long)NPTS*96,TB), TB>>>(pe, nullptr, 96, 96, 0);
    conv1_k<<<gs(G3,TB), TB>>>();
    attn_k<<<gs(NPTS,TB), TB>>>(pe, v_lw, v_lb);

    // --- out = tanh(sconv([q, attn*h])) ---
    zero_k<<<gs(G3*192,TB), TB>>>(pgrid, G3*192);
    scatter_k<<<gs((long long)NPTS*96,TB), TB>>>(pq, nullptr, 96, 192, 0);
    scatter_k<<<gs((long long)NPTS*96,TB), TB>>>(ph, pattn, 96, 192, 96);
    convert_pad_k<192,192><<<gs((long long)PGV*192,TB), TB>>>();
    conv_mma_k<192,3><<<256, 256, SM_TOT>>>(pupdB);
    devoxlin_k<<<gs((long long)NPTS*96,TB), TB>>>(pq, pupdlT, ph, pupdlT + 96*96, pattn, upd_lb, out, 1);
}

// round 5
// speedup vs baseline: 2.8526x; 1.2424x over previous
#include <cuda_runtime.h>
#include <cuda_bf16.h>
#include <cstdint>
#include <math.h>

#define NPTS 100000
#define CDIM 96
#define GRES 32
#define G3   (GRES*GRES*GRES)
#define PAD  34
#define PP2  (PAD*PAD)
#define PGV  (PP2*PAD)

// ======================= scratch (device globals) ===========================
__device__ int   g_vidx[NPTS];
__device__ int   g_icnt[G3];
__device__ int   g_start[G3+1];
__device__ int   g_pos[G3];
__device__ int   g_sorted[NPTS];
__device__ int   g_nbi[8*NPTS];
__device__ float g_nbw[8*NPTS];
__device__ float g_grid[G3*CDIM];       // fp32 meaned grid (attn stage only)
__device__ float g_conv[G3*CDIM];
__device__ float g_vout[G3];
__device__ float g_q[NPTS*CDIM];
__device__ float g_h[NPTS*CDIM];
__device__ float g_energy[NPTS*CDIM];
__device__ float g_attn[NPTS];
// padded bf16 split grid [px][py][zz][ci] (ci stride = KPAD)
__device__ __nv_bfloat16 g_pA_hi[PGV*192];
__device__ __nv_bfloat16 g_pA_lo[PGV*192];
// pre-swizzled split conv weights: [tap*nch+chunk][split(2)][6144 = 96 rows x 64 ci]
__device__ __nv_bfloat16 g_wqB [27*2*2*6144];
__device__ __nv_bfloat16 g_whB [27*2*2*6144];
__device__ __nv_bfloat16 g_attB[27*3*2*6144];
__device__ __nv_bfloat16 g_updB[27*3*2*6144];
__device__ float g_vT  [27*CDIM];
__device__ float g_wqlT [CDIM*CDIM];
__device__ float g_whlT [CDIM*CDIM];
__device__ float g_attlT[2*CDIM*CDIM];
__device__ float g_updlT[2*CDIM*CDIM];

// ======================= mma/ldmatrix/cp.async helpers =======================
__device__ __forceinline__ uint32_t smem_u32(const void* p) {
    uint32_t a;
    asm("{ .reg .u64 t; cvta.to.shared.u64 t, %1; cvt.u32.u64 %0, t; }" : "=r"(a) : "l"(p));
    return a;
}
__device__ __forceinline__ void ldsm4(uint32_t* r, uint32_t addr) {
    asm volatile("ldmatrix.sync.aligned.m8n8.x4.shared.b16 {%0,%1,%2,%3}, [%4];"
        : "=r"(r[0]), "=r"(r[1]), "=r"(r[2]), "=r"(r[3]) : "r"(addr));
}
__device__ __forceinline__ void mma16816(float* c, const uint32_t* a, const uint32_t* b) {
    asm volatile("mma.sync.aligned.m16n8k16.row.col.f32.bf16.bf16.f32 "
        "{%0,%1,%2,%3}, {%4,%5,%6,%7}, {%8,%9}, {%0,%1,%2,%3};"
        : "+f"(c[0]), "+f"(c[1]), "+f"(c[2]), "+f"(c[3])
        : "r"(a[0]), "r"(a[1]), "r"(a[2]), "r"(a[3]), "r"(b[0]), "r"(b[1]));
}
__device__ __forceinline__ void cpa16(uint32_t dst, const void* src) {
    asm volatile("cp.async.cg.shared.global [%0], [%1], 16;" :: "r"(dst), "l"(src));
}
__device__ __forceinline__ void cpa_commit() { asm volatile("cp.async.commit_group;"); }
__device__ __forceinline__ void cpa_wait0()  { asm volatile("cp.async.wait_group 0;"); }

// ======================= sort/index kernels ==================================
__global__ void zeroi_k(int* __restrict__ p, int n) {
    int i = blockIdx.x * blockDim.x + threadIdx.x;
    if (i < n) p[i] = 0;
}

__global__ void vox_k(const float* __restrict__ coords) {
    int p = blockIdx.x * blockDim.x + threadIdx.x;
    if (p >= NPTS) return;
    int vx = min(max((int)floorf(coords[3*p+0]), 0), GRES-1);
    int vy = min(max((int)floorf(coords[3*p+1]), 0), GRES-1);
    int vz = min(max((int)floorf(coords[3*p+2]), 0), GRES-1);
    int flat = (vx*GRES + vy)*GRES + vz;
    g_vidx[p] = flat;
    atomicAdd(&g_icnt[flat], 1);
}

// single block, 1024 threads, 32 items each: exclusive scan of g_icnt -> g_start, g_pos
__global__ void __launch_bounds__(1024) scan_k() {
    __shared__ int bs[1024];
    int t = threadIdx.x;
    int base = t * 32;
    int loc[32];
    int s = 0;
    #pragma unroll
    for (int k = 0; k < 32; k++) { loc[k] = s; s += g_icnt[base + k]; }
    bs[t] = s;
    __syncthreads();
    #pragma unroll
    for (int d = 1; d < 1024; d <<= 1) {
        int v = (t >= d) ? bs[t - d] : 0;
        __syncthreads();
        bs[t] += v;
        __syncthreads();
    }
    int off = bs[t] - s;   // exclusive prefix
    #pragma unroll
    for (int k = 0; k < 32; k++) {
        g_start[base + k] = off + loc[k];
        g_pos[base + k]   = off + loc[k];
    }
    if (t == 1023) g_start[G3] = off + s;
}

__global__ void fill_k() {
    int p = blockIdx.x * blockDim.x + threadIdx.x;
    if (p >= NPTS) return;
    int slot = atomicAdd(&g_pos[g_vidx[p]], 1);
    g_sorted[slot] = p;
}

__global__ void trilin_k(const float* __restrict__ coords) {
    int p = blockIdx.x * blockDim.x + threadIdx.x;
    if (p >= NPTS) return;
    float cx = coords[3*p+0], cy = coords[3*p+1], cz = coords[3*p+2];
    float bx = floorf(cx), by = floorf(cy), bz = floorf(cz);
    float fx = cx - bx, fy = cy - by, fz = cz - bz;
    int ix = (int)bx, iy = (int)by, iz = (int)bz;
    #pragma unroll
    for (int j = 0; j < 8; j++) {
        int dx = (j >> 2) & 1, dy = (j >> 1) & 1, dz = j & 1;
        int nx = ix + dx, ny = iy + dy, nz = iz + dz;
        bool valid = (nx >= 0 && nx < GRES && ny >= 0 && ny < GRES && nz >= 0 && nz < GRES);
        int cxc = min(max(nx,0),GRES-1), cyc = min(max(ny,0),GRES-1), czc = min(max(nz,0),GRES-1);
        int flc = (cxc*GRES + cyc)*GRES + czc;
        float w = (dx ? fx : 1.f-fx) * (dy ? fy : 1.f-fy) * (dz ? fz : 1.f-fz);
        if (!valid || g_icnt[flc] == 0) w = 0.f;
        g_nbi[j*NPTS + p] = flc;
        g_nbw[j*NPTS + p] = w;
    }
}

// ======================= fused gather-voxelize + pad + bf16 split ============
// CIN=96: channels from src1. CIN=192: [src1 | src2*scale2].
template<int CIN, int KPAD>
__global__ void gathervox_k(const float* __restrict__ src1,
                            const float* __restrict__ src2,
                            const float* __restrict__ scale2) {
    constexpr int NC4 = KPAD / 4;
    int i = blockIdx.x * blockDim.x + threadIdx.x;
    if (i >= PGV * NC4) return;
    int c4 = i % NC4;
    int pv = i / NC4;
    int zz = pv % PAD;
    int pp = pv / PAD;
    int py = pp % PAD;
    int px = pp / PAD;
    int ci = c4 * 4;

    float4 acc = make_float4(0.f, 0.f, 0.f, 0.f);
    if (px >= 1 && px <= GRES && py >= 1 && py <= GRES && zz >= 1 && zz <= GRES && ci < CIN) {
        int v = (((px-1) * GRES) + (py-1)) * GRES + (zz-1);
        int s0 = g_start[v], s1 = g_start[v+1];
        if (s1 > s0) {
            const float* src = src1;
            int cofs = ci;
            bool sc = false;
            if (CIN == 192 && ci >= 96) { src = src2; cofs = ci - 96; sc = (scale2 != nullptr); }
            for (int k = s0; k < s1; k++) {
                int pid = g_sorted[k];
                float4 f = *(const float4*)(src + (size_t)pid * 96 + cofs);
                float m = sc ? scale2[pid] : 1.f;
                acc.x += f.x * m; acc.y += f.y * m; acc.z += f.z * m; acc.w += f.w * m;
            }
            float invn = 1.f / (float)(s1 - s0);
            acc.x *= invn; acc.y *= invn; acc.z *= invn; acc.w *= invn;
        }
    }
    // bf16 split (hi + lo)
    __nv_bfloat16 h0 = __float2bfloat16(acc.x), h1 = __float2bfloat16(acc.y);
    __nv_bfloat16 h2 = __float2bfloat16(acc.z), h3 = __float2bfloat16(acc.w);
    __nv_bfloat16 l0 = __float2bfloat16(acc.x - __bfloat162float(h0));
    __nv_bfloat16 l1 = __float2bfloat16(acc.y - __bfloat162float(h1));
    __nv_bfloat16 l2 = __float2bfloat16(acc.z - __bfloat162float(h2));
    __nv_bfloat16 l3 = __float2bfloat16(acc.w - __bfloat162float(h3));
    size_t o = (size_t)pv * KPAD + ci;
    __nv_bfloat162 hA; hA.x = h0; hA.y = h1;
    __nv_bfloat162 hB; hB.x = h2; hB.y = h3;
    __nv_bfloat162 lA; lA.x = l0; lA.y = l1;
    __nv_bfloat162 lB; lB.x = l2; lB.y = l3;
    *(__nv_bfloat162*)(g_pA_hi + o)     = hA;
    *(__nv_bfloat162*)(g_pA_hi + o + 2) = hB;
    *(__nv_bfloat162*)(g_pA_lo + o)     = lA;
    *(__nv_bfloat162*)(g_pA_lo + o + 2) = lB;
}

// fp32 gather-voxelize (mean) into g_grid — attn stage
__global__ void voxf32_k(const float* __restrict__ src) {
    int i = blockIdx.x * blockDim.x + threadIdx.x;
    if (i >= G3 * 24) return;
    int c4 = i % 24;
    int v  = i / 24;
    int ci = c4 * 4;
    int s0 = g_start[v], s1 = g_start[v+1];
    float4 acc = make_float4(0.f, 0.f, 0.f, 0.f);
    if (s1 > s0) {
        for (int k = s0; k < s1; k++) {
            int pid = g_sorted[k];
            float4 f = *(const float4*)(src + (size_t)pid * 96 + ci);
            acc.x += f.x; acc.y += f.y; acc.z += f.z; acc.w += f.w;
        }
        float invn = 1.f / (float)(s1 - s0);
        acc.x *= invn; acc.y *= invn; acc.z *= invn; acc.w *= invn;
    }
    *(float4*)(g_grid + (size_t)v * 96 + ci) = acc;
}

// ======================= weight prep =========================================
template<int CIN, int KPAD, int NCH>
__global__ void prep_wB_k(const float* __restrict__ w, __nv_bfloat16* __restrict__ dst) {
    int i = blockIdx.x * blockDim.x + threadIdx.x;
    if (i >= 27 * KPAD * 96) return;
    int co  = i % 96;
    int r   = i / 96;
    int ci  = r % KPAD;
    int tap = r / KPAD;
    float val = (ci < CIN) ? w[((size_t)co * CIN + ci) * 27 + tap] : 0.f;
    __nv_bfloat16 hi = __float2bfloat16(val);
    __nv_bfloat16 lo = __float2bfloat16(val - __bfloat162float(hi));
    int chunk = ci >> 6;
    int cw = ci & 63;
    uint32_t elem = (uint32_t)co * 64 + (uint32_t)(((cw >> 3) ^ (co & 7)) * 8) + (cw & 7);
    size_t base = (size_t)(tap * NCH + chunk) * 2 * 6144;
    dst[base + elem] = hi;
    dst[base + 6144 + elem] = lo;
}

__global__ void tconv_k(const float* __restrict__ w, float* __restrict__ wT, int cin, int cout) {
    int i = blockIdx.x * blockDim.x + threadIdx.x;
    int total = cout * cin * 27;
    if (i >= total) return;
    int k  = i % 27;
    int r  = i / 27;
    int ci = r % cin;
    int co = r / cin;
    wT[(k*cin + ci)*cout + co] = w[i];
}
__global__ void tlin_k(const float* __restrict__ w, float* __restrict__ wT, int cin, int cout) {
    int i = blockIdx.x * blockDim.x + threadIdx.x;
    if (i >= cout * cin) return;
    int co = i / cin, ci = i - co * cin;
    wT[ci*cout + co] = w[i];
}

// ======================= HMMA 3x3x3 conv (slab-resident A) ==================
#define A_SPLIT 26112            // 204 rows * 128B
#define SM_B0   52224
#define SM_B1   76800
#define SM_TOT  101376

template<int KPAD, int NCH>
__global__ void __launch_bounds__(256, 2) conv_mma_k(const __nv_bfloat16* __restrict__ wB) {
    extern __shared__ char smem[];
    uint32_t sb = smem_u32(smem);
    int tid = threadIdx.x;
    int warp = tid >> 5, lane = tid & 31;
    int m_off = (warp & 3) * 32;
    int n_off = (warp >> 2) * 48;

    int x  = blockIdx.x >> 3;
    int y0 = (blockIdx.x & 7) * 4;

    float acc[2][6][4];
    #pragma unroll
    for (int mi = 0; mi < 2; mi++)
        #pragma unroll
        for (int nj = 0; nj < 6; nj++)
            #pragma unroll
            for (int e = 0; e < 4; e++) acc[mi][nj][e] = 0.f;

    int a_row_in = (lane & 7) + ((lane >> 3) & 1) * 8;
    int a_khalf  = lane >> 4;
    int b_row_in = (lane & 7) + ((lane >> 3) >> 1) * 8;
    int b_khalf  = (lane >> 3) & 1;

    int rb[2];
    #pragma unroll
    for (int mi = 0; mi < 2; mi++) {
        int m = m_off + mi * 16 + a_row_in;
        rb[mi] = (m >> 5) * 34 + (m & 31);
    }
    int brow[3];
    #pragma unroll
    for (int ni = 0; ni < 3; ni++) brow[ni] = n_off + ni * 16 + b_row_in;

    for (int cc = 0; cc < NCH; cc++) {
        for (int dx = 0; dx < 3; dx++) {
            __syncthreads();

            {
                const __nv_bfloat16* bs = wB + (size_t)((dx * 9) * NCH + cc) * 12288;
                #pragma unroll
                for (int t = tid; t < 1536; t += 256)
                    cpa16(sb + SM_B0 + t * 16, bs + t * 8);
                cpa_commit();
            }
            {
                size_t pvbase = ((size_t)(x + dx) * PAD + y0) * PAD;
                #pragma unroll
                for (int t = tid; t < 3264; t += 256) {
                    int split = (t >= 1632);
                    int e = split ? t - 1632 : t;
                    int r = e >> 3, c8 = e & 7;
                    const __nv_bfloat16* src =
                        (split ? g_pA_lo : g_pA_hi) + (pvbase + r) * KPAD + cc * 64 + c8 * 8;
                    uint4 v = *(const uint4*)src;
                    *(uint4*)(smem + split * A_SPLIT + r * 128 + ((c8 ^ (r & 7)) << 4)) = v;
                }
            }

            for (int t9 = 0; t9 < 9; t9++) {
                cpa_wait0();
                __syncthreads();
                if (t9 < 8) {
                    const __nv_bfloat16* bs =
                        wB + (size_t)((dx * 9 + t9 + 1) * NCH + cc) * 12288;
                    uint32_t dst = sb + ((t9 & 1) ? SM_B0 : SM_B1);
                    #pragma unroll
                    for (int t = tid; t < 1536; t += 256)
                        cpa16(dst + t * 16, bs + t * 8);
                    cpa_commit();
                }
                uint32_t bbase = sb + ((t9 & 1) ? SM_B1 : SM_B0);
                int toff = (t9 / 3) * PAD + (t9 % 3);

                #pragma unroll
                for (int kk = 0; kk < 4; kk++) {
                    uint32_t ah[2][4], al[2][4], bh[3][4], bl[3][4];
                    #pragma unroll
                    for (int mi = 0; mi < 2; mi++) {
                        int r = rb[mi] + toff;
                        int kc = kk * 2 + a_khalf;
                        uint32_t off = (uint32_t)r * 128 + (uint32_t)((kc ^ (r & 7)) << 4);
                        ldsm4(ah[mi], sb + off);
                        ldsm4(al[mi], sb + A_SPLIT + off);
                    }
                    #pragma unroll
                    for (int ni = 0; ni < 3; ni++) {
                        int r = brow[ni];
                        int kc = kk * 2 + b_khalf;
                        uint32_t off = (uint32_t)r * 128 + (uint32_t)((kc ^ (r & 7)) << 4);
                        ldsm4(bh[ni], bbase + off);
                        ldsm4(bl[ni], bbase + 12288 + off);
                    }
                    #pragma unroll
                    for (int mi = 0; mi < 2; mi++) {
                        #pragma unroll
                        for (int nj = 0; nj < 6; nj++) {
                            const uint32_t* bfh = &bh[nj >> 1][(nj & 1) * 2];
                            const uint32_t* bfl = &bl[nj >> 1][(nj & 1) * 2];
                            mma16816(acc[mi][nj], ah[mi], bfh);
                            mma16816(acc[mi][nj], ah[mi], bfl);
                            mma16816(acc[mi][nj], al[mi], bfh);
                        }
                    }
                }
            }
        }
    }

    #pragma unroll
    for (int mi = 0; mi < 2; mi++) {
        #pragma unroll
        for (int half = 0; half < 2; half++) {
            int r = m_off + mi * 16 + (lane >> 2) + half * 8;
            int j = r >> 5, z = r & 31;
            size_t vbase = ((size_t)(x * GRES + y0 + j) * GRES + z) * 96;
            #pragma unroll
            for (int nj = 0; nj < 6; nj++) {
                int co = n_off + nj * 8 + 2 * (lane & 3);
                float2 v = make_float2(acc[mi][nj][half * 2], acc[mi][nj][half * 2 + 1]);
                *(float2*)(&g_conv[vbase + co]) = v;
            }
        }
    }
}

// ======================= cout=1 conv (v_conv) ===============================
__global__ void conv1_k() {
    int v = blockIdx.x * blockDim.x + threadIdx.x;
    if (v >= G3) return;
    int px = v >> 10, py = (v >> 5) & 31, pz = v & 31;
    float acc = 0.f;
    for (int kx = 0; kx < 3; kx++) {
        int nx = px + kx - 1;
        if ((unsigned)nx >= GRES) continue;
        for (int ky = 0; ky < 3; ky++) {
            int ny = py + ky - 1;
            if ((unsigned)ny >= GRES) continue;
            for (int kz = 0; kz < 3; kz++) {
                int nz = pz + kz - 1;
                if ((unsigned)nz >= GRES) continue;
                int nf = ((nx<<5) + ny)*32 + nz;
                const float* ip = &g_grid[(size_t)nf * CDIM];
                const float* wp = &g_vT[((kx*3 + ky)*3 + kz) * CDIM];
                float a = 0.f;
                #pragma unroll 8
                for (int ci = 0; ci < CDIM; ci++) a += ip[ci] * wp[ci];
                acc += a;
            }
        }
    }
    g_vout[v] = acc;
}

// ======================= devox + linear (fused, float4) ======================
__global__ void devoxlin_k(const float* __restrict__ x1, const float* __restrict__ WT1,
                           const float* __restrict__ x2, const float* __restrict__ WT2,
                           const float* __restrict__ scale2,
                           const float* __restrict__ bias,
                           float* __restrict__ out, int do_tanh) {
    int i = blockIdx.x * blockDim.x + threadIdx.x;
    if (i >= NPTS * 24) return;
    int c4 = i % 24;
    int p  = i / 24;
    int co = c4 * 4;

    float4 acc = *(const float4*)(bias + co);
    #pragma unroll
    for (int j = 0; j < 8; j++) {
        float w = g_nbw[j*NPTS + p];
        if (w != 0.f) {
            float4 g = *(const float4*)(&g_conv[(size_t)g_nbi[j*NPTS + p]*96 + co]);
            acc.x += w * g.x; acc.y += w * g.y; acc.z += w * g.z; acc.w += w * g.w;
        }
    }
    const float4* xr4 = (const float4*)(x1 + (size_t)p * 96);
    const float4* W1  = (const float4*)WT1;
    #pragma unroll 6
    for (int cb = 0; cb < 24; cb++) {
        float4 xv = xr4[cb];
        float4 w0 = W1[(cb*4+0)*24 + c4];
        float4 w1 = W1[(cb*4+1)*24 + c4];
        float4 w2 = W1[(cb*4+2)*24 + c4];
        float4 w3 = W1[(cb*4+3)*24 + c4];
        acc.x += xv.x*w0.x + xv.y*w1.x + xv.z*w2.x + xv.w*w3.x;
        acc.y += xv.x*w0.y + xv.y*w1.y + xv.z*w2.y + xv.w*w3.y;
        acc.z += xv.x*w0.z + xv.y*w1.z + xv.z*w2.z + xv.w*w3.z;
        acc.w += xv.x*w0.w + xv.y*w1.w + xv.z*w2.w + xv.w*w3.w;
    }
    if (x2) {
        float4 a2 = make_float4(0.f, 0.f, 0.f, 0.f);
        const float4* x24 = (const float4*)(x2 + (size_t)p * 96);
        const float4* W2  = (const float4*)WT2;
        #pragma unroll 6
        for (int cb = 0; cb < 24; cb++) {
            float4 xv = x24[cb];
            float4 w0 = W2[(cb*4+0)*24 + c4];
            float4 w1 = W2[(cb*4+1)*24 + c4];
            float4 w2 = W2[(cb*4+2)*24 + c4];
            float4 w3 = W2[(cb*4+3)*24 + c4];
            a2.x += xv.x*w0.x + xv.y*w1.x + xv.z*w2.x + xv.w*w3.x;
            a2.y += xv.x*w0.y + xv.y*w1.y + xv.z*w2.y + xv.w*w3.y;
            a2.z += xv.x*w0.z + xv.y*w1.z + xv.z*w2.z + xv.w*w3.z;
            a2.w += xv.x*w0.w + xv.y*w1.w + xv.z*w2.w + xv.w*w3.w;
        }
        float s2 = scale2 ? scale2[p] : 1.f;
        acc.x += s2 * a2.x; acc.y += s2 * a2.y; acc.z += s2 * a2.z; acc.w += s2 * a2.w;
    }
    if (do_tanh) {
        acc.x = tanhf(acc.x); acc.y = tanhf(acc.y);
        acc.z = tanhf(acc.z); acc.w = tanhf(acc.w);
    }
    *(float4*)(out + (size_t)p * 96 + co) = acc;
}

__global__ void attn_k(const float* __restrict__ energy,
                       const float* __restrict__ v_lw, const float* __restrict__ v_lb) {
    int p = blockIdx.x * blockDim.x + threadIdx.x;
    if (p >= NPTS) return;
    float acc = v_lb[0];
    #pragma unroll
    for (int j = 0; j < 8; j++) {
        float w = g_nbw[j*NPTS + p];
        if (w != 0.f) acc += w * g_vout[g_nbi[j*NPTS + p]];
    }
    const float* er = energy + (size_t)p * CDIM;
    #pragma unroll 8
    for (int ci = 0; ci < CDIM; ci++) acc += er[ci] * v_lw[ci];
    g_attn[p] = acc;
}

// ======================= host orchestration =================================
extern "C" void kernel_launch(void* const* d_in, const int* in_sizes, int n_in,
                              void* d_out, int out_size) {
    const float* hidden   = (const float*)d_in[0];
    const float* query    = (const float*)d_in[1];
    const float* coords   = (const float*)d_in[2];
    const float* wq_conv  = (const float*)d_in[3];
    const float* wq_lw    = (const float*)d_in[4];
    const float* wq_lb    = (const float*)d_in[5];
    const float* wh_conv  = (const float*)d_in[6];
    const float* wh_lw    = (const float*)d_in[7];
    const float* wh_lb    = (const float*)d_in[8];
    const float* att_conv = (const float*)d_in[9];
    const float* att_lw   = (const float*)d_in[10];
    const float* att_lb   = (const float*)d_in[11];
    const float* v_conv   = (const float*)d_in[12];
    const float* v_lw     = (const float*)d_in[13];
    const float* v_lb     = (const float*)d_in[14];
    const float* upd_conv = (const float*)d_in[15];
    const float* upd_lw   = (const float*)d_in[16];
    const float* upd_lb   = (const float*)d_in[17];
    float* out = (float*)d_out;

    int *picnt;
    float *pq, *ph, *pe, *pattn, *pvT;
    float *pwqlT, *pwhlT, *pattlT, *pupdlT;
    __nv_bfloat16 *pwqB, *pwhB, *pattB, *pupdB;
    cudaGetSymbolAddress((void**)&picnt,  g_icnt);
    cudaGetSymbolAddress((void**)&pq,     g_q);
    cudaGetSymbolAddress((void**)&ph,     g_h);
    cudaGetSymbolAddress((void**)&pe,     g_energy);
    cudaGetSymbolAddress((void**)&pattn,  g_attn);
    cudaGetSymbolAddress((void**)&pvT,    g_vT);
    cudaGetSymbolAddress((void**)&pwqlT,  g_wqlT);
    cudaGetSymbolAddress((void**)&pwhlT,  g_whlT);
    cudaGetSymbolAddress((void**)&pattlT, g_attlT);
    cudaGetSymbolAddress((void**)&pupdlT, g_updlT);
    cudaGetSymbolAddress((void**)&pwqB,  g_wqB);
    cudaGetSymbolAddress((void**)&pwhB,  g_whB);
    cudaGetSymbolAddress((void**)&pattB, g_attB);
    cudaGetSymbolAddress((void**)&pupdB, g_updB);

    cudaFuncSetAttribute(conv_mma_k<128,2>, cudaFuncAttributeMaxDynamicSharedMemorySize, SM_TOT);
    cudaFuncSetAttribute(conv_mma_k<192,3>, cudaFuncAttributeMaxDynamicSharedMemorySize, SM_TOT);

    const int TB = 256;
    auto gs = [](long long n, int tb){ return (int)((n + tb - 1) / tb); };

    // --- shared precompute: counting sort + trilinear ---
    zeroi_k<<<gs(G3,TB), TB>>>(picnt, G3);
    vox_k<<<gs(NPTS,TB), TB>>>(coords);
    scan_k<<<1, 1024>>>();
    fill_k<<<gs(NPTS,TB), TB>>>();
    trilin_k<<<gs(NPTS,TB), TB>>>(coords);

    // --- weight prep ---
    prep_wB_k<96,128,2><<<gs(27LL*128*96,TB), TB>>>(wq_conv, pwqB);
    prep_wB_k<96,128,2><<<gs(27LL*128*96,TB), TB>>>(wh_conv, pwhB);
    prep_wB_k<192,192,3><<<gs(27LL*192*96,TB), TB>>>(att_conv, pattB);
    prep_wB_k<192,192,3><<<gs(27LL*192*96,TB), TB>>>(upd_conv, pupdB);
    tconv_k<<<gs(96*27,TB), TB>>>(v_conv, pvT, 96, 1);
    tlin_k<<<gs(96*96,TB),  TB>>>(wq_lw,  pwqlT, 96, 96);
    tlin_k<<<gs(96*96,TB),  TB>>>(wh_lw,  pwhlT, 96, 96);
    tlin_k<<<gs(96*192,TB), TB>>>(att_lw, pattlT, 192, 96);
    tlin_k<<<gs(96*192,TB), TB>>>(upd_lw, pupdlT, 192, 96);

    // --- sconv q ---
    gathervox_k<96,128><<<gs((long long)PGV*32,TB), TB>>>(query, nullptr, nullptr);
    conv_mma_k<128,2><<<256, 256, SM_TOT>>>(pwqB);
    devoxlin_k<<<gs((long long)NPTS*24,TB), TB>>>(query, pwqlT, nullptr, nullptr, nullptr, wq_lb, pq, 0);

    // --- sconv h ---
    gathervox_k<96,128><<<gs((long long)PGV*32,TB), TB>>>(hidden, nullptr, nullptr);
    conv_mma_k<128,2><<<256, 256, SM_TOT>>>(pwhB);
    devoxlin_k<<<gs((long long)NPTS*24,TB), TB>>>(hidden, pwhlT, nullptr, nullptr, nullptr, wh_lb, ph, 0);

    // --- energy = tanh(sconv([h, q])) ---
    gathervox_k<192,192><<<gs((long long)PGV*48,TB), TB>>>(ph, pq, nullptr);
    conv_mma_k<192,3><<<256, 256, SM_TOT>>>(pattB);
    devoxlin_k<<<gs((long long)NPTS*24,TB), TB>>>(ph, pattlT, pq, pattlT + 96*96, nullptr, att_lb, pe, 1);

    // --- attn = sconv(energy), cout=1 ---
    voxf32_k<<<gs((long long)G3*24,TB), TB>>>(pe);
    conv1_k<<<gs(G3,TB), TB>>>();
    attn_k<<<gs(NPTS,TB), TB>>>(pe, v_lw, v_lb);

    // --- out = tanh(sconv([q, attn*h])) ---
    gathervox_k<192,192><<<gs((long long)PGV*48,TB), TB>>>(pq, ph, pattn);
    conv_mma_k<192,3><<<256, 256, SM_TOT>>>(pupdB);
    devoxlin_k<<<gs((long long)NPTS*24,TB), TB>>>(pq, pupdlT, ph, pupdlT + 96*96, pattn, upd_lb, out, 1);
}

// round 6
// speedup vs baseline: 4.5072x; 1.5800x over previous
#include <cuda_runtime.h>
#include <cuda_bf16.h>
#include <cstdint>
#include <math.h>

#define NPTS 100000
#define CDIM 96
#define GRES 32
#define G3   (GRES*GRES*GRES)
#define PAD  34
#define PP2  (PAD*PAD)
#define PGV  (PP2*PAD)

// ======================= scratch (device globals) ===========================
__device__ int   g_vidx[NPTS];
__device__ int   g_icnt[G3];
__device__ int   g_start[G3+1];
__device__ int   g_pos[G3];
__device__ int   g_sorted[NPTS];
__device__ int   g_nbi[8*NPTS];
__device__ float g_nbw[8*NPTS];
__device__ float g_grid[G3*CDIM];       // fp32 meaned grid (attn stage only)
__device__ float g_conv[G3*CDIM];
__device__ float g_vout[G3];
__device__ float g_q[NPTS*CDIM];
__device__ float g_h[NPTS*CDIM];
__device__ float g_energy[NPTS*CDIM];
__device__ float g_attn[NPTS];
// padded bf16 split grids, per-layout (borders/pad-channels zeroed once)
__device__ __nv_bfloat16 g_pA96_hi [PGV*128];
__device__ __nv_bfloat16 g_pA96_lo [PGV*128];
__device__ __nv_bfloat16 g_pA192_hi[PGV*192];
__device__ __nv_bfloat16 g_pA192_lo[PGV*192];
// pre-swizzled split conv weights: [tap*nch+chunk][split(2)][6144 = 96 rows x 64 ci]
__device__ __nv_bfloat16 g_wqB [27*2*2*6144];
__device__ __nv_bfloat16 g_whB [27*2*2*6144];
__device__ __nv_bfloat16 g_attB[27*3*2*6144];
__device__ __nv_bfloat16 g_updB[27*3*2*6144];
// pre-swizzled split linear weights: [chunk][split(2)][6144]
__device__ __nv_bfloat16 g_wqlB [2*2*6144];
__device__ __nv_bfloat16 g_whlB [2*2*6144];
__device__ __nv_bfloat16 g_attlB[3*2*6144];
__device__ __nv_bfloat16 g_updlB[3*2*6144];
__device__ float g_vT[27*CDIM];

// ======================= mma/ldmatrix/cp.async helpers =======================
__device__ __forceinline__ uint32_t smem_u32(const void* p) {
    uint32_t a;
    asm("{ .reg .u64 t; cvta.to.shared.u64 t, %1; cvt.u32.u64 %0, t; }" : "=r"(a) : "l"(p));
    return a;
}
__device__ __forceinline__ void ldsm4(uint32_t* r, uint32_t addr) {
    asm volatile("ldmatrix.sync.aligned.m8n8.x4.shared.b16 {%0,%1,%2,%3}, [%4];"
        : "=r"(r[0]), "=r"(r[1]), "=r"(r[2]), "=r"(r[3]) : "r"(addr));
}
__device__ __forceinline__ void mma16816(float* c, const uint32_t* a, const uint32_t* b) {
    asm volatile("mma.sync.aligned.m16n8k16.row.col.f32.bf16.bf16.f32 "
        "{%0,%1,%2,%3}, {%4,%5,%6,%7}, {%8,%9}, {%0,%1,%2,%3};"
        : "+f"(c[0]), "+f"(c[1]), "+f"(c[2]), "+f"(c[3])
        : "r"(a[0]), "r"(a[1]), "r"(a[2]), "r"(a[3]), "r"(b[0]), "r"(b[1]));
}
__device__ __forceinline__ void cpa16(uint32_t dst, const void* src) {
    asm volatile("cp.async.cg.shared.global [%0], [%1], 16;" :: "r"(dst), "l"(src));
}
__device__ __forceinline__ void cpa_commit() { asm volatile("cp.async.commit_group;"); }
__device__ __forceinline__ void cpa_wait0()  { asm volatile("cp.async.wait_group 0;"); }
__device__ __forceinline__ void cpa_wait1()  { asm volatile("cp.async.wait_group 1;"); }

// ======================= sort/index kernels ==================================
__global__ void zeroi_k(int* __restrict__ p, int n) {
    int i = blockIdx.x * blockDim.x + threadIdx.x;
    if (i < n) p[i] = 0;
}
__global__ void zerob_k(__nv_bfloat16* __restrict__ p, int n16) {
    int i = blockIdx.x * blockDim.x + threadIdx.x;
    if (i < n16 / 8) ((uint4*)p)[i] = make_uint4(0u, 0u, 0u, 0u);
}

__global__ void vox_k(const float* __restrict__ coords) {
    int p = blockIdx.x * blockDim.x + threadIdx.x;
    if (p >= NPTS) return;
    int vx = min(max((int)floorf(coords[3*p+0]), 0), GRES-1);
    int vy = min(max((int)floorf(coords[3*p+1]), 0), GRES-1);
    int vz = min(max((int)floorf(coords[3*p+2]), 0), GRES-1);
    int flat = (vx*GRES + vy)*GRES + vz;
    g_vidx[p] = flat;
    atomicAdd(&g_icnt[flat], 1);
}

__global__ void __launch_bounds__(1024) scan_k() {
    __shared__ int bs[1024];
    int t = threadIdx.x;
    int base = t * 32;
    int loc[32];
    int s = 0;
    #pragma unroll
    for (int k = 0; k < 32; k++) { loc[k] = s; s += g_icnt[base + k]; }
    bs[t] = s;
    __syncthreads();
    #pragma unroll
    for (int d = 1; d < 1024; d <<= 1) {
        int v = (t >= d) ? bs[t - d] : 0;
        __syncthreads();
        bs[t] += v;
        __syncthreads();
    }
    int off = bs[t] - s;
    #pragma unroll
    for (int k = 0; k < 32; k++) {
        g_start[base + k] = off + loc[k];
        g_pos[base + k]   = off + loc[k];
    }
    if (t == 1023) g_start[G3] = off + s;
}

__global__ void fill_k() {
    int p = blockIdx.x * blockDim.x + threadIdx.x;
    if (p >= NPTS) return;
    int slot = atomicAdd(&g_pos[g_vidx[p]], 1);
    g_sorted[slot] = p;
}

__global__ void trilin_k(const float* __restrict__ coords) {
    int p = blockIdx.x * blockDim.x + threadIdx.x;
    if (p >= NPTS) return;
    float cx = coords[3*p+0], cy = coords[3*p+1], cz = coords[3*p+2];
    float bx = floorf(cx), by = floorf(cy), bz = floorf(cz);
    float fx = cx - bx, fy = cy - by, fz = cz - bz;
    int ix = (int)bx, iy = (int)by, iz = (int)bz;
    #pragma unroll
    for (int j = 0; j < 8; j++) {
        int dx = (j >> 2) & 1, dy = (j >> 1) & 1, dz = j & 1;
        int nx = ix + dx, ny = iy + dy, nz = iz + dz;
        bool valid = (nx >= 0 && nx < GRES && ny >= 0 && ny < GRES && nz >= 0 && nz < GRES);
        int cxc = min(max(nx,0),GRES-1), cyc = min(max(ny,0),GRES-1), czc = min(max(nz,0),GRES-1);
        int flc = (cxc*GRES + cyc)*GRES + czc;
        float w = (dx ? fx : 1.f-fx) * (dy ? fy : 1.f-fy) * (dz ? fz : 1.f-fz);
        if (!valid || g_icnt[flc] == 0) w = 0.f;
        g_nbi[j*NPTS + p] = flc;
        g_nbw[j*NPTS + p] = w;
    }
}

// ======================= fused gather-voxelize (interior only) ===============
template<int CIN, int KPAD>
__global__ void gathervox_k(const float* __restrict__ src1,
                            const float* __restrict__ src2,
                            const float* __restrict__ scale2,
                            __nv_bfloat16* __restrict__ dhi,
                            __nv_bfloat16* __restrict__ dlo) {
    constexpr int NC4 = CIN / 4;
    int i = blockIdx.x * blockDim.x + threadIdx.x;
    if (i >= G3 * NC4) return;
    int c4 = i % NC4;
    int v  = i / NC4;
    int vx = v >> 10, vy = (v >> 5) & 31, vz = v & 31;
    int pv = ((vx + 1) * PAD + (vy + 1)) * PAD + (vz + 1);
    int ci = c4 * 4;

    float4 acc = make_float4(0.f, 0.f, 0.f, 0.f);
    int s0 = g_start[v], s1 = g_start[v+1];
    if (s1 > s0) {
        const float* src = src1;
        int cofs = ci;
        bool sc = false;
        if (CIN == 192 && ci >= 96) { src = src2; cofs = ci - 96; sc = (scale2 != nullptr); }
        for (int k = s0; k < s1; k++) {
            int pid = g_sorted[k];
            float4 f = *(const float4*)(src + (size_t)pid * 96 + cofs);
            float m = sc ? scale2[pid] : 1.f;
            acc.x += f.x * m; acc.y += f.y * m; acc.z += f.z * m; acc.w += f.w * m;
        }
        float invn = 1.f / (float)(s1 - s0);
        acc.x *= invn; acc.y *= invn; acc.z *= invn; acc.w *= invn;
    }
    __nv_bfloat16 h0 = __float2bfloat16(acc.x), h1 = __float2bfloat16(acc.y);
    __nv_bfloat16 h2 = __float2bfloat16(acc.z), h3 = __float2bfloat16(acc.w);
    __nv_bfloat16 l0 = __float2bfloat16(acc.x - __bfloat162float(h0));
    __nv_bfloat16 l1 = __float2bfloat16(acc.y - __bfloat162float(h1));
    __nv_bfloat16 l2 = __float2bfloat16(acc.z - __bfloat162float(h2));
    __nv_bfloat16 l3 = __float2bfloat16(acc.w - __bfloat162float(h3));
    size_t o = (size_t)pv * KPAD + ci;
    __nv_bfloat162 hA; hA.x = h0; hA.y = h1;
    __nv_bfloat162 hB; hB.x = h2; hB.y = h3;
    __nv_bfloat162 lA; lA.x = l0; lA.y = l1;
    __nv_bfloat162 lB; lB.x = l2; lB.y = l3;
    *(__nv_bfloat162*)(dhi + o)     = hA;
    *(__nv_bfloat162*)(dhi + o + 2) = hB;
    *(__nv_bfloat162*)(dlo + o)     = lA;
    *(__nv_bfloat162*)(dlo + o + 2) = lB;
}

// fp32 gather-voxelize (mean) into g_grid — attn stage
__global__ void voxf32_k(const float* __restrict__ src) {
    int i = blockIdx.x * blockDim.x + threadIdx.x;
    if (i >= G3 * 24) return;
    int c4 = i % 24;
    int v  = i / 24;
    int ci = c4 * 4;
    int s0 = g_start[v], s1 = g_start[v+1];
    float4 acc = make_float4(0.f, 0.f, 0.f, 0.f);
    if (s1 > s0) {
        for (int k = s0; k < s1; k++) {
            int pid = g_sorted[k];
            float4 f = *(const float4*)(src + (size_t)pid * 96 + ci);
            acc.x += f.x; acc.y += f.y; acc.z += f.z; acc.w += f.w;
        }
        float invn = 1.f / (float)(s1 - s0);
        acc.x *= invn; acc.y *= invn; acc.z *= invn; acc.w *= invn;
    }
    *(float4*)(g_grid + (size_t)v * 96 + ci) = acc;
}

// ======================= weight prep =========================================
template<int CIN, int KPAD, int NCH>
__global__ void prep_wB_k(const float* __restrict__ w, __nv_bfloat16* __restrict__ dst) {
    int i = blockIdx.x * blockDim.x + threadIdx.x;
    if (i >= 27 * KPAD * 96) return;
    int co  = i % 96;
    int r   = i / 96;
    int ci  = r % KPAD;
    int tap = r / KPAD;
    float val = (ci < CIN) ? w[((size_t)co * CIN + ci) * 27 + tap] : 0.f;
    __nv_bfloat16 hi = __float2bfloat16(val);
    __nv_bfloat16 lo = __float2bfloat16(val - __bfloat162float(hi));
    int chunk = ci >> 6;
    int cw = ci & 63;
    uint32_t elem = (uint32_t)co * 64 + (uint32_t)(((cw >> 3) ^ (co & 7)) * 8) + (cw & 7);
    size_t base = (size_t)(tap * NCH + chunk) * 2 * 6144;
    dst[base + elem] = hi;
    dst[base + 6144 + elem] = lo;
}

// linear weights w (96, CIN) row-major -> split + pre-swizzled chunks
template<int CIN, int KPAD>
__global__ void prep_wlB_k(const float* __restrict__ w, __nv_bfloat16* __restrict__ dst) {
    int i = blockIdx.x * blockDim.x + threadIdx.x;
    if (i >= KPAD * 96) return;
    int co = i % 96;
    int ci = i / 96;
    float val = (ci < CIN) ? w[(size_t)co * CIN + ci] : 0.f;
    __nv_bfloat16 hi = __float2bfloat16(val);
    __nv_bfloat16 lo = __float2bfloat16(val - __bfloat162float(hi));
    int chunk = ci >> 6;
    int cw = ci & 63;
    uint32_t elem = (uint32_t)co * 64 + (uint32_t)(((cw >> 3) ^ (co & 7)) * 8) + (cw & 7);
    size_t base = (size_t)chunk * 2 * 6144;
    dst[base + elem] = hi;
    dst[base + 6144 + elem] = lo;
}

__global__ void tconv_k(const float* __restrict__ w, float* __restrict__ wT, int cin, int cout) {
    int i = blockIdx.x * blockDim.x + threadIdx.x;
    int total = cout * cin * 27;
    if (i >= total) return;
    int k  = i % 27;
    int r  = i / 27;
    int ci = r % cin;
    int co = r / cin;
    wT[(k*cin + ci)*cout + co] = w[i];
}

// ======================= HMMA 3x3x3 conv (slab-resident A) ==================
#define A_SPLIT 26112            // 204 rows * 128B
#define SM_B0   52224
#define SM_B1   76800
#define SM_TOT  101376

template<int KPAD, int NCH>
__global__ void __launch_bounds__(256, 2) conv_mma_k(const __nv_bfloat16* __restrict__ wB,
                                                     const __nv_bfloat16* __restrict__ pAhi,
                                                     const __nv_bfloat16* __restrict__ pAlo) {
    extern __shared__ char smem[];
    uint32_t sb = smem_u32(smem);
    int tid = threadIdx.x;
    int warp = tid >> 5, lane = tid & 31;
    int m_off = (warp & 3) * 32;
    int n_off = (warp >> 2) * 48;

    int x  = blockIdx.x >> 3;
    int y0 = (blockIdx.x & 7) * 4;

    float acc[2][6][4];
    #pragma unroll
    for (int mi = 0; mi < 2; mi++)
        #pragma unroll
        for (int nj = 0; nj < 6; nj++)
            #pragma unroll
            for (int e = 0; e < 4; e++) acc[mi][nj][e] = 0.f;

    int a_row_in = (lane & 7) + ((lane >> 3) & 1) * 8;
    int a_khalf  = lane >> 4;
    int b_row_in = (lane & 7) + ((lane >> 3) >> 1) * 8;
    int b_khalf  = (lane >> 3) & 1;

    int rb[2];
    #pragma unroll
    for (int mi = 0; mi < 2; mi++) {
        int m = m_off + mi * 16 + a_row_in;
        rb[mi] = (m >> 5) * 34 + (m & 31);
    }
    int brow[3];
    #pragma unroll
    for (int ni = 0; ni < 3; ni++) brow[ni] = n_off + ni * 16 + b_row_in;

    for (int cc = 0; cc < NCH; cc++) {
        for (int dx = 0; dx < 3; dx++) {
            __syncthreads();

            {
                const __nv_bfloat16* bs = wB + (size_t)((dx * 9) * NCH + cc) * 12288;
                #pragma unroll
                for (int t = tid; t < 1536; t += 256)
                    cpa16(sb + SM_B0 + t * 16, bs + t * 8);
                cpa_commit();
            }
            {
                size_t pvbase = ((size_t)(x + dx) * PAD + y0) * PAD;
                #pragma unroll
                for (int t = tid; t < 3264; t += 256) {
                    int split = (t >= 1632);
                    int e = split ? t - 1632 : t;
                    int r = e >> 3, c8 = e & 7;
                    const __nv_bfloat16* src =
                        (split ? pAlo : pAhi) + (pvbase + r) * KPAD + cc * 64 + c8 * 8;
                    uint4 v = *(const uint4*)src;
                    *(uint4*)(smem + split * A_SPLIT + r * 128 + ((c8 ^ (r & 7)) << 4)) = v;
                }
            }

            for (int t9 = 0; t9 < 9; t9++) {
                cpa_wait0();
                __syncthreads();
                if (t9 < 8) {
                    const __nv_bfloat16* bs =
                        wB + (size_t)((dx * 9 + t9 + 1) * NCH + cc) * 12288;
                    uint32_t dst = sb + ((t9 & 1) ? SM_B0 : SM_B1);
                    #pragma unroll
                    for (int t = tid; t < 1536; t += 256)
                        cpa16(dst + t * 16, bs + t * 8);
                    cpa_commit();
                }
                uint32_t bbase = sb + ((t9 & 1) ? SM_B1 : SM_B0);
                int toff = (t9 / 3) * PAD + (t9 % 3);

                #pragma unroll
                for (int kk = 0; kk < 4; kk++) {
                    uint32_t ah[2][4], al[2][4], bh[3][4], bl[3][4];
                    #pragma unroll
                    for (int mi = 0; mi < 2; mi++) {
                        int r = rb[mi] + toff;
                        int kc = kk * 2 + a_khalf;
                        uint32_t off = (uint32_t)r * 128 + (uint32_t)((kc ^ (r & 7)) << 4);
                        ldsm4(ah[mi], sb + off);
                        ldsm4(al[mi], sb + A_SPLIT + off);
                    }
                    #pragma unroll
                    for (int ni = 0; ni < 3; ni++) {
                        int r = brow[ni];
                        int kc = kk * 2 + b_khalf;
                        uint32_t off = (uint32_t)r * 128 + (uint32_t)((kc ^ (r & 7)) << 4);
                        ldsm4(bh[ni], bbase + off);
                        ldsm4(bl[ni], bbase + 12288 + off);
                    }
                    #pragma unroll
                    for (int mi = 0; mi < 2; mi++) {
                        #pragma unroll
                        for (int nj = 0; nj < 6; nj++) {
                            const uint32_t* bfh = &bh[nj >> 1][(nj & 1) * 2];
                            const uint32_t* bfl = &bl[nj >> 1][(nj & 1) * 2];
                            mma16816(acc[mi][nj], ah[mi], bfh);
                            mma16816(acc[mi][nj], ah[mi], bfl);
                            mma16816(acc[mi][nj], al[mi], bfh);
                        }
                    }
                }
            }
        }
    }

    #pragma unroll
    for (int mi = 0; mi < 2; mi++) {
        #pragma unroll
        for (int half = 0; half < 2; half++) {
            int r = m_off + mi * 16 + (lane >> 2) + half * 8;
            int j = r >> 5, z = r & 31;
            size_t vbase = ((size_t)(x * GRES + y0 + j) * GRES + z) * 96;
            #pragma unroll
            for (int nj = 0; nj < 6; nj++) {
                int co = n_off + nj * 8 + 2 * (lane & 3);
                float2 v = make_float2(acc[mi][nj][half * 2], acc[mi][nj][half * 2 + 1]);
                *(float2*)(&g_conv[vbase + co]) = v;
            }
        }
    }
}

// ======================= fused linear GEMM + devox epilogue ==================
// Block: 128 points x 96 couts. A = [x1 | x2*scale2] fp32 rows split to bf16
// hi/lo in smem; B = pre-split linear weights; epilogue adds 8-nb devox gather
// from g_conv + bias (+tanh) and writes the stage output.
#define L_AHI 0
#define L_ALO 16384
#define L_B0  32768
#define L_B1  57344
#define L_TOT 81920

template<int KPAD, int NCH>
__global__ void __launch_bounds__(256, 2) lindevox_k(
    const float* __restrict__ x1, const float* __restrict__ x2,
    const float* __restrict__ scale2, const __nv_bfloat16* __restrict__ wB,
    const float* __restrict__ bias, float* __restrict__ out, int do_tanh) {
    extern __shared__ char smem[];
    uint32_t sb = smem_u32(smem);
    int tid = threadIdx.x;
    int warp = tid >> 5, lane = tid & 31;
    int m_off = (warp & 3) * 32;
    int n_off = (warp >> 2) * 48;
    int pbase = blockIdx.x * 128;

    float acc[2][6][4];
    #pragma unroll
    for (int mi = 0; mi < 2; mi++)
        #pragma unroll
        for (int nj = 0; nj < 6; nj++)
            #pragma unroll
            for (int e = 0; e < 4; e++) acc[mi][nj][e] = 0.f;

    int a_row_in = (lane & 7) + ((lane >> 3) & 1) * 8;
    int a_khalf  = lane >> 4;
    int b_row_in = (lane & 7) + ((lane >> 3) >> 1) * 8;
    int b_khalf  = (lane >> 3) & 1;
    int brow[3];
    #pragma unroll
    for (int ni = 0; ni < 3; ni++) brow[ni] = n_off + ni * 16 + b_row_in;

    // prefetch B chunk 0
    #pragma unroll
    for (int t = tid; t < 1536; t += 256)
        cpa16(sb + L_B0 + t * 16, wB + t * 8);
    cpa_commit();

    for (int ch = 0; ch < NCH; ch++) {
        if (ch) __syncthreads();   // prior compute done before A restage
        // ---- stage A chunk: fp32 -> bf16 hi/lo, swizzled ----
        #pragma unroll
        for (int g = 0; g < 4; g++) {
            int gidx = tid + g * 256;
            int r = gidx >> 3, c8 = gidx & 7;
            int p = pbase + r;
            int colbase = ch * 64 + c8 * 8;
            float v[8];
            bool have = (p < NPTS) && (colbase < ((KPAD == 128) ? 96 : 192));
            if (have) {
                const float* srcp;
                float m = 1.f;
                if (colbase < 96) srcp = x1 + (size_t)p * 96 + colbase;
                else {
                    srcp = x2 + (size_t)p * 96 + (colbase - 96);
                    if (scale2) m = scale2[p];
                }
                float4 aa = *(const float4*)srcp;
                float4 bb = *(const float4*)(srcp + 4);
                v[0]=aa.x*m; v[1]=aa.y*m; v[2]=aa.z*m; v[3]=aa.w*m;
                v[4]=bb.x*m; v[5]=bb.y*m; v[6]=bb.z*m; v[7]=bb.w*m;
            } else {
                #pragma unroll
                for (int e = 0; e < 8; e++) v[e] = 0.f;
            }
            uint4 hv, lv;
            uint32_t* hp = (uint32_t*)&hv;
            uint32_t* lp = (uint32_t*)&lv;
            #pragma unroll
            for (int e = 0; e < 4; e++) {
                __nv_bfloat16 h0 = __float2bfloat16(v[2*e]);
                __nv_bfloat16 h1 = __float2bfloat16(v[2*e+1]);
                __nv_bfloat16 l0 = __float2bfloat16(v[2*e]   - __bfloat162float(h0));
                __nv_bfloat16 l1 = __float2bfloat16(v[2*e+1] - __bfloat162float(h1));
                __nv_bfloat162 hh; hh.x = h0; hh.y = h1;
                __nv_bfloat162 ll; ll.x = l0; ll.y = l1;
                hp[e] = *(uint32_t*)&hh;
                lp[e] = *(uint32_t*)&ll;
            }
            uint32_t addr = (uint32_t)r * 128 + (uint32_t)((c8 ^ (r & 7)) << 4);
            *(uint4*)(smem + L_AHI + addr) = hv;
            *(uint4*)(smem + L_ALO + addr) = lv;
        }
        // prefetch next B, wait current
        if (ch + 1 < NCH) {
            const __nv_bfloat16* bs = wB + (size_t)(ch + 1) * 12288;
            uint32_t dst = sb + ((ch & 1) ? L_B0 : L_B1);
            #pragma unroll
            for (int t = tid; t < 1536; t += 256)
                cpa16(dst + t * 16, bs + t * 8);
            cpa_commit();
            cpa_wait1();
        } else {
            cpa_wait0();
        }
        __syncthreads();

        uint32_t bbase = sb + ((ch & 1) ? L_B1 : L_B0);
        #pragma unroll
        for (int kk = 0; kk < 4; kk++) {
            uint32_t ah[2][4], al[2][4], bh[3][4], bl[3][4];
            #pragma unroll
            for (int mi = 0; mi < 2; mi++) {
                int r = m_off + mi * 16 + a_row_in;
                int kc = kk * 2 + a_khalf;
                uint32_t off = (uint32_t)r * 128 + (uint32_t)((kc ^ (r & 7)) << 4);
                ldsm4(ah[mi], sb + L_AHI + off);
                ldsm4(al[mi], sb + L_ALO + off);
            }
            #pragma unroll
            for (int ni = 0; ni < 3; ni++) {
                int r = brow[ni];
                int kc = kk * 2 + b_khalf;
                uint32_t off = (uint32_t)r * 128 + (uint32_t)((kc ^ (r & 7)) << 4);
                ldsm4(bh[ni], bbase + off);
                ldsm4(bl[ni], bbase + 12288 + off);
            }
            #pragma unroll
            for (int mi = 0; mi < 2; mi++) {
                #pragma unroll
                for (int nj = 0; nj < 6; nj++) {
                    const uint32_t* bfh = &bh[nj >> 1][(nj & 1) * 2];
                    const uint32_t* bfl = &bl[nj >> 1][(nj & 1) * 2];
                    mma16816(acc[mi][nj], ah[mi], bfh);
                    mma16816(acc[mi][nj], ah[mi], bfl);
                    mma16816(acc[mi][nj], al[mi], bfh);
                }
            }
        }
    }

    // ---- epilogue: devox gather + bias (+ tanh) + store ----
    #pragma unroll
    for (int mi = 0; mi < 2; mi++) {
        #pragma unroll
        for (int half = 0; half < 2; half++) {
            int r = m_off + mi * 16 + (lane >> 2) + half * 8;
            int p = pbase + r;
            if (p >= NPTS) continue;
            #pragma unroll
            for (int j = 0; j < 8; j++) {
                float w = g_nbw[j*NPTS + p];
                if (w != 0.f) {
                    const float* gp = g_conv + (size_t)g_nbi[j*NPTS + p] * 96;
                    #pragma unroll
                    for (int nj = 0; nj < 6; nj++) {
                        int co = n_off + nj * 8 + 2 * (lane & 3);
                        float2 gg = *(const float2*)(gp + co);
                        acc[mi][nj][half*2]   += w * gg.x;
                        acc[mi][nj][half*2+1] += w * gg.y;
                    }
                }
            }
            #pragma unroll
            for (int nj = 0; nj < 6; nj++) {
                int co = n_off + nj * 8 + 2 * (lane & 3);
                float2 bb = *(const float2*)(bias + co);
                float vx = acc[mi][nj][half*2]   + bb.x;
                float vy = acc[mi][nj][half*2+1] + bb.y;
                if (do_tanh) { vx = tanhf(vx); vy = tanhf(vy); }
                *(float2*)(out + (size_t)p * 96 + co) = make_float2(vx, vy);
            }
        }
    }
}

// ======================= cout=1 conv (v_conv), float4 ========================
__global__ void conv1_k() {
    int v = blockIdx.x * blockDim.x + threadIdx.x;
    if (v >= G3) return;
    int px = v >> 10, py = (v >> 5) & 31, pz = v & 31;
    float acc = 0.f;
    for (int kx = 0; kx < 3; kx++) {
        int nx = px + kx - 1;
        if ((unsigned)nx >= GRES) continue;
        for (int ky = 0; ky < 3; ky++) {
            int ny = py + ky - 1;
            if ((unsigned)ny >= GRES) continue;
            for (int kz = 0; kz < 3; kz++) {
                int nz = pz + kz - 1;
                if ((unsigned)nz >= GRES) continue;
                int nf = ((nx<<5) + ny)*32 + nz;
                const float4* ip = (const float4*)&g_grid[(size_t)nf * CDIM];
                const float4* wp = (const float4*)&g_vT[((kx*3 + ky)*3 + kz) * CDIM];
                float a = 0.f;
                #pragma unroll 6
                for (int c4 = 0; c4 < 24; c4++) {
                    float4 iv = ip[c4], wv = wp[c4];
                    a += iv.x*wv.x + iv.y*wv.y + iv.z*wv.z + iv.w*wv.w;
                }
                acc += a;
            }
        }
    }
    g_vout[v] = acc;
}

__global__ void attn_k(const float* __restrict__ energy,
                       const float* __restrict__ v_lw, const float* __restrict__ v_lb) {
    int p = blockIdx.x * blockDim.x + threadIdx.x;
    if (p >= NPTS) return;
    float acc = v_lb[0];
    #pragma unroll
    for (int j = 0; j < 8; j++) {
        float w = g_nbw[j*NPTS + p];
        if (w != 0.f) acc += w * g_vout[g_nbi[j*NPTS + p]];
    }
    const float* er = energy + (size_t)p * CDIM;
    #pragma unroll 8
    for (int ci = 0; ci < CDIM; ci++) acc += er[ci] * v_lw[ci];
    g_attn[p] = acc;
}

// ======================= host orchestration =================================
extern "C" void kernel_launch(void* const* d_in, const int* in_sizes, int n_in,
                              void* d_out, int out_size) {
    const float* hidden   = (const float*)d_in[0];
    const float* query    = (const float*)d_in[1];
    const float* coords   = (const float*)d_in[2];
    const float* wq_conv  = (const float*)d_in[3];
    const float* wq_lw    = (const float*)d_in[4];
    const float* wq_lb    = (const float*)d_in[5];
    const float* wh_conv  = (const float*)d_in[6];
    const float* wh_lw    = (const float*)d_in[7];
    const float* wh_lb    = (const float*)d_in[8];
    const float* att_conv = (const float*)d_in[9];
    const float* att_lw   = (const float*)d_in[10];
    const float* att_lb   = (const float*)d_in[11];
    const float* v_conv   = (const float*)d_in[12];
    const float* v_lw     = (const float*)d_in[13];
    const float* v_lb     = (const float*)d_in[14];
    const float* upd_conv = (const float*)d_in[15];
    const float* upd_lw   = (const float*)d_in[16];
    const float* upd_lb   = (const float*)d_in[17];
    float* out = (float*)d_out;

    int *picnt;
    float *pq, *ph, *pe, *pattn, *pvT;
    __nv_bfloat16 *pwqB, *pwhB, *pattB, *pupdB;
    __nv_bfloat16 *pwqlB, *pwhlB, *pattlB, *pupdlB;
    __nv_bfloat16 *pA96h, *pA96l, *pA192h, *pA192l;
    cudaGetSymbolAddress((void**)&picnt,  g_icnt);
    cudaGetSymbolAddress((void**)&pq,     g_q);
    cudaGetSymbolAddress((void**)&ph,     g_h);
    cudaGetSymbolAddress((void**)&pe,     g_energy);
    cudaGetSymbolAddress((void**)&pattn,  g_attn);
    cudaGetSymbolAddress((void**)&pvT,    g_vT);
    cudaGetSymbolAddress((void**)&pwqB,   g_wqB);
    cudaGetSymbolAddress((void**)&pwhB,   g_whB);
    cudaGetSymbolAddress((void**)&pattB,  g_attB);
    cudaGetSymbolAddress((void**)&pupdB,  g_updB);
    cudaGetSymbolAddress((void**)&pwqlB,  g_wqlB);
    cudaGetSymbolAddress((void**)&pwhlB,  g_whlB);
    cudaGetSymbolAddress((void**)&pattlB, g_attlB);
    cudaGetSymbolAddress((void**)&pupdlB, g_updlB);
    cudaGetSymbolAddress((void**)&pA96h,  g_pA96_hi);
    cudaGetSymbolAddress((void**)&pA96l,  g_pA96_lo);
    cudaGetSymbolAddress((void**)&pA192h, g_pA192_hi);
    cudaGetSymbolAddress((void**)&pA192l, g_pA192_lo);

    cudaFuncSetAttribute(conv_mma_k<128,2>, cudaFuncAttributeMaxDynamicSharedMemorySize, SM_TOT);
    cudaFuncSetAttribute(conv_mma_k<192,3>, cudaFuncAttributeMaxDynamicSharedMemorySize, SM_TOT);
    cudaFuncSetAttribute(lindevox_k<128,2>, cudaFuncAttributeMaxDynamicSharedMemorySize, L_TOT);
    cudaFuncSetAttribute(lindevox_k<192,3>, cudaFuncAttributeMaxDynamicSharedMemorySize, L_TOT);

    const int TB = 256;
    auto gs = [](long long n, int tb){ return (int)((n + tb - 1) / tb); };
    const int LBLK = (NPTS + 127) / 128;   // 782

    // --- shared precompute: counting sort + trilinear + pad-zero ---
    zeroi_k<<<gs(G3,TB), TB>>>(picnt, G3);
    vox_k<<<gs(NPTS,TB), TB>>>(coords);
    scan_k<<<1, 1024>>>();
    fill_k<<<gs(NPTS,TB), TB>>>();
    trilin_k<<<gs(NPTS,TB), TB>>>(coords);
    zerob_k<<<gs((long long)PGV*128/8,TB), TB>>>(pA96h,  PGV*128);
    zerob_k<<<gs((long long)PGV*128/8,TB), TB>>>(pA96l,  PGV*128);
    zerob_k<<<gs((long long)PGV*192/8,TB), TB>>>(pA192h, PGV*192);
    zerob_k<<<gs((long long)PGV*192/8,TB), TB>>>(pA192l, PGV*192);

    // --- weight prep ---
    prep_wB_k<96,128,2><<<gs(27LL*128*96,TB), TB>>>(wq_conv, pwqB);
    prep_wB_k<96,128,2><<<gs(27LL*128*96,TB), TB>>>(wh_conv, pwhB);
    prep_wB_k<192,192,3><<<gs(27LL*192*96,TB), TB>>>(att_conv, pattB);
    prep_wB_k<192,192,3><<<gs(27LL*192*96,TB), TB>>>(upd_conv, pupdB);
    prep_wlB_k<96,128><<<gs(128LL*96,TB), TB>>>(wq_lw,  pwqlB);
    prep_wlB_k<96,128><<<gs(128LL*96,TB), TB>>>(wh_lw,  pwhlB);
    prep_wlB_k<192,192><<<gs(192LL*96,TB), TB>>>(att_lw, pattlB);
    prep_wlB_k<192,192><<<gs(192LL*96,TB), TB>>>(upd_lw, pupdlB);
    tconv_k<<<gs(96*27,TB), TB>>>(v_conv, pvT, 96, 1);

    // --- sconv q ---
    gathervox_k<96,128><<<gs((long long)G3*24,TB), TB>>>(query, nullptr, nullptr, pA96h, pA96l);
    conv_mma_k<128,2><<<256, 256, SM_TOT>>>(pwqB, pA96h, pA96l);
    lindevox_k<128,2><<<LBLK, 256, L_TOT>>>(query, nullptr, nullptr, pwqlB, wq_lb, pq, 0);

    // --- sconv h ---
    gathervox_k<96,128><<<gs((long long)G3*24,TB), TB>>>(hidden, nullptr, nullptr, pA96h, pA96l);
    conv_mma_k<128,2><<<256, 256, SM_TOT>>>(pwhB, pA96h, pA96l);
    lindevox_k<128,2><<<LBLK, 256, L_TOT>>>(hidden, nullptr, nullptr, pwhlB, wh_lb, ph, 0);

    // --- energy = tanh(sconv([h, q])) ---
    gathervox_k<192,192><<<gs((long long)G3*48,TB), TB>>>(ph, pq, nullptr, pA192h, pA192l);
    conv_mma_k<192,3><<<256, 256, SM_TOT>>>(pattB, pA192h, pA192l);
    lindevox_k<192,3><<<LBLK, 256, L_TOT>>>(ph, pq, nullptr, pattlB, att_lb, pe, 1);

    // --- attn = sconv(energy), cout=1 ---
    voxf32_k<<<gs((long long)G3*24,TB), TB>>>(pe);
    conv1_k<<<gs(G3,TB), TB>>>();
    attn_k<<<gs(NPTS,TB), TB>>>(pe, v_lw, v_lb);

    // --- out = tanh(sconv([q, attn*h])) ---
    gathervox_k<192,192><<<gs((long long)G3*48,TB), TB>>>(pq, ph, pattn, pA192h, pA192l);
    conv_mma_k<192,3><<<256, 256, SM_TOT>>>(pupdB, pA192h, pA192l);
    lindevox_k<192,3><<<LBLK, 256, L_TOT>>>(pq, ph, pattn, pupdlB, upd_lb, out, 1);
}

// round 8
// speedup vs baseline: 4.6238x; 1.0259x over previous
#include <cuda_runtime.h>
#include <cuda_bf16.h>
#include <cstdint>
#include <math.h>

#define NPTS 100000
#define CDIM 96
#define GRES 32
#define G3   (GRES*GRES*GRES)
#define PAD  34
#define PP2  (PAD*PAD)
#define PGV  (PP2*PAD)

// ======================= scratch (device globals) ===========================
__device__ int   g_vidx[NPTS];
__device__ int   g_icnt[G3];
__device__ int   g_start[G3+1];
__device__ int   g_pos[G3];
__device__ int   g_sorted[NPTS];
__device__ int   g_nbi[8*NPTS];
__device__ float g_nbw[8*NPTS];
__device__ float g_grid[G3*CDIM];       // fp32 meaned grid (attn stage only)
__device__ float g_conv[G3*CDIM];
__device__ float g_conv2[G3*CDIM];
__device__ float g_vout[G3];
__device__ float g_q[NPTS*CDIM];
__device__ float g_h[NPTS*CDIM];
__device__ float g_energy[NPTS*CDIM];
__device__ float g_attn[NPTS];
// padded bf16 split grids (borders/pad-channels zeroed once per call)
__device__ __nv_bfloat16 g_pA96_hi [PGV*128];   // voxelized query input
__device__ __nv_bfloat16 g_pA96_lo [PGV*128];
__device__ __nv_bfloat16 g_pB96_hi [PGV*128];   // voxelized hidden input
__device__ __nv_bfloat16 g_pB96_lo [PGV*128];
__device__ __nv_bfloat16 g_pA192_hi[PGV*192];
__device__ __nv_bfloat16 g_pA192_lo[PGV*192];
// cached voxelized q_out (interior), reused stage3 -> stage5
__device__ __nv_bfloat16 g_pQ96_hi[PGV*96];
__device__ __nv_bfloat16 g_pQ96_lo[PGV*96];
// pre-swizzled split conv weights: [tap*nch+chunk][split(2)][6144 = 96 rows x 64 ci]
__device__ __nv_bfloat16 g_wqB [27*2*2*6144];
__device__ __nv_bfloat16 g_whB [27*2*2*6144];
__device__ __nv_bfloat16 g_attB[27*3*2*6144];
__device__ __nv_bfloat16 g_updB[27*3*2*6144];
// pre-swizzled split linear weights: [chunk][split(2)][6144]
__device__ __nv_bfloat16 g_wqlB [2*2*6144];
__device__ __nv_bfloat16 g_whlB [2*2*6144];
__device__ __nv_bfloat16 g_attlB[3*2*6144];
__device__ __nv_bfloat16 g_updlB[3*2*6144];
__device__ float g_vT[27*CDIM];

// ======================= mma/ldmatrix/cp.async helpers =======================
__device__ __forceinline__ uint32_t smem_u32(const void* p) {
    uint32_t a;
    asm("{ .reg .u64 t; cvta.to.shared.u64 t, %1; cvt.u32.u64 %0, t; }" : "=r"(a) : "l"(p));
    return a;
}
__device__ __forceinline__ void ldsm4(uint32_t* r, uint32_t addr) {
    asm volatile("ldmatrix.sync.aligned.m8n8.x4.shared.b16 {%0,%1,%2,%3}, [%4];"
        : "=r"(r[0]), "=r"(r[1]), "=r"(r[2]), "=r"(r[3]) : "r"(addr));
}
__device__ __forceinline__ void mma16816(float* c, const uint32_t* a, const uint32_t* b) {
    asm volatile("mma.sync.aligned.m16n8k16.row.col.f32.bf16.bf16.f32 "
        "{%0,%1,%2,%3}, {%4,%5,%6,%7}, {%8,%9}, {%0,%1,%2,%3};"
        : "+f"(c[0]), "+f"(c[1]), "+f"(c[2]), "+f"(c[3])
        : "r"(a[0]), "r"(a[1]), "r"(a[2]), "r"(a[3]), "r"(b[0]), "r"(b[1]));
}
__device__ __forceinline__ void cpa16(uint32_t dst, const void* src) {
    asm volatile("cp.async.cg.shared.global [%0], [%1], 16;" :: "r"(dst), "l"(src));
}
__device__ __forceinline__ void cpa_commit() { asm volatile("cp.async.commit_group;"); }
__device__ __forceinline__ void cpa_wait0()  { asm volatile("cp.async.wait_group 0;"); }
__device__ __forceinline__ void cpa_wait1()  { asm volatile("cp.async.wait_group 1;"); }

// ======================= sort/index kernels ==================================
__global__ void zeroi_k(int* __restrict__ p, int n) {
    int i = blockIdx.x * blockDim.x + threadIdx.x;
    if (i < n) p[i] = 0;
}
__global__ void zerob_k(__nv_bfloat16* __restrict__ p, int n16) {
    int i = blockIdx.x * blockDim.x + threadIdx.x;
    if (i < n16 / 8) ((uint4*)p)[i] = make_uint4(0u, 0u, 0u, 0u);
}

__global__ void vox_k(const float* __restrict__ coords) {
    int p = blockIdx.x * blockDim.x + threadIdx.x;
    if (p >= NPTS) return;
    int vx = min(max((int)floorf(coords[3*p+0]), 0), GRES-1);
    int vy = min(max((int)floorf(coords[3*p+1]), 0), GRES-1);
    int vz = min(max((int)floorf(coords[3*p+2]), 0), GRES-1);
    int flat = (vx*GRES + vy)*GRES + vz;
    g_vidx[p] = flat;
    atomicAdd(&g_icnt[flat], 1);
}

__global__ void __launch_bounds__(1024) scan_k() {
    __shared__ int bs[1024];
    int t = threadIdx.x;
    int base = t * 32;
    int loc[32];
    int s = 0;
    #pragma unroll
    for (int k = 0; k < 32; k++) { loc[k] = s; s += g_icnt[base + k]; }
    bs[t] = s;
    __syncthreads();
    #pragma unroll
    for (int d = 1; d < 1024; d <<= 1) {
        int v = (t >= d) ? bs[t - d] : 0;
        __syncthreads();
        bs[t] += v;
        __syncthreads();
    }
    int off = bs[t] - s;
    #pragma unroll
    for (int k = 0; k < 32; k++) {
        g_start[base + k] = off + loc[k];
        g_pos[base + k]   = off + loc[k];
    }
    if (t == 1023) g_start[G3] = off + s;
}

__global__ void fill_k() {
    int p = blockIdx.x * blockDim.x + threadIdx.x;
    if (p >= NPTS) return;
    int slot = atomicAdd(&g_pos[g_vidx[p]], 1);
    g_sorted[slot] = p;
}

__global__ void trilin_k(const float* __restrict__ coords) {
    int p = blockIdx.x * blockDim.x + threadIdx.x;
    if (p >= NPTS) return;
    float cx = coords[3*p+0], cy = coords[3*p+1], cz = coords[3*p+2];
    float bx = floorf(cx), by = floorf(cy), bz = floorf(cz);
    float fx = cx - bx, fy = cy - by, fz = cz - bz;
    int ix = (int)bx, iy = (int)by, iz = (int)bz;
    #pragma unroll
    for (int j = 0; j < 8; j++) {
        int dx = (j >> 2) & 1, dy = (j >> 1) & 1, dz = j & 1;
        int nx = ix + dx, ny = iy + dy, nz = iz + dz;
        bool valid = (nx >= 0 && nx < GRES && ny >= 0 && ny < GRES && nz >= 0 && nz < GRES);
        int cxc = min(max(nx,0),GRES-1), cyc = min(max(ny,0),GRES-1), czc = min(max(nz,0),GRES-1);
        int flc = (cxc*GRES + cyc)*GRES + czc;
        float w = (dx ? fx : 1.f-fx) * (dy ? fy : 1.f-fy) * (dz ? fz : 1.f-fz);
        if (!valid || g_icnt[flc] == 0) w = 0.f;
        g_nbi[j*NPTS + p] = flc;
        g_nbw[j*NPTS + p] = w;
    }
}

// ======================= gather-voxelize helpers =============================
__device__ __forceinline__ void bf16_split_store4(
    float4 acc, __nv_bfloat16* dhi, __nv_bfloat16* dlo, size_t o) {
    __nv_bfloat16 h0 = __float2bfloat16(acc.x), h1 = __float2bfloat16(acc.y);
    __nv_bfloat16 h2 = __float2bfloat16(acc.z), h3 = __float2bfloat16(acc.w);
    __nv_bfloat16 l0 = __float2bfloat16(acc.x - __bfloat162float(h0));
    __nv_bfloat16 l1 = __float2bfloat16(acc.y - __bfloat162float(h1));
    __nv_bfloat16 l2 = __float2bfloat16(acc.z - __bfloat162float(h2));
    __nv_bfloat16 l3 = __float2bfloat16(acc.w - __bfloat162float(h3));
    __nv_bfloat162 hA; hA.x = h0; hA.y = h1;
    __nv_bfloat162 hB; hB.x = h2; hB.y = h3;
    __nv_bfloat162 lA; lA.x = l0; lA.y = l1;
    __nv_bfloat162 lB; lB.x = l2; lB.y = l3;
    *(__nv_bfloat162*)(dhi + o)     = hA;
    *(__nv_bfloat162*)(dhi + o + 2) = hB;
    *(__nv_bfloat162*)(dlo + o)     = lA;
    *(__nv_bfloat162*)(dlo + o + 2) = lB;
}

// merged q+h INPUT voxelize: first G3*24 units -> pA96 (query), second -> pB96 (hidden)
__global__ void gathervox_qh_k(const float* __restrict__ q, const float* __restrict__ h) {
    int i = blockIdx.x * blockDim.x + threadIdx.x;
    if (i >= 2 * G3 * 24) return;
    bool sec = (i >= G3 * 24);
    int j = sec ? i - G3 * 24 : i;
    int c4 = j % 24;
    int v  = j / 24;
    int vx = v >> 10, vy = (v >> 5) & 31, vz = v & 31;
    int pv = ((vx + 1) * PAD + (vy + 1)) * PAD + (vz + 1);
    int ci = c4 * 4;
    const float* src = sec ? h : q;

    float4 acc = make_float4(0.f, 0.f, 0.f, 0.f);
    int s0 = g_start[v], s1 = g_start[v+1];
    if (s1 > s0) {
        for (int k = s0; k < s1; k++) {
            int pid = g_sorted[k];
            float4 f = *(const float4*)(src + (size_t)pid * 96 + ci);
            acc.x += f.x; acc.y += f.y; acc.z += f.z; acc.w += f.w;
        }
        float invn = 1.f / (float)(s1 - s0);
        acc.x *= invn; acc.y *= invn; acc.z *= invn; acc.w *= invn;
    }
    bf16_split_store4(acc,
        sec ? g_pB96_hi : g_pA96_hi, sec ? g_pB96_lo : g_pA96_lo,
        (size_t)pv * 128 + ci);
}

// stage-3 voxelize of OUTPUTS: pA192 = [mean(h_out) | mean(q_out)],
// also caches mean(q_out) into pQ96 for stage-5 reuse.
__global__ void gathervox192_k(const float* __restrict__ h, const float* __restrict__ q) {
    int i = blockIdx.x * blockDim.x + threadIdx.x;
    if (i >= 2 * G3 * 24) return;
    bool sec = (i >= G3 * 24);   // sec = q half
    int j = sec ? i - G3 * 24 : i;
    int c4 = j % 24;
    int v  = j / 24;
    int vx = v >> 10, vy = (v >> 5) & 31, vz = v & 31;
    int pv = ((vx + 1) * PAD + (vy + 1)) * PAD + (vz + 1);
    int ci = c4 * 4;
    const float* src = sec ? q : h;

    float4 acc = make_float4(0.f, 0.f, 0.f, 0.f);
    int s0 = g_start[v], s1 = g_start[v+1];
    if (s1 > s0) {
        for (int k = s0; k < s1; k++) {
            int pid = g_sorted[k];
            float4 f = *(const float4*)(src + (size_t)pid * 96 + ci);
            acc.x += f.x; acc.y += f.y; acc.z += f.z; acc.w += f.w;
        }
        float invn = 1.f / (float)(s1 - s0);
        acc.x *= invn; acc.y *= invn; acc.z *= invn; acc.w *= invn;
    }
    if (!sec) {
        bf16_split_store4(acc, g_pA192_hi, g_pA192_lo, (size_t)pv * 192 + ci);
    } else {
        bf16_split_store4(acc, g_pA192_hi, g_pA192_lo, (size_t)pv * 192 + 96 + ci);
        bf16_split_store4(acc, g_pQ96_hi, g_pQ96_lo, (size_t)pv * 96 + ci);
    }
}

// stage-5 first half: pA192[0:96] = cached mean(q_out) grid (interior copy)
__global__ void mkq_k() {
    int i = blockIdx.x * blockDim.x + threadIdx.x;
    if (i >= G3 * 12) return;
    int u = i % 12;
    int v = i / 12;
    int vx = v >> 10, vy = (v >> 5) & 31, vz = v & 31;
    int pv = ((vx + 1) * PAD + (vy + 1)) * PAD + (vz + 1);
    size_t s = (size_t)pv * 96 + u * 8;
    size_t d = (size_t)pv * 192 + u * 8;
    *(uint4*)(g_pA192_hi + d) = *(const uint4*)(g_pQ96_hi + s);
    *(uint4*)(g_pA192_lo + d) = *(const uint4*)(g_pQ96_lo + s);
}

// stage-5 second half: pA192[96:192] = mean(attn_p * h_p)
__global__ void gathervox_sc_k(const float* __restrict__ h, const float* __restrict__ scale) {
    int i = blockIdx.x * blockDim.x + threadIdx.x;
    if (i >= G3 * 24) return;
    int c4 = i % 24;
    int v  = i / 24;
    int vx = v >> 10, vy = (v >> 5) & 31, vz = v & 31;
    int pv = ((vx + 1) * PAD + (vy + 1)) * PAD + (vz + 1);
    int ci = c4 * 4;

    float4 acc = make_float4(0.f, 0.f, 0.f, 0.f);
    int s0 = g_start[v], s1 = g_start[v+1];
    if (s1 > s0) {
        for (int k = s0; k < s1; k++) {
            int pid = g_sorted[k];
            float4 f = *(const float4*)(h + (size_t)pid * 96 + ci);
            float m = scale[pid];
            acc.x += f.x * m; acc.y += f.y * m; acc.z += f.z * m; acc.w += f.w * m;
        }
        float invn = 1.f / (float)(s1 - s0);
        acc.x *= invn; acc.y *= invn; acc.z *= invn; acc.w *= invn;
    }
    bf16_split_store4(acc, g_pA192_hi, g_pA192_lo, (size_t)pv * 192 + 96 + ci);
}

// fp32 gather-voxelize (mean) into g_grid — attn stage
__global__ void voxf32_k(const float* __restrict__ src) {
    int i = blockIdx.x * blockDim.x + threadIdx.x;
    if (i >= G3 * 24) return;
    int c4 = i % 24;
    int v  = i / 24;
    int ci = c4 * 4;
    int s0 = g_start[v], s1 = g_start[v+1];
    float4 acc = make_float4(0.f, 0.f, 0.f, 0.f);
    if (s1 > s0) {
        for (int k = s0; k < s1; k++) {
            int pid = g_sorted[k];
            float4 f = *(const float4*)(src + (size_t)pid * 96 + ci);
            acc.x += f.x; acc.y += f.y; acc.z += f.z; acc.w += f.w;
        }
        float invn = 1.f / (float)(s1 - s0);
        acc.x *= invn; acc.y *= invn; acc.z *= invn; acc.w *= invn;
    }
    *(float4*)(g_grid + (size_t)v * 96 + ci) = acc;
}

// ======================= weight prep =========================================
template<int CIN, int KPAD, int NCH>
__global__ void prep_wB_k(const float* __restrict__ w, __nv_bfloat16* __restrict__ dst) {
    int i = blockIdx.x * blockDim.x + threadIdx.x;
    if (i >= 27 * KPAD * 96) return;
    int co  = i % 96;
    int r   = i / 96;
    int ci  = r % KPAD;
    int tap = r / KPAD;
    float val = (ci < CIN) ? w[((size_t)co * CIN + ci) * 27 + tap] : 0.f;
    __nv_bfloat16 hi = __float2bfloat16(val);
    __nv_bfloat16 lo = __float2bfloat16(val - __bfloat162float(hi));
    int chunk = ci >> 6;
    int cw = ci & 63;
    uint32_t elem = (uint32_t)co * 64 + (uint32_t)(((cw >> 3) ^ (co & 7)) * 8) + (cw & 7);
    size_t base = (size_t)(tap * NCH + chunk) * 2 * 6144;
    dst[base + elem] = hi;
    dst[base + 6144 + elem] = lo;
}

template<int CIN, int KPAD>
__global__ void prep_wlB_k(const float* __restrict__ w, __nv_bfloat16* __restrict__ dst) {
    int i = blockIdx.x * blockDim.x + threadIdx.x;
    if (i >= KPAD * 96) return;
    int co = i % 96;
    int ci = i / 96;
    float val = (ci < CIN) ? w[(size_t)co * CIN + ci] : 0.f;
    __nv_bfloat16 hi = __float2bfloat16(val);
    __nv_bfloat16 lo = __float2bfloat16(val - __bfloat162float(hi));
    int chunk = ci >> 6;
    int cw = ci & 63;
    uint32_t elem = (uint32_t)co * 64 + (uint32_t)(((cw >> 3) ^ (co & 7)) * 8) + (cw & 7);
    size_t base = (size_t)chunk * 2 * 6144;
    dst[base + elem] = hi;
    dst[base + 6144 + elem] = lo;
}

__global__ void tconv_k(const float* __restrict__ w, float* __restrict__ wT, int cin, int cout) {
    int i = blockIdx.x * blockDim.x + threadIdx.x;
    int total = cout * cin * 27;
    if (i >= total) return;
    int k  = i % 27;
    int r  = i / 27;
    int ci = r % cin;
    int co = r / cin;
    wT[(k*cin + ci)*cout + co] = w[i];
}

// ======================= HMMA 3x3x3 conv (slab A, dual-job) =================
#define A_SPLIT 26112            // 204 rows * 128B
#define SM_B0   52224
#define SM_B1   76800
#define SM_TOT  101376

template<int KPAD, int NCH>
__global__ void __launch_bounds__(256, 2) conv_mma_k(
    const __nv_bfloat16* __restrict__ wBa, const __nv_bfloat16* __restrict__ pAhiA,
    const __nv_bfloat16* __restrict__ pAloA, float* __restrict__ outA,
    const __nv_bfloat16* __restrict__ wBb, const __nv_bfloat16* __restrict__ pAhiB,
    const __nv_bfloat16* __restrict__ pAloB, float* __restrict__ outB,
    int split_blk) {
    extern __shared__ char smem[];
    uint32_t sb = smem_u32(smem);
    int tid = threadIdx.x;
    int warp = tid >> 5, lane = tid & 31;
    int m_off = (warp & 3) * 32;
    int n_off = (warp >> 2) * 48;

    int blk = blockIdx.x;
    bool sec = (blk >= split_blk);
    if (sec) blk -= split_blk;
    const __nv_bfloat16* wB   = sec ? wBb   : wBa;
    const __nv_bfloat16* pAhi = sec ? pAhiB : pAhiA;
    const __nv_bfloat16* pAlo = sec ? pAloB : pAloA;
    float* outp = sec ? outB : outA;

    int x  = blk >> 3;
    int y0 = (blk & 7) * 4;

    float acc[2][6][4];
    #pragma unroll
    for (int mi = 0; mi < 2; mi++)
        #pragma unroll
        for (int nj = 0; nj < 6; nj++)
            #pragma unroll
            for (int e = 0; e < 4; e++) acc[mi][nj][e] = 0.f;

    int a_row_in = (lane & 7) + ((lane >> 3) & 1) * 8;
    int a_khalf  = lane >> 4;
    int b_row_in = (lane & 7) + ((lane >> 3) >> 1) * 8;
    int b_khalf  = (lane >> 3) & 1;

    int rb[2];
    #pragma unroll
    for (int mi = 0; mi < 2; mi++) {
        int m = m_off + mi * 16 + a_row_in;
        rb[mi] = (m >> 5) * 34 + (m & 31);
    }
    int brow[3];
    #pragma unroll
    for (int ni = 0; ni < 3; ni++) brow[ni] = n_off + ni * 16 + b_row_in;

    for (int cc = 0; cc < NCH; cc++) {
        for (int dx = 0; dx < 3; dx++) {
            __syncthreads();

            {
                const __nv_bfloat16* bs = wB + (size_t)((dx * 9) * NCH + cc) * 12288;
                #pragma unroll
                for (int t = tid; t < 1536; t += 256)
                    cpa16(sb + SM_B0 + t * 16, bs + t * 8);
                cpa_commit();
            }
            {
                size_t pvbase = ((size_t)(x + dx) * PAD + y0) * PAD;
                #pragma unroll
                for (int t = tid; t < 3264; t += 256) {
                    int split = (t >= 1632);
                    int e = split ? t - 1632 : t;
                    int r = e >> 3, c8 = e & 7;
                    const __nv_bfloat16* src =
                        (split ? pAlo : pAhi) + (pvbase + r) * KPAD + cc * 64 + c8 * 8;
                    uint4 v = *(const uint4*)src;
                    *(uint4*)(smem + split * A_SPLIT + r * 128 + ((c8 ^ (r & 7)) << 4)) = v;
                }
            }

            for (int t9 = 0; t9 < 9; t9++) {
                cpa_wait0();
                __syncthreads();
                if (t9 < 8) {
                    const __nv_bfloat16* bs =
                        wB + (size_t)((dx * 9 + t9 + 1) * NCH + cc) * 12288;
                    uint32_t dst = sb + ((t9 & 1) ? SM_B0 : SM_B1);
                    #pragma unroll
                    for (int t = tid; t < 1536; t += 256)
                        cpa16(dst + t * 16, bs + t * 8);
                    cpa_commit();
                }
                uint32_t bbase = sb + ((t9 & 1) ? SM_B1 : SM_B0);
                int toff = (t9 / 3) * PAD + (t9 % 3);

                #pragma unroll
                for (int kk = 0; kk < 4; kk++) {
                    uint32_t ah[2][4], al[2][4], bh[3][4], bl[3][4];
                    #pragma unroll
                    for (int mi = 0; mi < 2; mi++) {
                        int r = rb[mi] + toff;
                        int kc = kk * 2 + a_khalf;
                        uint32_t off = (uint32_t)r * 128 + (uint32_t)((kc ^ (r & 7)) << 4);
                        ldsm4(ah[mi], sb + off);
                        ldsm4(al[mi], sb + A_SPLIT + off);
                    }
                    #pragma unroll
                    for (int ni = 0; ni < 3; ni++) {
                        int r = brow[ni];
                        int kc = kk * 2 + b_khalf;
                        uint32_t off = (uint32_t)r * 128 + (uint32_t)((kc ^ (r & 7)) << 4);
                        ldsm4(bh[ni], bbase + off);
                        ldsm4(bl[ni], bbase + 12288 + off);
                    }
                    #pragma unroll
                    for (int mi = 0; mi < 2; mi++) {
                        #pragma unroll
                        for (int nj = 0; nj < 6; nj++) {
                            const uint32_t* bfh = &bh[nj >> 1][(nj & 1) * 2];
                            const uint32_t* bfl = &bl[nj >> 1][(nj & 1) * 2];
                            mma16816(acc[mi][nj], ah[mi], bfh);
                            mma16816(acc[mi][nj], ah[mi], bfl);
                            mma16816(acc[mi][nj], al[mi], bfh);
                        }
                    }
                }
            }
        }
    }

    #pragma unroll
    for (int mi = 0; mi < 2; mi++) {
        #pragma unroll
        for (int half = 0; half < 2; half++) {
            int r = m_off + mi * 16 + (lane >> 2) + half * 8;
            int j = r >> 5, z = r & 31;
            size_t vbase = ((size_t)(x * GRES + y0 + j) * GRES + z) * 96;
            #pragma unroll
            for (int nj = 0; nj < 6; nj++) {
                int co = n_off + nj * 8 + 2 * (lane & 3);
                float2 v = make_float2(acc[mi][nj][half * 2], acc[mi][nj][half * 2 + 1]);
                *(float2*)(&outp[vbase + co]) = v;
            }
        }
    }
}

// ======================= fused linear GEMM + devox epilogue (dual) ===========
#define L_AHI 0
#define L_ALO 16384
#define L_B0  32768
#define L_B1  57344
#define L_TOT 81920

template<int KPAD, int NCH>
__global__ void __launch_bounds__(256, 2) lindevox_k(
    const float* __restrict__ x1a, const float* __restrict__ x2a,
    const float* __restrict__ s2a, const __nv_bfloat16* __restrict__ wBa,
    const float* __restrict__ biasa, const float* __restrict__ convA,
    float* __restrict__ outa,
    const float* __restrict__ x1b, const float* __restrict__ x2b,
    const float* __restrict__ s2b, const __nv_bfloat16* __restrict__ wBb,
    const float* __restrict__ biasb, const float* __restrict__ convB,
    float* __restrict__ outb,
    int split_blk, int do_tanh) {
    extern __shared__ char smem[];
    uint32_t sb = smem_u32(smem);
    int tid = threadIdx.x;
    int warp = tid >> 5, lane = tid & 31;
    int m_off = (warp & 3) * 32;
    int n_off = (warp >> 2) * 48;

    int blk = blockIdx.x;
    bool sec = (blk >= split_blk);
    if (sec) blk -= split_blk;
    const float* x1 = sec ? x1b : x1a;
    const float* x2 = sec ? x2b : x2a;
    const float* scale2 = sec ? s2b : s2a;
    const __nv_bfloat16* wB = sec ? wBb : wBa;
    const float* bias = sec ? biasb : biasa;
    const float* convsrc = sec ? convB : convA;
    float* out = sec ? outb : outa;
    int pbase = blk * 128;

    float acc[2][6][4];
    #pragma unroll
    for (int mi = 0; mi < 2; mi++)
        #pragma unroll
        for (int nj = 0; nj < 6; nj++)
            #pragma unroll
            for (int e = 0; e < 4; e++) acc[mi][nj][e] = 0.f;

    int a_row_in = (lane & 7) + ((lane >> 3) & 1) * 8;
    int a_khalf  = lane >> 4;
    int b_row_in = (lane & 7) + ((lane >> 3) >> 1) * 8;
    int b_khalf  = (lane >> 3) & 1;
    int brow[3];
    #pragma unroll
    for (int ni = 0; ni < 3; ni++) brow[ni] = n_off + ni * 16 + b_row_in;

    #pragma unroll
    for (int t = tid; t < 1536; t += 256)
        cpa16(sb + L_B0 + t * 16, wB + t * 8);
    cpa_commit();

    for (int ch = 0; ch < NCH; ch++) {
        if (ch) __syncthreads();
        #pragma unroll
        for (int g = 0; g < 4; g++) {
            int gidx = tid + g * 256;
            int r = gidx >> 3, c8 = gidx & 7;
            int p = pbase + r;
            int colbase = ch * 64 + c8 * 8;
            float v[8];
            bool have = (p < NPTS) && (colbase < ((KPAD == 128) ? 96 : 192));
            if (have) {
                const float* srcp;
                float m = 1.f;
                if (colbase < 96) srcp = x1 + (size_t)p * 96 + colbase;
                else {
                    srcp = x2 + (size_t)p * 96 + (colbase - 96);
                    if (scale2) m = scale2[p];
                }
                float4 aa = *(const float4*)srcp;
                float4 bb = *(const float4*)(srcp + 4);
                v[0]=aa.x*m; v[1]=aa.y*m; v[2]=aa.z*m; v[3]=aa.w*m;
                v[4]=bb.x*m; v[5]=bb.y*m; v[6]=bb.z*m; v[7]=bb.w*m;
            } else {
                #pragma unroll
                for (int e = 0; e < 8; e++) v[e] = 0.f;
            }
            uint4 hv, lv;
            uint32_t* hp = (uint32_t*)&hv;
            uint32_t* lp = (uint32_t*)&lv;
            #pragma unroll
            for (int e = 0; e < 4; e++) {
                __nv_bfloat16 h0 = __float2bfloat16(v[2*e]);
                __nv_bfloat16 h1 = __float2bfloat16(v[2*e+1]);
                __nv_bfloat16 l0 = __float2bfloat16(v[2*e]   - __bfloat162float(h0));
                __nv_bfloat16 l1 = __float2bfloat16(v[2*e+1] - __bfloat162float(h1));
                __nv_bfloat162 hh; hh.x = h0; hh.y = h1;
                __nv_bfloat162 ll; ll.x = l0; ll.y = l1;
                hp[e] = *(uint32_t*)&hh;
                lp[e] = *(uint32_t*)&ll;
            }
            uint32_t addr = (uint32_t)r * 128 + (uint32_t)((c8 ^ (r & 7)) << 4);
            *(uint4*)(smem + L_AHI + addr) = hv;
            *(uint4*)(smem + L_ALO + addr) = lv;
        }
        if (ch + 1 < NCH) {
            const __nv_bfloat16* bs = wB + (size_t)(ch + 1) * 12288;
            uint32_t dst = sb + ((ch & 1) ? L_B0 : L_B1);
            #pragma unroll
            for (int t = tid; t < 1536; t += 256)
                cpa16(dst + t * 16, bs + t * 8);
            cpa_commit();
            cpa_wait1();
        } else {
            cpa_wait0();
        }
        __syncthreads();

        uint32_t bbase = sb + ((ch & 1) ? L_B1 : L_B0);
        #pragma unroll
        for (int kk = 0; kk < 4; kk++) {
            uint32_t ah[2][4], al[2][4], bh[3][4], bl[3][4];
            #pragma unroll
            for (int mi = 0; mi < 2; mi++) {
                int r = m_off + mi * 16 + a_row_in;
                int kc = kk * 2 + a_khalf;
                uint32_t off = (uint32_t)r * 128 + (uint32_t)((kc ^ (r & 7)) << 4);
                ldsm4(ah[mi], sb + L_AHI + off);
                ldsm4(al[mi], sb + L_ALO + off);
            }
            #pragma unroll
            for (int ni = 0; ni < 3; ni++) {
                int r = brow[ni];
                int kc = kk * 2 + b_khalf;
                uint32_t off = (uint32_t)r * 128 + (uint32_t)((kc ^ (r & 7)) << 4);
                ldsm4(bh[ni], bbase + off);
                ldsm4(bl[ni], bbase + 12288 + off);
            }
            #pragma unroll
            for (int mi = 0; mi < 2; mi++) {
                #pragma unroll
                for (int nj = 0; nj < 6; nj++) {
                    const uint32_t* bfh = &bh[nj >> 1][(nj & 1) * 2];
                    const uint32_t* bfl = &bl[nj >> 1][(nj & 1) * 2];
                    mma16816(acc[mi][nj], ah[mi], bfh);
                    mma16816(acc[mi][nj], ah[mi], bfl);
                    mma16816(acc[mi][nj], al[mi], bfh);
                }
            }
        }
    }

    #pragma unroll
    for (int mi = 0; mi < 2; mi++) {
        #pragma unroll
        for (int half = 0; half < 2; half++) {
            int r = m_off + mi * 16 + (lane >> 2) + half * 8;
            int p = pbase + r;
            if (p >= NPTS) continue;
            #pragma unroll
            for (int j = 0; j < 8; j++) {
                float w = g_nbw[j*NPTS + p];
                if (w != 0.f) {
                    const float* gp = convsrc + (size_t)g_nbi[j*NPTS + p] * 96;
                    #pragma unroll
                    for (int nj = 0; nj < 6; nj++) {
                        int co = n_off + nj * 8 + 2 * (lane & 3);
                        float2 gg = *(const float2*)(gp + co);
                        acc[mi][nj][half*2]   += w * gg.x;
                        acc[mi][nj][half*2+1] += w * gg.y;
                    }
                }
            }
            #pragma unroll
            for (int nj = 0; nj < 6; nj++) {
                int co = n_off + nj * 8 + 2 * (lane & 3);
                float2 bb = *(const float2*)(bias + co);
                float vx = acc[mi][nj][half*2]   + bb.x;
                float vy = acc[mi][nj][half*2+1] + bb.y;
                if (do_tanh) { vx = tanhf(vx); vy = tanhf(vy); }
                *(float2*)(out + (size_t)p * 96 + co) = make_float2(vx, vy);
            }
        }
    }
}

// ======================= cout=1 conv (v_conv), float4 ========================
__global__ void conv1_k() {
    int v = blockIdx.x * blockDim.x + threadIdx.x;
    if (v >= G3) return;
    int px = v >> 10, py = (v >> 5) & 31, pz = v & 31;
    float acc = 0.f;
    for (int kx = 0; kx < 3; kx++) {
        int nx = px + kx - 1;
        if ((unsigned)nx >= GRES) continue;
        for (int ky = 0; ky < 3; ky++) {
            int ny = py + ky - 1;
            if ((unsigned)ny >= GRES) continue;
            for (int kz = 0; kz < 3; kz++) {
                int nz = pz + kz - 1;
                if ((unsigned)nz >= GRES) continue;
                int nf = ((nx<<5) + ny)*32 + nz;
                const float4* ip = (const float4*)&g_grid[(size_t)nf * CDIM];
                const float4* wp = (const float4*)&g_vT[((kx*3 + ky)*3 + kz) * CDIM];
                float a = 0.f;
                #pragma unroll 6
                for (int c4 = 0; c4 < 24; c4++) {
                    float4 iv = ip[c4], wv = wp[c4];
                    a += iv.x*wv.x + iv.y*wv.y + iv.z*wv.z + iv.w*wv.w;
                }
                acc += a;
            }
        }
    }
    g_vout[v] = acc;
}

__global__ void attn_k(const float* __restrict__ energy,
                       const float* __restrict__ v_lw, const float* __restrict__ v_lb) {
    int p = blockIdx.x * blockDim.x + threadIdx.x;
    if (p >= NPTS) return;
    float acc = v_lb[0];
    #pragma unroll
    for (int j = 0; j < 8; j++) {
        float w = g_nbw[j*NPTS + p];
        if (w != 0.f) acc += w * g_vout[g_nbi[j*NPTS + p]];
    }
    const float* er = energy + (size_t)p * CDIM;
    #pragma unroll 8
    for (int ci = 0; ci < CDIM; ci++) acc += er[ci] * v_lw[ci];
    g_attn[p] = acc;
}

// ======================= host orchestration =================================
extern "C" void kernel_launch(void* const* d_in, const int* in_sizes, int n_in,
                              void* d_out, int out_size) {
    const float* hidden   = (const float*)d_in[0];
    const float* query    = (const float*)d_in[1];
    const float* coords   = (const float*)d_in[2];
    const float* wq_conv  = (const float*)d_in[3];
    const float* wq_lw    = (const float*)d_in[4];
    const float* wq_lb    = (const float*)d_in[5];
    const float* wh_conv  = (const float*)d_in[6];
    const float* wh_lw    = (const float*)d_in[7];
    const float* wh_lb    = (const float*)d_in[8];
    const float* att_conv = (const float*)d_in[9];
    const float* att_lw   = (const float*)d_in[10];
    const float* att_lb   = (const float*)d_in[11];
    const float* v_conv   = (const float*)d_in[12];
    const float* v_lw     = (const float*)d_in[13];
    const float* v_lb     = (const float*)d_in[14];
    const float* upd_conv = (const float*)d_in[15];
    const float* upd_lw   = (const float*)d_in[16];
    const float* upd_lb   = (const float*)d_in[17];
    float* out = (float*)d_out;

    int *picnt;
    float *pq, *ph, *pe, *pattn, *pvT, *pconv, *pconv2;
    __nv_bfloat16 *pwqB, *pwhB, *pattB, *pupdB;
    __nv_bfloat16 *pwqlB, *pwhlB, *pattlB, *pupdlB;
    __nv_bfloat16 *pA96h, *pA96l, *pB96h, *pB96l, *pA192h, *pA192l;
    cudaGetSymbolAddress((void**)&picnt,  g_icnt);
    cudaGetSymbolAddress((void**)&pq,     g_q);
    cudaGetSymbolAddress((void**)&ph,     g_h);
    cudaGetSymbolAddress((void**)&pe,     g_energy);
    cudaGetSymbolAddress((void**)&pattn,  g_attn);
    cudaGetSymbolAddress((void**)&pvT,    g_vT);
    cudaGetSymbolAddress((void**)&pconv,  g_conv);
    cudaGetSymbolAddress((void**)&pconv2, g_conv2);
    cudaGetSymbolAddress((void**)&pwqB,   g_wqB);
    cudaGetSymbolAddress((void**)&pwhB,   g_whB);
    cudaGetSymbolAddress((void**)&pattB,  g_attB);
    cudaGetSymbolAddress((void**)&pupdB,  g_updB);
    cudaGetSymbolAddress((void**)&pwqlB,  g_wqlB);
    cudaGetSymbolAddress((void**)&pwhlB,  g_whlB);
    cudaGetSymbolAddress((void**)&pattlB, g_attlB);
    cudaGetSymbolAddress((void**)&pupdlB, g_updlB);
    cudaGetSymbolAddress((void**)&pA96h,  g_pA96_hi);
    cudaGetSymbolAddress((void**)&pA96l,  g_pA96_lo);
    cudaGetSymbolAddress((void**)&pB96h,  g_pB96_hi);
    cudaGetSymbolAddress((void**)&pB96l,  g_pB96_lo);
    cudaGetSymbolAddress((void**)&pA192h, g_pA192_hi);
    cudaGetSymbolAddress((void**)&pA192l, g_pA192_lo);

    cudaFuncSetAttribute(conv_mma_k<128,2>, cudaFuncAttributeMaxDynamicSharedMemorySize, SM_TOT);
    cudaFuncSetAttribute(conv_mma_k<192,3>, cudaFuncAttributeMaxDynamicSharedMemorySize, SM_TOT);
    cudaFuncSetAttribute(lindevox_k<128,2>, cudaFuncAttributeMaxDynamicSharedMemorySize, L_TOT);
    cudaFuncSetAttribute(lindevox_k<192,3>, cudaFuncAttributeMaxDynamicSharedMemorySize, L_TOT);

    const int TB = 256;
    auto gs = [](long long n, int tb){ return (int)((n + tb - 1) / tb); };
    const int LBLK = (NPTS + 127) / 128;   // 782

    // --- shared precompute: counting sort + trilinear + pad-zero ---
    zeroi_k<<<gs(G3,TB), TB>>>(picnt, G3);
    vox_k<<<gs(NPTS,TB), TB>>>(coords);
    scan_k<<<1, 1024>>>();
    fill_k<<<gs(NPTS,TB), TB>>>();
    trilin_k<<<gs(NPTS,TB), TB>>>(coords);
    zerob_k<<<gs((long long)PGV*128/8,TB), TB>>>(pA96h,  PGV*128);
    zerob_k<<<gs((long long)PGV*128/8,TB), TB>>>(pA96l,  PGV*128);
    zerob_k<<<gs((long long)PGV*128/8,TB), TB>>>(pB96h,  PGV*128);
    zerob_k<<<gs((long long)PGV*128/8,TB), TB>>>(pB96l,  PGV*128);
    zerob_k<<<gs((long long)PGV*192/8,TB), TB>>>(pA192h, PGV*192);
    zerob_k<<<gs((long long)PGV*192/8,TB), TB>>>(pA192l, PGV*192);

    // --- weight prep ---
    prep_wB_k<96,128,2><<<gs(27LL*128*96,TB), TB>>>(wq_conv, pwqB);
    prep_wB_k<96,128,2><<<gs(27LL*128*96,TB), TB>>>(wh_conv, pwhB);
    prep_wB_k<192,192,3><<<gs(27LL*192*96,TB), TB>>>(att_conv, pattB);
    prep_wB_k<192,192,3><<<gs(27LL*192*96,TB), TB>>>(upd_conv, pupdB);
    prep_wlB_k<96,128><<<gs(128LL*96,TB), TB>>>(wq_lw,  pwqlB);
    prep_wlB_k<96,128><<<gs(128LL*96,TB), TB>>>(wh_lw,  pwhlB);
    prep_wlB_k<192,192><<<gs(192LL*96,TB), TB>>>(att_lw, pattlB);
    prep_wlB_k<192,192><<<gs(192LL*96,TB), TB>>>(upd_lw, pupdlB);
    tconv_k<<<gs(96*27,TB), TB>>>(v_conv, pvT, 96, 1);

    // --- merged sconv q + sconv h (voxelize INPUTS) ---
    gathervox_qh_k<<<gs(2LL*G3*24,TB), TB>>>(query, hidden);
    conv_mma_k<128,2><<<512, 256, SM_TOT>>>(pwqB, pA96h, pA96l, pconv,
                                            pwhB, pB96h, pB96l, pconv2, 256);
    lindevox_k<128,2><<<2*LBLK, 256, L_TOT>>>(
        query, nullptr, nullptr, pwqlB, wq_lb, pconv, pq,
        hidden, nullptr, nullptr, pwhlB, wh_lb, pconv2, ph, LBLK, 0);

    // --- energy = tanh(sconv([h, q])) --- voxelize OUTPUTS fresh (+cache q grid)
    gathervox192_k<<<gs(2LL*G3*24,TB), TB>>>(ph, pq);
    conv_mma_k<192,3><<<256, 256, SM_TOT>>>(pattB, pA192h, pA192l, pconv,
                                            pattB, pA192h, pA192l, pconv, 256);
    lindevox_k<192,3><<<LBLK, 256, L_TOT>>>(
        ph, pq, nullptr, pattlB, att_lb, pconv, pe,
        ph, pq, nullptr, pattlB, att_lb, pconv, pe, LBLK, 1);

    // --- attn = sconv(energy), cout=1 ---
    voxf32_k<<<gs((long long)G3*24,TB), TB>>>(pe);
    conv1_k<<<gs(G3,TB), TB>>>();
    attn_k<<<gs(NPTS,TB), TB>>>(pe, v_lw, v_lb);

    // --- out = tanh(sconv([q, attn*h])) --- q half from cache, attn*h fresh
    mkq_k<<<gs((long long)G3*12,TB), TB>>>();
    gathervox_sc_k<<<gs((long long)G3*24,TB), TB>>>(ph, pattn);
    conv_mma_k<192,3><<<256, 256, SM_TOT>>>(pupdB, pA192h, pA192l, pconv,
                                            pupdB, pA192h, pA192l, pconv, 256);
    lindevox_k<192,3><<<LBLK, 256, L_TOT>>>(
        pq, ph, pattn, pupdlB, upd_lb, pconv, out,
        pq, ph, pattn, pupdlB, upd_lb, pconv, out, LBLK, 1);
}

// round 9
// speedup vs baseline: 4.8622x; 1.0516x over previous
#include <cuda_runtime.h>
#include <cuda_bf16.h>
#include <cstdint>
#include <math.h>

#define NPTS 100000
#define CDIM 96
#define GRES 32
#define G3   (GRES*GRES*GRES)
#define PAD  34
#define PP2  (PAD*PAD)
#define PGV  (PP2*PAD)

// ======================= scratch (device globals) ===========================
__device__ int   g_vidx[NPTS];
__device__ int   g_icnt[G3];
__device__ int   g_start[G3+1];
__device__ int   g_pos[G3];
__device__ int   g_sorted[NPTS];
__device__ int   g_rank[NPTS];
__device__ int   g_nbi[8*NPTS];       // indexed by SORTED slot
__device__ float g_nbw[8*NPTS];       // indexed by SORTED slot
__device__ float g_grid[G3*CDIM];     // fp32 meaned grid (attn stage only)
__device__ float g_P[27*G3];          // per-tap dot products (attn stage)
__device__ float g_conv[G3*CDIM];
__device__ float g_conv2[G3*CDIM];
__device__ float g_vout[G3];
__device__ float g_q[NPTS*CDIM];
__device__ float g_h[NPTS*CDIM];
__device__ float g_energy[NPTS*CDIM];
__device__ float g_attn[NPTS];
// padded bf16 split grids (borders/pad-channels zeroed once per call)
__device__ __nv_bfloat16 g_pA96_hi [PGV*128];   // voxelized query input
__device__ __nv_bfloat16 g_pA96_lo [PGV*128];
__device__ __nv_bfloat16 g_pB96_hi [PGV*128];   // voxelized hidden input
__device__ __nv_bfloat16 g_pB96_lo [PGV*128];
__device__ __nv_bfloat16 g_pA192_hi[PGV*192];
__device__ __nv_bfloat16 g_pA192_lo[PGV*192];
// cached voxelized q_out (interior), reused stage3 -> stage5
__device__ __nv_bfloat16 g_pQ96_hi[PGV*96];
__device__ __nv_bfloat16 g_pQ96_lo[PGV*96];
// pre-swizzled split conv weights: [tap*nch+chunk][split(2)][6144 = 96 rows x 64 ci]
__device__ __nv_bfloat16 g_wqB [27*2*2*6144];
__device__ __nv_bfloat16 g_whB [27*2*2*6144];
__device__ __nv_bfloat16 g_attB[27*3*2*6144];
__device__ __nv_bfloat16 g_updB[27*3*2*6144];
// pre-swizzled split linear weights: [chunk][split(2)][6144]
__device__ __nv_bfloat16 g_wqlB [2*2*6144];
__device__ __nv_bfloat16 g_whlB [2*2*6144];
__device__ __nv_bfloat16 g_attlB[3*2*6144];
__device__ __nv_bfloat16 g_updlB[3*2*6144];
__device__ float g_vT[27*CDIM];

// ======================= mma/ldmatrix/cp.async helpers =======================
__device__ __forceinline__ uint32_t smem_u32(const void* p) {
    uint32_t a;
    asm("{ .reg .u64 t; cvta.to.shared.u64 t, %1; cvt.u32.u64 %0, t; }" : "=r"(a) : "l"(p));
    return a;
}
__device__ __forceinline__ void ldsm4(uint32_t* r, uint32_t addr) {
    asm volatile("ldmatrix.sync.aligned.m8n8.x4.shared.b16 {%0,%1,%2,%3}, [%4];"
        : "=r"(r[0]), "=r"(r[1]), "=r"(r[2]), "=r"(r[3]) : "r"(addr));
}
__device__ __forceinline__ void mma16816(float* c, const uint32_t* a, const uint32_t* b) {
    asm volatile("mma.sync.aligned.m16n8k16.row.col.f32.bf16.bf16.f32 "
        "{%0,%1,%2,%3}, {%4,%5,%6,%7}, {%8,%9}, {%0,%1,%2,%3};"
        : "+f"(c[0]), "+f"(c[1]), "+f"(c[2]), "+f"(c[3])
        : "r"(a[0]), "r"(a[1]), "r"(a[2]), "r"(a[3]), "r"(b[0]), "r"(b[1]));
}
__device__ __forceinline__ void cpa16(uint32_t dst, const void* src) {
    asm volatile("cp.async.cg.shared.global [%0], [%1], 16;" :: "r"(dst), "l"(src));
}
__device__ __forceinline__ void cpa_commit() { asm volatile("cp.async.commit_group;"); }
__device__ __forceinline__ void cpa_wait0()  { asm volatile("cp.async.wait_group 0;"); }
__device__ __forceinline__ void cpa_wait1()  { asm volatile("cp.async.wait_group 1;"); }

// ======================= sort/index kernels ==================================
__global__ void zeroi_k(int* __restrict__ p, int n) {
    int i = blockIdx.x * blockDim.x + threadIdx.x;
    if (i < n) p[i] = 0;
}
// merged zero of all 6 padded grids (unit = uint4 = 8 bf16)
__global__ void zero6_k(__nv_bfloat16* a, __nv_bfloat16* b, __nv_bfloat16* c,
                        __nv_bfloat16* d, __nv_bfloat16* e, __nv_bfloat16* f) {
    const int U128 = PGV * 128 / 8;     // per 128-ch buffer
    const int U192 = PGV * 192 / 8;
    long long i = (long long)blockIdx.x * blockDim.x + threadIdx.x;
    uint4 z = make_uint4(0u, 0u, 0u, 0u);
    if      (i < U128)                      ((uint4*)a)[i] = z;
    else if (i < 2LL*U128)                  ((uint4*)b)[i - U128] = z;
    else if (i < 3LL*U128)                  ((uint4*)c)[i - 2LL*U128] = z;
    else if (i < 4LL*U128)                  ((uint4*)d)[i - 3LL*U128] = z;
    else if (i < 4LL*U128 + U192)           ((uint4*)e)[i - 4LL*U128] = z;
    else if (i < 4LL*U128 + 2LL*U192)       ((uint4*)f)[i - 4LL*U128 - U192] = z;
}

__global__ void vox_k(const float* __restrict__ coords) {
    int p = blockIdx.x * blockDim.x + threadIdx.x;
    if (p >= NPTS) return;
    int vx = min(max((int)floorf(coords[3*p+0]), 0), GRES-1);
    int vy = min(max((int)floorf(coords[3*p+1]), 0), GRES-1);
    int vz = min(max((int)floorf(coords[3*p+2]), 0), GRES-1);
    int flat = (vx*GRES + vy)*GRES + vz;
    g_vidx[p] = flat;
    atomicAdd(&g_icnt[flat], 1);
}

__global__ void __launch_bounds__(1024) scan_k() {
    __shared__ int bs[1024];
    int t = threadIdx.x;
    int base = t * 32;
    int loc[32];
    int s = 0;
    #pragma unroll
    for (int k = 0; k < 32; k++) { loc[k] = s; s += g_icnt[base + k]; }
    bs[t] = s;
    __syncthreads();
    #pragma unroll
    for (int d = 1; d < 1024; d <<= 1) {
        int v = (t >= d) ? bs[t - d] : 0;
        __syncthreads();
        bs[t] += v;
        __syncthreads();
    }
    int off = bs[t] - s;
    #pragma unroll
    for (int k = 0; k < 32; k++) {
        g_start[base + k] = off + loc[k];
        g_pos[base + k]   = off + loc[k];
    }
    if (t == 1023) g_start[G3] = off + s;
}

__global__ void fill_k() {
    int p = blockIdx.x * blockDim.x + threadIdx.x;
    if (p >= NPTS) return;
    int slot = atomicAdd(&g_pos[g_vidx[p]], 1);
    g_sorted[slot] = p;
    g_rank[p] = slot;
}

// writes nb arrays in SORTED-slot order
__global__ void trilin_k(const float* __restrict__ coords) {
    int p = blockIdx.x * blockDim.x + threadIdx.x;
    if (p >= NPTS) return;
    int s = g_rank[p];
    float cx = coords[3*p+0], cy = coords[3*p+1], cz = coords[3*p+2];
    float bx = floorf(cx), by = floorf(cy), bz = floorf(cz);
    float fx = cx - bx, fy = cy - by, fz = cz - bz;
    int ix = (int)bx, iy = (int)by, iz = (int)bz;
    #pragma unroll
    for (int j = 0; j < 8; j++) {
        int dx = (j >> 2) & 1, dy = (j >> 1) & 1, dz = j & 1;
        int nx = ix + dx, ny = iy + dy, nz = iz + dz;
        bool valid = (nx >= 0 && nx < GRES && ny >= 0 && ny < GRES && nz >= 0 && nz < GRES);
        int cxc = min(max(nx,0),GRES-1), cyc = min(max(ny,0),GRES-1), czc = min(max(nz,0),GRES-1);
        int flc = (cxc*GRES + cyc)*GRES + czc;
        float w = (dx ? fx : 1.f-fx) * (dy ? fy : 1.f-fy) * (dz ? fz : 1.f-fz);
        if (!valid || g_icnt[flc] == 0) w = 0.f;
        g_nbi[j*NPTS + s] = flc;
        g_nbw[j*NPTS + s] = w;
    }
}

// ======================= gather-voxelize helpers =============================
__device__ __forceinline__ void bf16_split_store4(
    float4 acc, __nv_bfloat16* dhi, __nv_bfloat16* dlo, size_t o) {
    __nv_bfloat16 h0 = __float2bfloat16(acc.x), h1 = __float2bfloat16(acc.y);
    __nv_bfloat16 h2 = __float2bfloat16(acc.z), h3 = __float2bfloat16(acc.w);
    __nv_bfloat16 l0 = __float2bfloat16(acc.x - __bfloat162float(h0));
    __nv_bfloat16 l1 = __float2bfloat16(acc.y - __bfloat162float(h1));
    __nv_bfloat16 l2 = __float2bfloat16(acc.z - __bfloat162float(h2));
    __nv_bfloat16 l3 = __float2bfloat16(acc.w - __bfloat162float(h3));
    __nv_bfloat162 hA; hA.x = h0; hA.y = h1;
    __nv_bfloat162 hB; hB.x = h2; hB.y = h3;
    __nv_bfloat162 lA; lA.x = l0; lA.y = l1;
    __nv_bfloat162 lB; lB.x = l2; lB.y = l3;
    *(__nv_bfloat162*)(dhi + o)     = hA;
    *(__nv_bfloat162*)(dhi + o + 2) = hB;
    *(__nv_bfloat162*)(dlo + o)     = lA;
    *(__nv_bfloat162*)(dlo + o + 2) = lB;
}

// merged q+h INPUT voxelize
__global__ void gathervox_qh_k(const float* __restrict__ q, const float* __restrict__ h) {
    int i = blockIdx.x * blockDim.x + threadIdx.x;
    if (i >= 2 * G3 * 24) return;
    bool sec = (i >= G3 * 24);
    int j = sec ? i - G3 * 24 : i;
    int c4 = j % 24;
    int v  = j / 24;
    int vx = v >> 10, vy = (v >> 5) & 31, vz = v & 31;
    int pv = ((vx + 1) * PAD + (vy + 1)) * PAD + (vz + 1);
    int ci = c4 * 4;
    const float* src = sec ? h : q;

    float4 acc = make_float4(0.f, 0.f, 0.f, 0.f);
    int s0 = g_start[v], s1 = g_start[v+1];
    if (s1 > s0) {
        for (int k = s0; k < s1; k++) {
            int pid = g_sorted[k];
            float4 f = *(const float4*)(src + (size_t)pid * 96 + ci);
            acc.x += f.x; acc.y += f.y; acc.z += f.z; acc.w += f.w;
        }
        float invn = 1.f / (float)(s1 - s0);
        acc.x *= invn; acc.y *= invn; acc.z *= invn; acc.w *= invn;
    }
    bf16_split_store4(acc,
        sec ? g_pB96_hi : g_pA96_hi, sec ? g_pB96_lo : g_pA96_lo,
        (size_t)pv * 128 + ci);
}

// stage-3 voxelize of OUTPUTS: pA192 = [mean(h_out) | mean(q_out)] + cache q grid
__global__ void gathervox192_k(const float* __restrict__ h, const float* __restrict__ q) {
    int i = blockIdx.x * blockDim.x + threadIdx.x;
    if (i >= 2 * G3 * 24) return;
    bool sec = (i >= G3 * 24);   // sec = q half
    int j = sec ? i - G3 * 24 : i;
    int c4 = j % 24;
    int v  = j / 24;
    int vx = v >> 10, vy = (v >> 5) & 31, vz = v & 31;
    int pv = ((vx + 1) * PAD + (vy + 1)) * PAD + (vz + 1);
    int ci = c4 * 4;
    const float* src = sec ? q : h;

    float4 acc = make_float4(0.f, 0.f, 0.f, 0.f);
    int s0 = g_start[v], s1 = g_start[v+1];
    if (s1 > s0) {
        for (int k = s0; k < s1; k++) {
            int pid = g_sorted[k];
            float4 f = *(const float4*)(src + (size_t)pid * 96 + ci);
            acc.x += f.x; acc.y += f.y; acc.z += f.z; acc.w += f.w;
        }
        float invn = 1.f / (float)(s1 - s0);
        acc.x *= invn; acc.y *= invn; acc.z *= invn; acc.w *= invn;
    }
    if (!sec) {
        bf16_split_store4(acc, g_pA192_hi, g_pA192_lo, (size_t)pv * 192 + ci);
    } else {
        bf16_split_store4(acc, g_pA192_hi, g_pA192_lo, (size_t)pv * 192 + 96 + ci);
        bf16_split_store4(acc, g_pQ96_hi, g_pQ96_lo, (size_t)pv * 96 + ci);
    }
}

// stage-5 first half: pA192[0:96] = cached mean(q_out) grid
__global__ void mkq_k() {
    int i = blockIdx.x * blockDim.x + threadIdx.x;
    if (i >= G3 * 12) return;
    int u = i % 12;
    int v = i / 12;
    int vx = v >> 10, vy = (v >> 5) & 31, vz = v & 31;
    int pv = ((vx + 1) * PAD + (vy + 1)) * PAD + (vz + 1);
    size_t s = (size_t)pv * 96 + u * 8;
    size_t d = (size_t)pv * 192 + u * 8;
    *(uint4*)(g_pA192_hi + d) = *(const uint4*)(g_pQ96_hi + s);
    *(uint4*)(g_pA192_lo + d) = *(const uint4*)(g_pQ96_lo + s);
}

// stage-5 second half: pA192[96:192] = mean(attn_p * h_p)
__global__ void gathervox_sc_k(const float* __restrict__ h, const float* __restrict__ scale) {
    int i = blockIdx.x * blockDim.x + threadIdx.x;
    if (i >= G3 * 24) return;
    int c4 = i % 24;
    int v  = i / 24;
    int vx = v >> 10, vy = (v >> 5) & 31, vz = v & 31;
    int pv = ((vx + 1) * PAD + (vy + 1)) * PAD + (vz + 1);
    int ci = c4 * 4;

    float4 acc = make_float4(0.f, 0.f, 0.f, 0.f);
    int s0 = g_start[v], s1 = g_start[v+1];
    if (s1 > s0) {
        for (int k = s0; k < s1; k++) {
            int pid = g_sorted[k];
            float4 f = *(const float4*)(h + (size_t)pid * 96 + ci);
            float m = scale[pid];
            acc.x += f.x * m; acc.y += f.y * m; acc.z += f.z * m; acc.w += f.w * m;
        }
        float invn = 1.f / (float)(s1 - s0);
        acc.x *= invn; acc.y *= invn; acc.z *= invn; acc.w *= invn;
    }
    bf16_split_store4(acc, g_pA192_hi, g_pA192_lo, (size_t)pv * 192 + 96 + ci);
}

// fp32 gather-voxelize (mean) into g_grid — attn stage
__global__ void voxf32_k(const float* __restrict__ src) {
    int i = blockIdx.x * blockDim.x + threadIdx.x;
    if (i >= G3 * 24) return;
    int c4 = i % 24;
    int v  = i / 24;
    int ci = c4 * 4;
    int s0 = g_start[v], s1 = g_start[v+1];
    float4 acc = make_float4(0.f, 0.f, 0.f, 0.f);
    if (s1 > s0) {
        for (int k = s0; k < s1; k++) {
            int pid = g_sorted[k];
            float4 f = *(const float4*)(src + (size_t)pid * 96 + ci);
            acc.x += f.x; acc.y += f.y; acc.z += f.z; acc.w += f.w;
        }
        float invn = 1.f / (float)(s1 - s0);
        acc.x *= invn; acc.y *= invn; acc.z *= invn; acc.w *= invn;
    }
    *(float4*)(g_grid + (size_t)v * 96 + ci) = acc;
}

// ======================= weight prep =========================================
template<int CIN, int KPAD, int NCH>
__global__ void prep_wB_k(const float* __restrict__ w, __nv_bfloat16* __restrict__ dst) {
    int i = blockIdx.x * blockDim.x + threadIdx.x;
    if (i >= 27 * KPAD * 96) return;
    int co  = i % 96;
    int r   = i / 96;
    int ci  = r % KPAD;
    int tap = r / KPAD;
    float val = (ci < CIN) ? w[((size_t)co * CIN + ci) * 27 + tap] : 0.f;
    __nv_bfloat16 hi = __float2bfloat16(val);
    __nv_bfloat16 lo = __float2bfloat16(val - __bfloat162float(hi));
    int chunk = ci >> 6;
    int cw = ci & 63;
    uint32_t elem = (uint32_t)co * 64 + (uint32_t)(((cw >> 3) ^ (co & 7)) * 8) + (cw & 7);
    size_t base = (size_t)(tap * NCH + chunk) * 2 * 6144;
    dst[base + elem] = hi;
    dst[base + 6144 + elem] = lo;
}

template<int CIN, int KPAD>
__global__ void prep_wlB_k(const float* __restrict__ w, __nv_bfloat16* __restrict__ dst) {
    int i = blockIdx.x * blockDim.x + threadIdx.x;
    if (i >= KPAD * 96) return;
    int co = i % 96;
    int ci = i / 96;
    float val = (ci < CIN) ? w[(size_t)co * CIN + ci] : 0.f;
    __nv_bfloat16 hi = __float2bfloat16(val);
    __nv_bfloat16 lo = __float2bfloat16(val - __bfloat162float(hi));
    int chunk = ci >> 6;
    int cw = ci & 63;
    uint32_t elem = (uint32_t)co * 64 + (uint32_t)(((cw >> 3) ^ (co & 7)) * 8) + (cw & 7);
    size_t base = (size_t)chunk * 2 * 6144;
    dst[base + elem] = hi;
    dst[base + 6144 + elem] = lo;
}

__global__ void tconv_k(const float* __restrict__ w, float* __restrict__ wT, int cin, int cout) {
    int i = blockIdx.x * blockDim.x + threadIdx.x;
    int total = cout * cin * 27;
    if (i >= total) return;
    int k  = i % 27;
    int r  = i / 27;
    int ci = r % cin;
    int co = r / cin;
    wT[(k*cin + ci)*cout + co] = w[i];
}

// ======================= HMMA 3x3x3 conv (slab A, dual-job) =================
#define A_SPLIT 26112            // 204 rows * 128B
#define SM_B0   52224
#define SM_B1   76800
#define SM_TOT  101376

template<int KPAD, int NCH>
__global__ void __launch_bounds__(256, 2) conv_mma_k(
    const __nv_bfloat16* __restrict__ wBa, const __nv_bfloat16* __restrict__ pAhiA,
    const __nv_bfloat16* __restrict__ pAloA, float* __restrict__ outA,
    const __nv_bfloat16* __restrict__ wBb, const __nv_bfloat16* __restrict__ pAhiB,
    const __nv_bfloat16* __restrict__ pAloB, float* __restrict__ outB,
    int split_blk) {
    extern __shared__ char smem[];
    uint32_t sb = smem_u32(smem);
    int tid = threadIdx.x;
    int warp = tid >> 5, lane = tid & 31;
    int m_off = (warp & 3) * 32;
    int n_off = (warp >> 2) * 48;

    int blk = blockIdx.x;
    bool sec = (blk >= split_blk);
    if (sec) blk -= split_blk;
    const __nv_bfloat16* wB   = sec ? wBb   : wBa;
    const __nv_bfloat16* pAhi = sec ? pAhiB : pAhiA;
    const __nv_bfloat16* pAlo = sec ? pAloB : pAloA;
    float* outp = sec ? outB : outA;

    int x  = blk >> 3;
    int y0 = (blk & 7) * 4;

    float acc[2][6][4];
    #pragma unroll
    for (int mi = 0; mi < 2; mi++)
        #pragma unroll
        for (int nj = 0; nj < 6; nj++)
            #pragma unroll
            for (int e = 0; e < 4; e++) acc[mi][nj][e] = 0.f;

    int a_row_in = (lane & 7) + ((lane >> 3) & 1) * 8;
    int a_khalf  = lane >> 4;
    int b_row_in = (lane & 7) + ((lane >> 3) >> 1) * 8;
    int b_khalf  = (lane >> 3) & 1;

    int rb[2];
    #pragma unroll
    for (int mi = 0; mi < 2; mi++) {
        int m = m_off + mi * 16 + a_row_in;
        rb[mi] = (m >> 5) * 34 + (m & 31);
    }
    int brow[3];
    #pragma unroll
    for (int ni = 0; ni < 3; ni++) brow[ni] = n_off + ni * 16 + b_row_in;

    for (int cc = 0; cc < NCH; cc++) {
        for (int dx = 0; dx < 3; dx++) {
            __syncthreads();

            {
                const __nv_bfloat16* bs = wB + (size_t)((dx * 9) * NCH + cc) * 12288;
                #pragma unroll
                for (int t = tid; t < 1536; t += 256)
                    cpa16(sb + SM_B0 + t * 16, bs + t * 8);
                cpa_commit();
            }
            {
                size_t pvbase = ((size_t)(x + dx) * PAD + y0) * PAD;
                #pragma unroll
                for (int t = tid; t < 3264; t += 256) {
                    int split = (t >= 1632);
                    int e = split ? t - 1632 : t;
                    int r = e >> 3, c8 = e & 7;
                    const __nv_bfloat16* src =
                        (split ? pAlo : pAhi) + (pvbase + r) * KPAD + cc * 64 + c8 * 8;
                    uint4 v = *(const uint4*)src;
                    *(uint4*)(smem + split * A_SPLIT + r * 128 + ((c8 ^ (r & 7)) << 4)) = v;
                }
            }

            for (int t9 = 0; t9 < 9; t9++) {
                cpa_wait0();
                __syncthreads();
                if (t9 < 8) {
                    const __nv_bfloat16* bs =
                        wB + (size_t)((dx * 9 + t9 + 1) * NCH + cc) * 12288;
                    uint32_t dst = sb + ((t9 & 1) ? SM_B0 : SM_B1);
                    #pragma unroll
                    for (int t = tid; t < 1536; t += 256)
                        cpa16(dst + t * 16, bs + t * 8);
                    cpa_commit();
                }
                uint32_t bbase = sb + ((t9 & 1) ? SM_B1 : SM_B0);
                int toff = (t9 / 3) * PAD + (t9 % 3);

                #pragma unroll
                for (int kk = 0; kk < 4; kk++) {
                    uint32_t ah[2][4], al[2][4], bh[3][4], bl[3][4];
                    #pragma unroll
                    for (int mi = 0; mi < 2; mi++) {
                        int r = rb[mi] + toff;
                        int kc = kk * 2 + a_khalf;
                        uint32_t off = (uint32_t)r * 128 + (uint32_t)((kc ^ (r & 7)) << 4);
                        ldsm4(ah[mi], sb + off);
                        ldsm4(al[mi], sb + A_SPLIT + off);
                    }
                    #pragma unroll
                    for (int ni = 0; ni < 3; ni++) {
                        int r = brow[ni];
                        int kc = kk * 2 + b_khalf;
                        uint32_t off = (uint32_t)r * 128 + (uint32_t)((kc ^ (r & 7)) << 4);
                        ldsm4(bh[ni], bbase + off);
                        ldsm4(bl[ni], bbase + 12288 + off);
                    }
                    #pragma unroll
                    for (int mi = 0; mi < 2; mi++) {
                        #pragma unroll
                        for (int nj = 0; nj < 6; nj++) {
                            const uint32_t* bfh = &bh[nj >> 1][(nj & 1) * 2];
                            const uint32_t* bfl = &bl[nj >> 1][(nj & 1) * 2];
                            mma16816(acc[mi][nj], ah[mi], bfh);
                            mma16816(acc[mi][nj], ah[mi], bfl);
                            mma16816(acc[mi][nj], al[mi], bfh);
                        }
                    }
                }
            }
        }
    }

    #pragma unroll
    for (int mi = 0; mi < 2; mi++) {
        #pragma unroll
        for (int half = 0; half < 2; half++) {
            int r = m_off + mi * 16 + (lane >> 2) + half * 8;
            int j = r >> 5, z = r & 31;
            size_t vbase = ((size_t)(x * GRES + y0 + j) * GRES + z) * 96;
            #pragma unroll
            for (int nj = 0; nj < 6; nj++) {
                int co = n_off + nj * 8 + 2 * (lane & 3);
                float2 v = make_float2(acc[mi][nj][half * 2], acc[mi][nj][half * 2 + 1]);
                *(float2*)(&outp[vbase + co]) = v;
            }
        }
    }
}

// ======================= fused linear GEMM + devox epilogue (dual, SORTED) ===
#define L_AHI 0
#define L_ALO 16384
#define L_B0  32768
#define L_B1  57344
#define L_TOT 81920

template<int KPAD, int NCH>
__global__ void __launch_bounds__(256, 2) lindevox_k(
    const float* __restrict__ x1a, const float* __restrict__ x2a,
    const float* __restrict__ s2a, const __nv_bfloat16* __restrict__ wBa,
    const float* __restrict__ biasa, const float* __restrict__ convA,
    float* __restrict__ outa,
    const float* __restrict__ x1b, const float* __restrict__ x2b,
    const float* __restrict__ s2b, const __nv_bfloat16* __restrict__ wBb,
    const float* __restrict__ biasb, const float* __restrict__ convB,
    float* __restrict__ outb,
    int split_blk, int do_tanh) {
    extern __shared__ char smem[];
    uint32_t sb = smem_u32(smem);
    int tid = threadIdx.x;
    int warp = tid >> 5, lane = tid & 31;
    int m_off = (warp & 3) * 32;
    int n_off = (warp >> 2) * 48;

    int blk = blockIdx.x;
    bool sec = (blk >= split_blk);
    if (sec) blk -= split_blk;
    const float* x1 = sec ? x1b : x1a;
    const float* x2 = sec ? x2b : x2a;
    const float* scale2 = sec ? s2b : s2a;
    const __nv_bfloat16* wB = sec ? wBb : wBa;
    const float* bias = sec ? biasb : biasa;
    const float* convsrc = sec ? convB : convA;
    float* out = sec ? outb : outa;
    int pbase = blk * 128;           // SORTED slot base

    float acc[2][6][4];
    #pragma unroll
    for (int mi = 0; mi < 2; mi++)
        #pragma unroll
        for (int nj = 0; nj < 6; nj++)
            #pragma unroll
            for (int e = 0; e < 4; e++) acc[mi][nj][e] = 0.f;

    int a_row_in = (lane & 7) + ((lane >> 3) & 1) * 8;
    int a_khalf  = lane >> 4;
    int b_row_in = (lane & 7) + ((lane >> 3) >> 1) * 8;
    int b_khalf  = (lane >> 3) & 1;
    int brow[3];
    #pragma unroll
    for (int ni = 0; ni < 3; ni++) brow[ni] = n_off + ni * 16 + b_row_in;

    #pragma unroll
    for (int t = tid; t < 1536; t += 256)
        cpa16(sb + L_B0 + t * 16, wB + t * 8);
    cpa_commit();

    for (int ch = 0; ch < NCH; ch++) {
        if (ch) __syncthreads();
        #pragma unroll
        for (int g = 0; g < 4; g++) {
            int gidx = tid + g * 256;
            int r = gidx >> 3, c8 = gidx & 7;
            int slot = pbase + r;
            int colbase = ch * 64 + c8 * 8;
            float v[8];
            bool have = (slot < NPTS) && (colbase < ((KPAD == 128) ? 96 : 192));
            if (have) {
                int p = g_sorted[slot];
                const float* srcp;
                float m = 1.f;
                if (colbase < 96) srcp = x1 + (size_t)p * 96 + colbase;
                else {
                    srcp = x2 + (size_t)p * 96 + (colbase - 96);
                    if (scale2) m = scale2[p];
                }
                float4 aa = *(const float4*)srcp;
                float4 bb = *(const float4*)(srcp + 4);
                v[0]=aa.x*m; v[1]=aa.y*m; v[2]=aa.z*m; v[3]=aa.w*m;
                v[4]=bb.x*m; v[5]=bb.y*m; v[6]=bb.z*m; v[7]=bb.w*m;
            } else {
                #pragma unroll
                for (int e = 0; e < 8; e++) v[e] = 0.f;
            }
            uint4 hv, lv;
            uint32_t* hp = (uint32_t*)&hv;
            uint32_t* lp = (uint32_t*)&lv;
            #pragma unroll
            for (int e = 0; e < 4; e++) {
                __nv_bfloat16 h0 = __float2bfloat16(v[2*e]);
                __nv_bfloat16 h1 = __float2bfloat16(v[2*e+1]);
                __nv_bfloat16 l0 = __float2bfloat16(v[2*e]   - __bfloat162float(h0));
                __nv_bfloat16 l1 = __float2bfloat16(v[2*e+1] - __bfloat162float(h1));
                __nv_bfloat162 hh; hh.x = h0; hh.y = h1;
                __nv_bfloat162 ll; ll.x = l0; ll.y = l1;
                hp[e] = *(uint32_t*)&hh;
                lp[e] = *(uint32_t*)&ll;
            }
            uint32_t addr = (uint32_t)r * 128 + (uint32_t)((c8 ^ (r & 7)) << 4);
            *(uint4*)(smem + L_AHI + addr) = hv;
            *(uint4*)(smem + L_ALO + addr) = lv;
        }
        if (ch + 1 < NCH) {
            const __nv_bfloat16* bs = wB + (size_t)(ch + 1) * 12288;
            uint32_t dst = sb + ((ch & 1) ? L_B0 : L_B1);
            #pragma unroll
            for (int t = tid; t < 1536; t += 256)
                cpa16(dst + t * 16, bs + t * 8);
            cpa_commit();
            cpa_wait1();
        } else {
            cpa_wait0();
        }
        __syncthreads();

        uint32_t bbase = sb + ((ch & 1) ? L_B1 : L_B0);
        #pragma unroll
        for (int kk = 0; kk < 4; kk++) {
            uint32_t ah[2][4], al[2][4], bh[3][4], bl[3][4];
            #pragma unroll
            for (int mi = 0; mi < 2; mi++) {
                int r = m_off + mi * 16 + a_row_in;
                int kc = kk * 2 + a_khalf;
                uint32_t off = (uint32_t)r * 128 + (uint32_t)((kc ^ (r & 7)) << 4);
                ldsm4(ah[mi], sb + L_AHI + off);
                ldsm4(al[mi], sb + L_ALO + off);
            }
            #pragma unroll
            for (int ni = 0; ni < 3; ni++) {
                int r = brow[ni];
                int kc = kk * 2 + b_khalf;
                uint32_t off = (uint32_t)r * 128 + (uint32_t)((kc ^ (r & 7)) << 4);
                ldsm4(bh[ni], bbase + off);
                ldsm4(bl[ni], bbase + 12288 + off);
            }
            #pragma unroll
            for (int mi = 0; mi < 2; mi++) {
                #pragma unroll
                for (int nj = 0; nj < 6; nj++) {
                    const uint32_t* bfh = &bh[nj >> 1][(nj & 1) * 2];
                    const uint32_t* bfl = &bl[nj >> 1][(nj & 1) * 2];
                    mma16816(acc[mi][nj], ah[mi], bfh);
                    mma16816(acc[mi][nj], ah[mi], bfl);
                    mma16816(acc[mi][nj], al[mi], bfh);
                }
            }
        }
    }

    // ---- epilogue: devox gather (sorted slots -> L1 reuse) + bias + tanh ----
    #pragma unroll
    for (int mi = 0; mi < 2; mi++) {
        #pragma unroll
        for (int half = 0; half < 2; half++) {
            int r = m_off + mi * 16 + (lane >> 2) + half * 8;
            int slot = pbase + r;
            if (slot >= NPTS) continue;
            int p = g_sorted[slot];
            #pragma unroll
            for (int j = 0; j < 8; j++) {
                float w = g_nbw[j*NPTS + slot];
                if (w != 0.f) {
                    const float* gp = convsrc + (size_t)g_nbi[j*NPTS + slot] * 96;
                    #pragma unroll
                    for (int nj = 0; nj < 6; nj++) {
                        int co = n_off + nj * 8 + 2 * (lane & 3);
                        float2 gg = *(const float2*)(gp + co);
                        acc[mi][nj][half*2]   += w * gg.x;
                        acc[mi][nj][half*2+1] += w * gg.y;
                    }
                }
            }
            #pragma unroll
            for (int nj = 0; nj < 6; nj++) {
                int co = n_off + nj * 8 + 2 * (lane & 3);
                float2 bb = *(const float2*)(bias + co);
                float vx = acc[mi][nj][half*2]   + bb.x;
                float vy = acc[mi][nj][half*2+1] + bb.y;
                if (do_tanh) { vx = tanhf(vx); vy = tanhf(vy); }
                *(float2*)(out + (size_t)p * 96 + co) = make_float2(vx, vy);
            }
        }
    }
}

// ======================= attn stage: factored cout=1 conv =====================
// P[tap][u] = dot(g_grid[u,:], vT[tap,:])  (warp per voxel)
__global__ void __launch_bounds__(256) pgemm_k() {
    __shared__ float ws[27*96];
    int tid = threadIdx.x;
    for (int i = tid; i < 27*96; i += 256) ws[i] = g_vT[i];
    __syncthreads();
    int wid = tid >> 5, lane = tid & 31;
    int u = blockIdx.x * 8 + wid;
    if (u >= G3) return;
    const float* row = g_grid + (size_t)u * 96;
    float f0 = row[lane], f1 = row[lane+32], f2 = row[lane+64];
    #pragma unroll 9
    for (int t = 0; t < 27; t++) {
        float s = f0*ws[t*96+lane] + f1*ws[t*96+lane+32] + f2*ws[t*96+lane+64];
        s += __shfl_xor_sync(0xFFFFFFFF, s, 16);
        s += __shfl_xor_sync(0xFFFFFFFF, s, 8);
        s += __shfl_xor_sync(0xFFFFFFFF, s, 4);
        s += __shfl_xor_sync(0xFFFFFFFF, s, 2);
        s += __shfl_xor_sync(0xFFFFFFFF, s, 1);
        if (lane == 0) g_P[t*G3 + u] = s;
    }
}

// vout[v] = sum over valid taps of P[tap][v + offset(tap)]
__global__ void stencil_k() {
    int v = blockIdx.x * blockDim.x + threadIdx.x;
    if (v >= G3) return;
    int px = v >> 10, py = (v >> 5) & 31, pz = v & 31;
    float acc = 0.f;
    #pragma unroll
    for (int t = 0; t < 27; t++) {
        int kx = t / 9, ky = (t / 3) % 3, kz = t % 3;
        int nx = px + kx - 1, ny = py + ky - 1, nz = pz + kz - 1;
        if ((unsigned)nx < GRES && (unsigned)ny < GRES && (unsigned)nz < GRES)
            acc += g_P[t*G3 + ((nx<<5) + ny)*32 + nz];
    }
    g_vout[v] = acc;
}

__global__ void attn_k(const float* __restrict__ energy,
                       const float* __restrict__ v_lw, const float* __restrict__ v_lb) {
    int s = blockIdx.x * blockDim.x + threadIdx.x;
    if (s >= NPTS) return;
    int p = g_sorted[s];
    float acc = v_lb[0];
    #pragma unroll
    for (int j = 0; j < 8; j++) {
        float w = g_nbw[j*NPTS + s];
        if (w != 0.f) acc += w * g_vout[g_nbi[j*NPTS + s]];
    }
    const float* er = energy + (size_t)p * CDIM;
    #pragma unroll 8
    for (int ci = 0; ci < CDIM; ci++) acc += er[ci] * v_lw[ci];
    g_attn[p] = acc;
}

// ======================= host orchestration =================================
extern "C" void kernel_launch(void* const* d_in, const int* in_sizes, int n_in,
                              void* d_out, int out_size) {
    const float* hidden   = (const float*)d_in[0];
    const float* query    = (const float*)d_in[1];
    const float* coords   = (const float*)d_in[2];
    const float* wq_conv  = (const float*)d_in[3];
    const float* wq_lw    = (const float*)d_in[4];
    const float* wq_lb    = (const float*)d_in[5];
    const float* wh_conv  = (const float*)d_in[6];
    const float* wh_lw    = (const float*)d_in[7];
    const float* wh_lb    = (const float*)d_in[8];
    const float* att_conv = (const float*)d_in[9];
    const float* att_lw   = (const float*)d_in[10];
    const float* att_lb   = (const float*)d_in[11];
    const float* v_conv   = (const float*)d_in[12];
    const float* v_lw     = (const float*)d_in[13];
    const float* v_lb     = (const float*)d_in[14];
    const float* upd_conv = (const float*)d_in[15];
    const float* upd_lw   = (const float*)d_in[16];
    const float* upd_lb   = (const float*)d_in[17];
    float* out = (float*)d_out;

    int *picnt;
    float *pq, *ph, *pe, *pattn, *pvT, *pconv, *pconv2;
    __nv_bfloat16 *pwqB, *pwhB, *pattB, *pupdB;
    __nv_bfloat16 *pwqlB, *pwhlB, *pattlB, *pupdlB;
    __nv_bfloat16 *pA96h, *pA96l, *pB96h, *pB96l, *pA192h, *pA192l;
    cudaGetSymbolAddress((void**)&picnt,  g_icnt);
    cudaGetSymbolAddress((void**)&pq,     g_q);
    cudaGetSymbolAddress((void**)&ph,     g_h);
    cudaGetSymbolAddress((void**)&pe,     g_energy);
    cudaGetSymbolAddress((void**)&pattn,  g_attn);
    cudaGetSymbolAddress((void**)&pvT,    g_vT);
    cudaGetSymbolAddress((void**)&pconv,  g_conv);
    cudaGetSymbolAddress((void**)&pconv2, g_conv2);
    cudaGetSymbolAddress((void**)&pwqB,   g_wqB);
    cudaGetSymbolAddress((void**)&pwhB,   g_whB);
    cudaGetSymbolAddress((void**)&pattB,  g_attB);
    cudaGetSymbolAddress((void**)&pupdB,  g_updB);
    cudaGetSymbolAddress((void**)&pwqlB,  g_wqlB);
    cudaGetSymbolAddress((void**)&pwhlB,  g_whlB);
    cudaGetSymbolAddress((void**)&pattlB, g_attlB);
    cudaGetSymbolAddress((void**)&pupdlB, g_updlB);
    cudaGetSymbolAddress((void**)&pA96h,  g_pA96_hi);
    cudaGetSymbolAddress((void**)&pA96l,  g_pA96_lo);
    cudaGetSymbolAddress((void**)&pB96h,  g_pB96_hi);
    cudaGetSymbolAddress((void**)&pB96l,  g_pB96_lo);
    cudaGetSymbolAddress((void**)&pA192h, g_pA192_hi);
    cudaGetSymbolAddress((void**)&pA192l, g_pA192_lo);

    cudaFuncSetAttribute(conv_mma_k<128,2>, cudaFuncAttributeMaxDynamicSharedMemorySize, SM_TOT);
    cudaFuncSetAttribute(conv_mma_k<192,3>, cudaFuncAttributeMaxDynamicSharedMemorySize, SM_TOT);
    cudaFuncSetAttribute(lindevox_k<128,2>, cudaFuncAttributeMaxDynamicSharedMemorySize, L_TOT);
    cudaFuncSetAttribute(lindevox_k<192,3>, cudaFuncAttributeMaxDynamicSharedMemorySize, L_TOT);

    const int TB = 256;
    auto gs = [](long long n, int tb){ return (int)((n + tb - 1) / tb); };
    const int LBLK = (NPTS + 127) / 128;   // 782

    // --- shared precompute: counting sort + trilinear + pad-zero ---
    zeroi_k<<<gs(G3,TB), TB>>>(picnt, G3);
    vox_k<<<gs(NPTS,TB), TB>>>(coords);
    scan_k<<<1, 1024>>>();
    fill_k<<<gs(NPTS,TB), TB>>>();
    trilin_k<<<gs(NPTS,TB), TB>>>(coords);
    zero6_k<<<gs((long long)PGV*896/8,TB), TB>>>(pA96h, pA96l, pB96h, pB96l, pA192h, pA192l);

    // --- weight prep ---
    prep_wB_k<96,128,2><<<gs(27LL*128*96,TB), TB>>>(wq_conv, pwqB);
    prep_wB_k<96,128,2><<<gs(27LL*128*96,TB), TB>>>(wh_conv, pwhB);
    prep_wB_k<192,192,3><<<gs(27LL*192*96,TB), TB>>>(att_conv, pattB);
    prep_wB_k<192,192,3><<<gs(27LL*192*96,TB), TB>>>(upd_conv, pupdB);
    prep_wlB_k<96,128><<<gs(128LL*96,TB), TB>>>(wq_lw,  pwqlB);
    prep_wlB_k<96,128><<<gs(128LL*96,TB), TB>>>(wh_lw,  pwhlB);
    prep_wlB_k<192,192><<<gs(192LL*96,TB), TB>>>(att_lw, pattlB);
    prep_wlB_k<192,192><<<gs(192LL*96,TB), TB>>>(upd_lw, pupdlB);
    tconv_k<<<gs(96*27,TB), TB>>>(v_conv, pvT, 96, 1);

    // --- merged sconv q + sconv h (voxelize INPUTS) ---
    gathervox_qh_k<<<gs(2LL*G3*24,TB), TB>>>(query, hidden);
    conv_mma_k<128,2><<<512, 256, SM_TOT>>>(pwqB, pA96h, pA96l, pconv,
                                            pwhB, pB96h, pB96l, pconv2, 256);
    lindevox_k<128,2><<<2*LBLK, 256, L_TOT>>>(
        query, nullptr, nullptr, pwqlB, wq_lb, pconv, pq,
        hidden, nullptr, nullptr, pwhlB, wh_lb, pconv2, ph, LBLK, 0);

    // --- energy = tanh(sconv([h, q])) --- voxelize OUTPUTS fresh (+cache q grid)
    gathervox192_k<<<gs(2LL*G3*24,TB), TB>>>(ph, pq);
    conv_mma_k<192,3><<<256, 256, SM_TOT>>>(pattB, pA192h, pA192l, pconv,
                                            pattB, pA192h, pA192l, pconv, 256);
    lindevox_k<192,3><<<LBLK, 256, L_TOT>>>(
        ph, pq, nullptr, pattlB, att_lb, pconv, pe,
        ph, pq, nullptr, pattlB, att_lb, pconv, pe, LBLK, 1);

    // --- attn = sconv(energy), cout=1: factored P-GEMM + stencil ---
    voxf32_k<<<gs((long long)G3*24,TB), TB>>>(pe);
    pgemm_k<<<G3/8, 256>>>();
    stencil_k<<<gs(G3,TB), TB>>>();
    attn_k<<<gs(NPTS,TB), TB>>>(pe, v_lw, v_lb);

    // --- out = tanh(sconv([q, attn*h])) --- q half from cache, attn*h fresh
    mkq_k<<<gs((long long)G3*12,TB), TB>>>();
    gathervox_sc_k<<<gs((long long)G3*24,TB), TB>>>(ph, pattn);
    conv_mma_k<192,3><<<256, 256, SM_TOT>>>(pupdB, pA192h, pA192l, pconv,
                                            pupdB, pA192h, pA192l, pconv, 256);
    lindevox_k<192,3><<<LBLK, 256, L_TOT>>>(
        pq, ph, pattn, pupdlB, upd_lb, pconv, out,
        pq, ph, pattn, pupdlB, upd_lb, pconv, out, LBLK, 1);
}

// round 10
// speedup vs baseline: 6.2511x; 1.2856x over previous
#include <cuda_runtime.h>
#include <cuda_fp16.h>
#include <cstdint>
#include <math.h>

#define NPTS 100000
#define CDIM 96
#define GRES 32
#define G3   (GRES*GRES*GRES)
#define PAD  34
#define PP2  (PAD*PAD)
#define PGV  (PP2*PAD)

// ======================= scratch (device globals) ===========================
__device__ int   g_vidx[NPTS];
__device__ int   g_icnt[G3];
__device__ int   g_start[G3+1];
__device__ int   g_pos[G3];
__device__ int   g_sorted[NPTS];
__device__ int   g_rank[NPTS];
__device__ int   g_nbi[8*NPTS];       // indexed by SORTED slot
__device__ float g_nbw[8*NPTS];       // indexed by SORTED slot
__device__ float g_P[27*G3];          // per-tap dot products (attn stage)
__device__ float g_conv[G3*CDIM];
__device__ float g_conv2[G3*CDIM];
__device__ float g_vout[G3];
__device__ float g_q[NPTS*CDIM];
__device__ float g_h[NPTS*CDIM];
__device__ float g_energy[NPTS*CDIM];
__device__ float g_attn[NPTS];
// padded fp16 split grids (borders/pad-channels zeroed once per call)
__device__ __half g_pA96_hi [PGV*128];   // voxelized query input
__device__ __half g_pA96_lo [PGV*128];
__device__ __half g_pB96_hi [PGV*128];   // voxelized hidden input
__device__ __half g_pB96_lo [PGV*128];
__device__ __half g_pA192_hi[PGV*192];
__device__ __half g_pA192_lo[PGV*192];
// cached voxelized q_out (interior), reused stage3 -> stage5
__device__ __half g_pQ96_hi[PGV*96];
__device__ __half g_pQ96_lo[PGV*96];
// pre-swizzled fp16 conv weights (hi only): [tap*nch+chunk][6144 = 96 rows x 64 ci]
__device__ __half g_wqB [27*2*6144];
__device__ __half g_whB [27*2*6144];
__device__ __half g_attB[27*3*6144];
__device__ __half g_updB[27*3*6144];
// pre-swizzled fp16 linear weights: [chunk][6144]
__device__ __half g_wqlB [2*6144];
__device__ __half g_whlB [2*6144];
__device__ __half g_attlB[3*6144];
__device__ __half g_updlB[3*6144];
__device__ float g_vT[27*CDIM];

// ======================= mma/ldmatrix/cp.async helpers =======================
__device__ __forceinline__ uint32_t smem_u32(const void* p) {
    uint32_t a;
    asm("{ .reg .u64 t; cvta.to.shared.u64 t, %1; cvt.u32.u64 %0, t; }" : "=r"(a) : "l"(p));
    return a;
}
__device__ __forceinline__ void ldsm4(uint32_t* r, uint32_t addr) {
    asm volatile("ldmatrix.sync.aligned.m8n8.x4.shared.b16 {%0,%1,%2,%3}, [%4];"
        : "=r"(r[0]), "=r"(r[1]), "=r"(r[2]), "=r"(r[3]) : "r"(addr));
}
__device__ __forceinline__ void mma16816h(float* c, const uint32_t* a, const uint32_t* b) {
    asm volatile("mma.sync.aligned.m16n8k16.row.col.f32.f16.f16.f32 "
        "{%0,%1,%2,%3}, {%4,%5,%6,%7}, {%8,%9}, {%0,%1,%2,%3};"
        : "+f"(c[0]), "+f"(c[1]), "+f"(c[2]), "+f"(c[3])
        : "r"(a[0]), "r"(a[1]), "r"(a[2]), "r"(a[3]), "r"(b[0]), "r"(b[1]));
}
__device__ __forceinline__ void cpa16(uint32_t dst, const void* src) {
    asm volatile("cp.async.cg.shared.global [%0], [%1], 16;" :: "r"(dst), "l"(src));
}
__device__ __forceinline__ void cpa_commit() { asm volatile("cp.async.commit_group;"); }
__device__ __forceinline__ void cpa_wait0()  { asm volatile("cp.async.wait_group 0;"); }
__device__ __forceinline__ void cpa_wait1()  { asm volatile("cp.async.wait_group 1;"); }

// ======================= sort/index kernels ==================================
__global__ void zeroi_k(int* __restrict__ p, int n) {
    int i = blockIdx.x * blockDim.x + threadIdx.x;
    if (i < n) p[i] = 0;
}
__global__ void zero6_k(__half* a, __half* b, __half* c,
                        __half* d, __half* e, __half* f) {
    const int U128 = PGV * 128 / 8;
    const int U192 = PGV * 192 / 8;
    long long i = (long long)blockIdx.x * blockDim.x + threadIdx.x;
    uint4 z = make_uint4(0u, 0u, 0u, 0u);
    if      (i < U128)                      ((uint4*)a)[i] = z;
    else if (i < 2LL*U128)                  ((uint4*)b)[i - U128] = z;
    else if (i < 3LL*U128)                  ((uint4*)c)[i - 2LL*U128] = z;
    else if (i < 4LL*U128)                  ((uint4*)d)[i - 3LL*U128] = z;
    else if (i < 4LL*U128 + U192)           ((uint4*)e)[i - 4LL*U128] = z;
    else if (i < 4LL*U128 + 2LL*U192)       ((uint4*)f)[i - 4LL*U128 - U192] = z;
}

__global__ void vox_k(const float* __restrict__ coords) {
    int p = blockIdx.x * blockDim.x + threadIdx.x;
    if (p >= NPTS) return;
    int vx = min(max((int)floorf(coords[3*p+0]), 0), GRES-1);
    int vy = min(max((int)floorf(coords[3*p+1]), 0), GRES-1);
    int vz = min(max((int)floorf(coords[3*p+2]), 0), GRES-1);
    int flat = (vx*GRES + vy)*GRES + vz;
    g_vidx[p] = flat;
    atomicAdd(&g_icnt[flat], 1);
}

__global__ void __launch_bounds__(1024) scan_k() {
    __shared__ int bs[1024];
    int t = threadIdx.x;
    int base = t * 32;
    int loc[32];
    int s = 0;
    #pragma unroll
    for (int k = 0; k < 32; k++) { loc[k] = s; s += g_icnt[base + k]; }
    bs[t] = s;
    __syncthreads();
    #pragma unroll
    for (int d = 1; d < 1024; d <<= 1) {
        int v = (t >= d) ? bs[t - d] : 0;
        __syncthreads();
        bs[t] += v;
        __syncthreads();
    }
    int off = bs[t] - s;
    #pragma unroll
    for (int k = 0; k < 32; k++) {
        g_start[base + k] = off + loc[k];
        g_pos[base + k]   = off + loc[k];
    }
    if (t == 1023) g_start[G3] = off + s;
}

__global__ void fill_k() {
    int p = blockIdx.x * blockDim.x + threadIdx.x;
    if (p >= NPTS) return;
    int slot = atomicAdd(&g_pos[g_vidx[p]], 1);
    g_sorted[slot] = p;
    g_rank[p] = slot;
}

__global__ void trilin_k(const float* __restrict__ coords) {
    int p = blockIdx.x * blockDim.x + threadIdx.x;
    if (p >= NPTS) return;
    int s = g_rank[p];
    float cx = coords[3*p+0], cy = coords[3*p+1], cz = coords[3*p+2];
    float bx = floorf(cx), by = floorf(cy), bz = floorf(cz);
    float fx = cx - bx, fy = cy - by, fz = cz - bz;
    int ix = (int)bx, iy = (int)by, iz = (int)bz;
    #pragma unroll
    for (int j = 0; j < 8; j++) {
        int dx = (j >> 2) & 1, dy = (j >> 1) & 1, dz = j & 1;
        int nx = ix + dx, ny = iy + dy, nz = iz + dz;
        bool valid = (nx >= 0 && nx < GRES && ny >= 0 && ny < GRES && nz >= 0 && nz < GRES);
        int cxc = min(max(nx,0),GRES-1), cyc = min(max(ny,0),GRES-1), czc = min(max(nz,0),GRES-1);
        int flc = (cxc*GRES + cyc)*GRES + czc;
        float w = (dx ? fx : 1.f-fx) * (dy ? fy : 1.f-fy) * (dz ? fz : 1.f-fz);
        if (!valid || g_icnt[flc] == 0) w = 0.f;
        g_nbi[j*NPTS + s] = flc;
        g_nbw[j*NPTS + s] = w;
    }
}

// ======================= fp16 split helpers ==================================
__device__ __forceinline__ void f16_split_store4(
    float4 acc, __half* dhi, __half* dlo, size_t o) {
    __half h0 = __float2half_rn(acc.x), h1 = __float2half_rn(acc.y);
    __half h2 = __float2half_rn(acc.z), h3 = __float2half_rn(acc.w);
    __half l0 = __float2half_rn(acc.x - __half2float(h0));
    __half l1 = __float2half_rn(acc.y - __half2float(h1));
    __half l2 = __float2half_rn(acc.z - __half2float(h2));
    __half l3 = __float2half_rn(acc.w - __half2float(h3));
    __half2 hA = __halves2half2(h0, h1);
    __half2 hB = __halves2half2(h2, h3);
    __half2 lA = __halves2half2(l0, l1);
    __half2 lB = __halves2half2(l2, l3);
    *(__half2*)(dhi + o)     = hA;
    *(__half2*)(dhi + o + 2) = hB;
    *(__half2*)(dlo + o)     = lA;
    *(__half2*)(dlo + o + 2) = lB;
}

// merged q+h INPUT voxelize
__global__ void gathervox_qh_k(const float* __restrict__ q, const float* __restrict__ h) {
    int i = blockIdx.x * blockDim.x + threadIdx.x;
    if (i >= 2 * G3 * 24) return;
    bool sec = (i >= G3 * 24);
    int j = sec ? i - G3 * 24 : i;
    int c4 = j % 24;
    int v  = j / 24;
    int vx = v >> 10, vy = (v >> 5) & 31, vz = v & 31;
    int pv = ((vx + 1) * PAD + (vy + 1)) * PAD + (vz + 1);
    int ci = c4 * 4;
    const float* src = sec ? h : q;

    float4 acc = make_float4(0.f, 0.f, 0.f, 0.f);
    int s0 = g_start[v], s1 = g_start[v+1];
    if (s1 > s0) {
        for (int k = s0; k < s1; k++) {
            int pid = g_sorted[k];
            float4 f = *(const float4*)(src + (size_t)pid * 96 + ci);
            acc.x += f.x; acc.y += f.y; acc.z += f.z; acc.w += f.w;
        }
        float invn = 1.f / (float)(s1 - s0);
        acc.x *= invn; acc.y *= invn; acc.z *= invn; acc.w *= invn;
    }
    f16_split_store4(acc,
        sec ? g_pB96_hi : g_pA96_hi, sec ? g_pB96_lo : g_pA96_lo,
        (size_t)pv * 128 + ci);
}

// stage-3 voxelize of OUTPUTS: pA192 = [mean(h_out) | mean(q_out)] + cache q grid
__global__ void gathervox192_k(const float* __restrict__ h, const float* __restrict__ q) {
    int i = blockIdx.x * blockDim.x + threadIdx.x;
    if (i >= 2 * G3 * 24) return;
    bool sec = (i >= G3 * 24);   // sec = q half
    int j = sec ? i - G3 * 24 : i;
    int c4 = j % 24;
    int v  = j / 24;
    int vx = v >> 10, vy = (v >> 5) & 31, vz = v & 31;
    int pv = ((vx + 1) * PAD + (vy + 1)) * PAD + (vz + 1);
    int ci = c4 * 4;
    const float* src = sec ? q : h;

    float4 acc = make_float4(0.f, 0.f, 0.f, 0.f);
    int s0 = g_start[v], s1 = g_start[v+1];
    if (s1 > s0) {
        for (int k = s0; k < s1; k++) {
            int pid = g_sorted[k];
            float4 f = *(const float4*)(src + (size_t)pid * 96 + ci);
            acc.x += f.x; acc.y += f.y; acc.z += f.z; acc.w += f.w;
        }
        float invn = 1.f / (float)(s1 - s0);
        acc.x *= invn; acc.y *= invn; acc.z *= invn; acc.w *= invn;
    }
    if (!sec) {
        f16_split_store4(acc, g_pA192_hi, g_pA192_lo, (size_t)pv * 192 + ci);
    } else {
        f16_split_store4(acc, g_pA192_hi, g_pA192_lo, (size_t)pv * 192 + 96 + ci);
        f16_split_store4(acc, g_pQ96_hi, g_pQ96_lo, (size_t)pv * 96 + ci);
    }
}

// stage-5: merged (q-cache copy) + (mean(attn*h) gather)
__global__ void mkq_sc_k(const float* __restrict__ h, const float* __restrict__ scale) {
    const int NCOPY = G3 * 12;
    int i = blockIdx.x * blockDim.x + threadIdx.x;
    if (i < NCOPY) {
        int u = i % 12;
        int v = i / 12;
        int vx = v >> 10, vy = (v >> 5) & 31, vz = v & 31;
        int pv = ((vx + 1) * PAD + (vy + 1)) * PAD + (vz + 1);
        size_t s = (size_t)pv * 96 + u * 8;
        size_t d = (size_t)pv * 192 + u * 8;
        *(uint4*)(g_pA192_hi + d) = *(const uint4*)(g_pQ96_hi + s);
        *(uint4*)(g_pA192_lo + d) = *(const uint4*)(g_pQ96_lo + s);
        return;
    }
    int j = i - NCOPY;
    if (j >= G3 * 24) return;
    int c4 = j % 24;
    int v  = j / 24;
    int vx = v >> 10, vy = (v >> 5) & 31, vz = v & 31;
    int pv = ((vx + 1) * PAD + (vy + 1)) * PAD + (vz + 1);
    int ci = c4 * 4;
    float4 acc = make_float4(0.f, 0.f, 0.f, 0.f);
    int s0 = g_start[v], s1 = g_start[v+1];
    if (s1 > s0) {
        for (int k = s0; k < s1; k++) {
            int pid = g_sorted[k];
            float4 f = *(const float4*)(h + (size_t)pid * 96 + ci);
            float m = scale[pid];
            acc.x += f.x * m; acc.y += f.y * m; acc.z += f.z * m; acc.w += f.w * m;
        }
        float invn = 1.f / (float)(s1 - s0);
        acc.x *= invn; acc.y *= invn; acc.z *= invn; acc.w *= invn;
    }
    f16_split_store4(acc, g_pA192_hi, g_pA192_lo, (size_t)pv * 192 + 96 + ci);
}

// ======================= merged weight prep ==================================
__device__ __forceinline__ void conv_prep(int i, const float* w, __half* dst,
                                          int CIN, int KPAD, int NCH) {
    int co  = i % 96;
    int r   = i / 96;
    int ci  = r % KPAD;
    int tap = r / KPAD;
    float val = (ci < CIN) ? w[((size_t)co * CIN + ci) * 27 + tap] : 0.f;
    int chunk = ci >> 6;
    int cw = ci & 63;
    uint32_t elem = (uint32_t)co * 64 + (uint32_t)(((cw >> 3) ^ (co & 7)) * 8) + (cw & 7);
    dst[(size_t)(tap * NCH + chunk) * 6144 + elem] = __float2half_rn(val);
}
__device__ __forceinline__ void lin_prep(int i, const float* w, __half* dst, int CIN) {
    int co = i % 96;
    int ci = i / 96;
    float val = (ci < CIN) ? w[(size_t)co * CIN + ci] : 0.f;
    int chunk = ci >> 6;
    int cw = ci & 63;
    uint32_t elem = (uint32_t)co * 64 + (uint32_t)(((cw >> 3) ^ (co & 7)) * 8) + (cw & 7);
    dst[(size_t)chunk * 6144 + elem] = __float2half_rn(val);
}

__global__ void prep_all_k(const float* wq, const float* wh, const float* att,
                           const float* upd, const float* wql, const float* whl,
                           const float* attl, const float* updl, const float* vconv,
                           __half* dwq, __half* dwh, __half* datt, __half* dupd,
                           __half* dwql, __half* dwhl, __half* dattl, __half* dupdl) {
    const int C96 = 27*128*96, C192 = 27*192*96, L96 = 128*96, L192 = 192*96;
    int i = blockIdx.x * blockDim.x + threadIdx.x;
    if (i < C96) { conv_prep(i, wq, dwq, 96, 128, 2); return; }
    i -= C96;
    if (i < C96) { conv_prep(i, wh, dwh, 96, 128, 2); return; }
    i -= C96;
    if (i < C192) { conv_prep(i, att, datt, 192, 192, 3); return; }
    i -= C192;
    if (i < C192) { conv_prep(i, upd, dupd, 192, 192, 3); return; }
    i -= C192;
    if (i < L96) { lin_prep(i, wql, dwql, 96); return; }
    i -= L96;
    if (i < L96) { lin_prep(i, whl, dwhl, 96); return; }
    i -= L96;
    if (i < L192) { lin_prep(i, attl, dattl, 192); return; }
    i -= L192;
    if (i < L192) { lin_prep(i, updl, dupdl, 192); return; }
    i -= L192;
    if (i < 27*96) { int k = i % 27, ci = i / 27; g_vT[k*96 + ci] = vconv[ci*27 + k]; }
}

// ======================= HMMA 3x3x3 conv (slab A, dual-job, fp16 2-term) =====
#define A_SPLIT 26112            // 204 rows * 128B
#define SM_B0   52224
#define SM_B1   64512
#define SM_TOT  76928

template<int KPAD, int NCH>
__global__ void __launch_bounds__(256, 2) conv_mma_k(
    const __half* __restrict__ wBa, const __half* __restrict__ pAhiA,
    const __half* __restrict__ pAloA, float* __restrict__ outA,
    const __half* __restrict__ wBb, const __half* __restrict__ pAhiB,
    const __half* __restrict__ pAloB, float* __restrict__ outB,
    int split_blk) {
    extern __shared__ char smem[];
    uint32_t sb = smem_u32(smem);
    int tid = threadIdx.x;
    int warp = tid >> 5, lane = tid & 31;
    int m_off = (warp & 3) * 32;
    int n_off = (warp >> 2) * 48;

    int blk = blockIdx.x;
    bool sec = (blk >= split_blk);
    if (sec) blk -= split_blk;
    const __half* wB   = sec ? wBb   : wBa;
    const __half* pAhi = sec ? pAhiB : pAhiA;
    const __half* pAlo = sec ? pAloB : pAloA;
    float* outp = sec ? outB : outA;

    int x  = blk >> 3;
    int y0 = (blk & 7) * 4;

    float acc[2][6][4];
    #pragma unroll
    for (int mi = 0; mi < 2; mi++)
        #pragma unroll
        for (int nj = 0; nj < 6; nj++)
            #pragma unroll
            for (int e = 0; e < 4; e++) acc[mi][nj][e] = 0.f;

    int a_row_in = (lane & 7) + ((lane >> 3) & 1) * 8;
    int a_khalf  = lane >> 4;
    int b_row_in = (lane & 7) + ((lane >> 3) >> 1) * 8;
    int b_khalf  = (lane >> 3) & 1;

    int rb[2];
    #pragma unroll
    for (int mi = 0; mi < 2; mi++) {
        int m = m_off + mi * 16 + a_row_in;
        rb[mi] = (m >> 5) * 34 + (m & 31);
    }
    int brow[3];
    #pragma unroll
    for (int ni = 0; ni < 3; ni++) brow[ni] = n_off + ni * 16 + b_row_in;

    for (int cc = 0; cc < NCH; cc++) {
        for (int dx = 0; dx < 3; dx++) {
            __syncthreads();

            {
                const __half* bs = wB + (size_t)((dx * 9) * NCH + cc) * 6144;
                #pragma unroll
                for (int t = tid; t < 768; t += 256)
                    cpa16(sb + SM_B0 + t * 16, bs + t * 8);
                cpa_commit();
            }
            {
                size_t pvbase = ((size_t)(x + dx) * PAD + y0) * PAD;
                #pragma unroll
                for (int t = tid; t < 3264; t += 256) {
                    int split = (t >= 1632);
                    int e = split ? t - 1632 : t;
                    int r = e >> 3, c8 = e & 7;
                    const __half* src =
                        (split ? pAlo : pAhi) + (pvbase + r) * KPAD + cc * 64 + c8 * 8;
                    uint4 v = *(const uint4*)src;
                    *(uint4*)(smem + split * A_SPLIT + r * 128 + ((c8 ^ (r & 7)) << 4)) = v;
                }
            }

            for (int t9 = 0; t9 < 9; t9++) {
                cpa_wait0();
                __syncthreads();
                if (t9 < 8) {
                    const __half* bs =
                        wB + (size_t)((dx * 9 + t9 + 1) * NCH + cc) * 6144;
                    uint32_t dst = sb + ((t9 & 1) ? SM_B0 : SM_B1);
                    #pragma unroll
                    for (int t = tid; t < 768; t += 256)
                        cpa16(dst + t * 16, bs + t * 8);
                    cpa_commit();
                }
                uint32_t bbase = sb + ((t9 & 1) ? SM_B1 : SM_B0);
                int toff = (t9 / 3) * PAD + (t9 % 3);

                #pragma unroll
                for (int kk = 0; kk < 4; kk++) {
                    uint32_t ah[2][4], al[2][4], bh[3][4];
                    #pragma unroll
                    for (int mi = 0; mi < 2; mi++) {
                        int r = rb[mi] + toff;
                        int kc = kk * 2 + a_khalf;
                        uint32_t off = (uint32_t)r * 128 + (uint32_t)((kc ^ (r & 7)) << 4);
                        ldsm4(ah[mi], sb + off);
                        ldsm4(al[mi], sb + A_SPLIT + off);
                    }
                    #pragma unroll
                    for (int ni = 0; ni < 3; ni++) {
                        int r = brow[ni];
                        int kc = kk * 2 + b_khalf;
                        uint32_t off = (uint32_t)r * 128 + (uint32_t)((kc ^ (r & 7)) << 4);
                        ldsm4(bh[ni], bbase + off);
                    }
                    #pragma unroll
                    for (int mi = 0; mi < 2; mi++) {
                        #pragma unroll
                        for (int nj = 0; nj < 6; nj++) {
                            const uint32_t* bfh = &bh[nj >> 1][(nj & 1) * 2];
                            mma16816h(acc[mi][nj], ah[mi], bfh);
                            mma16816h(acc[mi][nj], al[mi], bfh);
                        }
                    }
                }
            }
        }
    }

    #pragma unroll
    for (int mi = 0; mi < 2; mi++) {
        #pragma unroll
        for (int half = 0; half < 2; half++) {
            int r = m_off + mi * 16 + (lane >> 2) + half * 8;
            int j = r >> 5, z = r & 31;
            size_t vbase = ((size_t)(x * GRES + y0 + j) * GRES + z) * 96;
            #pragma unroll
            for (int nj = 0; nj < 6; nj++) {
                int co = n_off + nj * 8 + 2 * (lane & 3);
                float2 v = make_float2(acc[mi][nj][half * 2], acc[mi][nj][half * 2 + 1]);
                *(float2*)(&outp[vbase + co]) = v;
            }
        }
    }
}

// ======================= fused linear GEMM + devox epilogue (dual, SORTED) ===
#define L_AHI 0
#define L_ALO 16384
#define L_B0  32768
#define L_B1  45056
#define L_TOT 57344

template<int KPAD, int NCH>
__global__ void __launch_bounds__(256, 2) lindevox_k(
    const float* __restrict__ x1a, const float* __restrict__ x2a,
    const float* __restrict__ s2a, const __half* __restrict__ wBa,
    const float* __restrict__ biasa, const float* __restrict__ convA,
    float* __restrict__ outa,
    const float* __restrict__ x1b, const float* __restrict__ x2b,
    const float* __restrict__ s2b, const __half* __restrict__ wBb,
    const float* __restrict__ biasb, const float* __restrict__ convB,
    float* __restrict__ outb,
    int split_blk, int do_tanh) {
    extern __shared__ char smem[];
    uint32_t sb = smem_u32(smem);
    int tid = threadIdx.x;
    int warp = tid >> 5, lane = tid & 31;
    int m_off = (warp & 3) * 32;
    int n_off = (warp >> 2) * 48;

    int blk = blockIdx.x;
    bool sec = (blk >= split_blk);
    if (sec) blk -= split_blk;
    const float* x1 = sec ? x1b : x1a;
    const float* x2 = sec ? x2b : x2a;
    const float* scale2 = sec ? s2b : s2a;
    const __half* wB = sec ? wBb : wBa;
    const float* bias = sec ? biasb : biasa;
    const float* convsrc = sec ? convB : convA;
    float* out = sec ? outb : outa;
    int pbase = blk * 128;           // SORTED slot base

    float acc[2][6][4];
    #pragma unroll
    for (int mi = 0; mi < 2; mi++)
        #pragma unroll
        for (int nj = 0; nj < 6; nj++)
            #pragma unroll
            for (int e = 0; e < 4; e++) acc[mi][nj][e] = 0.f;

    int a_row_in = (lane & 7) + ((lane >> 3) & 1) * 8;
    int a_khalf  = lane >> 4;
    int b_row_in = (lane & 7) + ((lane >> 3) >> 1) * 8;
    int b_khalf  = (lane >> 3) & 1;
    int brow[3];
    #pragma unroll
    for (int ni = 0; ni < 3; ni++) brow[ni] = n_off + ni * 16 + b_row_in;

    #pragma unroll
    for (int t = tid; t < 768; t += 256)
        cpa16(sb + L_B0 + t * 16, wB + t * 8);
    cpa_commit();

    for (int ch = 0; ch < NCH; ch++) {
        if (ch) __syncthreads();
        #pragma unroll
        for (int g = 0; g < 4; g++) {
            int gidx = tid + g * 256;
            int r = gidx >> 3, c8 = gidx & 7;
            int slot = pbase + r;
            int colbase = ch * 64 + c8 * 8;
            float v[8];
            bool have = (slot < NPTS) && (colbase < ((KPAD == 128) ? 96 : 192));
            if (have) {
                int p = g_sorted[slot];
                const float* srcp;
                float m = 1.f;
                if (colbase < 96) srcp = x1 + (size_t)p * 96 + colbase;
                else {
                    srcp = x2 + (size_t)p * 96 + (colbase - 96);
                    if (scale2) m = scale2[p];
                }
                float4 aa = *(const float4*)srcp;
                float4 bb = *(const float4*)(srcp + 4);
                v[0]=aa.x*m; v[1]=aa.y*m; v[2]=aa.z*m; v[3]=aa.w*m;
                v[4]=bb.x*m; v[5]=bb.y*m; v[6]=bb.z*m; v[7]=bb.w*m;
            } else {
                #pragma unroll
                for (int e = 0; e < 8; e++) v[e] = 0.f;
            }
            uint4 hv, lv;
            uint32_t* hp = (uint32_t*)&hv;
            uint32_t* lp = (uint32_t*)&lv;
            #pragma unroll
            for (int e = 0; e < 4; e++) {
                __half h0 = __float2half_rn(v[2*e]);
                __half h1 = __float2half_rn(v[2*e+1]);
                __half l0 = __float2half_rn(v[2*e]   - __half2float(h0));
                __half l1 = __float2half_rn(v[2*e+1] - __half2float(h1));
                __half2 hh = __halves2half2(h0, h1);
                __half2 ll = __halves2half2(l0, l1);
                hp[e] = *(uint32_t*)&hh;
                lp[e] = *(uint32_t*)&ll;
            }
            uint32_t addr = (uint32_t)r * 128 + (uint32_t)((c8 ^ (r & 7)) << 4);
            *(uint4*)(smem + L_AHI + addr) = hv;
            *(uint4*)(smem + L_ALO + addr) = lv;
        }
        if (ch + 1 < NCH) {
            const __half* bs = wB + (size_t)(ch + 1) * 6144;
            uint32_t dst = sb + ((ch & 1) ? L_B0 : L_B1);
            #pragma unroll
            for (int t = tid; t < 768; t += 256)
                cpa16(dst + t * 16, bs + t * 8);
            cpa_commit();
            cpa_wait1();
        } else {
            cpa_wait0();
        }
        __syncthreads();

        uint32_t bbase = sb + ((ch & 1) ? L_B1 : L_B0);
        #pragma unroll
        for (int kk = 0; kk < 4; kk++) {
            uint32_t ah[2][4], al[2][4], bh[3][4];
            #pragma unroll
            for (int mi = 0; mi < 2; mi++) {
                int r = m_off + mi * 16 + a_row_in;
                int kc = kk * 2 + a_khalf;
                uint32_t off = (uint32_t)r * 128 + (uint32_t)((kc ^ (r & 7)) << 4);
                ldsm4(ah[mi], sb + L_AHI + off);
                ldsm4(al[mi], sb + L_ALO + off);
            }
            #pragma unroll
            for (int ni = 0; ni < 3; ni++) {
                int r = brow[ni];
                int kc = kk * 2 + b_khalf;
                uint32_t off = (uint32_t)r * 128 + (uint32_t)((kc ^ (r & 7)) << 4);
                ldsm4(bh[ni], bbase + off);
            }
            #pragma unroll
            for (int mi = 0; mi < 2; mi++) {
                #pragma unroll
                for (int nj = 0; nj < 6; nj++) {
                    const uint32_t* bfh = &bh[nj >> 1][(nj & 1) * 2];
                    mma16816h(acc[mi][nj], ah[mi], bfh);
                    mma16816h(acc[mi][nj], al[mi], bfh);
                }
            }
        }
    }

    // ---- epilogue: devox gather (sorted slots) + bias + tanh ----
    #pragma unroll
    for (int mi = 0; mi < 2; mi++) {
        #pragma unroll
        for (int half = 0; half < 2; half++) {
            int r = m_off + mi * 16 + (lane >> 2) + half * 8;
            int slot = pbase + r;
            if (slot >= NPTS) continue;
            int p = g_sorted[slot];
            #pragma unroll
            for (int j = 0; j < 8; j++) {
                float w = g_nbw[j*NPTS + slot];
                if (w != 0.f) {
                    const float* gp = convsrc + (size_t)g_nbi[j*NPTS + slot] * 96;
                    #pragma unroll
                    for (int nj = 0; nj < 6; nj++) {
                        int co = n_off + nj * 8 + 2 * (lane & 3);
                        float2 gg = *(const float2*)(gp + co);
                        acc[mi][nj][half*2]   += w * gg.x;
                        acc[mi][nj][half*2+1] += w * gg.y;
                    }
                }
            }
            #pragma unroll
            for (int nj = 0; nj < 6; nj++) {
                int co = n_off + nj * 8 + 2 * (lane & 3);
                float2 bb = *(const float2*)(bias + co);
                float vx = acc[mi][nj][half*2]   + bb.x;
                float vy = acc[mi][nj][half*2+1] + bb.y;
                if (do_tanh) { vx = tanhf(vx); vy = tanhf(vy); }
                *(float2*)(out + (size_t)p * 96 + co) = make_float2(vx, vy);
            }
        }
    }
}

// ======================= attn stage ==========================================
// fused voxelize-mean + 27-tap dot: warp per voxel
__global__ void __launch_bounds__(256) voxdot_k(const float* __restrict__ src) {
    __shared__ float ws[27*96];
    int tid = threadIdx.x;
    for (int i = tid; i < 27*96; i += 256) ws[i] = g_vT[i];
    __syncthreads();
    int wid = tid >> 5, lane = tid & 31;
    int v = blockIdx.x * 8 + wid;
    if (v >= G3) return;
    int s0 = g_start[v], s1 = g_start[v+1];
    float a0 = 0.f, a1 = 0.f, a2 = 0.f;
    for (int k = s0; k < s1; k++) {
        const float* r = src + (size_t)g_sorted[k] * 96;
        a0 += r[lane]; a1 += r[lane+32]; a2 += r[lane+64];
    }
    if (s1 > s0) {
        float invn = 1.f / (float)(s1 - s0);
        a0 *= invn; a1 *= invn; a2 *= invn;
    }
    #pragma unroll 9
    for (int t = 0; t < 27; t++) {
        float s = a0*ws[t*96+lane] + a1*ws[t*96+lane+32] + a2*ws[t*96+lane+64];
        s += __shfl_xor_sync(0xFFFFFFFF, s, 16);
        s += __shfl_xor_sync(0xFFFFFFFF, s, 8);
        s += __shfl_xor_sync(0xFFFFFFFF, s, 4);
        s += __shfl_xor_sync(0xFFFFFFFF, s, 2);
        s += __shfl_xor_sync(0xFFFFFFFF, s, 1);
        if (lane == 0) g_P[t*G3 + v] = s;
    }
}

__global__ void stencil_k() {
    int v = blockIdx.x * blockDim.x + threadIdx.x;
    if (v >= G3) return;
    int px = v >> 10, py = (v >> 5) & 31, pz = v & 31;
    float acc = 0.f;
    #pragma unroll
    for (int t = 0; t < 27; t++) {
        int kx = t / 9, ky = (t / 3) % 3, kz = t % 3;
        int nx = px + kx - 1, ny = py + ky - 1, nz = pz + kz - 1;
        if ((unsigned)nx < GRES && (unsigned)ny < GRES && (unsigned)nz < GRES)
            acc += g_P[t*G3 + ((nx<<5) + ny)*32 + nz];
    }
    g_vout[v] = acc;
}

__global__ void attn_k(const float* __restrict__ energy,
                       const float* __restrict__ v_lw, const float* __restrict__ v_lb) {
    int s = blockIdx.x * blockDim.x + threadIdx.x;
    if (s >= NPTS) return;
    int p = g_sorted[s];
    float acc = v_lb[0];
    #pragma unroll
    for (int j = 0; j < 8; j++) {
        float w = g_nbw[j*NPTS + s];
        if (w != 0.f) acc += w * g_vout[g_nbi[j*NPTS + s]];
    }
    const float4* er4 = (const float4*)(energy + (size_t)p * CDIM);
    const float4* vw4 = (const float4*)v_lw;
    #pragma unroll 6
    for (int cb = 0; cb < 24; cb++) {
        float4 e = er4[cb], w = vw4[cb];
        acc += e.x*w.x + e.y*w.y + e.z*w.z + e.w*w.w;
    }
    g_attn[p] = acc;
}

// ======================= host orchestration =================================
extern "C" void kernel_launch(void* const* d_in, const int* in_sizes, int n_in,
                              void* d_out, int out_size) {
    const float* hidden   = (const float*)d_in[0];
    const float* query    = (const float*)d_in[1];
    const float* coords   = (const float*)d_in[2];
    const float* wq_conv  = (const float*)d_in[3];
    const float* wq_lw    = (const float*)d_in[4];
    const float* wq_lb    = (const float*)d_in[5];
    const float* wh_conv  = (const float*)d_in[6];
    const float* wh_lw    = (const float*)d_in[7];
    const float* wh_lb    = (const float*)d_in[8];
    const float* att_conv = (const float*)d_in[9];
    const float* att_lw   = (const float*)d_in[10];
    const float* att_lb   = (const float*)d_in[11];
    const float* v_conv   = (const float*)d_in[12];
    const float* v_lw     = (const float*)d_in[13];
    const float* v_lb     = (const float*)d_in[14];
    const float* upd_conv = (const float*)d_in[15];
    const float* upd_lw   = (const float*)d_in[16];
    const float* upd_lb   = (const float*)d_in[17];
    float* out = (float*)d_out;

    int *picnt;
    float *pq, *ph, *pe, *pattn, *pconv, *pconv2;
    __half *pwqB, *pwhB, *pattB, *pupdB;
    __half *pwqlB, *pwhlB, *pattlB, *pupdlB;
    __half *pA96h, *pA96l, *pB96h, *pB96l, *pA192h, *pA192l;
    cudaGetSymbolAddress((void**)&picnt,  g_icnt);
    cudaGetSymbolAddress((void**)&pq,     g_q);
    cudaGetSymbolAddress((void**)&ph,     g_h);
    cudaGetSymbolAddress((void**)&pe,     g_energy);
    cudaGetSymbolAddress((void**)&pattn,  g_attn);
    cudaGetSymbolAddress((void**)&pconv,  g_conv);
    cudaGetSymbolAddress((void**)&pconv2, g_conv2);
    cudaGetSymbolAddress((void**)&pwqB,   g_wqB);
    cudaGetSymbolAddress((void**)&pwhB,   g_whB);
    cudaGetSymbolAddress((void**)&pattB,  g_attB);
    cudaGetSymbolAddress((void**)&pupdB,  g_updB);
    cudaGetSymbolAddress((void**)&pwqlB,  g_wqlB);
    cudaGetSymbolAddress((void**)&pwhlB,  g_whlB);
    cudaGetSymbolAddress((void**)&pattlB, g_attlB);
    cudaGetSymbolAddress((void**)&pupdlB, g_updlB);
    cudaGetSymbolAddress((void**)&pA96h,  g_pA96_hi);
    cudaGetSymbolAddress((void**)&pA96l,  g_pA96_lo);
    cudaGetSymbolAddress((void**)&pB96h,  g_pB96_hi);
    cudaGetSymbolAddress((void**)&pB96l,  g_pB96_lo);
    cudaGetSymbolAddress((void**)&pA192h, g_pA192_hi);
    cudaGetSymbolAddress((void**)&pA192l, g_pA192_lo);

    cudaFuncSetAttribute(conv_mma_k<128,2>, cudaFuncAttributeMaxDynamicSharedMemorySize, SM_TOT);
    cudaFuncSetAttribute(conv_mma_k<192,3>, cudaFuncAttributeMaxDynamicSharedMemorySize, SM_TOT);
    cudaFuncSetAttribute(lindevox_k<128,2>, cudaFuncAttributeMaxDynamicSharedMemorySize, L_TOT);
    cudaFuncSetAttribute(lindevox_k<192,3>, cudaFuncAttributeMaxDynamicSharedMemorySize, L_TOT);

    const int TB = 256;
    auto gs = [](long long n, int tb){ return (int)((n + tb - 1) / tb); };
    const int LBLK = (NPTS + 127) / 128;   // 782
    const long long PREP_N = 2LL*27*128*96 + 2LL*27*192*96 + 2LL*128*96 + 2LL*192*96 + 27*96;

    // --- shared precompute ---
    zeroi_k<<<gs(G3,TB), TB>>>(picnt, G3);
    vox_k<<<gs(NPTS,TB), TB>>>(coords);
    scan_k<<<1, 1024>>>();
    fill_k<<<gs(NPTS,TB), TB>>>();
    trilin_k<<<gs(NPTS,TB), TB>>>(coords);
    zero6_k<<<gs((long long)PGV*896/8,TB), TB>>>(pA96h, pA96l, pB96h, pB96l, pA192h, pA192l);
    prep_all_k<<<gs(PREP_N,TB), TB>>>(wq_conv, wh_conv, att_conv, upd_conv,
                                      wq_lw, wh_lw, att_lw, upd_lw, v_conv,
                                      pwqB, pwhB, pattB, pupdB,
                                      pwqlB, pwhlB, pattlB, pupdlB);

    // --- merged sconv q + sconv h ---
    gathervox_qh_k<<<gs(2LL*G3*24,TB), TB>>>(query, hidden);
    conv_mma_k<128,2><<<512, 256, SM_TOT>>>(pwqB, pA96h, pA96l, pconv,
                                            pwhB, pB96h, pB96l, pconv2, 256);
    lindevox_k<128,2><<<2*LBLK, 256, L_TOT>>>(
        query, nullptr, nullptr, pwqlB, wq_lb, pconv, pq,
        hidden, nullptr, nullptr, pwhlB, wh_lb, pconv2, ph, LBLK, 0);

    // --- energy = tanh(sconv([h, q])) ---
    gathervox192_k<<<gs(2LL*G3*24,TB), TB>>>(ph, pq);
    conv_mma_k<192,3><<<256, 256, SM_TOT>>>(pattB, pA192h, pA192l, pconv,
                                            pattB, pA192h, pA192l, pconv, 256);
    lindevox_k<192,3><<<LBLK, 256, L_TOT>>>(
        ph, pq, nullptr, pattlB, att_lb, pconv, pe,
        ph, pq, nullptr, pattlB, att_lb, pconv, pe, LBLK, 1);

    // --- attn = sconv(energy), cout=1 ---
    voxdot_k<<<G3/8, 256>>>(pe);
    stencil_k<<<gs(G3,TB), TB>>>();
    attn_k<<<gs(NPTS,TB), TB>>>(pe, v_lw, v_lb);

    // --- out = tanh(sconv([q, attn*h])) ---
    mkq_sc_k<<<gs((long long)G3*36,TB), TB>>>(ph, pattn);
    conv_mma_k<192,3><<<256, 256, SM_TOT>>>(pupdB, pA192h, pA192l, pconv,
                                            pupdB, pA192h, pA192l, pconv, 256);
    lindevox_k<192,3><<<LBLK, 256, L_TOT>>>(
        pq, ph, pattn, pupdlB, upd_lb, pconv, out,
        pq, ph, pattn, pupdlB, upd_lb, pconv, out, LBLK, 1);
}

// round 11
// speedup vs baseline: 6.4547x; 1.0326x over previous
#include <cuda_runtime.h>
#include <cuda_fp16.h>
#include <cstdint>
#include <math.h>

#define NPTS 100000
#define CDIM 96
#define GRES 32
#define G3   (GRES*GRES*GRES)
#define PAD  34
#define PP2  (PAD*PAD)
#define PGV  (PP2*PAD)

// ======================= scratch (device globals) ===========================
__device__ int   g_vidx[NPTS];
__device__ int   g_icnt[G3];
__device__ int   g_start[G3+1];
__device__ int   g_pos[G3];
__device__ int   g_sorted[NPTS];
__device__ int   g_rank[NPTS];
__device__ int   g_nbi[8*NPTS];       // indexed by SORTED slot
__device__ float g_nbw[8*NPTS];       // indexed by SORTED slot
__device__ float g_P[27*G3];          // per-tap dot products (attn stage)
__device__ float g_conv[G3*CDIM];
__device__ float g_conv2[G3*CDIM];
__device__ float g_vout[G3];
__device__ float g_q[NPTS*CDIM];
__device__ float g_h[NPTS*CDIM];
__device__ float g_energy[NPTS*CDIM];
__device__ float g_attn[NPTS];
// padded fp16 split grids (borders/pad-channels zeroed once per call)
__device__ __half g_pA96_hi [PGV*128];   // voxelized query input
__device__ __half g_pA96_lo [PGV*128];
__device__ __half g_pB96_hi [PGV*128];   // voxelized hidden input
__device__ __half g_pB96_lo [PGV*128];
__device__ __half g_pA192_hi[PGV*192];
__device__ __half g_pA192_lo[PGV*192];
// cached voxelized q_out (interior), reused stage3 -> stage5
__device__ __half g_pQ96_hi[PGV*96];
__device__ __half g_pQ96_lo[PGV*96];
// pre-swizzled fp16 conv weights (hi only): [tap*nch+chunk][6144 = 96 rows x 64 ci]
__device__ __half g_wqB [27*2*6144];
__device__ __half g_whB [27*2*6144];
__device__ __half g_attB[27*3*6144];
__device__ __half g_updB[27*3*6144];
// pre-swizzled fp16 linear weights: [chunk][6144]
__device__ __half g_wqlB [2*6144];
__device__ __half g_whlB [2*6144];
__device__ __half g_attlB[3*6144];
__device__ __half g_updlB[3*6144];
__device__ float g_vT[27*CDIM];

// ======================= mma/ldmatrix/cp.async helpers =======================
__device__ __forceinline__ uint32_t smem_u32(const void* p) {
    uint32_t a;
    asm("{ .reg .u64 t; cvta.to.shared.u64 t, %1; cvt.u32.u64 %0, t; }" : "=r"(a) : "l"(p));
    return a;
}
__device__ __forceinline__ void ldsm4(uint32_t* r, uint32_t addr) {
    asm volatile("ldmatrix.sync.aligned.m8n8.x4.shared.b16 {%0,%1,%2,%3}, [%4];"
        : "=r"(r[0]), "=r"(r[1]), "=r"(r[2]), "=r"(r[3]) : "r"(addr));
}
__device__ __forceinline__ void mma16816h(float* c, const uint32_t* a, const uint32_t* b) {
    asm volatile("mma.sync.aligned.m16n8k16.row.col.f32.f16.f16.f32 "
        "{%0,%1,%2,%3}, {%4,%5,%6,%7}, {%8,%9}, {%0,%1,%2,%3};"
        : "+f"(c[0]), "+f"(c[1]), "+f"(c[2]), "+f"(c[3])
        : "r"(a[0]), "r"(a[1]), "r"(a[2]), "r"(a[3]), "r"(b[0]), "r"(b[1]));
}
__device__ __forceinline__ void cpa16(uint32_t dst, const void* src) {
    asm volatile("cp.async.cg.shared.global [%0], [%1], 16;" :: "r"(dst), "l"(src));
}
__device__ __forceinline__ void cpa_commit() { asm volatile("cp.async.commit_group;"); }
__device__ __forceinline__ void cpa_wait0()  { asm volatile("cp.async.wait_group 0;"); }
__device__ __forceinline__ void cpa_wait1()  { asm volatile("cp.async.wait_group 1;"); }

// ======================= sort/index kernels ==================================
__global__ void zeroi_k(int* __restrict__ p, int n) {
    int i = blockIdx.x * blockDim.x + threadIdx.x;
    if (i < n) p[i] = 0;
}
__global__ void zero6_k(__half* a, __half* b, __half* c,
                        __half* d, __half* e, __half* f) {
    const int U128 = PGV * 128 / 8;
    const int U192 = PGV * 192 / 8;
    long long i = (long long)blockIdx.x * blockDim.x + threadIdx.x;
    uint4 z = make_uint4(0u, 0u, 0u, 0u);
    if      (i < U128)                      ((uint4*)a)[i] = z;
    else if (i < 2LL*U128)                  ((uint4*)b)[i - U128] = z;
    else if (i < 3LL*U128)                  ((uint4*)c)[i - 2LL*U128] = z;
    else if (i < 4LL*U128)                  ((uint4*)d)[i - 3LL*U128] = z;
    else if (i < 4LL*U128 + U192)           ((uint4*)e)[i - 4LL*U128] = z;
    else if (i < 4LL*U128 + 2LL*U192)       ((uint4*)f)[i - 4LL*U128 - U192] = z;
}

__global__ void vox_k(const float* __restrict__ coords) {
    int p = blockIdx.x * blockDim.x + threadIdx.x;
    if (p >= NPTS) return;
    int vx = min(max((int)floorf(coords[3*p+0]), 0), GRES-1);
    int vy = min(max((int)floorf(coords[3*p+1]), 0), GRES-1);
    int vz = min(max((int)floorf(coords[3*p+2]), 0), GRES-1);
    int flat = (vx*GRES + vy)*GRES + vz;
    g_vidx[p] = flat;
    atomicAdd(&g_icnt[flat], 1);
}

__global__ void __launch_bounds__(1024) scan_k() {
    __shared__ int bs[1024];
    int t = threadIdx.x;
    int base = t * 32;
    int loc[32];
    int s = 0;
    #pragma unroll
    for (int k = 0; k < 32; k++) { loc[k] = s; s += g_icnt[base + k]; }
    bs[t] = s;
    __syncthreads();
    #pragma unroll
    for (int d = 1; d < 1024; d <<= 1) {
        int v = (t >= d) ? bs[t - d] : 0;
        __syncthreads();
        bs[t] += v;
        __syncthreads();
    }
    int off = bs[t] - s;
    #pragma unroll
    for (int k = 0; k < 32; k++) {
        g_start[base + k] = off + loc[k];
        g_pos[base + k]   = off + loc[k];
    }
    if (t == 1023) g_start[G3] = off + s;
}

__global__ void fill_k() {
    int p = blockIdx.x * blockDim.x + threadIdx.x;
    if (p >= NPTS) return;
    int slot = atomicAdd(&g_pos[g_vidx[p]], 1);
    g_sorted[slot] = p;
    g_rank[p] = slot;
}

__global__ void trilin_k(const float* __restrict__ coords) {
    int p = blockIdx.x * blockDim.x + threadIdx.x;
    if (p >= NPTS) return;
    int s = g_rank[p];
    float cx = coords[3*p+0], cy = coords[3*p+1], cz = coords[3*p+2];
    float bx = floorf(cx), by = floorf(cy), bz = floorf(cz);
    float fx = cx - bx, fy = cy - by, fz = cz - bz;
    int ix = (int)bx, iy = (int)by, iz = (int)bz;
    #pragma unroll
    for (int j = 0; j < 8; j++) {
        int dx = (j >> 2) & 1, dy = (j >> 1) & 1, dz = j & 1;
        int nx = ix + dx, ny = iy + dy, nz = iz + dz;
        bool valid = (nx >= 0 && nx < GRES && ny >= 0 && ny < GRES && nz >= 0 && nz < GRES);
        int cxc = min(max(nx,0),GRES-1), cyc = min(max(ny,0),GRES-1), czc = min(max(nz,0),GRES-1);
        int flc = (cxc*GRES + cyc)*GRES + czc;
        float w = (dx ? fx : 1.f-fx) * (dy ? fy : 1.f-fy) * (dz ? fz : 1.f-fz);
        if (!valid || g_icnt[flc] == 0) w = 0.f;
        g_nbi[j*NPTS + s] = flc;
        g_nbw[j*NPTS + s] = w;
    }
}

// ======================= fp16 split helpers ==================================
__device__ __forceinline__ void f16_split_store4(
    float4 acc, __half* dhi, __half* dlo, size_t o) {
    __half h0 = __float2half_rn(acc.x), h1 = __float2half_rn(acc.y);
    __half h2 = __float2half_rn(acc.z), h3 = __float2half_rn(acc.w);
    __half l0 = __float2half_rn(acc.x - __half2float(h0));
    __half l1 = __float2half_rn(acc.y - __half2float(h1));
    __half l2 = __float2half_rn(acc.z - __half2float(h2));
    __half l3 = __float2half_rn(acc.w - __half2float(h3));
    __half2 hA = __halves2half2(h0, h1);
    __half2 hB = __halves2half2(h2, h3);
    __half2 lA = __halves2half2(l0, l1);
    __half2 lB = __halves2half2(l2, l3);
    *(__half2*)(dhi + o)     = hA;
    *(__half2*)(dhi + o + 2) = hB;
    *(__half2*)(dlo + o)     = lA;
    *(__half2*)(dlo + o + 2) = lB;
}

// merged q+h INPUT voxelize
__global__ void gathervox_qh_k(const float* __restrict__ q, const float* __restrict__ h) {
    int i = blockIdx.x * blockDim.x + threadIdx.x;
    if (i >= 2 * G3 * 24) return;
    bool sec = (i >= G3 * 24);
    int j = sec ? i - G3 * 24 : i;
    int c4 = j % 24;
    int v  = j / 24;
    int vx = v >> 10, vy = (v >> 5) & 31, vz = v & 31;
    int pv = ((vx + 1) * PAD + (vy + 1)) * PAD + (vz + 1);
    int ci = c4 * 4;
    const float* src = sec ? h : q;

    float4 acc = make_float4(0.f, 0.f, 0.f, 0.f);
    int s0 = g_start[v], s1 = g_start[v+1];
    if (s1 > s0) {
        for (int k = s0; k < s1; k++) {
            int pid = g_sorted[k];
            float4 f = *(const float4*)(src + (size_t)pid * 96 + ci);
            acc.x += f.x; acc.y += f.y; acc.z += f.z; acc.w += f.w;
        }
        float invn = 1.f / (float)(s1 - s0);
        acc.x *= invn; acc.y *= invn; acc.z *= invn; acc.w *= invn;
    }
    f16_split_store4(acc,
        sec ? g_pB96_hi : g_pA96_hi, sec ? g_pB96_lo : g_pA96_lo,
        (size_t)pv * 128 + ci);
}

// stage-3 voxelize of OUTPUTS: pA192 = [mean(h_out) | mean(q_out)] + cache q grid
__global__ void gathervox192_k(const float* __restrict__ h, const float* __restrict__ q) {
    int i = blockIdx.x * blockDim.x + threadIdx.x;
    if (i >= 2 * G3 * 24) return;
    bool sec = (i >= G3 * 24);   // sec = q half
    int j = sec ? i - G3 * 24 : i;
    int c4 = j % 24;
    int v  = j / 24;
    int vx = v >> 10, vy = (v >> 5) & 31, vz = v & 31;
    int pv = ((vx + 1) * PAD + (vy + 1)) * PAD + (vz + 1);
    int ci = c4 * 4;
    const float* src = sec ? q : h;

    float4 acc = make_float4(0.f, 0.f, 0.f, 0.f);
    int s0 = g_start[v], s1 = g_start[v+1];
    if (s1 > s0) {
        for (int k = s0; k < s1; k++) {
            int pid = g_sorted[k];
            float4 f = *(const float4*)(src + (size_t)pid * 96 + ci);
            acc.x += f.x; acc.y += f.y; acc.z += f.z; acc.w += f.w;
        }
        float invn = 1.f / (float)(s1 - s0);
        acc.x *= invn; acc.y *= invn; acc.z *= invn; acc.w *= invn;
    }
    if (!sec) {
        f16_split_store4(acc, g_pA192_hi, g_pA192_lo, (size_t)pv * 192 + ci);
    } else {
        f16_split_store4(acc, g_pA192_hi, g_pA192_lo, (size_t)pv * 192 + 96 + ci);
        f16_split_store4(acc, g_pQ96_hi, g_pQ96_lo, (size_t)pv * 96 + ci);
    }
}

// stage-5: merged (q-cache copy) + (mean(attn*h) gather)
__global__ void mkq_sc_k(const float* __restrict__ h, const float* __restrict__ scale) {
    const int NCOPY = G3 * 12;
    int i = blockIdx.x * blockDim.x + threadIdx.x;
    if (i < NCOPY) {
        int u = i % 12;
        int v = i / 12;
        int vx = v >> 10, vy = (v >> 5) & 31, vz = v & 31;
        int pv = ((vx + 1) * PAD + (vy + 1)) * PAD + (vz + 1);
        size_t s = (size_t)pv * 96 + u * 8;
        size_t d = (size_t)pv * 192 + u * 8;
        *(uint4*)(g_pA192_hi + d) = *(const uint4*)(g_pQ96_hi + s);
        *(uint4*)(g_pA192_lo + d) = *(const uint4*)(g_pQ96_lo + s);
        return;
    }
    int j = i - NCOPY;
    if (j >= G3 * 24) return;
    int c4 = j % 24;
    int v  = j / 24;
    int vx = v >> 10, vy = (v >> 5) & 31, vz = v & 31;
    int pv = ((vx + 1) * PAD + (vy + 1)) * PAD + (vz + 1);
    int ci = c4 * 4;
    float4 acc = make_float4(0.f, 0.f, 0.f, 0.f);
    int s0 = g_start[v], s1 = g_start[v+1];
    if (s1 > s0) {
        for (int k = s0; k < s1; k++) {
            int pid = g_sorted[k];
            float4 f = *(const float4*)(h + (size_t)pid * 96 + ci);
            float m = scale[pid];
            acc.x += f.x * m; acc.y += f.y * m; acc.z += f.z * m; acc.w += f.w * m;
        }
        float invn = 1.f / (float)(s1 - s0);
        acc.x *= invn; acc.y *= invn; acc.z *= invn; acc.w *= invn;
    }
    f16_split_store4(acc, g_pA192_hi, g_pA192_lo, (size_t)pv * 192 + 96 + ci);
}

// ======================= merged weight prep ==================================
__device__ __forceinline__ void conv_prep(int i, const float* w, __half* dst,
                                          int CIN, int KPAD, int NCH) {
    int co  = i % 96;
    int r   = i / 96;
    int ci  = r % KPAD;
    int tap = r / KPAD;
    float val = (ci < CIN) ? w[((size_t)co * CIN + ci) * 27 + tap] : 0.f;
    int chunk = ci >> 6;
    int cw = ci & 63;
    uint32_t elem = (uint32_t)co * 64 + (uint32_t)(((cw >> 3) ^ (co & 7)) * 8) + (cw & 7);
    dst[(size_t)(tap * NCH + chunk) * 6144 + elem] = __float2half_rn(val);
}
__device__ __forceinline__ void lin_prep(int i, const float* w, __half* dst, int CIN) {
    int co = i % 96;
    int ci = i / 96;
    float val = (ci < CIN) ? w[(size_t)co * CIN + ci] : 0.f;
    int chunk = ci >> 6;
    int cw = ci & 63;
    uint32_t elem = (uint32_t)co * 64 + (uint32_t)(((cw >> 3) ^ (co & 7)) * 8) + (cw & 7);
    dst[(size_t)chunk * 6144 + elem] = __float2half_rn(val);
}

__global__ void prep_all_k(const float* wq, const float* wh, const float* att,
                           const float* upd, const float* wql, const float* whl,
                           const float* attl, const float* updl, const float* vconv,
                           __half* dwq, __half* dwh, __half* datt, __half* dupd,
                           __half* dwql, __half* dwhl, __half* dattl, __half* dupdl) {
    const int C96 = 27*128*96, C192 = 27*192*96, L96 = 128*96, L192 = 192*96;
    int i = blockIdx.x * blockDim.x + threadIdx.x;
    if (i < C96) { conv_prep(i, wq, dwq, 96, 128, 2); return; }
    i -= C96;
    if (i < C96) { conv_prep(i, wh, dwh, 96, 128, 2); return; }
    i -= C96;
    if (i < C192) { conv_prep(i, att, datt, 192, 192, 3); return; }
    i -= C192;
    if (i < C192) { conv_prep(i, upd, dupd, 192, 192, 3); return; }
    i -= C192;
    if (i < L96) { lin_prep(i, wql, dwql, 96); return; }
    i -= L96;
    if (i < L96) { lin_prep(i, whl, dwhl, 96); return; }
    i -= L96;
    if (i < L192) { lin_prep(i, attl, dattl, 192); return; }
    i -= L192;
    if (i < L192) { lin_prep(i, updl, dupdl, 192); return; }
    i -= L192;
    if (i < 27*96) { int k = i % 27, ci = i / 27; g_vT[k*96 + ci] = vconv[ci*27 + k]; }
}

// ======================= HMMA 3x3x3 conv (slab A, dual-job, fp16 2-term) =====
// K=96 paths (KPAD=128): chunk 1 holds only 32 valid k -> kmax=2, stage c8<4.
#define A_SPLIT 26112            // 204 rows * 128B
#define SM_B0   52224
#define SM_B1   64512
#define SM_TOT  76928

template<int KPAD, int NCH>
__global__ void __launch_bounds__(256, 2) conv_mma_k(
    const __half* __restrict__ wBa, const __half* __restrict__ pAhiA,
    const __half* __restrict__ pAloA, float* __restrict__ outA,
    const __half* __restrict__ wBb, const __half* __restrict__ pAhiB,
    const __half* __restrict__ pAloB, float* __restrict__ outB,
    int split_blk) {
    extern __shared__ char smem[];
    uint32_t sb = smem_u32(smem);
    int tid = threadIdx.x;
    int warp = tid >> 5, lane = tid & 31;
    int m_off = (warp & 3) * 32;
    int n_off = (warp >> 2) * 48;

    int blk = blockIdx.x;
    bool sec = (blk >= split_blk);
    if (sec) blk -= split_blk;
    const __half* wB   = sec ? wBb   : wBa;
    const __half* pAhi = sec ? pAhiB : pAhiA;
    const __half* pAlo = sec ? pAloB : pAloA;
    float* outp = sec ? outB : outA;

    int x  = blk >> 3;
    int y0 = (blk & 7) * 4;

    float acc[2][6][4];
    #pragma unroll
    for (int mi = 0; mi < 2; mi++)
        #pragma unroll
        for (int nj = 0; nj < 6; nj++)
            #pragma unroll
            for (int e = 0; e < 4; e++) acc[mi][nj][e] = 0.f;

    int a_row_in = (lane & 7) + ((lane >> 3) & 1) * 8;
    int a_khalf  = lane >> 4;
    int b_row_in = (lane & 7) + ((lane >> 3) >> 1) * 8;
    int b_khalf  = (lane >> 3) & 1;

    int rb[2];
    #pragma unroll
    for (int mi = 0; mi < 2; mi++) {
        int m = m_off + mi * 16 + a_row_in;
        rb[mi] = (m >> 5) * 34 + (m & 31);
    }
    int brow[3];
    #pragma unroll
    for (int ni = 0; ni < 3; ni++) brow[ni] = n_off + ni * 16 + b_row_in;

    for (int cc = 0; cc < NCH; cc++) {
        // K=96: second chunk has only 32 valid k values
        bool shortk = (KPAD == 128 && cc == 1);
        int kmax  = shortk ? 2 : 4;
        int c8max = shortk ? 4 : 8;
        int c8sh  = shortk ? 2 : 3;
        int ahalf = 204 * c8max;

        for (int dx = 0; dx < 3; dx++) {
            __syncthreads();

            {
                const __half* bs = wB + (size_t)((dx * 9) * NCH + cc) * 6144;
                #pragma unroll
                for (int t = tid; t < 768; t += 256)
                    cpa16(sb + SM_B0 + t * 16, bs + t * 8);
                cpa_commit();
            }
            {
                size_t pvbase = ((size_t)(x + dx) * PAD + y0) * PAD;
                for (int t = tid; t < 2 * ahalf; t += 256) {
                    int split = (t >= ahalf);
                    int e = split ? t - ahalf : t;
                    int r = e >> c8sh, c8 = e & (c8max - 1);
                    const __half* src =
                        (split ? pAlo : pAhi) + (pvbase + r) * KPAD + cc * 64 + c8 * 8;
                    uint4 v = *(const uint4*)src;
                    *(uint4*)(smem + split * A_SPLIT + r * 128 + ((c8 ^ (r & 7)) << 4)) = v;
                }
            }

            for (int t9 = 0; t9 < 9; t9++) {
                cpa_wait0();
                __syncthreads();
                if (t9 < 8) {
                    const __half* bs =
                        wB + (size_t)((dx * 9 + t9 + 1) * NCH + cc) * 6144;
                    uint32_t dst = sb + ((t9 & 1) ? SM_B0 : SM_B1);
                    #pragma unroll
                    for (int t = tid; t < 768; t += 256)
                        cpa16(dst + t * 16, bs + t * 8);
                    cpa_commit();
                }
                uint32_t bbase = sb + ((t9 & 1) ? SM_B1 : SM_B0);
                int toff = (t9 / 3) * PAD + (t9 % 3);

                #pragma unroll 4
                for (int kk = 0; kk < kmax; kk++) {
                    uint32_t ah[2][4], al[2][4], bh[3][4];
                    #pragma unroll
                    for (int mi = 0; mi < 2; mi++) {
                        int r = rb[mi] + toff;
                        int kc = kk * 2 + a_khalf;
                        uint32_t off = (uint32_t)r * 128 + (uint32_t)((kc ^ (r & 7)) << 4);
                        ldsm4(ah[mi], sb + off);
                        ldsm4(al[mi], sb + A_SPLIT + off);
                    }
                    #pragma unroll
                    for (int ni = 0; ni < 3; ni++) {
                        int r = brow[ni];
                        int kc = kk * 2 + b_khalf;
                        uint32_t off = (uint32_t)r * 128 + (uint32_t)((kc ^ (r & 7)) << 4);
                        ldsm4(bh[ni], bbase + off);
                    }
                    #pragma unroll
                    for (int mi = 0; mi < 2; mi++) {
                        #pragma unroll
                        for (int nj = 0; nj < 6; nj++) {
                            const uint32_t* bfh = &bh[nj >> 1][(nj & 1) * 2];
                            mma16816h(acc[mi][nj], ah[mi], bfh);
                            mma16816h(acc[mi][nj], al[mi], bfh);
                        }
                    }
                }
            }
        }
    }

    #pragma unroll
    for (int mi = 0; mi < 2; mi++) {
        #pragma unroll
        for (int half = 0; half < 2; half++) {
            int r = m_off + mi * 16 + (lane >> 2) + half * 8;
            int j = r >> 5, z = r & 31;
            size_t vbase = ((size_t)(x * GRES + y0 + j) * GRES + z) * 96;
            #pragma unroll
            for (int nj = 0; nj < 6; nj++) {
                int co = n_off + nj * 8 + 2 * (lane & 3);
                float2 v = make_float2(acc[mi][nj][half * 2], acc[mi][nj][half * 2 + 1]);
                *(float2*)(&outp[vbase + co]) = v;
            }
        }
    }
}

// ======================= fused linear GEMM + devox epilogue (dual, SORTED) ===
#define L_AHI 0
#define L_ALO 16384
#define L_B0  32768
#define L_B1  45056
#define L_TOT 57344

template<int KPAD, int NCH>
__global__ void __launch_bounds__(256, 2) lindevox_k(
    const float* __restrict__ x1a, const float* __restrict__ x2a,
    const float* __restrict__ s2a, const __half* __restrict__ wBa,
    const float* __restrict__ biasa, const float* __restrict__ convA,
    float* __restrict__ outa,
    const float* __restrict__ x1b, const float* __restrict__ x2b,
    const float* __restrict__ s2b, const __half* __restrict__ wBb,
    const float* __restrict__ biasb, const float* __restrict__ convB,
    float* __restrict__ outb,
    int split_blk, int do_tanh) {
    extern __shared__ char smem[];
    uint32_t sb = smem_u32(smem);
    int tid = threadIdx.x;
    int warp = tid >> 5, lane = tid & 31;
    int m_off = (warp & 3) * 32;
    int n_off = (warp >> 2) * 48;

    int blk = blockIdx.x;
    bool sec = (blk >= split_blk);
    if (sec) blk -= split_blk;
    const float* x1 = sec ? x1b : x1a;
    const float* x2 = sec ? x2b : x2a;
    const float* scale2 = sec ? s2b : s2a;
    const __half* wB = sec ? wBb : wBa;
    const float* bias = sec ? biasb : biasa;
    const float* convsrc = sec ? convB : convA;
    float* out = sec ? outb : outa;
    int pbase = blk * 128;           // SORTED slot base

    float acc[2][6][4];
    #pragma unroll
    for (int mi = 0; mi < 2; mi++)
        #pragma unroll
        for (int nj = 0; nj < 6; nj++)
            #pragma unroll
            for (int e = 0; e < 4; e++) acc[mi][nj][e] = 0.f;

    int a_row_in = (lane & 7) + ((lane >> 3) & 1) * 8;
    int a_khalf  = lane >> 4;
    int b_row_in = (lane & 7) + ((lane >> 3) >> 1) * 8;
    int b_khalf  = (lane >> 3) & 1;
    int brow[3];
    #pragma unroll
    for (int ni = 0; ni < 3; ni++) brow[ni] = n_off + ni * 16 + b_row_in;

    #pragma unroll
    for (int t = tid; t < 768; t += 256)
        cpa16(sb + L_B0 + t * 16, wB + t * 8);
    cpa_commit();

    for (int ch = 0; ch < NCH; ch++) {
        if (ch) __syncthreads();
        bool shortk = (KPAD == 128 && ch == 1);
        int kmax  = shortk ? 2 : 4;
        int c8max = shortk ? 4 : 8;
        int c8sh  = shortk ? 2 : 3;

        for (int gidx = tid; gidx < 128 * c8max; gidx += 256) {
            int r = gidx >> c8sh, c8 = gidx & (c8max - 1);
            int slot = pbase + r;
            int colbase = ch * 64 + c8 * 8;
            float v[8];
            bool have = (slot < NPTS) && (colbase < ((KPAD == 128) ? 96 : 192));
            if (have) {
                int p = g_sorted[slot];
                const float* srcp;
                float m = 1.f;
                if (colbase < 96) srcp = x1 + (size_t)p * 96 + colbase;
                else {
                    srcp = x2 + (size_t)p * 96 + (colbase - 96);
                    if (scale2) m = scale2[p];
                }
                float4 aa = *(const float4*)srcp;
                float4 bb = *(const float4*)(srcp + 4);
                v[0]=aa.x*m; v[1]=aa.y*m; v[2]=aa.z*m; v[3]=aa.w*m;
                v[4]=bb.x*m; v[5]=bb.y*m; v[6]=bb.z*m; v[7]=bb.w*m;
            } else {
                #pragma unroll
                for (int e = 0; e < 8; e++) v[e] = 0.f;
            }
            uint4 hv, lv;
            uint32_t* hp = (uint32_t*)&hv;
            uint32_t* lp = (uint32_t*)&lv;
            #pragma unroll
            for (int e = 0; e < 4; e++) {
                __half h0 = __float2half_rn(v[2*e]);
                __half h1 = __float2half_rn(v[2*e+1]);
                __half l0 = __float2half_rn(v[2*e]   - __half2float(h0));
                __half l1 = __float2half_rn(v[2*e+1] - __half2float(h1));
                __half2 hh = __halves2half2(h0, h1);
                __half2 ll = __halves2half2(l0, l1);
                hp[e] = *(uint32_t*)&hh;
                lp[e] = *(uint32_t*)&ll;
            }
            uint32_t addr = (uint32_t)r * 128 + (uint32_t)((c8 ^ (r & 7)) << 4);
            *(uint4*)(smem + L_AHI + addr) = hv;
            *(uint4*)(smem + L_ALO + addr) = lv;
        }
        if (ch + 1 < NCH) {
            const __half* bs = wB + (size_t)(ch + 1) * 6144;
            uint32_t dst = sb + ((ch & 1) ? L_B0 : L_B1);
            #pragma unroll
            for (int t = tid; t < 768; t += 256)
                cpa16(dst + t * 16, bs + t * 8);
            cpa_commit();
            cpa_wait1();
        } else {
            cpa_wait0();
        }
        __syncthreads();

        uint32_t bbase = sb + ((ch & 1) ? L_B1 : L_B0);
        #pragma unroll 4
        for (int kk = 0; kk < kmax; kk++) {
            uint32_t ah[2][4], al[2][4], bh[3][4];
            #pragma unroll
            for (int mi = 0; mi < 2; mi++) {
                int r = m_off + mi * 16 + a_row_in;
                int kc = kk * 2 + a_khalf;
                uint32_t off = (uint32_t)r * 128 + (uint32_t)((kc ^ (r & 7)) << 4);
                ldsm4(ah[mi], sb + L_AHI + off);
                ldsm4(al[mi], sb + L_ALO + off);
            }
            #pragma unroll
            for (int ni = 0; ni < 3; ni++) {
                int r = brow[ni];
                int kc = kk * 2 + b_khalf;
                uint32_t off = (uint32_t)r * 128 + (uint32_t)((kc ^ (r & 7)) << 4);
                ldsm4(bh[ni], bbase + off);
            }
            #pragma unroll
            for (int mi = 0; mi < 2; mi++) {
                #pragma unroll
                for (int nj = 0; nj < 6; nj++) {
                    const uint32_t* bfh = &bh[nj >> 1][(nj & 1) * 2];
                    mma16816h(acc[mi][nj], ah[mi], bfh);
                    mma16816h(acc[mi][nj], al[mi], bfh);
                }
            }
        }
    }

    // ---- epilogue: devox gather (sorted slots) + bias + tanh ----
    #pragma unroll
    for (int mi = 0; mi < 2; mi++) {
        #pragma unroll
        for (int half = 0; half < 2; half++) {
            int r = m_off + mi * 16 + (lane >> 2) + half * 8;
            int slot = pbase + r;
            if (slot >= NPTS) continue;
            int p = g_sorted[slot];
            #pragma unroll
            for (int j = 0; j < 8; j++) {
                float w = g_nbw[j*NPTS + slot];
                if (w != 0.f) {
                    const float* gp = convsrc + (size_t)g_nbi[j*NPTS + slot] * 96;
                    #pragma unroll
                    for (int nj = 0; nj < 6; nj++) {
                        int co = n_off + nj * 8 + 2 * (lane & 3);
                        float2 gg = *(const float2*)(gp + co);
                        acc[mi][nj][half*2]   += w * gg.x;
                        acc[mi][nj][half*2+1] += w * gg.y;
                    }
                }
            }
            #pragma unroll
            for (int nj = 0; nj < 6; nj++) {
                int co = n_off + nj * 8 + 2 * (lane & 3);
                float2 bb = *(const float2*)(bias + co);
                float vx = acc[mi][nj][half*2]   + bb.x;
                float vy = acc[mi][nj][half*2+1] + bb.y;
                if (do_tanh) { vx = tanhf(vx); vy = tanhf(vy); }
                *(float2*)(out + (size_t)p * 96 + co) = make_float2(vx, vy);
            }
        }
    }
}

// ======================= attn stage ==========================================
__global__ void __launch_bounds__(256) voxdot_k(const float* __restrict__ src) {
    __shared__ float ws[27*96];
    int tid = threadIdx.x;
    for (int i = tid; i < 27*96; i += 256) ws[i] = g_vT[i];
    __syncthreads();
    int wid = tid >> 5, lane = tid & 31;
    int v = blockIdx.x * 8 + wid;
    if (v >= G3) return;
    int s0 = g_start[v], s1 = g_start[v+1];
    float a0 = 0.f, a1 = 0.f, a2 = 0.f;
    for (int k = s0; k < s1; k++) {
        const float* r = src + (size_t)g_sorted[k] * 96;
        a0 += r[lane]; a1 += r[lane+32]; a2 += r[lane+64];
    }
    if (s1 > s0) {
        float invn = 1.f / (float)(s1 - s0);
        a0 *= invn; a1 *= invn; a2 *= invn;
    }
    #pragma unroll 9
    for (int t = 0; t < 27; t++) {
        float s = a0*ws[t*96+lane] + a1*ws[t*96+lane+32] + a2*ws[t*96+lane+64];
        s += __shfl_xor_sync(0xFFFFFFFF, s, 16);
        s += __shfl_xor_sync(0xFFFFFFFF, s, 8);
        s += __shfl_xor_sync(0xFFFFFFFF, s, 4);
        s += __shfl_xor_sync(0xFFFFFFFF, s, 2);
        s += __shfl_xor_sync(0xFFFFFFFF, s, 1);
        if (lane == 0) g_P[t*G3 + v] = s;
    }
}

__global__ void stencil_k() {
    int v = blockIdx.x * blockDim.x + threadIdx.x;
    if (v >= G3) return;
    int px = v >> 10, py = (v >> 5) & 31, pz = v & 31;
    float acc = 0.f;
    #pragma unroll
    for (int t = 0; t < 27; t++) {
        int kx = t / 9, ky = (t / 3) % 3, kz = t % 3;
        int nx = px + kx - 1, ny = py + ky - 1, nz = pz + kz - 1;
        if ((unsigned)nx < GRES && (unsigned)ny < GRES && (unsigned)nz < GRES)
            acc += g_P[t*G3 + ((nx<<5) + ny)*32 + nz];
    }
    g_vout[v] = acc;
}

__global__ void attn_k(const float* __restrict__ energy,
                       const float* __restrict__ v_lw, const float* __restrict__ v_lb) {
    int s = blockIdx.x * blockDim.x + threadIdx.x;
    if (s >= NPTS) return;
    int p = g_sorted[s];
    float acc = v_lb[0];
    #pragma unroll
    for (int j = 0; j < 8; j++) {
        float w = g_nbw[j*NPTS + s];
        if (w != 0.f) acc += w * g_vout[g_nbi[j*NPTS + s]];
    }
    const float4* er4 = (const float4*)(energy + (size_t)p * CDIM);
    const float4* vw4 = (const float4*)v_lw;
    #pragma unroll 6
    for (int cb = 0; cb < 24; cb++) {
        float4 e = er4[cb], w = vw4[cb];
        acc += e.x*w.x + e.y*w.y + e.z*w.z + e.w*w.w;
    }
    g_attn[p] = acc;
}

// ======================= host orchestration =================================
extern "C" void kernel_launch(void* const* d_in, const int* in_sizes, int n_in,
                              void* d_out, int out_size) {
    const float* hidden   = (const float*)d_in[0];
    const float* query    = (const float*)d_in[1];
    const float* coords   = (const float*)d_in[2];
    const float* wq_conv  = (const float*)d_in[3];
    const float* wq_lw    = (const float*)d_in[4];
    const float* wq_lb    = (const float*)d_in[5];
    const float* wh_conv  = (const float*)d_in[6];
    const float* wh_lw    = (const float*)d_in[7];
    const float* wh_lb    = (const float*)d_in[8];
    const float* att_conv = (const float*)d_in[9];
    const float* att_lw   = (const float*)d_in[10];
    const float* att_lb   = (const float*)d_in[11];
    const float* v_conv   = (const float*)d_in[12];
    const float* v_lw     = (const float*)d_in[13];
    const float* v_lb     = (const float*)d_in[14];
    const float* upd_conv = (const float*)d_in[15];
    const float* upd_lw   = (const float*)d_in[16];
    const float* upd_lb   = (const float*)d_in[17];
    float* out = (float*)d_out;

    int *picnt;
    float *pq, *ph, *pe, *pattn, *pconv, *pconv2;
    __half *pwqB, *pwhB, *pattB, *pupdB;
    __half *pwqlB, *pwhlB, *pattlB, *pupdlB;
    __half *pA96h, *pA96l, *pB96h, *pB96l, *pA192h, *pA192l;
    cudaGetSymbolAddress((void**)&picnt,  g_icnt);
    cudaGetSymbolAddress((void**)&pq,     g_q);
    cudaGetSymbolAddress((void**)&ph,     g_h);
    cudaGetSymbolAddress((void**)&pe,     g_energy);
    cudaGetSymbolAddress((void**)&pattn,  g_attn);
    cudaGetSymbolAddress((void**)&pconv,  g_conv);
    cudaGetSymbolAddress((void**)&pconv2, g_conv2);
    cudaGetSymbolAddress((void**)&pwqB,   g_wqB);
    cudaGetSymbolAddress((void**)&pwhB,   g_whB);
    cudaGetSymbolAddress((void**)&pattB,  g_attB);
    cudaGetSymbolAddress((void**)&pupdB,  g_updB);
    cudaGetSymbolAddress((void**)&pwqlB,  g_wqlB);
    cudaGetSymbolAddress((void**)&pwhlB,  g_whlB);
    cudaGetSymbolAddress((void**)&pattlB, g_attlB);
    cudaGetSymbolAddress((void**)&pupdlB, g_updlB);
    cudaGetSymbolAddress((void**)&pA96h,  g_pA96_hi);
    cudaGetSymbolAddress((void**)&pA96l,  g_pA96_lo);
    cudaGetSymbolAddress((void**)&pB96h,  g_pB96_hi);
    cudaGetSymbolAddress((void**)&pB96l,  g_pB96_lo);
    cudaGetSymbolAddress((void**)&pA192h, g_pA192_hi);
    cudaGetSymbolAddress((void**)&pA192l, g_pA192_lo);

    cudaFuncSetAttribute(conv_mma_k<128,2>, cudaFuncAttributeMaxDynamicSharedMemorySize, SM_TOT);
    cudaFuncSetAttribute(conv_mma_k<192,3>, cudaFuncAttributeMaxDynamicSharedMemorySize, SM_TOT);
    cudaFuncSetAttribute(lindevox_k<128,2>, cudaFuncAttributeMaxDynamicSharedMemorySize, L_TOT);
    cudaFuncSetAttribute(lindevox_k<192,3>, cudaFuncAttributeMaxDynamicSharedMemorySize, L_TOT);

    const int TB = 256;
    auto gs = [](long long n, int tb){ return (int)((n + tb - 1) / tb); };
    const int LBLK = (NPTS + 127) / 128;   // 782
    const long long PREP_N = 2LL*27*128*96 + 2LL*27*192*96 + 2LL*128*96 + 2LL*192*96 + 27*96;

    // --- shared precompute ---
    zeroi_k<<<gs(G3,TB), TB>>>(picnt, G3);
    vox_k<<<gs(NPTS,TB), TB>>>(coords);
    scan_k<<<1, 1024>>>();
    fill_k<<<gs(NPTS,TB), TB>>>();
    trilin_k<<<gs(NPTS,TB), TB>>>(coords);
    zero6_k<<<gs((long long)PGV*896/8,TB), TB>>>(pA96h, pA96l, pB96h, pB96l, pA192h, pA192l);
    prep_all_k<<<gs(PREP_N,TB), TB>>>(wq_conv, wh_conv, att_conv, upd_conv,
                                      wq_lw, wh_lw, att_lw, upd_lw, v_conv,
                                      pwqB, pwhB, pattB, pupdB,
                                      pwqlB, pwhlB, pattlB, pupdlB);

    // --- merged sconv q + sconv h ---
    gathervox_qh_k<<<gs(2LL*G3*24,TB), TB>>>(query, hidden);
    conv_mma_k<128,2><<<512, 256, SM_TOT>>>(pwqB, pA96h, pA96l, pconv,
                                            pwhB, pB96h, pB96l, pconv2, 256);
    lindevox_k<128,2><<<2*LBLK, 256, L_TOT>>>(
        query, nullptr, nullptr, pwqlB, wq_lb, pconv, pq,
        hidden, nullptr, nullptr, pwhlB, wh_lb, pconv2, ph, LBLK, 0);

    // --- energy = tanh(sconv([h, q])) ---
    gathervox192_k<<<gs(2LL*G3*24,TB), TB>>>(ph, pq);
    conv_mma_k<192,3><<<256, 256, SM_TOT>>>(pattB, pA192h, pA192l, pconv,
                                            pattB, pA192h, pA192l, pconv, 256);
    lindevox_k<192,3><<<LBLK, 256, L_TOT>>>(
        ph, pq, nullptr, pattlB, att_lb, pconv, pe,
        ph, pq, nullptr, pattlB, att_lb, pconv, pe, LBLK, 1);

    // --- attn = sconv(energy), cout=1 ---
    voxdot_k<<<G3/8, 256>>>(pe);
    stencil_k<<<gs(G3,TB), TB>>>();
    attn_k<<<gs(NPTS,TB), TB>>>(pe, v_lw, v_lb);

    // --- out = tanh(sconv([q, attn*h])) ---
    mkq_sc_k<<<gs((long long)G3*36,TB), TB>>>(ph, pattn);
    conv_mma_k<192,3><<<256, 256, SM_TOT>>>(pupdB, pA192h, pA192l, pconv,
                                            pupdB, pA192h, pA192l, pconv, 256);
    lindevox_k<192,3><<<LBLK, 256, L_TOT>>>(
        pq, ph, pattn, pupdlB, upd_lb, pconv, out,
        pq, ph, pattn, pupdlB, upd_lb, pconv, out, LBLK, 1);
}

// round 12
// speedup vs baseline: 6.5915x; 1.0212x over previous
#include <cuda_runtime.h>
#include <cuda_fp16.h>
#include <cstdint>
#include <math.h>

#define NPTS 100000
#define CDIM 96
#define GRES 32
#define G3   (GRES*GRES*GRES)
#define PAD  34
#define PP2  (PAD*PAD)
#define PGV  (PP2*PAD)

// ======================= scratch (device globals) ===========================
__device__ int   g_vidx[NPTS];
__device__ int   g_icnt[G3];
__device__ int   g_start[G3+1];
__device__ int   g_pos[G3];
__device__ int   g_sorted[NPTS];
__device__ int   g_nbi[8*NPTS];       // indexed by SORTED slot
__device__ float g_nbw[8*NPTS];       // indexed by SORTED slot
__device__ float g_P[27*G3];          // per-tap dot products (attn stage)
__device__ float g_conv[G3*CDIM];
__device__ float g_conv2[G3*CDIM];
__device__ float g_vout[G3];
__device__ float g_q[NPTS*CDIM];
__device__ float g_h[NPTS*CDIM];
__device__ float g_energy[NPTS*CDIM];
__device__ float g_attn[NPTS];
// padded fp16 split grids
__device__ __half g_pA96_hi [PGV*128];   // voxelized query input
__device__ __half g_pA96_lo [PGV*128];
__device__ __half g_pB96_hi [PGV*128];   // voxelized hidden input
__device__ __half g_pB96_lo [PGV*128];
__device__ __half g_pA192_hi[PGV*192];
__device__ __half g_pA192_lo[PGV*192];
// cached voxelized q_out (interior), reused stage3 -> stage5
__device__ __half g_pQ96_hi[PGV*96];
__device__ __half g_pQ96_lo[PGV*96];
// pre-swizzled fp16 conv weights (hi only): [tap*nch+chunk][6144 = 96 rows x 64 ci]
__device__ __half g_wqB [27*2*6144];
__device__ __half g_whB [27*2*6144];
__device__ __half g_attB[27*3*6144];
__device__ __half g_updB[27*3*6144];
// pre-swizzled fp16 linear weights: [chunk][6144]
__device__ __half g_wqlB [2*6144];
__device__ __half g_whlB [2*6144];
__device__ __half g_attlB[3*6144];
__device__ __half g_updlB[3*6144];
__device__ float g_vT[27*CDIM];

// ======================= mma/ldmatrix/cp.async helpers =======================
__device__ __forceinline__ uint32_t smem_u32(const void* p) {
    uint32_t a;
    asm("{ .reg .u64 t; cvta.to.shared.u64 t, %1; cvt.u32.u64 %0, t; }" : "=r"(a) : "l"(p));
    return a;
}
__device__ __forceinline__ void ldsm4(uint32_t* r, uint32_t addr) {
    asm volatile("ldmatrix.sync.aligned.m8n8.x4.shared.b16 {%0,%1,%2,%3}, [%4];"
        : "=r"(r[0]), "=r"(r[1]), "=r"(r[2]), "=r"(r[3]) : "r"(addr));
}
__device__ __forceinline__ void mma16816h(float* c, const uint32_t* a, const uint32_t* b) {
    asm volatile("mma.sync.aligned.m16n8k16.row.col.f32.f16.f16.f32 "
        "{%0,%1,%2,%3}, {%4,%5,%6,%7}, {%8,%9}, {%0,%1,%2,%3};"
        : "+f"(c[0]), "+f"(c[1]), "+f"(c[2]), "+f"(c[3])
        : "r"(a[0]), "r"(a[1]), "r"(a[2]), "r"(a[3]), "r"(b[0]), "r"(b[1]));
}
__device__ __forceinline__ void cpa16(uint32_t dst, const void* src) {
    asm volatile("cp.async.cg.shared.global [%0], [%1], 16;" :: "r"(dst), "l"(src));
}
__device__ __forceinline__ void cpa_commit() { asm volatile("cp.async.commit_group;"); }
__device__ __forceinline__ void cpa_wait0()  { asm volatile("cp.async.wait_group 0;"); }
__device__ __forceinline__ void cpa_wait1()  { asm volatile("cp.async.wait_group 1;"); }

// ======================= sort/index kernels ==================================
__global__ void zeroi_k(int* __restrict__ p, int n) {
    int i = blockIdx.x * blockDim.x + threadIdx.x;
    if (i < n) p[i] = 0;
}

__global__ void vox_k(const float* __restrict__ coords) {
    int p = blockIdx.x * blockDim.x + threadIdx.x;
    if (p >= NPTS) return;
    int vx = min(max((int)floorf(coords[3*p+0]), 0), GRES-1);
    int vy = min(max((int)floorf(coords[3*p+1]), 0), GRES-1);
    int vz = min(max((int)floorf(coords[3*p+2]), 0), GRES-1);
    int flat = (vx*GRES + vy)*GRES + vz;
    g_vidx[p] = flat;
    atomicAdd(&g_icnt[flat], 1);
}

__global__ void __launch_bounds__(1024) scan_k() {
    __shared__ int bs[1024];
    int t = threadIdx.x;
    int base = t * 32;
    int loc[32];
    int s = 0;
    #pragma unroll
    for (int k = 0; k < 32; k++) { loc[k] = s; s += g_icnt[base + k]; }
    bs[t] = s;
    __syncthreads();
    #pragma unroll
    for (int d = 1; d < 1024; d <<= 1) {
        int v = (t >= d) ? bs[t - d] : 0;
        __syncthreads();
        bs[t] += v;
        __syncthreads();
    }
    int off = bs[t] - s;
    #pragma unroll
    for (int k = 0; k < 32; k++) {
        g_start[base + k] = off + loc[k];
        g_pos[base + k]   = off + loc[k];
    }
    if (t == 1023) g_start[G3] = off + s;
}

// fused counting-sort fill + trilinear neighbor precompute (sorted-slot order)
__global__ void filltrilin_k(const float* __restrict__ coords) {
    int p = blockIdx.x * blockDim.x + threadIdx.x;
    if (p >= NPTS) return;
    int s = atomicAdd(&g_pos[g_vidx[p]], 1);
    g_sorted[s] = p;
    float cx = coords[3*p+0], cy = coords[3*p+1], cz = coords[3*p+2];
    float bx = floorf(cx), by = floorf(cy), bz = floorf(cz);
    float fx = cx - bx, fy = cy - by, fz = cz - bz;
    int ix = (int)bx, iy = (int)by, iz = (int)bz;
    #pragma unroll
    for (int j = 0; j < 8; j++) {
        int dx = (j >> 2) & 1, dy = (j >> 1) & 1, dz = j & 1;
        int nx = ix + dx, ny = iy + dy, nz = iz + dz;
        bool valid = (nx >= 0 && nx < GRES && ny >= 0 && ny < GRES && nz >= 0 && nz < GRES);
        int cxc = min(max(nx,0),GRES-1), cyc = min(max(ny,0),GRES-1), czc = min(max(nz,0),GRES-1);
        int flc = (cxc*GRES + cyc)*GRES + czc;
        float w = (dx ? fx : 1.f-fx) * (dy ? fy : 1.f-fy) * (dz ? fz : 1.f-fz);
        if (!valid || g_icnt[flc] == 0) w = 0.f;
        g_nbi[j*NPTS + s] = flc;
        g_nbw[j*NPTS + s] = w;
    }
}

// ======================= fp16 split helpers ==================================
__device__ __forceinline__ void f16_split_store4(
    float4 acc, __half* dhi, __half* dlo, size_t o) {
    __half h0 = __float2half_rn(acc.x), h1 = __float2half_rn(acc.y);
    __half h2 = __float2half_rn(acc.z), h3 = __float2half_rn(acc.w);
    __half l0 = __float2half_rn(acc.x - __half2float(h0));
    __half l1 = __float2half_rn(acc.y - __half2float(h1));
    __half l2 = __float2half_rn(acc.z - __half2float(h2));
    __half l3 = __float2half_rn(acc.w - __half2float(h3));
    __half2 hA = __halves2half2(h0, h1);
    __half2 hB = __halves2half2(h2, h3);
    __half2 lA = __halves2half2(l0, l1);
    __half2 lB = __halves2half2(l2, l3);
    *(__half2*)(dhi + o)     = hA;
    *(__half2*)(dhi + o + 2) = hB;
    *(__half2*)(dlo + o)     = lA;
    *(__half2*)(dlo + o + 2) = lB;
}

// merged q+h INPUT voxelize
__global__ void gathervox_qh_k(const float* __restrict__ q, const float* __restrict__ h) {
    int i = blockIdx.x * blockDim.x + threadIdx.x;
    if (i >= 2 * G3 * 24) return;
    bool sec = (i >= G3 * 24);
    int j = sec ? i - G3 * 24 : i;
    int c4 = j % 24;
    int v  = j / 24;
    int vx = v >> 10, vy = (v >> 5) & 31, vz = v & 31;
    int pv = ((vx + 1) * PAD + (vy + 1)) * PAD + (vz + 1);
    int ci = c4 * 4;
    const float* src = sec ? h : q;

    float4 acc = make_float4(0.f, 0.f, 0.f, 0.f);
    int s0 = g_start[v], s1 = g_start[v+1];
    if (s1 > s0) {
        for (int k = s0; k < s1; k++) {
            int pid = g_sorted[k];
            float4 f = *(const float4*)(src + (size_t)pid * 96 + ci);
            acc.x += f.x; acc.y += f.y; acc.z += f.z; acc.w += f.w;
        }
        float invn = 1.f / (float)(s1 - s0);
        acc.x *= invn; acc.y *= invn; acc.z *= invn; acc.w *= invn;
    }
    f16_split_store4(acc,
        sec ? g_pB96_hi : g_pA96_hi, sec ? g_pB96_lo : g_pA96_lo,
        (size_t)pv * 128 + ci);
}

// stage-3 voxelize of OUTPUTS: pA192 = [mean(h_out) | mean(q_out)] + cache q grid
__global__ void gathervox192_k(const float* __restrict__ h, const float* __restrict__ q) {
    int i = blockIdx.x * blockDim.x + threadIdx.x;
    if (i >= 2 * G3 * 24) return;
    bool sec = (i >= G3 * 24);   // sec = q half
    int j = sec ? i - G3 * 24 : i;
    int c4 = j % 24;
    int v  = j / 24;
    int vx = v >> 10, vy = (v >> 5) & 31, vz = v & 31;
    int pv = ((vx + 1) * PAD + (vy + 1)) * PAD + (vz + 1);
    int ci = c4 * 4;
    const float* src = sec ? q : h;

    float4 acc = make_float4(0.f, 0.f, 0.f, 0.f);
    int s0 = g_start[v], s1 = g_start[v+1];
    if (s1 > s0) {
        for (int k = s0; k < s1; k++) {
            int pid = g_sorted[k];
            float4 f = *(const float4*)(src + (size_t)pid * 96 + ci);
            acc.x += f.x; acc.y += f.y; acc.z += f.z; acc.w += f.w;
        }
        float invn = 1.f / (float)(s1 - s0);
        acc.x *= invn; acc.y *= invn; acc.z *= invn; acc.w *= invn;
    }
    if (!sec) {
        f16_split_store4(acc, g_pA192_hi, g_pA192_lo, (size_t)pv * 192 + ci);
    } else {
        f16_split_store4(acc, g_pA192_hi, g_pA192_lo, (size_t)pv * 192 + 96 + ci);
        f16_split_store4(acc, g_pQ96_hi, g_pQ96_lo, (size_t)pv * 96 + ci);
    }
}

// stage-5: merged (q-cache copy) + (mean(attn*h) gather)
__global__ void mkq_sc_k(const float* __restrict__ h, const float* __restrict__ scale) {
    const int NCOPY = G3 * 12;
    int i = blockIdx.x * blockDim.x + threadIdx.x;
    if (i < NCOPY) {
        int u = i % 12;
        int v = i / 12;
        int vx = v >> 10, vy = (v >> 5) & 31, vz = v & 31;
        int pv = ((vx + 1) * PAD + (vy + 1)) * PAD + (vz + 1);
        size_t s = (size_t)pv * 96 + u * 8;
        size_t d = (size_t)pv * 192 + u * 8;
        *(uint4*)(g_pA192_hi + d) = *(const uint4*)(g_pQ96_hi + s);
        *(uint4*)(g_pA192_lo + d) = *(const uint4*)(g_pQ96_lo + s);
        return;
    }
    int j = i - NCOPY;
    if (j >= G3 * 24) return;
    int c4 = j % 24;
    int v  = j / 24;
    int vx = v >> 10, vy = (v >> 5) & 31, vz = v & 31;
    int pv = ((vx + 1) * PAD + (vy + 1)) * PAD + (vz + 1);
    int ci = c4 * 4;
    float4 acc = make_float4(0.f, 0.f, 0.f, 0.f);
    int s0 = g_start[v], s1 = g_start[v+1];
    if (s1 > s0) {
        for (int k = s0; k < s1; k++) {
            int pid = g_sorted[k];
            float4 f = *(const float4*)(h + (size_t)pid * 96 + ci);
            float m = scale[pid];
            acc.x += f.x * m; acc.y += f.y * m; acc.z += f.z * m; acc.w += f.w * m;
        }
        float invn = 1.f / (float)(s1 - s0);
        acc.x *= invn; acc.y *= invn; acc.z *= invn; acc.w *= invn;
    }
    f16_split_store4(acc, g_pA192_hi, g_pA192_lo, (size_t)pv * 192 + 96 + ci);
}

// ======================= merged weight prep + grid zero ======================
__device__ __forceinline__ void conv_prep(int i, const float* w, __half* dst,
                                          int CIN, int KPAD, int NCH) {
    int co  = i % 96;
    int r   = i / 96;
    int ci  = r % KPAD;
    int tap = r / KPAD;
    float val = (ci < CIN) ? w[((size_t)co * CIN + ci) * 27 + tap] : 0.f;
    int chunk = ci >> 6;
    int cw = ci & 63;
    uint32_t elem = (uint32_t)co * 64 + (uint32_t)(((cw >> 3) ^ (co & 7)) * 8) + (cw & 7);
    dst[(size_t)(tap * NCH + chunk) * 6144 + elem] = __float2half_rn(val);
}
__device__ __forceinline__ void lin_prep(int i, const float* w, __half* dst, int CIN) {
    int co = i % 96;
    int ci = i / 96;
    float val = (ci < CIN) ? w[(size_t)co * CIN + ci] : 0.f;
    int chunk = ci >> 6;
    int cw = ci & 63;
    uint32_t elem = (uint32_t)co * 64 + (uint32_t)(((cw >> 3) ^ (co & 7)) * 8) + (cw & 7);
    dst[(size_t)chunk * 6144 + elem] = __float2half_rn(val);
}

#define U128 (PGV * 128 / 8)
#define U192 (PGV * 192 / 8)

__global__ void prep_all_k(const float* wq, const float* wh, const float* att,
                           const float* upd, const float* wql, const float* whl,
                           const float* attl, const float* updl, const float* vconv,
                           __half* dwq, __half* dwh, __half* datt, __half* dupd,
                           __half* dwql, __half* dwhl, __half* dattl, __half* dupdl,
                           __half* za, __half* zb, __half* zc, __half* zd,
                           __half* ze, __half* zf) {
    const int C96 = 27*128*96, C192 = 27*192*96, L96 = 128*96, L192 = 192*96;
    long long i = (long long)blockIdx.x * blockDim.x + threadIdx.x;
    // grid zeroing first (bulk)
    uint4 z = make_uint4(0u, 0u, 0u, 0u);
    if (i < U128)            { ((uint4*)za)[i] = z; return; }
    i -= U128;
    if (i < U128)            { ((uint4*)zb)[i] = z; return; }
    i -= U128;
    if (i < U128)            { ((uint4*)zc)[i] = z; return; }
    i -= U128;
    if (i < U128)            { ((uint4*)zd)[i] = z; return; }
    i -= U128;
    if (i < U192)            { ((uint4*)ze)[i] = z; return; }
    i -= U192;
    if (i < U192)            { ((uint4*)zf)[i] = z; return; }
    i -= U192;
    int k = (int)i;
    if (k < C96) { conv_prep(k, wq, dwq, 96, 128, 2); return; }
    k -= C96;
    if (k < C96) { conv_prep(k, wh, dwh, 96, 128, 2); return; }
    k -= C96;
    if (k < C192) { conv_prep(k, att, datt, 192, 192, 3); return; }
    k -= C192;
    if (k < C192) { conv_prep(k, upd, dupd, 192, 192, 3); return; }
    k -= C192;
    if (k < L96) { lin_prep(k, wql, dwql, 96); return; }
    k -= L96;
    if (k < L96) { lin_prep(k, whl, dwhl, 96); return; }
    k -= L96;
    if (k < L192) { lin_prep(k, attl, dattl, 192); return; }
    k -= L192;
    if (k < L192) { lin_prep(k, updl, dupdl, 192); return; }
    k -= L192;
    if (k < 27*96) { int t = k % 27, ci = k / 27; g_vT[t*96 + ci] = vconv[ci*27 + t]; }
}

// ======================= HMMA 3x3x3 conv (slab A, dual-job, fp16 2-term) =====
// A slab + B tiles staged via cp.async; K=96 chunk-1 short path (kmax=2).
#define A_SPLIT 26112            // 204 rows * 128B
#define SM_B0   52224
#define SM_B1   64512
#define SM_TOT  76928

template<int KPAD, int NCH>
__global__ void __launch_bounds__(256, 2) conv_mma_k(
    const __half* __restrict__ wBa, const __half* __restrict__ pAhiA,
    const __half* __restrict__ pAloA, float* __restrict__ outA,
    const __half* __restrict__ wBb, const __half* __restrict__ pAhiB,
    const __half* __restrict__ pAloB, float* __restrict__ outB,
    int split_blk) {
    extern __shared__ char smem[];
    uint32_t sb = smem_u32(smem);
    int tid = threadIdx.x;
    int warp = tid >> 5, lane = tid & 31;
    int m_off = (warp & 3) * 32;
    int n_off = (warp >> 2) * 48;

    int blk = blockIdx.x;
    bool sec = (blk >= split_blk);
    if (sec) blk -= split_blk;
    const __half* wB   = sec ? wBb   : wBa;
    const __half* pAhi = sec ? pAhiB : pAhiA;
    const __half* pAlo = sec ? pAloB : pAloA;
    float* outp = sec ? outB : outA;

    int x  = blk >> 3;
    int y0 = (blk & 7) * 4;

    float acc[2][6][4];
    #pragma unroll
    for (int mi = 0; mi < 2; mi++)
        #pragma unroll
        for (int nj = 0; nj < 6; nj++)
            #pragma unroll
            for (int e = 0; e < 4; e++) acc[mi][nj][e] = 0.f;

    int a_row_in = (lane & 7) + ((lane >> 3) & 1) * 8;
    int a_khalf  = lane >> 4;
    int b_row_in = (lane & 7) + ((lane >> 3) >> 1) * 8;
    int b_khalf  = (lane >> 3) & 1;

    int rb[2];
    #pragma unroll
    for (int mi = 0; mi < 2; mi++) {
        int m = m_off + mi * 16 + a_row_in;
        rb[mi] = (m >> 5) * 34 + (m & 31);
    }
    int brow[3];
    #pragma unroll
    for (int ni = 0; ni < 3; ni++) brow[ni] = n_off + ni * 16 + b_row_in;

    for (int cc = 0; cc < NCH; cc++) {
        bool shortk = (KPAD == 128 && cc == 1);
        int kmax  = shortk ? 2 : 4;
        int c8max = shortk ? 4 : 8;
        int c8sh  = shortk ? 2 : 3;
        int ahalf = 204 * c8max;

        for (int dx = 0; dx < 3; dx++) {
            __syncthreads();   // all warps done with A slab + B buffers

            // B[tap0] + A slab in ONE cp.async group (no LDG->STS latency chain)
            {
                const __half* bs = wB + (size_t)((dx * 9) * NCH + cc) * 6144;
                #pragma unroll
                for (int t = tid; t < 768; t += 256)
                    cpa16(sb + SM_B0 + t * 16, bs + t * 8);
                size_t pvbase = ((size_t)(x + dx) * PAD + y0) * PAD;
                for (int t = tid; t < 2 * ahalf; t += 256) {
                    int split = (t >= ahalf);
                    int e = split ? t - ahalf : t;
                    int r = e >> c8sh, c8 = e & (c8max - 1);
                    const __half* src =
                        (split ? pAlo : pAhi) + (pvbase + r) * KPAD + cc * 64 + c8 * 8;
                    cpa16(sb + split * A_SPLIT + (uint32_t)r * 128 + ((c8 ^ (r & 7)) << 4), src);
                }
                cpa_commit();
            }

            for (int t9 = 0; t9 < 9; t9++) {
                cpa_wait0();
                __syncthreads();
                if (t9 < 8) {
                    const __half* bs =
                        wB + (size_t)((dx * 9 + t9 + 1) * NCH + cc) * 6144;
                    uint32_t dst = sb + ((t9 & 1) ? SM_B0 : SM_B1);
                    #pragma unroll
                    for (int t = tid; t < 768; t += 256)
                        cpa16(dst + t * 16, bs + t * 8);
                    cpa_commit();
                }
                uint32_t bbase = sb + ((t9 & 1) ? SM_B1 : SM_B0);
                int toff = (t9 / 3) * PAD + (t9 % 3);

                #pragma unroll 4
                for (int kk = 0; kk < kmax; kk++) {
                    uint32_t ah[2][4], al[2][4], bh[3][4];
                    #pragma unroll
                    for (int mi = 0; mi < 2; mi++) {
                        int r = rb[mi] + toff;
                        int kc = kk * 2 + a_khalf;
                        uint32_t off = (uint32_t)r * 128 + (uint32_t)((kc ^ (r & 7)) << 4);
                        ldsm4(ah[mi], sb + off);
                        ldsm4(al[mi], sb + A_SPLIT + off);
                    }
                    #pragma unroll
                    for (int ni = 0; ni < 3; ni++) {
                        int r = brow[ni];
                        int kc = kk * 2 + b_khalf;
                        uint32_t off = (uint32_t)r * 128 + (uint32_t)((kc ^ (r & 7)) << 4);
                        ldsm4(bh[ni], bbase + off);
                    }
                    #pragma unroll
                    for (int mi = 0; mi < 2; mi++) {
                        #pragma unroll
                        for (int nj = 0; nj < 6; nj++) {
                            const uint32_t* bfh = &bh[nj >> 1][(nj & 1) * 2];
                            mma16816h(acc[mi][nj], ah[mi], bfh);
                            mma16816h(acc[mi][nj], al[mi], bfh);
                        }
                    }
                }
            }
        }
    }

    #pragma unroll
    for (int mi = 0; mi < 2; mi++) {
        #pragma unroll
        for (int half = 0; half < 2; half++) {
            int r = m_off + mi * 16 + (lane >> 2) + half * 8;
            int j = r >> 5, z = r & 31;
            size_t vbase = ((size_t)(x * GRES + y0 + j) * GRES + z) * 96;
            #pragma unroll
            for (int nj = 0; nj < 6; nj++) {
                int co = n_off + nj * 8 + 2 * (lane & 3);
                float2 v = make_float2(acc[mi][nj][half * 2], acc[mi][nj][half * 2 + 1]);
                *(float2*)(&outp[vbase + co]) = v;
            }
        }
    }
}

// ======================= fused linear GEMM + devox epilogue (dual, SORTED) ===
#define L_AHI 0
#define L_ALO 16384
#define L_B0  32768
#define L_B1  45056
#define L_TOT 57344

template<int KPAD, int NCH>
__global__ void __launch_bounds__(256, 2) lindevox_k(
    const float* __restrict__ x1a, const float* __restrict__ x2a,
    const float* __restrict__ s2a, const __half* __restrict__ wBa,
    const float* __restrict__ biasa, const float* __restrict__ convA,
    float* __restrict__ outa,
    const float* __restrict__ x1b, const float* __restrict__ x2b,
    const float* __restrict__ s2b, const __half* __restrict__ wBb,
    const float* __restrict__ biasb, const float* __restrict__ convB,
    float* __restrict__ outb,
    int split_blk, int do_tanh) {
    extern __shared__ char smem[];
    uint32_t sb = smem_u32(smem);
    int tid = threadIdx.x;
    int warp = tid >> 5, lane = tid & 31;
    int m_off = (warp & 3) * 32;
    int n_off = (warp >> 2) * 48;

    int blk = blockIdx.x;
    bool sec = (blk >= split_blk);
    if (sec) blk -= split_blk;
    const float* x1 = sec ? x1b : x1a;
    const float* x2 = sec ? x2b : x2a;
    const float* scale2 = sec ? s2b : s2a;
    const __half* wB = sec ? wBb : wBa;
    const float* bias = sec ? biasb : biasa;
    const float* convsrc = sec ? convB : convA;
    float* out = sec ? outb : outa;
    int pbase = blk * 128;           // SORTED slot base

    float acc[2][6][4];
    #pragma unroll
    for (int mi = 0; mi < 2; mi++)
        #pragma unroll
        for (int nj = 0; nj < 6; nj++)
            #pragma unroll
            for (int e = 0; e < 4; e++) acc[mi][nj][e] = 0.f;

    int a_row_in = (lane & 7) + ((lane >> 3) & 1) * 8;
    int a_khalf  = lane >> 4;
    int b_row_in = (lane & 7) + ((lane >> 3) >> 1) * 8;
    int b_khalf  = (lane >> 3) & 1;
    int brow[3];
    #pragma unroll
    for (int ni = 0; ni < 3; ni++) brow[ni] = n_off + ni * 16 + b_row_in;

    #pragma unroll
    for (int t = tid; t < 768; t += 256)
        cpa16(sb + L_B0 + t * 16, wB + t * 8);
    cpa_commit();

    for (int ch = 0; ch < NCH; ch++) {
        if (ch) __syncthreads();
        bool shortk = (KPAD == 128 && ch == 1);
        int kmax  = shortk ? 2 : 4;
        int c8max = shortk ? 4 : 8;
        int c8sh  = shortk ? 2 : 3;

        for (int gidx = tid; gidx < 128 * c8max; gidx += 256) {
            int r = gidx >> c8sh, c8 = gidx & (c8max - 1);
            int slot = pbase + r;
            int colbase = ch * 64 + c8 * 8;
            float v[8];
            bool have = (slot < NPTS) && (colbase < ((KPAD == 128) ? 96 : 192));
            if (have) {
                int p = g_sorted[slot];
                const float* srcp;
                float m = 1.f;
                if (colbase < 96) srcp = x1 + (size_t)p * 96 + colbase;
                else {
                    srcp = x2 + (size_t)p * 96 + (colbase - 96);
                    if (scale2) m = scale2[p];
                }
                float4 aa = *(const float4*)srcp;
                float4 bb = *(const float4*)(srcp + 4);
                v[0]=aa.x*m; v[1]=aa.y*m; v[2]=aa.z*m; v[3]=aa.w*m;
                v[4]=bb.x*m; v[5]=bb.y*m; v[6]=bb.z*m; v[7]=bb.w*m;
            } else {
                #pragma unroll
                for (int e = 0; e < 8; e++) v[e] = 0.f;
            }
            uint4 hv, lv;
            uint32_t* hp = (uint32_t*)&hv;
            uint32_t* lp = (uint32_t*)&lv;
            #pragma unroll
            for (int e = 0; e < 4; e++) {
                __half h0 = __float2half_rn(v[2*e]);
                __half h1 = __float2half_rn(v[2*e+1]);
                __half l0 = __float2half_rn(v[2*e]   - __half2float(h0));
                __half l1 = __float2half_rn(v[2*e+1] - __half2float(h1));
                __half2 hh = __halves2half2(h0, h1);
                __half2 ll = __halves2half2(l0, l1);
                hp[e] = *(uint32_t*)&hh;
                lp[e] = *(uint32_t*)&ll;
            }
            uint32_t addr = (uint32_t)r * 128 + (uint32_t)((c8 ^ (r & 7)) << 4);
            *(uint4*)(smem + L_AHI + addr) = hv;
            *(uint4*)(smem + L_ALO + addr) = lv;
        }
        if (ch + 1 < NCH) {
            const __half* bs = wB + (size_t)(ch + 1) * 6144;
            uint32_t dst = sb + ((ch & 1) ? L_B0 : L_B1);
            #pragma unroll
            for (int t = tid; t < 768; t += 256)
                cpa16(dst + t * 16, bs + t * 8);
            cpa_commit();
            cpa_wait1();
        } else {
            cpa_wait0();
        }
        __syncthreads();

        uint32_t bbase = sb + ((ch & 1) ? L_B1 : L_B0);
        #pragma unroll 4
        for (int kk = 0; kk < kmax; kk++) {
            uint32_t ah[2][4], al[2][4], bh[3][4];
            #pragma unroll
            for (int mi = 0; mi < 2; mi++) {
                int r = m_off + mi * 16 + a_row_in;
                int kc = kk * 2 + a_khalf;
                uint32_t off = (uint32_t)r * 128 + (uint32_t)((kc ^ (r & 7)) << 4);
                ldsm4(ah[mi], sb + L_AHI + off);
                ldsm4(al[mi], sb + L_ALO + off);
            }
            #pragma unroll
            for (int ni = 0; ni < 3; ni++) {
                int r = brow[ni];
                int kc = kk * 2 + b_khalf;
                uint32_t off = (uint32_t)r * 128 + (uint32_t)((kc ^ (r & 7)) << 4);
                ldsm4(bh[ni], bbase + off);
            }
            #pragma unroll
            for (int mi = 0; mi < 2; mi++) {
                #pragma unroll
                for (int nj = 0; nj < 6; nj++) {
                    const uint32_t* bfh = &bh[nj >> 1][(nj & 1) * 2];
                    mma16816h(acc[mi][nj], ah[mi], bfh);
                    mma16816h(acc[mi][nj], al[mi], bfh);
                }
            }
        }
    }

    // ---- epilogue: devox gather (sorted slots) + bias + tanh ----
    #pragma unroll
    for (int mi = 0; mi < 2; mi++) {
        #pragma unroll
        for (int half = 0; half < 2; half++) {
            int r = m_off + mi * 16 + (lane >> 2) + half * 8;
            int slot = pbase + r;
            if (slot >= NPTS) continue;
            int p = g_sorted[slot];
            #pragma unroll
            for (int j = 0; j < 8; j++) {
                float w = g_nbw[j*NPTS + slot];
                if (w != 0.f) {
                    const float* gp = convsrc + (size_t)g_nbi[j*NPTS + slot] * 96;
                    #pragma unroll
                    for (int nj = 0; nj < 6; nj++) {
                        int co = n_off + nj * 8 + 2 * (lane & 3);
                        float2 gg = *(const float2*)(gp + co);
                        acc[mi][nj][half*2]   += w * gg.x;
                        acc[mi][nj][half*2+1] += w * gg.y;
                    }
                }
            }
            #pragma unroll
            for (int nj = 0; nj < 6; nj++) {
                int co = n_off + nj * 8 + 2 * (lane & 3);
                float2 bb = *(const float2*)(bias + co);
                float vx = acc[mi][nj][half*2]   + bb.x;
                float vy = acc[mi][nj][half*2+1] + bb.y;
                if (do_tanh) { vx = tanhf(vx); vy = tanhf(vy); }
                *(float2*)(out + (size_t)p * 96 + co) = make_float2(vx, vy);
            }
        }
    }
}

// ======================= attn stage ==========================================
__global__ void __launch_bounds__(256) voxdot_k(const float* __restrict__ src) {
    __shared__ float ws[27*96];
    int tid = threadIdx.x;
    for (int i = tid; i < 27*96; i += 256) ws[i] = g_vT[i];
    __syncthreads();
    int wid = tid >> 5, lane = tid & 31;
    int v = blockIdx.x * 8 + wid;
    if (v >= G3) return;
    int s0 = g_start[v], s1 = g_start[v+1];
    float a0 = 0.f, a1 = 0.f, a2 = 0.f;
    for (int k = s0; k < s1; k++) {
        const float* r = src + (size_t)g_sorted[k] * 96;
        a0 += r[lane]; a1 += r[lane+32]; a2 += r[lane+64];
    }
    if (s1 > s0) {
        float invn = 1.f / (float)(s1 - s0);
        a0 *= invn; a1 *= invn; a2 *= invn;
    }
    #pragma unroll 9
    for (int t = 0; t < 27; t++) {
        float s = a0*ws[t*96+lane] + a1*ws[t*96+lane+32] + a2*ws[t*96+lane+64];
        s += __shfl_xor_sync(0xFFFFFFFF, s, 16);
        s += __shfl_xor_sync(0xFFFFFFFF, s, 8);
        s += __shfl_xor_sync(0xFFFFFFFF, s, 4);
        s += __shfl_xor_sync(0xFFFFFFFF, s, 2);
        s += __shfl_xor_sync(0xFFFFFFFF, s, 1);
        if (lane == 0) g_P[t*G3 + v] = s;
    }
}

__global__ void stencil_k() {
    int v = blockIdx.x * blockDim.x + threadIdx.x;
    if (v >= G3) return;
    int px = v >> 10, py = (v >> 5) & 31, pz = v & 31;
    float acc = 0.f;
    #pragma unroll
    for (int t = 0; t < 27; t++) {
        int kx = t / 9, ky = (t / 3) % 3, kz = t % 3;
        int nx = px + kx - 1, ny = py + ky - 1, nz = pz + kz - 1;
        if ((unsigned)nx < GRES && (unsigned)ny < GRES && (unsigned)nz < GRES)
            acc += g_P[t*G3 + ((nx<<5) + ny)*32 + nz];
    }
    g_vout[v] = acc;
}

__global__ void attn_k(const float* __restrict__ energy,
                       const float* __restrict__ v_lw, const float* __restrict__ v_lb) {
    int s = blockIdx.x * blockDim.x + threadIdx.x;
    if (s >= NPTS) return;
    int p = g_sorted[s];
    float acc = v_lb[0];
    #pragma unroll
    for (int j = 0; j < 8; j++) {
        float w = g_nbw[j*NPTS + s];
        if (w != 0.f) acc += w * g_vout[g_nbi[j*NPTS + s]];
    }
    const float4* er4 = (const float4*)(energy + (size_t)p * CDIM);
    const float4* vw4 = (const float4*)v_lw;
    #pragma unroll 6
    for (int cb = 0; cb < 24; cb++) {
        float4 e = er4[cb], w = vw4[cb];
        acc += e.x*w.x + e.y*w.y + e.z*w.z + e.w*w.w;
    }
    g_attn[p] = acc;
}

// ======================= host orchestration =================================
extern "C" void kernel_launch(void* const* d_in, const int* in_sizes, int n_in,
                              void* d_out, int out_size) {
    const float* hidden   = (const float*)d_in[0];
    const float* query    = (const float*)d_in[1];
    const float* coords   = (const float*)d_in[2];
    const float* wq_conv  = (const float*)d_in[3];
    const float* wq_lw    = (const float*)d_in[4];
    const float* wq_lb    = (const float*)d_in[5];
    const float* wh_conv  = (const float*)d_in[6];
    const float* wh_lw    = (const float*)d_in[7];
    const float* wh_lb    = (const float*)d_in[8];
    const float* att_conv = (const float*)d_in[9];
    const float* att_lw   = (const float*)d_in[10];
    const float* att_lb   = (const float*)d_in[11];
    const float* v_conv   = (const float*)d_in[12];
    const float* v_lw     = (const float*)d_in[13];
    const float* v_lb     = (const float*)d_in[14];
    const float* upd_conv = (const float*)d_in[15];
    const float* upd_lw   = (const float*)d_in[16];
    const float* upd_lb   = (const float*)d_in[17];
    float* out = (float*)d_out;

    int *picnt;
    float *pq, *ph, *pe, *pattn, *pconv, *pconv2;
    __half *pwqB, *pwhB, *pattB, *pupdB;
    __half *pwqlB, *pwhlB, *pattlB, *pupdlB;
    __half *pA96h, *pA96l, *pB96h, *pB96l, *pA192h, *pA192l;
    cudaGetSymbolAddress((void**)&picnt,  g_icnt);
    cudaGetSymbolAddress((void**)&pq,     g_q);
    cudaGetSymbolAddress((void**)&ph,     g_h);
    cudaGetSymbolAddress((void**)&pe,     g_energy);
    cudaGetSymbolAddress((void**)&pattn,  g_attn);
    cudaGetSymbolAddress((void**)&pconv,  g_conv);
    cudaGetSymbolAddress((void**)&pconv2, g_conv2);
    cudaGetSymbolAddress((void**)&pwqB,   g_wqB);
    cudaGetSymbolAddress((void**)&pwhB,   g_whB);
    cudaGetSymbolAddress((void**)&pattB,  g_attB);
    cudaGetSymbolAddress((void**)&pupdB,  g_updB);
    cudaGetSymbolAddress((void**)&pwqlB,  g_wqlB);
    cudaGetSymbolAddress((void**)&pwhlB,  g_whlB);
    cudaGetSymbolAddress((void**)&pattlB, g_attlB);
    cudaGetSymbolAddress((void**)&pupdlB, g_updlB);
    cudaGetSymbolAddress((void**)&pA96h,  g_pA96_hi);
    cudaGetSymbolAddress((void**)&pA96l,  g_pA96_lo);
    cudaGetSymbolAddress((void**)&pB96h,  g_pB96_hi);
    cudaGetSymbolAddress((void**)&pB96l,  g_pB96_lo);
    cudaGetSymbolAddress((void**)&pA192h, g_pA192_hi);
    cudaGetSymbolAddress((void**)&pA192l, g_pA192_lo);

    cudaFuncSetAttribute(conv_mma_k<128,2>, cudaFuncAttributeMaxDynamicSharedMemorySize, SM_TOT);
    cudaFuncSetAttribute(conv_mma_k<192,3>, cudaFuncAttributeMaxDynamicSharedMemorySize, SM_TOT);
    cudaFuncSetAttribute(lindevox_k<128,2>, cudaFuncAttributeMaxDynamicSharedMemorySize, L_TOT);
    cudaFuncSetAttribute(lindevox_k<192,3>, cudaFuncAttributeMaxDynamicSharedMemorySize, L_TOT);

    const int TB = 256;
    auto gs = [](long long n, int tb){ return (int)((n + tb - 1) / tb); };
    const int LBLK = (NPTS + 127) / 128;   // 782
    const long long ZN = 4LL*U128 + 2LL*U192;
    const long long PREP_N = ZN + 2LL*27*128*96 + 2LL*27*192*96
                           + 2LL*128*96 + 2LL*192*96 + 27*96;

    // --- shared precompute ---
    zeroi_k<<<gs(G3,TB), TB>>>(picnt, G3);
    vox_k<<<gs(NPTS,TB), TB>>>(coords);
    scan_k<<<1, 1024>>>();
    filltrilin_k<<<gs(NPTS,TB), TB>>>(coords);
    prep_all_k<<<gs(PREP_N,TB), TB>>>(wq_conv, wh_conv, att_conv, upd_conv,
                                      wq_lw, wh_lw, att_lw, upd_lw, v_conv,
                                      pwqB, pwhB, pattB, pupdB,
                                      pwqlB, pwhlB, pattlB, pupdlB,
                                      pA96h, pA96l, pB96h, pB96l, pA192h, pA192l);

    // --- merged sconv q + sconv h ---
    gathervox_qh_k<<<gs(2LL*G3*24,TB), TB>>>(query, hidden);
    conv_mma_k<128,2><<<512, 256, SM_TOT>>>(pwqB, pA96h, pA96l, pconv,
                                            pwhB, pB96h, pB96l, pconv2, 256);
    lindevox_k<128,2><<<2*LBLK, 256, L_TOT>>>(
        query, nullptr, nullptr, pwqlB, wq_lb, pconv, pq,
        hidden, nullptr, nullptr, pwhlB, wh_lb, pconv2, ph, LBLK, 0);

    // --- energy = tanh(sconv([h, q])) ---
    gathervox192_k<<<gs(2LL*G3*24,TB), TB>>>(ph, pq);
    conv_mma_k<192,3><<<256, 256, SM_TOT>>>(pattB, pA192h, pA192l, pconv,
                                            pattB, pA192h, pA192l, pconv, 256);
    lindevox_k<192,3><<<LBLK, 256, L_TOT>>>(
        ph, pq, nullptr, pattlB, att_lb, pconv, pe,
        ph, pq, nullptr, pattlB, att_lb, pconv, pe, LBLK, 1);

    // --- attn = sconv(energy), cout=1 ---
    voxdot_k<<<G3/8, 256>>>(pe);
    stencil_k<<<gs(G3,TB), TB>>>();
    attn_k<<<gs(NPTS,TB), TB>>>(pe, v_lw, v_lb);

    // --- out = tanh(sconv([q, attn*h])) ---
    mkq_sc_k<<<gs((long long)G3*36,TB), TB>>>(ph, pattn);
    conv_mma_k<192,3><<<256, 256, SM_TOT>>>(pupdB, pA192h, pA192l, pconv,
                                            pupdB, pA192h, pA192l, pconv, 256);
    lindevox_k<192,3><<<LBLK, 256, L_TOT>>>(
        pq, ph, pattn, pupdlB, upd_lb, pconv, out,
        pq, ph, pattn, pupdlB, upd_lb, pconv, out, LBLK, 1);
}

// round 13
// speedup vs baseline: 6.6432x; 1.0078x over previous
#include <cuda_runtime.h>
#include <cuda_fp16.h>
#include <cstdint>
#include <math.h>

#define NPTS 100000
#define CDIM 96
#define GRES 32
#define G3   (GRES*GRES*GRES)
#define PAD  34
#define PP2  (PAD*PAD)
#define PGV  (PP2*PAD)

// ======================= scratch (device globals) ===========================
__device__ int   g_vidx[NPTS];
__device__ int   g_icnt[G3];
__device__ int   g_start[G3+1];
__device__ int   g_pos[G3];
__device__ int   g_sorted[NPTS];
__device__ int   g_nbi[8*NPTS];       // indexed by SORTED slot
__device__ float g_nbw[8*NPTS];       // indexed by SORTED slot
__device__ float g_P[27*G3];          // per-tap dot products (attn stage)
__device__ __half g_conv [G3*CDIM];   // conv outputs in fp16
__device__ __half g_conv2[G3*CDIM];
__device__ float g_vout[G3];
__device__ float g_q[NPTS*CDIM];
__device__ float g_h[NPTS*CDIM];
__device__ float g_energy[NPTS*CDIM];
__device__ float g_attn[NPTS];
// padded fp16 split grids
__device__ __half g_pA96_hi [PGV*128];   // voxelized query input
__device__ __half g_pA96_lo [PGV*128];
__device__ __half g_pB96_hi [PGV*128];   // voxelized hidden input
__device__ __half g_pB96_lo [PGV*128];
__device__ __half g_pA192_hi[PGV*192];
__device__ __half g_pA192_lo[PGV*192];
// cached voxelized q_out (interior), reused stage3 -> stage5
__device__ __half g_pQ96_hi[PGV*96];
__device__ __half g_pQ96_lo[PGV*96];
// pre-swizzled fp16 conv weights (hi only): [tap*nch+chunk][6144 = 96 rows x 64 ci]
__device__ __half g_wqB [27*2*6144];
__device__ __half g_whB [27*2*6144];
__device__ __half g_attB[27*3*6144];
__device__ __half g_updB[27*3*6144];
// pre-swizzled fp16 linear weights: [chunk][6144]
__device__ __half g_wqlB [2*6144];
__device__ __half g_whlB [2*6144];
__device__ __half g_attlB[3*6144];
__device__ __half g_updlB[3*6144];
__device__ float g_vT[27*CDIM];

// ======================= mma/ldmatrix/cp.async helpers =======================
__device__ __forceinline__ uint32_t smem_u32(const void* p) {
    uint32_t a;
    asm("{ .reg .u64 t; cvta.to.shared.u64 t, %1; cvt.u32.u64 %0, t; }" : "=r"(a) : "l"(p));
    return a;
}
__device__ __forceinline__ void ldsm4(uint32_t* r, uint32_t addr) {
    asm volatile("ldmatrix.sync.aligned.m8n8.x4.shared.b16 {%0,%1,%2,%3}, [%4];"
        : "=r"(r[0]), "=r"(r[1]), "=r"(r[2]), "=r"(r[3]) : "r"(addr));
}
__device__ __forceinline__ void mma16816h(float* c, const uint32_t* a, const uint32_t* b) {
    asm volatile("mma.sync.aligned.m16n8k16.row.col.f32.f16.f16.f32 "
        "{%0,%1,%2,%3}, {%4,%5,%6,%7}, {%8,%9}, {%0,%1,%2,%3};"
        : "+f"(c[0]), "+f"(c[1]), "+f"(c[2]), "+f"(c[3])
        : "r"(a[0]), "r"(a[1]), "r"(a[2]), "r"(a[3]), "r"(b[0]), "r"(b[1]));
}
__device__ __forceinline__ void cpa16(uint32_t dst, const void* src) {
    asm volatile("cp.async.cg.shared.global [%0], [%1], 16;" :: "r"(dst), "l"(src));
}
__device__ __forceinline__ void cpa_commit() { asm volatile("cp.async.commit_group;"); }
__device__ __forceinline__ void cpa_wait0()  { asm volatile("cp.async.wait_group 0;"); }
__device__ __forceinline__ void cpa_wait1()  { asm volatile("cp.async.wait_group 1;"); }

// ======================= sort/index kernels ==================================
__global__ void zeroi_k(int* __restrict__ p, int n) {
    int i = blockIdx.x * blockDim.x + threadIdx.x;
    if (i < n) p[i] = 0;
}

__global__ void vox_k(const float* __restrict__ coords) {
    int p = blockIdx.x * blockDim.x + threadIdx.x;
    if (p >= NPTS) return;
    int vx = min(max((int)floorf(coords[3*p+0]), 0), GRES-1);
    int vy = min(max((int)floorf(coords[3*p+1]), 0), GRES-1);
    int vz = min(max((int)floorf(coords[3*p+2]), 0), GRES-1);
    int flat = (vx*GRES + vy)*GRES + vz;
    g_vidx[p] = flat;
    atomicAdd(&g_icnt[flat], 1);
}

__global__ void __launch_bounds__(1024) scan_k() {
    __shared__ int bs[1024];
    int t = threadIdx.x;
    int base = t * 32;
    int loc[32];
    int s = 0;
    #pragma unroll
    for (int k = 0; k < 32; k++) { loc[k] = s; s += g_icnt[base + k]; }
    bs[t] = s;
    __syncthreads();
    #pragma unroll
    for (int d = 1; d < 1024; d <<= 1) {
        int v = (t >= d) ? bs[t - d] : 0;
        __syncthreads();
        bs[t] += v;
        __syncthreads();
    }
    int off = bs[t] - s;
    #pragma unroll
    for (int k = 0; k < 32; k++) {
        g_start[base + k] = off + loc[k];
        g_pos[base + k]   = off + loc[k];
    }
    if (t == 1023) g_start[G3] = off + s;
}

// fused counting-sort fill + trilinear neighbor precompute (sorted-slot order)
__global__ void filltrilin_k(const float* __restrict__ coords) {
    int p = blockIdx.x * blockDim.x + threadIdx.x;
    if (p >= NPTS) return;
    int s = atomicAdd(&g_pos[g_vidx[p]], 1);
    g_sorted[s] = p;
    float cx = coords[3*p+0], cy = coords[3*p+1], cz = coords[3*p+2];
    float bx = floorf(cx), by = floorf(cy), bz = floorf(cz);
    float fx = cx - bx, fy = cy - by, fz = cz - bz;
    int ix = (int)bx, iy = (int)by, iz = (int)bz;
    #pragma unroll
    for (int j = 0; j < 8; j++) {
        int dx = (j >> 2) & 1, dy = (j >> 1) & 1, dz = j & 1;
        int nx = ix + dx, ny = iy + dy, nz = iz + dz;
        bool valid = (nx >= 0 && nx < GRES && ny >= 0 && ny < GRES && nz >= 0 && nz < GRES);
        int cxc = min(max(nx,0),GRES-1), cyc = min(max(ny,0),GRES-1), czc = min(max(nz,0),GRES-1);
        int flc = (cxc*GRES + cyc)*GRES + czc;
        float w = (dx ? fx : 1.f-fx) * (dy ? fy : 1.f-fy) * (dz ? fz : 1.f-fz);
        if (!valid || g_icnt[flc] == 0) w = 0.f;
        g_nbi[j*NPTS + s] = flc;
        g_nbw[j*NPTS + s] = w;
    }
}

// ======================= fp16 split helpers ==================================
__device__ __forceinline__ void f16_split_store4(
    float4 acc, __half* dhi, __half* dlo, size_t o) {
    __half h0 = __float2half_rn(acc.x), h1 = __float2half_rn(acc.y);
    __half h2 = __float2half_rn(acc.z), h3 = __float2half_rn(acc.w);
    __half l0 = __float2half_rn(acc.x - __half2float(h0));
    __half l1 = __float2half_rn(acc.y - __half2float(h1));
    __half l2 = __float2half_rn(acc.z - __half2float(h2));
    __half l3 = __float2half_rn(acc.w - __half2float(h3));
    __half2 hA = __halves2half2(h0, h1);
    __half2 hB = __halves2half2(h2, h3);
    __half2 lA = __halves2half2(l0, l1);
    __half2 lB = __halves2half2(l2, l3);
    *(__half2*)(dhi + o)     = hA;
    *(__half2*)(dhi + o + 2) = hB;
    *(__half2*)(dlo + o)     = lA;
    *(__half2*)(dlo + o + 2) = lB;
}

// merged q+h INPUT voxelize
__global__ void gathervox_qh_k(const float* __restrict__ q, const float* __restrict__ h) {
    int i = blockIdx.x * blockDim.x + threadIdx.x;
    if (i >= 2 * G3 * 24) return;
    bool sec = (i >= G3 * 24);
    int j = sec ? i - G3 * 24 : i;
    int c4 = j % 24;
    int v  = j / 24;
    int vx = v >> 10, vy = (v >> 5) & 31, vz = v & 31;
    int pv = ((vx + 1) * PAD + (vy + 1)) * PAD + (vz + 1);
    int ci = c4 * 4;
    const float* src = sec ? h : q;

    float4 acc = make_float4(0.f, 0.f, 0.f, 0.f);
    int s0 = g_start[v], s1 = g_start[v+1];
    if (s1 > s0) {
        for (int k = s0; k < s1; k++) {
            int pid = g_sorted[k];
            float4 f = *(const float4*)(src + (size_t)pid * 96 + ci);
            acc.x += f.x; acc.y += f.y; acc.z += f.z; acc.w += f.w;
        }
        float invn = 1.f / (float)(s1 - s0);
        acc.x *= invn; acc.y *= invn; acc.z *= invn; acc.w *= invn;
    }
    f16_split_store4(acc,
        sec ? g_pB96_hi : g_pA96_hi, sec ? g_pB96_lo : g_pA96_lo,
        (size_t)pv * 128 + ci);
}

// stage-3 voxelize of OUTPUTS: pA192 = [mean(h_out) | mean(q_out)] + cache q grid
__global__ void gathervox192_k(const float* __restrict__ h, const float* __restrict__ q) {
    int i = blockIdx.x * blockDim.x + threadIdx.x;
    if (i >= 2 * G3 * 24) return;
    bool sec = (i >= G3 * 24);   // sec = q half
    int j = sec ? i - G3 * 24 : i;
    int c4 = j % 24;
    int v  = j / 24;
    int vx = v >> 10, vy = (v >> 5) & 31, vz = v & 31;
    int pv = ((vx + 1) * PAD + (vy + 1)) * PAD + (vz + 1);
    int ci = c4 * 4;
    const float* src = sec ? q : h;

    float4 acc = make_float4(0.f, 0.f, 0.f, 0.f);
    int s0 = g_start[v], s1 = g_start[v+1];
    if (s1 > s0) {
        for (int k = s0; k < s1; k++) {
            int pid = g_sorted[k];
            float4 f = *(const float4*)(src + (size_t)pid * 96 + ci);
            acc.x += f.x; acc.y += f.y; acc.z += f.z; acc.w += f.w;
        }
        float invn = 1.f / (float)(s1 - s0);
        acc.x *= invn; acc.y *= invn; acc.z *= invn; acc.w *= invn;
    }
    if (!sec) {
        f16_split_store4(acc, g_pA192_hi, g_pA192_lo, (size_t)pv * 192 + ci);
    } else {
        f16_split_store4(acc, g_pA192_hi, g_pA192_lo, (size_t)pv * 192 + 96 + ci);
        f16_split_store4(acc, g_pQ96_hi, g_pQ96_lo, (size_t)pv * 96 + ci);
    }
}

// stage-5: merged (q-cache copy) + (mean(attn*h) gather)
__global__ void mkq_sc_k(const float* __restrict__ h, const float* __restrict__ scale) {
    const int NCOPY = G3 * 12;
    int i = blockIdx.x * blockDim.x + threadIdx.x;
    if (i < NCOPY) {
        int u = i % 12;
        int v = i / 12;
        int vx = v >> 10, vy = (v >> 5) & 31, vz = v & 31;
        int pv = ((vx + 1) * PAD + (vy + 1)) * PAD + (vz + 1);
        size_t s = (size_t)pv * 96 + u * 8;
        size_t d = (size_t)pv * 192 + u * 8;
        *(uint4*)(g_pA192_hi + d) = *(const uint4*)(g_pQ96_hi + s);
        *(uint4*)(g_pA192_lo + d) = *(const uint4*)(g_pQ96_lo + s);
        return;
    }
    int j = i - NCOPY;
    if (j >= G3 * 24) return;
    int c4 = j % 24;
    int v  = j / 24;
    int vx = v >> 10, vy = (v >> 5) & 31, vz = v & 31;
    int pv = ((vx + 1) * PAD + (vy + 1)) * PAD + (vz + 1);
    int ci = c4 * 4;
    float4 acc = make_float4(0.f, 0.f, 0.f, 0.f);
    int s0 = g_start[v], s1 = g_start[v+1];
    if (s1 > s0) {
        for (int k = s0; k < s1; k++) {
            int pid = g_sorted[k];
            float4 f = *(const float4*)(h + (size_t)pid * 96 + ci);
            float m = scale[pid];
            acc.x += f.x * m; acc.y += f.y * m; acc.z += f.z * m; acc.w += f.w * m;
        }
        float invn = 1.f / (float)(s1 - s0);
        acc.x *= invn; acc.y *= invn; acc.z *= invn; acc.w *= invn;
    }
    f16_split_store4(acc, g_pA192_hi, g_pA192_lo, (size_t)pv * 192 + 96 + ci);
}

// ======================= merged weight prep + grid zero ======================
__device__ __forceinline__ void conv_prep(int i, const float* w, __half* dst,
                                          int CIN, int KPAD, int NCH) {
    int co  = i % 96;
    int r   = i / 96;
    int ci  = r % KPAD;
    int tap = r / KPAD;
    float val = (ci < CIN) ? w[((size_t)co * CIN + ci) * 27 + tap] : 0.f;
    int chunk = ci >> 6;
    int cw = ci & 63;
    uint32_t elem = (uint32_t)co * 64 + (uint32_t)(((cw >> 3) ^ (co & 7)) * 8) + (cw & 7);
    dst[(size_t)(tap * NCH + chunk) * 6144 + elem] = __float2half_rn(val);
}
__device__ __forceinline__ void lin_prep(int i, const float* w, __half* dst, int CIN) {
    int co = i % 96;
    int ci = i / 96;
    float val = (ci < CIN) ? w[(size_t)co * CIN + ci] : 0.f;
    int chunk = ci >> 6;
    int cw = ci & 63;
    uint32_t elem = (uint32_t)co * 64 + (uint32_t)(((cw >> 3) ^ (co & 7)) * 8) + (cw & 7);
    dst[(size_t)chunk * 6144 + elem] = __float2half_rn(val);
}

#define U128 (PGV * 128 / 8)
#define U192 (PGV * 192 / 8)

__global__ void prep_all_k(const float* wq, const float* wh, const float* att,
                           const float* upd, const float* wql, const float* whl,
                           const float* attl, const float* updl, const float* vconv,
                           __half* dwq, __half* dwh, __half* datt, __half* dupd,
                           __half* dwql, __half* dwhl, __half* dattl, __half* dupdl,
                           __half* za, __half* zb, __half* zc, __half* zd,
                           __half* ze, __half* zf) {
    const int C96 = 27*128*96, C192 = 27*192*96, L96 = 128*96, L192 = 192*96;
    long long i = (long long)blockIdx.x * blockDim.x + threadIdx.x;
    uint4 z = make_uint4(0u, 0u, 0u, 0u);
    if (i < U128)            { ((uint4*)za)[i] = z; return; }
    i -= U128;
    if (i < U128)            { ((uint4*)zb)[i] = z; return; }
    i -= U128;
    if (i < U128)            { ((uint4*)zc)[i] = z; return; }
    i -= U128;
    if (i < U128)            { ((uint4*)zd)[i] = z; return; }
    i -= U128;
    if (i < U192)            { ((uint4*)ze)[i] = z; return; }
    i -= U192;
    if (i < U192)            { ((uint4*)zf)[i] = z; return; }
    i -= U192;
    int k = (int)i;
    if (k < C96) { conv_prep(k, wq, dwq, 96, 128, 2); return; }
    k -= C96;
    if (k < C96) { conv_prep(k, wh, dwh, 96, 128, 2); return; }
    k -= C96;
    if (k < C192) { conv_prep(k, att, datt, 192, 192, 3); return; }
    k -= C192;
    if (k < C192) { conv_prep(k, upd, dupd, 192, 192, 3); return; }
    k -= C192;
    if (k < L96) { lin_prep(k, wql, dwql, 96); return; }
    k -= L96;
    if (k < L96) { lin_prep(k, whl, dwhl, 96); return; }
    k -= L96;
    if (k < L192) { lin_prep(k, attl, dattl, 192); return; }
    k -= L192;
    if (k < L192) { lin_prep(k, updl, dupdl, 192); return; }
    k -= L192;
    if (k < 27*96) { int t = k % 27, ci = k / 27; g_vT[t*96 + ci] = vconv[ci*27 + t]; }
}

// ======================= HMMA 3x3x3 conv (slab A, dual-job, fp16 2-term) =====
#define A_SPLIT 26112            // 204 rows * 128B
#define SM_B0   52224
#define SM_B1   64512
#define SM_TOT  76928

template<int KPAD, int NCH>
__global__ void __launch_bounds__(256, 2) conv_mma_k(
    const __half* __restrict__ wBa, const __half* __restrict__ pAhiA,
    const __half* __restrict__ pAloA, __half* __restrict__ outA,
    const __half* __restrict__ wBb, const __half* __restrict__ pAhiB,
    const __half* __restrict__ pAloB, __half* __restrict__ outB,
    int split_blk) {
    extern __shared__ char smem[];
    uint32_t sb = smem_u32(smem);
    int tid = threadIdx.x;
    int warp = tid >> 5, lane = tid & 31;
    int m_off = (warp & 3) * 32;
    int n_off = (warp >> 2) * 48;

    int blk = blockIdx.x;
    bool sec = (blk >= split_blk);
    if (sec) blk -= split_blk;
    const __half* wB   = sec ? wBb   : wBa;
    const __half* pAhi = sec ? pAhiB : pAhiA;
    const __half* pAlo = sec ? pAloB : pAloA;
    __half* outp = sec ? outB : outA;

    int x  = blk >> 3;
    int y0 = (blk & 7) * 4;

    float acc[2][6][4];
    #pragma unroll
    for (int mi = 0; mi < 2; mi++)
        #pragma unroll
        for (int nj = 0; nj < 6; nj++)
            #pragma unroll
            for (int e = 0; e < 4; e++) acc[mi][nj][e] = 0.f;

    int a_row_in = (lane & 7) + ((lane >> 3) & 1) * 8;
    int a_khalf  = lane >> 4;
    int b_row_in = (lane & 7) + ((lane >> 3) >> 1) * 8;
    int b_khalf  = (lane >> 3) & 1;

    int rb[2];
    #pragma unroll
    for (int mi = 0; mi < 2; mi++) {
        int m = m_off + mi * 16 + a_row_in;
        rb[mi] = (m >> 5) * 34 + (m & 31);
    }
    int brow[3];
    #pragma unroll
    for (int ni = 0; ni < 3; ni++) brow[ni] = n_off + ni * 16 + b_row_in;

    for (int cc = 0; cc < NCH; cc++) {
        bool shortk = (KPAD == 128 && cc == 1);
        int kmax  = shortk ? 2 : 4;
        int c8max = shortk ? 4 : 8;
        int c8sh  = shortk ? 2 : 3;
        int ahalf = 204 * c8max;

        for (int dx = 0; dx < 3; dx++) {
            __syncthreads();

            {
                const __half* bs = wB + (size_t)((dx * 9) * NCH + cc) * 6144;
                #pragma unroll
                for (int t = tid; t < 768; t += 256)
                    cpa16(sb + SM_B0 + t * 16, bs + t * 8);
                size_t pvbase = ((size_t)(x + dx) * PAD + y0) * PAD;
                for (int t = tid; t < 2 * ahalf; t += 256) {
                    int split = (t >= ahalf);
                    int e = split ? t - ahalf : t;
                    int r = e >> c8sh, c8 = e & (c8max - 1);
                    const __half* src =
                        (split ? pAlo : pAhi) + (pvbase + r) * KPAD + cc * 64 + c8 * 8;
                    cpa16(sb + split * A_SPLIT + (uint32_t)r * 128 + ((c8 ^ (r & 7)) << 4), src);
                }
                cpa_commit();
            }

            for (int t9 = 0; t9 < 9; t9++) {
                cpa_wait0();
                __syncthreads();
                if (t9 < 8) {
                    const __half* bs =
                        wB + (size_t)((dx * 9 + t9 + 1) * NCH + cc) * 6144;
                    uint32_t dst = sb + ((t9 & 1) ? SM_B0 : SM_B1);
                    #pragma unroll
                    for (int t = tid; t < 768; t += 256)
                        cpa16(dst + t * 16, bs + t * 8);
                    cpa_commit();
                }
                uint32_t bbase = sb + ((t9 & 1) ? SM_B1 : SM_B0);
                int toff = (t9 / 3) * PAD + (t9 % 3);

                #pragma unroll 4
                for (int kk = 0; kk < kmax; kk++) {
                    uint32_t ah[2][4], al[2][4], bh[3][4];
                    #pragma unroll
                    for (int mi = 0; mi < 2; mi++) {
                        int r = rb[mi] + toff;
                        int kc = kk * 2 + a_khalf;
                        uint32_t off = (uint32_t)r * 128 + (uint32_t)((kc ^ (r & 7)) << 4);
                        ldsm4(ah[mi], sb + off);
                        ldsm4(al[mi], sb + A_SPLIT + off);
                    }
                    #pragma unroll
                    for (int ni = 0; ni < 3; ni++) {
                        int r = brow[ni];
                        int kc = kk * 2 + b_khalf;
                        uint32_t off = (uint32_t)r * 128 + (uint32_t)((kc ^ (r & 7)) << 4);
                        ldsm4(bh[ni], bbase + off);
                    }
                    #pragma unroll
                    for (int mi = 0; mi < 2; mi++) {
                        #pragma unroll
                        for (int nj = 0; nj < 6; nj++) {
                            const uint32_t* bfh = &bh[nj >> 1][(nj & 1) * 2];
                            mma16816h(acc[mi][nj], ah[mi], bfh);
                            mma16816h(acc[mi][nj], al[mi], bfh);
                        }
                    }
                }
            }
        }
    }

    #pragma unroll
    for (int mi = 0; mi < 2; mi++) {
        #pragma unroll
        for (int half = 0; half < 2; half++) {
            int r = m_off + mi * 16 + (lane >> 2) + half * 8;
            int j = r >> 5, z = r & 31;
            size_t vbase = ((size_t)(x * GRES + y0 + j) * GRES + z) * 96;
            #pragma unroll
            for (int nj = 0; nj < 6; nj++) {
                int co = n_off + nj * 8 + 2 * (lane & 3);
                __half2 hv = __floats2half2_rn(acc[mi][nj][half * 2],
                                               acc[mi][nj][half * 2 + 1]);
                *(__half2*)(&outp[vbase + co]) = hv;
            }
        }
    }
}

// ======================= fused linear GEMM + devox epilogue (dual, SORTED) ===
#define L_AHI 0
#define L_ALO 16384
#define L_B0  32768
#define L_B1  45056
#define L_TOT 57344

template<int KPAD, int NCH>
__global__ void __launch_bounds__(256, 2) lindevox_k(
    const float* __restrict__ x1a, const float* __restrict__ x2a,
    const float* __restrict__ s2a, const __half* __restrict__ wBa,
    const float* __restrict__ biasa, const __half* __restrict__ convA,
    float* __restrict__ outa,
    const float* __restrict__ x1b, const float* __restrict__ x2b,
    const float* __restrict__ s2b, const __half* __restrict__ wBb,
    const float* __restrict__ biasb, const __half* __restrict__ convB,
    float* __restrict__ outb,
    int split_blk, int do_tanh) {
    extern __shared__ char smem[];
    uint32_t sb = smem_u32(smem);
    int tid = threadIdx.x;
    int warp = tid >> 5, lane = tid & 31;
    int m_off = (warp & 3) * 32;
    int n_off = (warp >> 2) * 48;

    int blk = blockIdx.x;
    bool sec = (blk >= split_blk);
    if (sec) blk -= split_blk;
    const float* x1 = sec ? x1b : x1a;
    const float* x2 = sec ? x2b : x2a;
    const float* scale2 = sec ? s2b : s2a;
    const __half* wB = sec ? wBb : wBa;
    const float* bias = sec ? biasb : biasa;
    const __half* convsrc = sec ? convB : convA;
    float* out = sec ? outb : outa;
    int pbase = blk * 128;           // SORTED slot base

    float acc[2][6][4];
    #pragma unroll
    for (int mi = 0; mi < 2; mi++)
        #pragma unroll
        for (int nj = 0; nj < 6; nj++)
            #pragma unroll
            for (int e = 0; e < 4; e++) acc[mi][nj][e] = 0.f;

    int a_row_in = (lane & 7) + ((lane >> 3) & 1) * 8;
    int a_khalf  = lane >> 4;
    int b_row_in = (lane & 7) + ((lane >> 3) >> 1) * 8;
    int b_khalf  = (lane >> 3) & 1;
    int brow[3];
    #pragma unroll
    for (int ni = 0; ni < 3; ni++) brow[ni] = n_off + ni * 16 + b_row_in;

    #pragma unroll
    for (int t = tid; t < 768; t += 256)
        cpa16(sb + L_B0 + t * 16, wB + t * 8);
    cpa_commit();

    for (int ch = 0; ch < NCH; ch++) {
        if (ch) __syncthreads();
        bool shortk = (KPAD == 128 && ch == 1);
        int kmax  = shortk ? 2 : 4;
        int c8max = shortk ? 4 : 8;
        int c8sh  = shortk ? 2 : 3;

        for (int gidx = tid; gidx < 128 * c8max; gidx += 256) {
            int r = gidx >> c8sh, c8 = gidx & (c8max - 1);
            int slot = pbase + r;
            int colbase = ch * 64 + c8 * 8;
            float v[8];
            bool have = (slot < NPTS) && (colbase < ((KPAD == 128) ? 96 : 192));
            if (have) {
                int p = g_sorted[slot];
                const float* srcp;
                float m = 1.f;
                if (colbase < 96) srcp = x1 + (size_t)p * 96 + colbase;
                else {
                    srcp = x2 + (size_t)p * 96 + (colbase - 96);
                    if (scale2) m = scale2[p];
                }
                float4 aa = *(const float4*)srcp;
                float4 bb = *(const float4*)(srcp + 4);
                v[0]=aa.x*m; v[1]=aa.y*m; v[2]=aa.z*m; v[3]=aa.w*m;
                v[4]=bb.x*m; v[5]=bb.y*m; v[6]=bb.z*m; v[7]=bb.w*m;
            } else {
                #pragma unroll
                for (int e = 0; e < 8; e++) v[e] = 0.f;
            }
            uint4 hv, lv;
            uint32_t* hp = (uint32_t*)&hv;
            uint32_t* lp = (uint32_t*)&lv;
            #pragma unroll
            for (int e = 0; e < 4; e++) {
                __half h0 = __float2half_rn(v[2*e]);
                __half h1 = __float2half_rn(v[2*e+1]);
                __half l0 = __float2half_rn(v[2*e]   - __half2float(h0));
                __half l1 = __float2half_rn(v[2*e+1] - __half2float(h1));
                __half2 hh = __halves2half2(h0, h1);
                __half2 ll = __halves2half2(l0, l1);
                hp[e] = *(uint32_t*)&hh;
                lp[e] = *(uint32_t*)&ll;
            }
            uint32_t addr = (uint32_t)r * 128 + (uint32_t)((c8 ^ (r & 7)) << 4);
            *(uint4*)(smem + L_AHI + addr) = hv;
            *(uint4*)(smem + L_ALO + addr) = lv;
        }
        if (ch + 1 < NCH) {
            const __half* bs = wB + (size_t)(ch + 1) * 6144;
            uint32_t dst = sb + ((ch & 1) ? L_B0 : L_B1);
            #pragma unroll
            for (int t = tid; t < 768; t += 256)
                cpa16(dst + t * 16, bs + t * 8);
            cpa_commit();
            cpa_wait1();
        } else {
            cpa_wait0();
        }
        __syncthreads();

        uint32_t bbase = sb + ((ch & 1) ? L_B1 : L_B0);
        #pragma unroll 4
        for (int kk = 0; kk < kmax; kk++) {
            uint32_t ah[2][4], al[2][4], bh[3][4];
            #pragma unroll
            for (int mi = 0; mi < 2; mi++) {
                int r = m_off + mi * 16 + a_row_in;
                int kc = kk * 2 + a_khalf;
                uint32_t off = (uint32_t)r * 128 + (uint32_t)((kc ^ (r & 7)) << 4);
                ldsm4(ah[mi], sb + L_AHI + off);
                ldsm4(al[mi], sb + L_ALO + off);
            }
            #pragma unroll
            for (int ni = 0; ni < 3; ni++) {
                int r = brow[ni];
                int kc = kk * 2 + b_khalf;
                uint32_t off = (uint32_t)r * 128 + (uint32_t)((kc ^ (r & 7)) << 4);
                ldsm4(bh[ni], bbase + off);
            }
            #pragma unroll
            for (int mi = 0; mi < 2; mi++) {
                #pragma unroll
                for (int nj = 0; nj < 6; nj++) {
                    const uint32_t* bfh = &bh[nj >> 1][(nj & 1) * 2];
                    mma16816h(acc[mi][nj], ah[mi], bfh);
                    mma16816h(acc[mi][nj], al[mi], bfh);
                }
            }
        }
    }

    // ---- epilogue: devox gather (fp16 conv, sorted slots) + bias + tanh ----
    #pragma unroll
    for (int mi = 0; mi < 2; mi++) {
        #pragma unroll
        for (int half = 0; half < 2; half++) {
            int r = m_off + mi * 16 + (lane >> 2) + half * 8;
            int slot = pbase + r;
            if (slot >= NPTS) continue;
            int p = g_sorted[slot];
            #pragma unroll
            for (int j = 0; j < 8; j++) {
                float w = g_nbw[j*NPTS + slot];
                if (w != 0.f) {
                    const __half* gp = convsrc + (size_t)g_nbi[j*NPTS + slot] * 96;
                    #pragma unroll
                    for (int nj = 0; nj < 6; nj++) {
                        int co = n_off + nj * 8 + 2 * (lane & 3);
                        float2 gg = __half22float2(*(const __half2*)(gp + co));
                        acc[mi][nj][half*2]   += w * gg.x;
                        acc[mi][nj][half*2+1] += w * gg.y;
                    }
                }
            }
            #pragma unroll
            for (int nj = 0; nj < 6; nj++) {
                int co = n_off + nj * 8 + 2 * (lane & 3);
                float2 bb = *(const float2*)(bias + co);
                float vx = acc[mi][nj][half*2]   + bb.x;
                float vy = acc[mi][nj][half*2+1] + bb.y;
                if (do_tanh) { vx = tanhf(vx); vy = tanhf(vy); }
                *(float2*)(out + (size_t)p * 96 + co) = make_float2(vx, vy);
            }
        }
    }
}

// ======================= attn stage ==========================================
__global__ void __launch_bounds__(256) voxdot_k(const float* __restrict__ src) {
    __shared__ float ws[27*96];
    int tid = threadIdx.x;
    for (int i = tid; i < 27*96; i += 256) ws[i] = g_vT[i];
    __syncthreads();
    int wid = tid >> 5, lane = tid & 31;
    int v = blockIdx.x * 8 + wid;
    if (v >= G3) return;
    int s0 = g_start[v], s1 = g_start[v+1];
    float a0 = 0.f, a1 = 0.f, a2 = 0.f;
    for (int k = s0; k < s1; k++) {
        const float* r = src + (size_t)g_sorted[k] * 96;
        a0 += r[lane]; a1 += r[lane+32]; a2 += r[lane+64];
    }
    if (s1 > s0) {
        float invn = 1.f / (float)(s1 - s0);
        a0 *= invn; a1 *= invn; a2 *= invn;
    }
    #pragma unroll 9
    for (int t = 0; t < 27; t++) {
        float s = a0*ws[t*96+lane] + a1*ws[t*96+lane+32] + a2*ws[t*96+lane+64];
        s += __shfl_xor_sync(0xFFFFFFFF, s, 16);
        s += __shfl_xor_sync(0xFFFFFFFF, s, 8);
        s += __shfl_xor_sync(0xFFFFFFFF, s, 4);
        s += __shfl_xor_sync(0xFFFFFFFF, s, 2);
        s += __shfl_xor_sync(0xFFFFFFFF, s, 1);
        if (lane == 0) g_P[t*G3 + v] = s;
    }
}

__global__ void stencil_k() {
    int v = blockIdx.x * blockDim.x + threadIdx.x;
    if (v >= G3) return;
    int px = v >> 10, py = (v >> 5) & 31, pz = v & 31;
    float acc = 0.f;
    #pragma unroll
    for (int t = 0; t < 27; t++) {
        int kx = t / 9, ky = (t / 3) % 3, kz = t % 3;
        int nx = px + kx - 1, ny = py + ky - 1, nz = pz + kz - 1;
        if ((unsigned)nx < GRES && (unsigned)ny < GRES && (unsigned)nz < GRES)
            acc += g_P[t*G3 + ((nx<<5) + ny)*32 + nz];
    }
    g_vout[v] = acc;
}

__global__ void attn_k(const float* __restrict__ energy,
                       const float* __restrict__ v_lw, const float* __restrict__ v_lb) {
    int s = blockIdx.x * blockDim.x + threadIdx.x;
    if (s >= NPTS) return;
    int p = g_sorted[s];
    float acc = v_lb[0];
    #pragma unroll
    for (int j = 0; j < 8; j++) {
        float w = g_nbw[j*NPTS + s];
        if (w != 0.f) acc += w * g_vout[g_nbi[j*NPTS + s]];
    }
    const float4* er4 = (const float4*)(energy + (size_t)p * CDIM);
    const float4* vw4 = (const float4*)v_lw;
    #pragma unroll 6
    for (int cb = 0; cb < 24; cb++) {
        float4 e = er4[cb], w = vw4[cb];
        acc += e.x*w.x + e.y*w.y + e.z*w.z + e.w*w.w;
    }
    g_attn[p] = acc;
}

// ======================= host orchestration =================================
extern "C" void kernel_launch(void* const* d_in, const int* in_sizes, int n_in,
                              void* d_out, int out_size) {
    const float* hidden   = (const float*)d_in[0];
    const float* query    = (const float*)d_in[1];
    const float* coords   = (const float*)d_in[2];
    const float* wq_conv  = (const float*)d_in[3];
    const float* wq_lw    = (const float*)d_in[4];
    const float* wq_lb    = (const float*)d_in[5];
    const float* wh_conv  = (const float*)d_in[6];
    const float* wh_lw    = (const float*)d_in[7];
    const float* wh_lb    = (const float*)d_in[8];
    const float* att_conv = (const float*)d_in[9];
    const float* att_lw   = (const float*)d_in[10];
    const float* att_lb   = (const float*)d_in[11];
    const float* v_conv   = (const float*)d_in[12];
    const float* v_lw     = (const float*)d_in[13];
    const float* v_lb     = (const float*)d_in[14];
    const float* upd_conv = (const float*)d_in[15];
    const float* upd_lw   = (const float*)d_in[16];
    const float* upd_lb   = (const float*)d_in[17];
    float* out = (float*)d_out;

    int *picnt;
    float *pq, *ph, *pe, *pattn;
    __half *pconv, *pconv2;
    __half *pwqB, *pwhB, *pattB, *pupdB;
    __half *pwqlB, *pwhlB, *pattlB, *pupdlB;
    __half *pA96h, *pA96l, *pB96h, *pB96l, *pA192h, *pA192l;
    cudaGetSymbolAddress((void**)&picnt,  g_icnt);
    cudaGetSymbolAddress((void**)&pq,     g_q);
    cudaGetSymbolAddress((void**)&ph,     g_h);
    cudaGetSymbolAddress((void**)&pe,     g_energy);
    cudaGetSymbolAddress((void**)&pattn,  g_attn);
    cudaGetSymbolAddress((void**)&pconv,  g_conv);
    cudaGetSymbolAddress((void**)&pconv2, g_conv2);
    cudaGetSymbolAddress((void**)&pwqB,   g_wqB);
    cudaGetSymbolAddress((void**)&pwhB,   g_whB);
    cudaGetSymbolAddress((void**)&pattB,  g_attB);
    cudaGetSymbolAddress((void**)&pupdB,  g_updB);
    cudaGetSymbolAddress((void**)&pwqlB,  g_wqlB);
    cudaGetSymbolAddress((void**)&pwhlB,  g_whlB);
    cudaGetSymbolAddress((void**)&pattlB, g_attlB);
    cudaGetSymbolAddress((void**)&pupdlB, g_updlB);
    cudaGetSymbolAddress((void**)&pA96h,  g_pA96_hi);
    cudaGetSymbolAddress((void**)&pA96l,  g_pA96_lo);
    cudaGetSymbolAddress((void**)&pB96h,  g_pB96_hi);
    cudaGetSymbolAddress((void**)&pB96l,  g_pB96_lo);
    cudaGetSymbolAddress((void**)&pA192h, g_pA192_hi);
    cudaGetSymbolAddress((void**)&pA192l, g_pA192_lo);

    cudaFuncSetAttribute(conv_mma_k<128,2>, cudaFuncAttributeMaxDynamicSharedMemorySize, SM_TOT);
    cudaFuncSetAttribute(conv_mma_k<192,3>, cudaFuncAttributeMaxDynamicSharedMemorySize, SM_TOT);
    cudaFuncSetAttribute(lindevox_k<128,2>, cudaFuncAttributeMaxDynamicSharedMemorySize, L_TOT);
    cudaFuncSetAttribute(lindevox_k<192,3>, cudaFuncAttributeMaxDynamicSharedMemorySize, L_TOT);

    const int TB = 256;
    auto gs = [](long long n, int tb){ return (int)((n + tb - 1) / tb); };
    const int LBLK = (NPTS + 127) / 128;   // 782
    const long long ZN = 4LL*U128 + 2LL*U192;
    const long long PREP_N = ZN + 2LL*27*128*96 + 2LL*27*192*96
                           + 2LL*128*96 + 2LL*192*96 + 27*96;

    // --- shared precompute ---
    zeroi_k<<<gs(G3,TB), TB>>>(picnt, G3);
    vox_k<<<gs(NPTS,TB), TB>>>(coords);
    scan_k<<<1, 1024>>>();
    filltrilin_k<<<gs(NPTS,TB), TB>>>(coords);
    prep_all_k<<<gs(PREP_N,TB), TB>>>(wq_conv, wh_conv, att_conv, upd_conv,
                                      wq_lw, wh_lw, att_lw, upd_lw, v_conv,
                                      pwqB, pwhB, pattB, pupdB,
                                      pwqlB, pwhlB, pattlB, pupdlB,
                                      pA96h, pA96l, pB96h, pB96l, pA192h, pA192l);

    // --- merged sconv q + sconv h ---
    gathervox_qh_k<<<gs(2LL*G3*24,TB), TB>>>(query, hidden);
    conv_mma_k<128,2><<<512, 256, SM_TOT>>>(pwqB, pA96h, pA96l, pconv,
                                            pwhB, pB96h, pB96l, pconv2, 256);
    lindevox_k<128,2><<<2*LBLK, 256, L_TOT>>>(
        query, nullptr, nullptr, pwqlB, wq_lb, pconv, pq,
        hidden, nullptr, nullptr, pwhlB, wh_lb, pconv2, ph, LBLK, 0);

    // --- energy = tanh(sconv([h, q])) ---
    gathervox192_k<<<gs(2LL*G3*24,TB), TB>>>(ph, pq);
    conv_mma_k<192,3><<<256, 256, SM_TOT>>>(pattB, pA192h, pA192l, pconv,
                                            pattB, pA192h, pA192l, pconv, 256);
    lindevox_k<192,3><<<LBLK, 256, L_TOT>>>(
        ph, pq, nullptr, pattlB, att_lb, pconv, pe,
        ph, pq, nullptr, pattlB, att_lb, pconv, pe, LBLK, 1);

    // --- attn = sconv(energy), cout=1 ---
    voxdot_k<<<G3/8, 256>>>(pe);
    stencil_k<<<gs(G3,TB), TB>>>();
    attn_k<<<gs(NPTS,TB), TB>>>(pe, v_lw, v_lb);

    // --- out = tanh(sconv([q, attn*h])) ---
    mkq_sc_k<<<gs((long long)G3*36,TB), TB>>>(ph, pattn);
    conv_mma_k<192,3><<<256, 256, SM_TOT>>>(pupdB, pA192h, pA192l, pconv,
                                            pupdB, pA192h, pA192l, pconv, 256);
    lindevox_k<192,3><<<LBLK, 256, L_TOT>>>(
        pq, ph, pattn, pupdlB, upd_lb, pconv, out,
        pq, ph, pattn, pupdlB, upd_lb, pconv, out, LBLK, 1);
}

// round 14
// speedup vs baseline: 7.1124x; 1.0706x over previous
#include <cuda_runtime.h>
#include <cuda_fp16.h>
#include <cstdint>
#include <math.h>

#define NPTS 100000
#define CDIM 96
#define GRES 32
#define G3   (GRES*GRES*GRES)
#define PAD  34
#define PP2  (PAD*PAD)
#define PGV  (PP2*PAD)

// ======================= scratch (device globals) ===========================
__device__ int   g_vidx[NPTS];
__device__ int   g_icnt[G3];
__device__ int   g_start[G3+1];
__device__ int   g_pos[G3];
__device__ int   g_sorted[NPTS];
__device__ int   g_nbi[8*NPTS];       // indexed by SORTED slot
__device__ float g_nbw[8*NPTS];       // indexed by SORTED slot
__device__ float g_P[27*G3];          // per-tap dot products (attn stage)
__device__ __half g_conv [G3*CDIM];   // conv outputs in fp16
__device__ __half g_conv2[G3*CDIM];
__device__ float g_vout[G3];
__device__ float g_q[NPTS*CDIM];
__device__ float g_h[NPTS*CDIM];
__device__ float g_energy[NPTS*CDIM];
__device__ float g_attn[NPTS];
// padded fp16 grids (stage-1: hi only; stage-3/5: hi+lo split)
__device__ __half g_pA96_hi [PGV*128];   // voxelized query input
__device__ __half g_pB96_hi [PGV*128];   // voxelized hidden input
__device__ __half g_pA192_hi[PGV*192];
__device__ __half g_pA192_lo[PGV*192];
// cached voxelized q_out (interior), reused stage3 -> stage5
__device__ __half g_pQ96_hi[PGV*96];
__device__ __half g_pQ96_lo[PGV*96];
// pre-swizzled fp16 conv weights (hi only): [tap*nch+chunk][6144 = 96 rows x 64 ci]
__device__ __half g_wqB [27*2*6144];
__device__ __half g_whB [27*2*6144];
__device__ __half g_attB[27*3*6144];
__device__ __half g_updB[27*3*6144];
// pre-swizzled fp16 linear weights: [chunk][6144]
__device__ __half g_wqlB [2*6144];
__device__ __half g_whlB [2*6144];
__device__ __half g_attlB[3*6144];
__device__ __half g_updlB[3*6144];
__device__ float g_vT[27*CDIM];

// ======================= mma/ldmatrix/cp.async helpers =======================
__device__ __forceinline__ uint32_t smem_u32(const void* p) {
    uint32_t a;
    asm("{ .reg .u64 t; cvta.to.shared.u64 t, %1; cvt.u32.u64 %0, t; }" : "=r"(a) : "l"(p));
    return a;
}
__device__ __forceinline__ void ldsm4(uint32_t* r, uint32_t addr) {
    asm volatile("ldmatrix.sync.aligned.m8n8.x4.shared.b16 {%0,%1,%2,%3}, [%4];"
        : "=r"(r[0]), "=r"(r[1]), "=r"(r[2]), "=r"(r[3]) : "r"(addr));
}
__device__ __forceinline__ void mma16816h(float* c, const uint32_t* a, const uint32_t* b) {
    asm volatile("mma.sync.aligned.m16n8k16.row.col.f32.f16.f16.f32 "
        "{%0,%1,%2,%3}, {%4,%5,%6,%7}, {%8,%9}, {%0,%1,%2,%3};"
        : "+f"(c[0]), "+f"(c[1]), "+f"(c[2]), "+f"(c[3])
        : "r"(a[0]), "r"(a[1]), "r"(a[2]), "r"(a[3]), "r"(b[0]), "r"(b[1]));
}
__device__ __forceinline__ void cpa16(uint32_t dst, const void* src) {
    asm volatile("cp.async.cg.shared.global [%0], [%1], 16;" :: "r"(dst), "l"(src));
}
__device__ __forceinline__ void cpa_commit() { asm volatile("cp.async.commit_group;"); }
__device__ __forceinline__ void cpa_wait0()  { asm volatile("cp.async.wait_group 0;"); }
__device__ __forceinline__ void cpa_wait1()  { asm volatile("cp.async.wait_group 1;"); }

// ======================= sort/index kernels ==================================
__global__ void zeroi_k(int* __restrict__ p, int n) {
    int i = blockIdx.x * blockDim.x + threadIdx.x;
    if (i < n) p[i] = 0;
}

__global__ void vox_k(const float* __restrict__ coords) {
    int p = blockIdx.x * blockDim.x + threadIdx.x;
    if (p >= NPTS) return;
    int vx = min(max((int)floorf(coords[3*p+0]), 0), GRES-1);
    int vy = min(max((int)floorf(coords[3*p+1]), 0), GRES-1);
    int vz = min(max((int)floorf(coords[3*p+2]), 0), GRES-1);
    int flat = (vx*GRES + vy)*GRES + vz;
    g_vidx[p] = flat;
    atomicAdd(&g_icnt[flat], 1);
}

__global__ void __launch_bounds__(1024) scan_k() {
    __shared__ int bs[1024];
    int t = threadIdx.x;
    int base = t * 32;
    int loc[32];
    int s = 0;
    #pragma unroll
    for (int k = 0; k < 32; k++) { loc[k] = s; s += g_icnt[base + k]; }
    bs[t] = s;
    __syncthreads();
    #pragma unroll
    for (int d = 1; d < 1024; d <<= 1) {
        int v = (t >= d) ? bs[t - d] : 0;
        __syncthreads();
        bs[t] += v;
        __syncthreads();
    }
    int off = bs[t] - s;
    #pragma unroll
    for (int k = 0; k < 32; k++) {
        g_start[base + k] = off + loc[k];
        g_pos[base + k]   = off + loc[k];
    }
    if (t == 1023) g_start[G3] = off + s;
}

// fused counting-sort fill + trilinear neighbor precompute (sorted-slot order)
__global__ void filltrilin_k(const float* __restrict__ coords) {
    int p = blockIdx.x * blockDim.x + threadIdx.x;
    if (p >= NPTS) return;
    int s = atomicAdd(&g_pos[g_vidx[p]], 1);
    g_sorted[s] = p;
    float cx = coords[3*p+0], cy = coords[3*p+1], cz = coords[3*p+2];
    float bx = floorf(cx), by = floorf(cy), bz = floorf(cz);
    float fx = cx - bx, fy = cy - by, fz = cz - bz;
    int ix = (int)bx, iy = (int)by, iz = (int)bz;
    #pragma unroll
    for (int j = 0; j < 8; j++) {
        int dx = (j >> 2) & 1, dy = (j >> 1) & 1, dz = j & 1;
        int nx = ix + dx, ny = iy + dy, nz = iz + dz;
        bool valid = (nx >= 0 && nx < GRES && ny >= 0 && ny < GRES && nz >= 0 && nz < GRES);
        int cxc = min(max(nx,0),GRES-1), cyc = min(max(ny,0),GRES-1), czc = min(max(nz,0),GRES-1);
        int flc = (cxc*GRES + cyc)*GRES + czc;
        float w = (dx ? fx : 1.f-fx) * (dy ? fy : 1.f-fy) * (dz ? fz : 1.f-fz);
        if (!valid || g_icnt[flc] == 0) w = 0.f;
        g_nbi[j*NPTS + s] = flc;
        g_nbw[j*NPTS + s] = w;
    }
}

// ======================= fp16 split helpers ==================================
__device__ __forceinline__ void f16_split_store4(
    float4 acc, __half* dhi, __half* dlo, size_t o) {
    __half h0 = __float2half_rn(acc.x), h1 = __float2half_rn(acc.y);
    __half h2 = __float2half_rn(acc.z), h3 = __float2half_rn(acc.w);
    __half l0 = __float2half_rn(acc.x - __half2float(h0));
    __half l1 = __float2half_rn(acc.y - __half2float(h1));
    __half l2 = __float2half_rn(acc.z - __half2float(h2));
    __half l3 = __float2half_rn(acc.w - __half2float(h3));
    __half2 hA = __halves2half2(h0, h1);
    __half2 hB = __halves2half2(h2, h3);
    __half2 lA = __halves2half2(l0, l1);
    __half2 lB = __halves2half2(l2, l3);
    *(__half2*)(dhi + o)     = hA;
    *(__half2*)(dhi + o + 2) = hB;
    *(__half2*)(dlo + o)     = lA;
    *(__half2*)(dlo + o + 2) = lB;
}
__device__ __forceinline__ void f16_store4(float4 acc, __half* dhi, size_t o) {
    __half2 hA = __floats2half2_rn(acc.x, acc.y);
    __half2 hB = __floats2half2_rn(acc.z, acc.w);
    *(__half2*)(dhi + o)     = hA;
    *(__half2*)(dhi + o + 2) = hB;
}

// merged q+h INPUT voxelize (hi only — stage-1 convs use 1-term A)
__global__ void gathervox_qh_k(const float* __restrict__ q, const float* __restrict__ h) {
    int i = blockIdx.x * blockDim.x + threadIdx.x;
    if (i >= 2 * G3 * 24) return;
    bool sec = (i >= G3 * 24);
    int j = sec ? i - G3 * 24 : i;
    int c4 = j % 24;
    int v  = j / 24;
    int vx = v >> 10, vy = (v >> 5) & 31, vz = v & 31;
    int pv = ((vx + 1) * PAD + (vy + 1)) * PAD + (vz + 1);
    int ci = c4 * 4;
    const float* src = sec ? h : q;

    float4 acc = make_float4(0.f, 0.f, 0.f, 0.f);
    int s0 = g_start[v], s1 = g_start[v+1];
    if (s1 > s0) {
        for (int k = s0; k < s1; k++) {
            int pid = g_sorted[k];
            float4 f = *(const float4*)(src + (size_t)pid * 96 + ci);
            acc.x += f.x; acc.y += f.y; acc.z += f.z; acc.w += f.w;
        }
        float invn = 1.f / (float)(s1 - s0);
        acc.x *= invn; acc.y *= invn; acc.z *= invn; acc.w *= invn;
    }
    f16_store4(acc, sec ? g_pB96_hi : g_pA96_hi, (size_t)pv * 128 + ci);
}

// stage-3 voxelize of OUTPUTS: pA192 = [mean(h_out) | mean(q_out)] + cache q grid
__global__ void gathervox192_k(const float* __restrict__ h, const float* __restrict__ q) {
    int i = blockIdx.x * blockDim.x + threadIdx.x;
    if (i >= 2 * G3 * 24) return;
    bool sec = (i >= G3 * 24);   // sec = q half
    int j = sec ? i - G3 * 24 : i;
    int c4 = j % 24;
    int v  = j / 24;
    int vx = v >> 10, vy = (v >> 5) & 31, vz = v & 31;
    int pv = ((vx + 1) * PAD + (vy + 1)) * PAD + (vz + 1);
    int ci = c4 * 4;
    const float* src = sec ? q : h;

    float4 acc = make_float4(0.f, 0.f, 0.f, 0.f);
    int s0 = g_start[v], s1 = g_start[v+1];
    if (s1 > s0) {
        for (int k = s0; k < s1; k++) {
            int pid = g_sorted[k];
            float4 f = *(const float4*)(src + (size_t)pid * 96 + ci);
            acc.x += f.x; acc.y += f.y; acc.z += f.z; acc.w += f.w;
        }
        float invn = 1.f / (float)(s1 - s0);
        acc.x *= invn; acc.y *= invn; acc.z *= invn; acc.w *= invn;
    }
    if (!sec) {
        f16_split_store4(acc, g_pA192_hi, g_pA192_lo, (size_t)pv * 192 + ci);
    } else {
        f16_split_store4(acc, g_pA192_hi, g_pA192_lo, (size_t)pv * 192 + 96 + ci);
        f16_split_store4(acc, g_pQ96_hi, g_pQ96_lo, (size_t)pv * 96 + ci);
    }
}

// stage-5: merged (q-cache copy) + (mean(attn*h) gather)
__global__ void mkq_sc_k(const float* __restrict__ h, const float* __restrict__ scale) {
    const int NCOPY = G3 * 12;
    int i = blockIdx.x * blockDim.x + threadIdx.x;
    if (i < NCOPY) {
        int u = i % 12;
        int v = i / 12;
        int vx = v >> 10, vy = (v >> 5) & 31, vz = v & 31;
        int pv = ((vx + 1) * PAD + (vy + 1)) * PAD + (vz + 1);
        size_t s = (size_t)pv * 96 + u * 8;
        size_t d = (size_t)pv * 192 + u * 8;
        *(uint4*)(g_pA192_hi + d) = *(const uint4*)(g_pQ96_hi + s);
        *(uint4*)(g_pA192_lo + d) = *(const uint4*)(g_pQ96_lo + s);
        return;
    }
    int j = i - NCOPY;
    if (j >= G3 * 24) return;
    int c4 = j % 24;
    int v  = j / 24;
    int vx = v >> 10, vy = (v >> 5) & 31, vz = v & 31;
    int pv = ((vx + 1) * PAD + (vy + 1)) * PAD + (vz + 1);
    int ci = c4 * 4;
    float4 acc = make_float4(0.f, 0.f, 0.f, 0.f);
    int s0 = g_start[v], s1 = g_start[v+1];
    if (s1 > s0) {
        for (int k = s0; k < s1; k++) {
            int pid = g_sorted[k];
            float4 f = *(const float4*)(h + (size_t)pid * 96 + ci);
            float m = scale[pid];
            acc.x += f.x * m; acc.y += f.y * m; acc.z += f.z * m; acc.w += f.w * m;
        }
        float invn = 1.f / (float)(s1 - s0);
        acc.x *= invn; acc.y *= invn; acc.z *= invn; acc.w *= invn;
    }
    f16_split_store4(acc, g_pA192_hi, g_pA192_lo, (size_t)pv * 192 + 96 + ci);
}

// ======================= merged weight prep + grid zero ======================
__device__ __forceinline__ void conv_prep(int i, const float* w, __half* dst,
                                          int CIN, int KPAD, int NCH) {
    int co  = i % 96;
    int r   = i / 96;
    int ci  = r % KPAD;
    int tap = r / KPAD;
    float val = (ci < CIN) ? w[((size_t)co * CIN + ci) * 27 + tap] : 0.f;
    int chunk = ci >> 6;
    int cw = ci & 63;
    uint32_t elem = (uint32_t)co * 64 + (uint32_t)(((cw >> 3) ^ (co & 7)) * 8) + (cw & 7);
    dst[(size_t)(tap * NCH + chunk) * 6144 + elem] = __float2half_rn(val);
}
__device__ __forceinline__ void lin_prep(int i, const float* w, __half* dst, int CIN) {
    int co = i % 96;
    int ci = i / 96;
    float val = (ci < CIN) ? w[(size_t)co * CIN + ci] : 0.f;
    int chunk = ci >> 6;
    int cw = ci & 63;
    uint32_t elem = (uint32_t)co * 64 + (uint32_t)(((cw >> 3) ^ (co & 7)) * 8) + (cw & 7);
    dst[(size_t)chunk * 6144 + elem] = __float2half_rn(val);
}

#define U128 (PGV * 128 / 8)
#define U192 (PGV * 192 / 8)

__global__ void prep_all_k(const float* wq, const float* wh, const float* att,
                           const float* upd, const float* wql, const float* whl,
                           const float* attl, const float* updl, const float* vconv,
                           __half* dwq, __half* dwh, __half* datt, __half* dupd,
                           __half* dwql, __half* dwhl, __half* dattl, __half* dupdl,
                           __half* za, __half* zb, __half* ze, __half* zf) {
    const int C96 = 27*128*96, C192 = 27*192*96, L96 = 128*96, L192 = 192*96;
    long long i = (long long)blockIdx.x * blockDim.x + threadIdx.x;
    uint4 z = make_uint4(0u, 0u, 0u, 0u);
    if (i < U128)            { ((uint4*)za)[i] = z; return; }
    i -= U128;
    if (i < U128)            { ((uint4*)zb)[i] = z; return; }
    i -= U128;
    if (i < U192)            { ((uint4*)ze)[i] = z; return; }
    i -= U192;
    if (i < U192)            { ((uint4*)zf)[i] = z; return; }
    i -= U192;
    int k = (int)i;
    if (k < C96) { conv_prep(k, wq, dwq, 96, 128, 2); return; }
    k -= C96;
    if (k < C96) { conv_prep(k, wh, dwh, 96, 128, 2); return; }
    k -= C96;
    if (k < C192) { conv_prep(k, att, datt, 192, 192, 3); return; }
    k -= C192;
    if (k < C192) { conv_prep(k, upd, dupd, 192, 192, 3); return; }
    k -= C192;
    if (k < L96) { lin_prep(k, wql, dwql, 96); return; }
    k -= L96;
    if (k < L96) { lin_prep(k, whl, dwhl, 96); return; }
    k -= L96;
    if (k < L192) { lin_prep(k, attl, dattl, 192); return; }
    k -= L192;
    if (k < L192) { lin_prep(k, updl, dupdl, 192); return; }
    k -= L192;
    if (k < 27*96) { int t = k % 27, ci = k / 27; g_vT[t*96 + ci] = vconv[ci*27 + t]; }
}

// ======================= HMMA 3x3x3 conv (slab A, dual-job) ==================
// TWOA: fp16 2-term A (hi+lo). Stage-1 (q,h) uses TWOA=false (1-term A).
#define A_SPLIT 26112            // 204 rows * 128B
#define SM_B0   52224
#define SM_B1   64512
#define SM_TOT  76928

template<int KPAD, int NCH, bool TWOA>
__global__ void __launch_bounds__(256, 2) conv_mma_k(
    const __half* __restrict__ wBa, const __half* __restrict__ pAhiA,
    const __half* __restrict__ pAloA, __half* __restrict__ outA,
    const __half* __restrict__ wBb, const __half* __restrict__ pAhiB,
    const __half* __restrict__ pAloB, __half* __restrict__ outB,
    int split_blk) {
    extern __shared__ char smem[];
    uint32_t sb = smem_u32(smem);
    int tid = threadIdx.x;
    int warp = tid >> 5, lane = tid & 31;
    int m_off = (warp & 3) * 32;
    int n_off = (warp >> 2) * 48;

    int blk = blockIdx.x;
    bool sec = (blk >= split_blk);
    if (sec) blk -= split_blk;
    const __half* wB   = sec ? wBb   : wBa;
    const __half* pAhi = sec ? pAhiB : pAhiA;
    const __half* pAlo = sec ? pAloB : pAloA;
    __half* outp = sec ? outB : outA;

    int x  = blk >> 3;
    int y0 = (blk & 7) * 4;

    float acc[2][6][4];
    #pragma unroll
    for (int mi = 0; mi < 2; mi++)
        #pragma unroll
        for (int nj = 0; nj < 6; nj++)
            #pragma unroll
            for (int e = 0; e < 4; e++) acc[mi][nj][e] = 0.f;

    int a_row_in = (lane & 7) + ((lane >> 3) & 1) * 8;
    int a_khalf  = lane >> 4;
    int b_row_in = (lane & 7) + ((lane >> 3) >> 1) * 8;
    int b_khalf  = (lane >> 3) & 1;

    int rb[2];
    #pragma unroll
    for (int mi = 0; mi < 2; mi++) {
        int m = m_off + mi * 16 + a_row_in;
        rb[mi] = (m >> 5) * 34 + (m & 31);
    }
    int brow[3];
    #pragma unroll
    for (int ni = 0; ni < 3; ni++) brow[ni] = n_off + ni * 16 + b_row_in;

    for (int cc = 0; cc < NCH; cc++) {
        bool shortk = (KPAD == 128 && cc == 1);
        int kmax  = shortk ? 2 : 4;
        int c8max = shortk ? 4 : 8;
        int c8sh  = shortk ? 2 : 3;
        int ahalf = 204 * c8max;
        int atot  = TWOA ? 2 * ahalf : ahalf;

        for (int dx = 0; dx < 3; dx++) {
            __syncthreads();

            {
                const __half* bs = wB + (size_t)((dx * 9) * NCH + cc) * 6144;
                #pragma unroll
                for (int t = tid; t < 768; t += 256)
                    cpa16(sb + SM_B0 + t * 16, bs + t * 8);
                size_t pvbase = ((size_t)(x + dx) * PAD + y0) * PAD;
                for (int t = tid; t < atot; t += 256) {
                    int split = (t >= ahalf);
                    int e = split ? t - ahalf : t;
                    int r = e >> c8sh, c8 = e & (c8max - 1);
                    const __half* src =
                        (split ? pAlo : pAhi) + (pvbase + r) * KPAD + cc * 64 + c8 * 8;
                    cpa16(sb + split * A_SPLIT + (uint32_t)r * 128 + ((c8 ^ (r & 7)) << 4), src);
                }
                cpa_commit();
            }

            for (int t9 = 0; t9 < 9; t9++) {
                cpa_wait0();
                __syncthreads();
                if (t9 < 8) {
                    const __half* bs =
                        wB + (size_t)((dx * 9 + t9 + 1) * NCH + cc) * 6144;
                    uint32_t dst = sb + ((t9 & 1) ? SM_B0 : SM_B1);
                    #pragma unroll
                    for (int t = tid; t < 768; t += 256)
                        cpa16(dst + t * 16, bs + t * 8);
                    cpa_commit();
                }
                uint32_t bbase = sb + ((t9 & 1) ? SM_B1 : SM_B0);
                int toff = (t9 / 3) * PAD + (t9 % 3);

                #pragma unroll 4
                for (int kk = 0; kk < kmax; kk++) {
                    uint32_t ah[2][4], al[2][4], bh[3][4];
                    #pragma unroll
                    for (int mi = 0; mi < 2; mi++) {
                        int r = rb[mi] + toff;
                        int kc = kk * 2 + a_khalf;
                        uint32_t off = (uint32_t)r * 128 + (uint32_t)((kc ^ (r & 7)) << 4);
                        ldsm4(ah[mi], sb + off);
                        if (TWOA) ldsm4(al[mi], sb + A_SPLIT + off);
                    }
                    #pragma unroll
                    for (int ni = 0; ni < 3; ni++) {
                        int r = brow[ni];
                        int kc = kk * 2 + b_khalf;
                        uint32_t off = (uint32_t)r * 128 + (uint32_t)((kc ^ (r & 7)) << 4);
                        ldsm4(bh[ni], bbase + off);
                    }
                    #pragma unroll
                    for (int mi = 0; mi < 2; mi++) {
                        #pragma unroll
                        for (int nj = 0; nj < 6; nj++) {
                            const uint32_t* bfh = &bh[nj >> 1][(nj & 1) * 2];
                            mma16816h(acc[mi][nj], ah[mi], bfh);
                            if (TWOA) mma16816h(acc[mi][nj], al[mi], bfh);
                        }
                    }
                }
            }
        }
    }

    #pragma unroll
    for (int mi = 0; mi < 2; mi++) {
        #pragma unroll
        for (int half = 0; half < 2; half++) {
            int r = m_off + mi * 16 + (lane >> 2) + half * 8;
            int j = r >> 5, z = r & 31;
            size_t vbase = ((size_t)(x * GRES + y0 + j) * GRES + z) * 96;
            #pragma unroll
            for (int nj = 0; nj < 6; nj++) {
                int co = n_off + nj * 8 + 2 * (lane & 3);
                __half2 hv = __floats2half2_rn(acc[mi][nj][half * 2],
                                               acc[mi][nj][half * 2 + 1]);
                *(__half2*)(&outp[vbase + co]) = hv;
            }
        }
    }
}

// ======================= fused linear GEMM + devox epilogue (dual, SORTED) ===
#define L_AHI 0
#define L_ALO 16384
#define L_B0  32768
#define L_B1  45056
#define L_TOT 57344

template<int KPAD, int NCH>
__global__ void __launch_bounds__(256, 2) lindevox_k(
    const float* __restrict__ x1a, const float* __restrict__ x2a,
    const float* __restrict__ s2a, const __half* __restrict__ wBa,
    const float* __restrict__ biasa, const __half* __restrict__ convA,
    float* __restrict__ outa,
    const float* __restrict__ x1b, const float* __restrict__ x2b,
    const float* __restrict__ s2b, const __half* __restrict__ wBb,
    const float* __restrict__ biasb, const __half* __restrict__ convB,
    float* __restrict__ outb,
    int split_blk, int do_tanh) {
    extern __shared__ char smem[];
    uint32_t sb = smem_u32(smem);
    int tid = threadIdx.x;
    int warp = tid >> 5, lane = tid & 31;
    int m_off = (warp & 3) * 32;
    int n_off = (warp >> 2) * 48;

    int blk = blockIdx.x;
    bool sec = (blk >= split_blk);
    if (sec) blk -= split_blk;
    const float* x1 = sec ? x1b : x1a;
    const float* x2 = sec ? x2b : x2a;
    const float* scale2 = sec ? s2b : s2a;
    const __half* wB = sec ? wBb : wBa;
    const float* bias = sec ? biasb : biasa;
    const __half* convsrc = sec ? convB : convA;
    float* out = sec ? outb : outa;
    int pbase = blk * 128;           // SORTED slot base

    float acc[2][6][4];
    #pragma unroll
    for (int mi = 0; mi < 2; mi++)
        #pragma unroll
        for (int nj = 0; nj < 6; nj++)
            #pragma unroll
            for (int e = 0; e < 4; e++) acc[mi][nj][e] = 0.f;

    int a_row_in = (lane & 7) + ((lane >> 3) & 1) * 8;
    int a_khalf  = lane >> 4;
    int b_row_in = (lane & 7) + ((lane >> 3) >> 1) * 8;
    int b_khalf  = (lane >> 3) & 1;
    int brow[3];
    #pragma unroll
    for (int ni = 0; ni < 3; ni++) brow[ni] = n_off + ni * 16 + b_row_in;

    #pragma unroll
    for (int t = tid; t < 768; t += 256)
        cpa16(sb + L_B0 + t * 16, wB + t * 8);
    cpa_commit();

    for (int ch = 0; ch < NCH; ch++) {
        if (ch) __syncthreads();
        bool shortk = (KPAD == 128 && ch == 1);
        int kmax  = shortk ? 2 : 4;
        int c8max = shortk ? 4 : 8;
        int c8sh  = shortk ? 2 : 3;

        for (int gidx = tid; gidx < 128 * c8max; gidx += 256) {
            int r = gidx >> c8sh, c8 = gidx & (c8max - 1);
            int slot = pbase + r;
            int colbase = ch * 64 + c8 * 8;
            float v[8];
            bool have = (slot < NPTS) && (colbase < ((KPAD == 128) ? 96 : 192));
            if (have) {
                int p = g_sorted[slot];
                const float* srcp;
                float m = 1.f;
                if (colbase < 96) srcp = x1 + (size_t)p * 96 + colbase;
                else {
                    srcp = x2 + (size_t)p * 96 + (colbase - 96);
                    if (scale2) m = scale2[p];
                }
                float4 aa = *(const float4*)srcp;
                float4 bb = *(const float4*)(srcp + 4);
                v[0]=aa.x*m; v[1]=aa.y*m; v[2]=aa.z*m; v[3]=aa.w*m;
                v[4]=bb.x*m; v[5]=bb.y*m; v[6]=bb.z*m; v[7]=bb.w*m;
            } else {
                #pragma unroll
                for (int e = 0; e < 8; e++) v[e] = 0.f;
            }
            uint4 hv, lv;
            uint32_t* hp = (uint32_t*)&hv;
            uint32_t* lp = (uint32_t*)&lv;
            #pragma unroll
            for (int e = 0; e < 4; e++) {
                __half h0 = __float2half_rn(v[2*e]);
                __half h1 = __float2half_rn(v[2*e+1]);
                __half l0 = __float2half_rn(v[2*e]   - __half2float(h0));
                __half l1 = __float2half_rn(v[2*e+1] - __half2float(h1));
                __half2 hh = __halves2half2(h0, h1);
                __half2 ll = __halves2half2(l0, l1);
                hp[e] = *(uint32_t*)&hh;
                lp[e] = *(uint32_t*)&ll;
            }
            uint32_t addr = (uint32_t)r * 128 + (uint32_t)((c8 ^ (r & 7)) << 4);
            *(uint4*)(smem + L_AHI + addr) = hv;
            *(uint4*)(smem + L_ALO + addr) = lv;
        }
        if (ch + 1 < NCH) {
            const __half* bs = wB + (size_t)(ch + 1) * 6144;
            uint32_t dst = sb + ((ch & 1) ? L_B0 : L_B1);
            #pragma unroll
            for (int t = tid; t < 768; t += 256)
                cpa16(dst + t * 16, bs + t * 8);
            cpa_commit();
            cpa_wait1();
        } else {
            cpa_wait0();
        }
        __syncthreads();

        uint32_t bbase = sb + ((ch & 1) ? L_B1 : L_B0);
        #pragma unroll 4
        for (int kk = 0; kk < kmax; kk++) {
            uint32_t ah[2][4], al[2][4], bh[3][4];
            #pragma unroll
            for (int mi = 0; mi < 2; mi++) {
                int r = m_off + mi * 16 + a_row_in;
                int kc = kk * 2 + a_khalf;
                uint32_t off = (uint32_t)r * 128 + (uint32_t)((kc ^ (r & 7)) << 4);
                ldsm4(ah[mi], sb + L_AHI + off);
                ldsm4(al[mi], sb + L_ALO + off);
            }
            #pragma unroll
            for (int ni = 0; ni < 3; ni++) {
                int r = brow[ni];
                int kc = kk * 2 + b_khalf;
                uint32_t off = (uint32_t)r * 128 + (uint32_t)((kc ^ (r & 7)) << 4);
                ldsm4(bh[ni], bbase + off);
            }
            #pragma unroll
            for (int mi = 0; mi < 2; mi++) {
                #pragma unroll
                for (int nj = 0; nj < 6; nj++) {
                    const uint32_t* bfh = &bh[nj >> 1][(nj & 1) * 2];
                    mma16816h(acc[mi][nj], ah[mi], bfh);
                    mma16816h(acc[mi][nj], al[mi], bfh);
                }
            }
        }
    }

    // ---- epilogue: devox gather (fp16 conv, sorted slots) + bias + tanh ----
    #pragma unroll
    for (int mi = 0; mi < 2; mi++) {
        #pragma unroll
        for (int half = 0; half < 2; half++) {
            int r = m_off + mi * 16 + (lane >> 2) + half * 8;
            int slot = pbase + r;
            if (slot >= NPTS) continue;
            int p = g_sorted[slot];
            #pragma unroll
            for (int j = 0; j < 8; j++) {
                float w = g_nbw[j*NPTS + slot];
                if (w != 0.f) {
                    const __half* gp = convsrc + (size_t)g_nbi[j*NPTS + slot] * 96;
                    #pragma unroll
                    for (int nj = 0; nj < 6; nj++) {
                        int co = n_off + nj * 8 + 2 * (lane & 3);
                        float2 gg = __half22float2(*(const __half2*)(gp + co));
                        acc[mi][nj][half*2]   += w * gg.x;
                        acc[mi][nj][half*2+1] += w * gg.y;
                    }
                }
            }
            #pragma unroll
            for (int nj = 0; nj < 6; nj++) {
                int co = n_off + nj * 8 + 2 * (lane & 3);
                float2 bb = *(const float2*)(bias + co);
                float vx = acc[mi][nj][half*2]   + bb.x;
                float vy = acc[mi][nj][half*2+1] + bb.y;
                if (do_tanh) { vx = tanhf(vx); vy = tanhf(vy); }
                *(float2*)(out + (size_t)p * 96 + co) = make_float2(vx, vy);
            }
        }
    }
}

// ======================= attn stage ==========================================
__global__ void __launch_bounds__(256) voxdot_k(const float* __restrict__ src) {
    __shared__ float ws[27*96];
    int tid = threadIdx.x;
    for (int i = tid; i < 27*96; i += 256) ws[i] = g_vT[i];
    __syncthreads();
    int wid = tid >> 5, lane = tid & 31;
    int v = blockIdx.x * 8 + wid;
    if (v >= G3) return;
    int s0 = g_start[v], s1 = g_start[v+1];
    float a0 = 0.f, a1 = 0.f, a2 = 0.f;
    for (int k = s0; k < s1; k++) {
        const float* r = src + (size_t)g_sorted[k] * 96;
        a0 += r[lane]; a1 += r[lane+32]; a2 += r[lane+64];
    }
    if (s1 > s0) {
        float invn = 1.f / (float)(s1 - s0);
        a0 *= invn; a1 *= invn; a2 *= invn;
    }
    #pragma unroll 9
    for (int t = 0; t < 27; t++) {
        float s = a0*ws[t*96+lane] + a1*ws[t*96+lane+32] + a2*ws[t*96+lane+64];
        s += __shfl_xor_sync(0xFFFFFFFF, s, 16);
        s += __shfl_xor_sync(0xFFFFFFFF, s, 8);
        s += __shfl_xor_sync(0xFFFFFFFF, s, 4);
        s += __shfl_xor_sync(0xFFFFFFFF, s, 2);
        s += __shfl_xor_sync(0xFFFFFFFF, s, 1);
        if (lane == 0) g_P[t*G3 + v] = s;
    }
}

__global__ void stencil_k() {
    int v = blockIdx.x * blockDim.x + threadIdx.x;
    if (v >= G3) return;
    int px = v >> 10, py = (v >> 5) & 31, pz = v & 31;
    float acc = 0.f;
    #pragma unroll
    for (int t = 0; t < 27; t++) {
        int kx = t / 9, ky = (t / 3) % 3, kz = t % 3;
        int nx = px + kx - 1, ny = py + ky - 1, nz = pz + kz - 1;
        if ((unsigned)nx < GRES && (unsigned)ny < GRES && (unsigned)nz < GRES)
            acc += g_P[t*G3 + ((nx<<5) + ny)*32 + nz];
    }
    g_vout[v] = acc;
}

__global__ void attn_k(const float* __restrict__ energy,
                       const float* __restrict__ v_lw, const float* __restrict__ v_lb) {
    int s = blockIdx.x * blockDim.x + threadIdx.x;
    if (s >= NPTS) return;
    int p = g_sorted[s];
    float acc = v_lb[0];
    #pragma unroll
    for (int j = 0; j < 8; j++) {
        float w = g_nbw[j*NPTS + s];
        if (w != 0.f) acc += w * g_vout[g_nbi[j*NPTS + s]];
    }
    const float4* er4 = (const float4*)(energy + (size_t)p * CDIM);
    const float4* vw4 = (const float4*)v_lw;
    #pragma unroll 6
    for (int cb = 0; cb < 24; cb++) {
        float4 e = er4[cb], w = vw4[cb];
        acc += e.x*w.x + e.y*w.y + e.z*w.z + e.w*w.w;
    }
    g_attn[p] = acc;
}

// ======================= host orchestration =================================
extern "C" void kernel_launch(void* const* d_in, const int* in_sizes, int n_in,
                              void* d_out, int out_size) {
    const float* hidden   = (const float*)d_in[0];
    const float* query    = (const float*)d_in[1];
    const float* coords   = (const float*)d_in[2];
    const float* wq_conv  = (const float*)d_in[3];
    const float* wq_lw    = (const float*)d_in[4];
    const float* wq_lb    = (const float*)d_in[5];
    const float* wh_conv  = (const float*)d_in[6];
    const float* wh_lw    = (const float*)d_in[7];
    const float* wh_lb    = (const float*)d_in[8];
    const float* att_conv = (const float*)d_in[9];
    const float* att_lw   = (const float*)d_in[10];
    const float* att_lb   = (const float*)d_in[11];
    const float* v_conv   = (const float*)d_in[12];
    const float* v_lw     = (const float*)d_in[13];
    const float* v_lb     = (const float*)d_in[14];
    const float* upd_conv = (const float*)d_in[15];
    const float* upd_lw   = (const float*)d_in[16];
    const float* upd_lb   = (const float*)d_in[17];
    float* out = (float*)d_out;

    int *picnt;
    float *pq, *ph, *pe, *pattn;
    __half *pconv, *pconv2;
    __half *pwqB, *pwhB, *pattB, *pupdB;
    __half *pwqlB, *pwhlB, *pattlB, *pupdlB;
    __half *pA96h, *pB96h, *pA192h, *pA192l;
    cudaGetSymbolAddress((void**)&picnt,  g_icnt);
    cudaGetSymbolAddress((void**)&pq,     g_q);
    cudaGetSymbolAddress((void**)&ph,     g_h);
    cudaGetSymbolAddress((void**)&pe,     g_energy);
    cudaGetSymbolAddress((void**)&pattn,  g_attn);
    cudaGetSymbolAddress((void**)&pconv,  g_conv);
    cudaGetSymbolAddress((void**)&pconv2, g_conv2);
    cudaGetSymbolAddress((void**)&pwqB,   g_wqB);
    cudaGetSymbolAddress((void**)&pwhB,   g_whB);
    cudaGetSymbolAddress((void**)&pattB,  g_attB);
    cudaGetSymbolAddress((void**)&pupdB,  g_updB);
    cudaGetSymbolAddress((void**)&pwqlB,  g_wqlB);
    cudaGetSymbolAddress((void**)&pwhlB,  g_whlB);
    cudaGetSymbolAddress((void**)&pattlB, g_attlB);
    cudaGetSymbolAddress((void**)&pupdlB, g_updlB);
    cudaGetSymbolAddress((void**)&pA96h,  g_pA96_hi);
    cudaGetSymbolAddress((void**)&pB96h,  g_pB96_hi);
    cudaGetSymbolAddress((void**)&pA192h, g_pA192_hi);
    cudaGetSymbolAddress((void**)&pA192l, g_pA192_lo);

    cudaFuncSetAttribute(conv_mma_k<128,2,false>, cudaFuncAttributeMaxDynamicSharedMemorySize, SM_TOT);
    cudaFuncSetAttribute(conv_mma_k<192,3,true>,  cudaFuncAttributeMaxDynamicSharedMemorySize, SM_TOT);
    cudaFuncSetAttribute(lindevox_k<128,2>, cudaFuncAttributeMaxDynamicSharedMemorySize, L_TOT);
    cudaFuncSetAttribute(lindevox_k<192,3>, cudaFuncAttributeMaxDynamicSharedMemorySize, L_TOT);

    const int TB = 256;
    auto gs = [](long long n, int tb){ return (int)((n + tb - 1) / tb); };
    const int LBLK = (NPTS + 127) / 128;   // 782
    const long long ZN = 2LL*U128 + 2LL*U192;
    const long long PREP_N = ZN + 2LL*27*128*96 + 2LL*27*192*96
                           + 2LL*128*96 + 2LL*192*96 + 27*96;

    // --- shared precompute ---
    zeroi_k<<<gs(G3,TB), TB>>>(picnt, G3);
    vox_k<<<gs(NPTS,TB), TB>>>(coords);
    scan_k<<<1, 1024>>>();
    filltrilin_k<<<gs(NPTS,TB), TB>>>(coords);
    prep_all_k<<<gs(PREP_N,TB), TB>>>(wq_conv, wh_conv, att_conv, upd_conv,
                                      wq_lw, wh_lw, att_lw, upd_lw, v_conv,
                                      pwqB, pwhB, pattB, pupdB,
                                      pwqlB, pwhlB, pattlB, pupdlB,
                                      pA96h, pB96h, pA192h, pA192l);

    // --- merged sconv q + sconv h (1-term A) ---
    gathervox_qh_k<<<gs(2LL*G3*24,TB), TB>>>(query, hidden);
    conv_mma_k<128,2,false><<<512, 256, SM_TOT>>>(pwqB, pA96h, pA96h, pconv,
                                                  pwhB, pB96h, pB96h, pconv2, 256);
    lindevox_k<128,2><<<2*LBLK, 256, L_TOT>>>(
        query, nullptr, nullptr, pwqlB, wq_lb, pconv, pq,
        hidden, nullptr, nullptr, pwhlB, wh_lb, pconv2, ph, LBLK, 0);

    // --- energy = tanh(sconv([h, q])) (2-term A) ---
    gathervox192_k<<<gs(2LL*G3*24,TB), TB>>>(ph, pq);
    conv_mma_k<192,3,true><<<256, 256, SM_TOT>>>(pattB, pA192h, pA192l, pconv,
                                                 pattB, pA192h, pA192l, pconv, 256);
    lindevox_k<192,3><<<LBLK, 256, L_TOT>>>(
        ph, pq, nullptr, pattlB, att_lb, pconv, pe,
        ph, pq, nullptr, pattlB, att_lb, pconv, pe, LBLK, 1);

    // --- attn = sconv(energy), cout=1 ---
    voxdot_k<<<G3/8, 256>>>(pe);
    stencil_k<<<gs(G3,TB), TB>>>();
    attn_k<<<gs(NPTS,TB), TB>>>(pe, v_lw, v_lb);

    // --- out = tanh(sconv([q, attn*h])) (2-term A) ---
    mkq_sc_k<<<gs((long long)G3*36,TB), TB>>>(ph, pattn);
    conv_mma_k<192,3,true><<<256, 256, SM_TOT>>>(pupdB, pA192h, pA192l, pconv,
                                                 pupdB, pA192h, pA192l, pconv, 256);
    lindevox_k<192,3><<<LBLK, 256, L_TOT>>>(
        pq, ph, pattn, pupdlB, upd_lb, pconv, out,
        pq, ph, pattn, pupdlB, upd_lb, pconv, out, LBLK, 1);
}

// round 15
// speedup vs baseline: 8.5755x; 1.2057x over previous
#include <cuda_runtime.h>
#include <cuda_fp16.h>
#include <cstdint>
#include <math.h>

#define NPTS 100000
#define CDIM 96
#define GRES 32
#define G3   (GRES*GRES*GRES)
#define PAD  34
#define PP2  (PAD*PAD)
#define PGV  (PP2*PAD)

// ======================= scratch (device globals) ===========================
__device__ int   g_vidx[NPTS];
__device__ int   g_icnt[G3];
__device__ int   g_start[G3+1];
__device__ int   g_pos[G3];
__device__ int   g_sorted[NPTS];
__device__ int   g_nbi[8*NPTS];       // indexed by SORTED slot
__device__ float g_nbw[8*NPTS];       // indexed by SORTED slot
__device__ float g_P[27*G3];          // per-tap dot products (attn stage)
__device__ __half g_conv [G3*CDIM];   // conv outputs in fp16
__device__ __half g_conv2[G3*CDIM];
__device__ float g_vout[G3];
__device__ float g_q[NPTS*CDIM];
__device__ float g_h[NPTS*CDIM];
__device__ float g_energy[NPTS*CDIM];
__device__ float g_attn[NPTS];
// padded fp16 grids (all hi-only; 1-term A everywhere)
__device__ __half g_pA96_hi [PGV*128];   // voxelized query input
__device__ __half g_pB96_hi [PGV*128];   // voxelized hidden input
__device__ __half g_pA192_hi[PGV*192];
// cached voxelized q_out (interior), reused stage3 -> stage5
__device__ __half g_pQ96_hi[PGV*96];
// pre-swizzled fp16 conv weights: [tap*nch+chunk][6144 = 96 rows x 64 ci]
__device__ __half g_wqB [27*2*6144];
__device__ __half g_whB [27*2*6144];
__device__ __half g_attB[27*3*6144];
__device__ __half g_updB[27*3*6144];
// pre-swizzled fp16 linear weights: [chunk][6144]
__device__ __half g_wqlB [2*6144];
__device__ __half g_whlB [2*6144];
__device__ __half g_attlB[3*6144];
__device__ __half g_updlB[3*6144];
__device__ float g_vT[27*CDIM];

// ======================= mma/ldmatrix/cp.async helpers =======================
__device__ __forceinline__ uint32_t smem_u32(const void* p) {
    uint32_t a;
    asm("{ .reg .u64 t; cvta.to.shared.u64 t, %1; cvt.u32.u64 %0, t; }" : "=r"(a) : "l"(p));
    return a;
}
__device__ __forceinline__ void ldsm4(uint32_t* r, uint32_t addr) {
    asm volatile("ldmatrix.sync.aligned.m8n8.x4.shared.b16 {%0,%1,%2,%3}, [%4];"
        : "=r"(r[0]), "=r"(r[1]), "=r"(r[2]), "=r"(r[3]) : "r"(addr));
}
__device__ __forceinline__ void mma16816h(float* c, const uint32_t* a, const uint32_t* b) {
    asm volatile("mma.sync.aligned.m16n8k16.row.col.f32.f16.f16.f32 "
        "{%0,%1,%2,%3}, {%4,%5,%6,%7}, {%8,%9}, {%0,%1,%2,%3};"
        : "+f"(c[0]), "+f"(c[1]), "+f"(c[2]), "+f"(c[3])
        : "r"(a[0]), "r"(a[1]), "r"(a[2]), "r"(a[3]), "r"(b[0]), "r"(b[1]));
}
__device__ __forceinline__ void cpa16(uint32_t dst, const void* src) {
    asm volatile("cp.async.cg.shared.global [%0], [%1], 16;" :: "r"(dst), "l"(src));
}
__device__ __forceinline__ void cpa_commit() { asm volatile("cp.async.commit_group;"); }
__device__ __forceinline__ void cpa_wait0()  { asm volatile("cp.async.wait_group 0;"); }
__device__ __forceinline__ void cpa_wait1()  { asm volatile("cp.async.wait_group 1;"); }

// ======================= sort/index kernels ==================================
__global__ void zeroi_k(int* __restrict__ p, int n) {
    int i = blockIdx.x * blockDim.x + threadIdx.x;
    if (i < n) p[i] = 0;
}

__global__ void vox_k(const float* __restrict__ coords) {
    int p = blockIdx.x * blockDim.x + threadIdx.x;
    if (p >= NPTS) return;
    int vx = min(max((int)floorf(coords[3*p+0]), 0), GRES-1);
    int vy = min(max((int)floorf(coords[3*p+1]), 0), GRES-1);
    int vz = min(max((int)floorf(coords[3*p+2]), 0), GRES-1);
    int flat = (vx*GRES + vy)*GRES + vz;
    g_vidx[p] = flat;
    atomicAdd(&g_icnt[flat], 1);
}

__global__ void __launch_bounds__(1024) scan_k() {
    __shared__ int bs[1024];
    int t = threadIdx.x;
    int base = t * 32;
    int loc[32];
    int s = 0;
    #pragma unroll
    for (int k = 0; k < 32; k++) { loc[k] = s; s += g_icnt[base + k]; }
    bs[t] = s;
    __syncthreads();
    #pragma unroll
    for (int d = 1; d < 1024; d <<= 1) {
        int v = (t >= d) ? bs[t - d] : 0;
        __syncthreads();
        bs[t] += v;
        __syncthreads();
    }
    int off = bs[t] - s;
    #pragma unroll
    for (int k = 0; k < 32; k++) {
        g_start[base + k] = off + loc[k];
        g_pos[base + k]   = off + loc[k];
    }
    if (t == 1023) g_start[G3] = off + s;
}

// fused counting-sort fill + trilinear neighbor precompute (sorted-slot order)
__global__ void filltrilin_k(const float* __restrict__ coords) {
    int p = blockIdx.x * blockDim.x + threadIdx.x;
    if (p >= NPTS) return;
    int s = atomicAdd(&g_pos[g_vidx[p]], 1);
    g_sorted[s] = p;
    float cx = coords[3*p+0], cy = coords[3*p+1], cz = coords[3*p+2];
    float bx = floorf(cx), by = floorf(cy), bz = floorf(cz);
    float fx = cx - bx, fy = cy - by, fz = cz - bz;
    int ix = (int)bx, iy = (int)by, iz = (int)bz;
    #pragma unroll
    for (int j = 0; j < 8; j++) {
        int dx = (j >> 2) & 1, dy = (j >> 1) & 1, dz = j & 1;
        int nx = ix + dx, ny = iy + dy, nz = iz + dz;
        bool valid = (nx >= 0 && nx < GRES && ny >= 0 && ny < GRES && nz >= 0 && nz < GRES);
        int cxc = min(max(nx,0),GRES-1), cyc = min(max(ny,0),GRES-1), czc = min(max(nz,0),GRES-1);
        int flc = (cxc*GRES + cyc)*GRES + czc;
        float w = (dx ? fx : 1.f-fx) * (dy ? fy : 1.f-fy) * (dz ? fz : 1.f-fz);
        if (!valid || g_icnt[flc] == 0) w = 0.f;
        g_nbi[j*NPTS + s] = flc;
        g_nbw[j*NPTS + s] = w;
    }
}

// ======================= fp16 helpers ========================================
__device__ __forceinline__ void f16_store4(float4 acc, __half* dhi, size_t o) {
    __half2 hA = __floats2half2_rn(acc.x, acc.y);
    __half2 hB = __floats2half2_rn(acc.z, acc.w);
    *(__half2*)(dhi + o)     = hA;
    *(__half2*)(dhi + o + 2) = hB;
}

// merged q+h INPUT voxelize (hi only)
__global__ void gathervox_qh_k(const float* __restrict__ q, const float* __restrict__ h) {
    int i = blockIdx.x * blockDim.x + threadIdx.x;
    if (i >= 2 * G3 * 24) return;
    bool sec = (i >= G3 * 24);
    int j = sec ? i - G3 * 24 : i;
    int c4 = j % 24;
    int v  = j / 24;
    int vx = v >> 10, vy = (v >> 5) & 31, vz = v & 31;
    int pv = ((vx + 1) * PAD + (vy + 1)) * PAD + (vz + 1);
    int ci = c4 * 4;
    const float* src = sec ? h : q;

    float4 acc = make_float4(0.f, 0.f, 0.f, 0.f);
    int s0 = g_start[v], s1 = g_start[v+1];
    if (s1 > s0) {
        for (int k = s0; k < s1; k++) {
            int pid = g_sorted[k];
            float4 f = *(const float4*)(src + (size_t)pid * 96 + ci);
            acc.x += f.x; acc.y += f.y; acc.z += f.z; acc.w += f.w;
        }
        float invn = 1.f / (float)(s1 - s0);
        acc.x *= invn; acc.y *= invn; acc.z *= invn; acc.w *= invn;
    }
    f16_store4(acc, sec ? g_pB96_hi : g_pA96_hi, (size_t)pv * 128 + ci);
}

// stage-3 voxelize of OUTPUTS: pA192 = [mean(h_out) | mean(q_out)] + cache q grid
__global__ void gathervox192_k(const float* __restrict__ h, const float* __restrict__ q) {
    int i = blockIdx.x * blockDim.x + threadIdx.x;
    if (i >= 2 * G3 * 24) return;
    bool sec = (i >= G3 * 24);   // sec = q half
    int j = sec ? i - G3 * 24 : i;
    int c4 = j % 24;
    int v  = j / 24;
    int vx = v >> 10, vy = (v >> 5) & 31, vz = v & 31;
    int pv = ((vx + 1) * PAD + (vy + 1)) * PAD + (vz + 1);
    int ci = c4 * 4;
    const float* src = sec ? q : h;

    float4 acc = make_float4(0.f, 0.f, 0.f, 0.f);
    int s0 = g_start[v], s1 = g_start[v+1];
    if (s1 > s0) {
        for (int k = s0; k < s1; k++) {
            int pid = g_sorted[k];
            float4 f = *(const float4*)(src + (size_t)pid * 96 + ci);
            acc.x += f.x; acc.y += f.y; acc.z += f.z; acc.w += f.w;
        }
        float invn = 1.f / (float)(s1 - s0);
        acc.x *= invn; acc.y *= invn; acc.z *= invn; acc.w *= invn;
    }
    if (!sec) {
        f16_store4(acc, g_pA192_hi, (size_t)pv * 192 + ci);
    } else {
        f16_store4(acc, g_pA192_hi, (size_t)pv * 192 + 96 + ci);
        f16_store4(acc, g_pQ96_hi, (size_t)pv * 96 + ci);
    }
}

// stage-5: merged (q-cache copy) + (mean(attn*h) gather)
__global__ void mkq_sc_k(const float* __restrict__ h, const float* __restrict__ scale) {
    const int NCOPY = G3 * 12;
    int i = blockIdx.x * blockDim.x + threadIdx.x;
    if (i < NCOPY) {
        int u = i % 12;
        int v = i / 12;
        int vx = v >> 10, vy = (v >> 5) & 31, vz = v & 31;
        int pv = ((vx + 1) * PAD + (vy + 1)) * PAD + (vz + 1);
        size_t s = (size_t)pv * 96 + u * 8;
        size_t d = (size_t)pv * 192 + u * 8;
        *(uint4*)(g_pA192_hi + d) = *(const uint4*)(g_pQ96_hi + s);
        return;
    }
    int j = i - NCOPY;
    if (j >= G3 * 24) return;
    int c4 = j % 24;
    int v  = j / 24;
    int vx = v >> 10, vy = (v >> 5) & 31, vz = v & 31;
    int pv = ((vx + 1) * PAD + (vy + 1)) * PAD + (vz + 1);
    int ci = c4 * 4;
    float4 acc = make_float4(0.f, 0.f, 0.f, 0.f);
    int s0 = g_start[v], s1 = g_start[v+1];
    if (s1 > s0) {
        for (int k = s0; k < s1; k++) {
            int pid = g_sorted[k];
            float4 f = *(const float4*)(h + (size_t)pid * 96 + ci);
            float m = scale[pid];
            acc.x += f.x * m; acc.y += f.y * m; acc.z += f.z * m; acc.w += f.w * m;
        }
        float invn = 1.f / (float)(s1 - s0);
        acc.x *= invn; acc.y *= invn; acc.z *= invn; acc.w *= invn;
    }
    f16_store4(acc, g_pA192_hi, (size_t)pv * 192 + 96 + ci);
}

// ======================= merged weight prep + grid zero ======================
__device__ __forceinline__ void conv_prep(int i, const float* w, __half* dst,
                                          int CIN, int KPAD, int NCH) {
    int co  = i % 96;
    int r   = i / 96;
    int ci  = r % KPAD;
    int tap = r / KPAD;
    float val = (ci < CIN) ? w[((size_t)co * CIN + ci) * 27 + tap] : 0.f;
    int chunk = ci >> 6;
    int cw = ci & 63;
    uint32_t elem = (uint32_t)co * 64 + (uint32_t)(((cw >> 3) ^ (co & 7)) * 8) + (cw & 7);
    dst[(size_t)(tap * NCH + chunk) * 6144 + elem] = __float2half_rn(val);
}
__device__ __forceinline__ void lin_prep(int i, const float* w, __half* dst, int CIN) {
    int co = i % 96;
    int ci = i / 96;
    float val = (ci < CIN) ? w[(size_t)co * CIN + ci] : 0.f;
    int chunk = ci >> 6;
    int cw = ci & 63;
    uint32_t elem = (uint32_t)co * 64 + (uint32_t)(((cw >> 3) ^ (co & 7)) * 8) + (cw & 7);
    dst[(size_t)chunk * 6144 + elem] = __float2half_rn(val);
}

#define U128 (PGV * 128 / 8)
#define U192 (PGV * 192 / 8)

__global__ void prep_all_k(const float* wq, const float* wh, const float* att,
                           const float* upd, const float* wql, const float* whl,
                           const float* attl, const float* updl, const float* vconv,
                           __half* dwq, __half* dwh, __half* datt, __half* dupd,
                           __half* dwql, __half* dwhl, __half* dattl, __half* dupdl,
                           __half* za, __half* zb, __half* ze) {
    const int C96 = 27*128*96, C192 = 27*192*96, L96 = 128*96, L192 = 192*96;
    long long i = (long long)blockIdx.x * blockDim.x + threadIdx.x;
    uint4 z = make_uint4(0u, 0u, 0u, 0u);
    if (i < U128)            { ((uint4*)za)[i] = z; return; }
    i -= U128;
    if (i < U128)            { ((uint4*)zb)[i] = z; return; }
    i -= U128;
    if (i < U192)            { ((uint4*)ze)[i] = z; return; }
    i -= U192;
    int k = (int)i;
    if (k < C96) { conv_prep(k, wq, dwq, 96, 128, 2); return; }
    k -= C96;
    if (k < C96) { conv_prep(k, wh, dwh, 96, 128, 2); return; }
    k -= C96;
    if (k < C192) { conv_prep(k, att, datt, 192, 192, 3); return; }
    k -= C192;
    if (k < C192) { conv_prep(k, upd, dupd, 192, 192, 3); return; }
    k -= C192;
    if (k < L96) { lin_prep(k, wql, dwql, 96); return; }
    k -= L96;
    if (k < L96) { lin_prep(k, whl, dwhl, 96); return; }
    k -= L96;
    if (k < L192) { lin_prep(k, attl, dattl, 192); return; }
    k -= L192;
    if (k < L192) { lin_prep(k, updl, dupdl, 192); return; }
    k -= L192;
    if (k < 27*96) { int t = k % 27, ci = k / 27; g_vT[t*96 + ci] = vconv[ci*27 + t]; }
}

// ======================= HMMA 3x3x3 conv (slab A hi-only, dual-job) ==========
#define SM_B0   26112            // A slab: 204 rows * 128B
#define SM_B1   38400
#define SM_TOT  50688

template<int KPAD, int NCH>
__global__ void __launch_bounds__(256, 2) conv_mma_k(
    const __half* __restrict__ wBa, const __half* __restrict__ pAhiA,
    __half* __restrict__ outA,
    const __half* __restrict__ wBb, const __half* __restrict__ pAhiB,
    __half* __restrict__ outB,
    int split_blk) {
    extern __shared__ char smem[];
    uint32_t sb = smem_u32(smem);
    int tid = threadIdx.x;
    int warp = tid >> 5, lane = tid & 31;
    int m_off = (warp & 3) * 32;
    int n_off = (warp >> 2) * 48;

    int blk = blockIdx.x;
    bool sec = (blk >= split_blk);
    if (sec) blk -= split_blk;
    const __half* wB   = sec ? wBb   : wBa;
    const __half* pAhi = sec ? pAhiB : pAhiA;
    __half* outp = sec ? outB : outA;

    int x  = blk >> 3;
    int y0 = (blk & 7) * 4;

    float acc[2][6][4];
    #pragma unroll
    for (int mi = 0; mi < 2; mi++)
        #pragma unroll
        for (int nj = 0; nj < 6; nj++)
            #pragma unroll
            for (int e = 0; e < 4; e++) acc[mi][nj][e] = 0.f;

    int a_row_in = (lane & 7) + ((lane >> 3) & 1) * 8;
    int a_khalf  = lane >> 4;
    int b_row_in = (lane & 7) + ((lane >> 3) >> 1) * 8;
    int b_khalf  = (lane >> 3) & 1;

    int rb[2];
    #pragma unroll
    for (int mi = 0; mi < 2; mi++) {
        int m = m_off + mi * 16 + a_row_in;
        rb[mi] = (m >> 5) * 34 + (m & 31);
    }
    int brow[3];
    #pragma unroll
    for (int ni = 0; ni < 3; ni++) brow[ni] = n_off + ni * 16 + b_row_in;

    for (int cc = 0; cc < NCH; cc++) {
        bool shortk = (KPAD == 128 && cc == 1);
        int kmax  = shortk ? 2 : 4;
        int c8max = shortk ? 4 : 8;
        int c8sh  = shortk ? 2 : 3;
        int ahalf = 204 * c8max;

        for (int dx = 0; dx < 3; dx++) {
            __syncthreads();

            {
                const __half* bs = wB + (size_t)((dx * 9) * NCH + cc) * 6144;
                #pragma unroll
                for (int t = tid; t < 768; t += 256)
                    cpa16(sb + SM_B0 + t * 16, bs + t * 8);
                size_t pvbase = ((size_t)(x + dx) * PAD + y0) * PAD;
                for (int t = tid; t < ahalf; t += 256) {
                    int r = t >> c8sh, c8 = t & (c8max - 1);
                    const __half* src = pAhi + (pvbase + r) * KPAD + cc * 64 + c8 * 8;
                    cpa16(sb + (uint32_t)r * 128 + ((c8 ^ (r & 7)) << 4), src);
                }
                cpa_commit();
            }

            for (int t9 = 0; t9 < 9; t9++) {
                cpa_wait0();
                __syncthreads();
                if (t9 < 8) {
                    const __half* bs =
                        wB + (size_t)((dx * 9 + t9 + 1) * NCH + cc) * 6144;
                    uint32_t dst = sb + ((t9 & 1) ? SM_B0 : SM_B1);
                    #pragma unroll
                    for (int t = tid; t < 768; t += 256)
                        cpa16(dst + t * 16, bs + t * 8);
                    cpa_commit();
                }
                uint32_t bbase = sb + ((t9 & 1) ? SM_B1 : SM_B0);
                int toff = (t9 / 3) * PAD + (t9 % 3);

                #pragma unroll 4
                for (int kk = 0; kk < kmax; kk++) {
                    uint32_t ah[2][4], bh[3][4];
                    #pragma unroll
                    for (int mi = 0; mi < 2; mi++) {
                        int r = rb[mi] + toff;
                        int kc = kk * 2 + a_khalf;
                        uint32_t off = (uint32_t)r * 128 + (uint32_t)((kc ^ (r & 7)) << 4);
                        ldsm4(ah[mi], sb + off);
                    }
                    #pragma unroll
                    for (int ni = 0; ni < 3; ni++) {
                        int r = brow[ni];
                        int kc = kk * 2 + b_khalf;
                        uint32_t off = (uint32_t)r * 128 + (uint32_t)((kc ^ (r & 7)) << 4);
                        ldsm4(bh[ni], bbase + off);
                    }
                    #pragma unroll
                    for (int mi = 0; mi < 2; mi++) {
                        #pragma unroll
                        for (int nj = 0; nj < 6; nj++) {
                            const uint32_t* bfh = &bh[nj >> 1][(nj & 1) * 2];
                            mma16816h(acc[mi][nj], ah[mi], bfh);
                        }
                    }
                }
            }
        }
    }

    #pragma unroll
    for (int mi = 0; mi < 2; mi++) {
        #pragma unroll
        for (int half = 0; half < 2; half++) {
            int r = m_off + mi * 16 + (lane >> 2) + half * 8;
            int j = r >> 5, z = r & 31;
            size_t vbase = ((size_t)(x * GRES + y0 + j) * GRES + z) * 96;
            #pragma unroll
            for (int nj = 0; nj < 6; nj++) {
                int co = n_off + nj * 8 + 2 * (lane & 3);
                __half2 hv = __floats2half2_rn(acc[mi][nj][half * 2],
                                               acc[mi][nj][half * 2 + 1]);
                *(__half2*)(&outp[vbase + co]) = hv;
            }
        }
    }
}

// ======================= fused linear GEMM + devox epilogue (dual, SORTED) ===
#define L_B0  16384              // A: 128 rows * 128B
#define L_B1  28672
#define L_TOT 40960

template<int KPAD, int NCH>
__global__ void __launch_bounds__(256, 2) lindevox_k(
    const float* __restrict__ x1a, const float* __restrict__ x2a,
    const float* __restrict__ s2a, const __half* __restrict__ wBa,
    const float* __restrict__ biasa, const __half* __restrict__ convA,
    float* __restrict__ outa,
    const float* __restrict__ x1b, const float* __restrict__ x2b,
    const float* __restrict__ s2b, const __half* __restrict__ wBb,
    const float* __restrict__ biasb, const __half* __restrict__ convB,
    float* __restrict__ outb,
    int split_blk, int do_tanh) {
    extern __shared__ char smem[];
    uint32_t sb = smem_u32(smem);
    int tid = threadIdx.x;
    int warp = tid >> 5, lane = tid & 31;
    int m_off = (warp & 3) * 32;
    int n_off = (warp >> 2) * 48;

    int blk = blockIdx.x;
    bool sec = (blk >= split_blk);
    if (sec) blk -= split_blk;
    const float* x1 = sec ? x1b : x1a;
    const float* x2 = sec ? x2b : x2a;
    const float* scale2 = sec ? s2b : s2a;
    const __half* wB = sec ? wBb : wBa;
    const float* bias = sec ? biasb : biasa;
    const __half* convsrc = sec ? convB : convA;
    float* out = sec ? outb : outa;
    int pbase = blk * 128;           // SORTED slot base

    float acc[2][6][4];
    #pragma unroll
    for (int mi = 0; mi < 2; mi++)
        #pragma unroll
        for (int nj = 0; nj < 6; nj++)
            #pragma unroll
            for (int e = 0; e < 4; e++) acc[mi][nj][e] = 0.f;

    int a_row_in = (lane & 7) + ((lane >> 3) & 1) * 8;
    int a_khalf  = lane >> 4;
    int b_row_in = (lane & 7) + ((lane >> 3) >> 1) * 8;
    int b_khalf  = (lane >> 3) & 1;
    int brow[3];
    #pragma unroll
    for (int ni = 0; ni < 3; ni++) brow[ni] = n_off + ni * 16 + b_row_in;

    #pragma unroll
    for (int t = tid; t < 768; t += 256)
        cpa16(sb + L_B0 + t * 16, wB + t * 8);
    cpa_commit();

    for (int ch = 0; ch < NCH; ch++) {
        if (ch) __syncthreads();
        bool shortk = (KPAD == 128 && ch == 1);
        int kmax  = shortk ? 2 : 4;
        int c8max = shortk ? 4 : 8;
        int c8sh  = shortk ? 2 : 3;

        for (int gidx = tid; gidx < 128 * c8max; gidx += 256) {
            int r = gidx >> c8sh, c8 = gidx & (c8max - 1);
            int slot = pbase + r;
            int colbase = ch * 64 + c8 * 8;
            float v[8];
            bool have = (slot < NPTS) && (colbase < ((KPAD == 128) ? 96 : 192));
            if (have) {
                int p = g_sorted[slot];
                const float* srcp;
                float m = 1.f;
                if (colbase < 96) srcp = x1 + (size_t)p * 96 + colbase;
                else {
                    srcp = x2 + (size_t)p * 96 + (colbase - 96);
                    if (scale2) m = scale2[p];
                }
                float4 aa = *(const float4*)srcp;
                float4 bb = *(const float4*)(srcp + 4);
                v[0]=aa.x*m; v[1]=aa.y*m; v[2]=aa.z*m; v[3]=aa.w*m;
                v[4]=bb.x*m; v[5]=bb.y*m; v[6]=bb.z*m; v[7]=bb.w*m;
            } else {
                #pragma unroll
                for (int e = 0; e < 8; e++) v[e] = 0.f;
            }
            uint4 hv;
            uint32_t* hp = (uint32_t*)&hv;
            #pragma unroll
            for (int e = 0; e < 4; e++) {
                __half2 hh = __floats2half2_rn(v[2*e], v[2*e+1]);
                hp[e] = *(uint32_t*)&hh;
            }
            uint32_t addr = (uint32_t)r * 128 + (uint32_t)((c8 ^ (r & 7)) << 4);
            *(uint4*)(smem + addr) = hv;
        }
        if (ch + 1 < NCH) {
            const __half* bs = wB + (size_t)(ch + 1) * 6144;
            uint32_t dst = sb + ((ch & 1) ? L_B0 : L_B1);
            #pragma unroll
            for (int t = tid; t < 768; t += 256)
                cpa16(dst + t * 16, bs + t * 8);
            cpa_commit();
            cpa_wait1();
        } else {
            cpa_wait0();
        }
        __syncthreads();

        uint32_t bbase = sb + ((ch & 1) ? L_B1 : L_B0);
        #pragma unroll 4
        for (int kk = 0; kk < kmax; kk++) {
            uint32_t ah[2][4], bh[3][4];
            #pragma unroll
            for (int mi = 0; mi < 2; mi++) {
                int r = m_off + mi * 16 + a_row_in;
                int kc = kk * 2 + a_khalf;
                uint32_t off = (uint32_t)r * 128 + (uint32_t)((kc ^ (r & 7)) << 4);
                ldsm4(ah[mi], sb + off);
            }
            #pragma unroll
            for (int ni = 0; ni < 3; ni++) {
                int r = brow[ni];
                int kc = kk * 2 + b_khalf;
                uint32_t off = (uint32_t)r * 128 + (uint32_t)((kc ^ (r & 7)) << 4);
                ldsm4(bh[ni], bbase + off);
            }
            #pragma unroll
            for (int mi = 0; mi < 2; mi++) {
                #pragma unroll
                for (int nj = 0; nj < 6; nj++) {
                    const uint32_t* bfh = &bh[nj >> 1][(nj & 1) * 2];
                    mma16816h(acc[mi][nj], ah[mi], bfh);
                }
            }
        }
    }

    // ---- epilogue: devox gather (fp16 conv, sorted slots) + bias + tanh ----
    #pragma unroll
    for (int mi = 0; mi < 2; mi++) {
        #pragma unroll
        for (int half = 0; half < 2; half++) {
            int r = m_off + mi * 16 + (lane >> 2) + half * 8;
            int slot = pbase + r;
            if (slot >= NPTS) continue;
            int p = g_sorted[slot];
            #pragma unroll
            for (int j = 0; j < 8; j++) {
                float w = g_nbw[j*NPTS + slot];
                if (w != 0.f) {
                    const __half* gp = convsrc + (size_t)g_nbi[j*NPTS + slot] * 96;
                    #pragma unroll
                    for (int nj = 0; nj < 6; nj++) {
                        int co = n_off + nj * 8 + 2 * (lane & 3);
                        float2 gg = __half22float2(*(const __half2*)(gp + co));
                        acc[mi][nj][half*2]   += w * gg.x;
                        acc[mi][nj][half*2+1] += w * gg.y;
                    }
                }
            }
            #pragma unroll
            for (int nj = 0; nj < 6; nj++) {
                int co = n_off + nj * 8 + 2 * (lane & 3);
                float2 bb = *(const float2*)(bias + co);
                float vx = acc[mi][nj][half*2]   + bb.x;
                float vy = acc[mi][nj][half*2+1] + bb.y;
                if (do_tanh) { vx = tanhf(vx); vy = tanhf(vy); }
                *(float2*)(out + (size_t)p * 96 + co) = make_float2(vx, vy);
            }
        }
    }
}

// ======================= attn stage ==========================================
__global__ void __launch_bounds__(256) voxdot_k(const float* __restrict__ src) {
    __shared__ float ws[27*96];
    int tid = threadIdx.x;
    for (int i = tid; i < 27*96; i += 256) ws[i] = g_vT[i];
    __syncthreads();
    int wid = tid >> 5, lane = tid & 31;
    int v = blockIdx.x * 8 + wid;
    if (v >= G3) return;
    int s0 = g_start[v], s1 = g_start[v+1];
    float a0 = 0.f, a1 = 0.f, a2 = 0.f;
    for (int k = s0; k < s1; k++) {
        const float* r = src + (size_t)g_sorted[k] * 96;
        a0 += r[lane]; a1 += r[lane+32]; a2 += r[lane+64];
    }
    if (s1 > s0) {
        float invn = 1.f / (float)(s1 - s0);
        a0 *= invn; a1 *= invn; a2 *= invn;
    }
    #pragma unroll 9
    for (int t = 0; t < 27; t++) {
        float s = a0*ws[t*96+lane] + a1*ws[t*96+lane+32] + a2*ws[t*96+lane+64];
        s += __shfl_xor_sync(0xFFFFFFFF, s, 16);
        s += __shfl_xor_sync(0xFFFFFFFF, s, 8);
        s += __shfl_xor_sync(0xFFFFFFFF, s, 4);
        s += __shfl_xor_sync(0xFFFFFFFF, s, 2);
        s += __shfl_xor_sync(0xFFFFFFFF, s, 1);
        if (lane == 0) g_P[t*G3 + v] = s;
    }
}

__global__ void stencil_k() {
    int v = blockIdx.x * blockDim.x + threadIdx.x;
    if (v >= G3) return;
    int px = v >> 10, py = (v >> 5) & 31, pz = v & 31;
    float acc = 0.f;
    #pragma unroll
    for (int t = 0; t < 27; t++) {
        int kx = t / 9, ky = (t / 3) % 3, kz = t % 3;
        int nx = px + kx - 1, ny = py + ky - 1, nz = pz + kz - 1;
        if ((unsigned)nx < GRES && (unsigned)ny < GRES && (unsigned)nz < GRES)
            acc += g_P[t*G3 + ((nx<<5) + ny)*32 + nz];
    }
    g_vout[v] = acc;
}

__global__ void attn_k(const float* __restrict__ energy,
                       const float* __restrict__ v_lw, const float* __restrict__ v_lb) {
    int s = blockIdx.x * blockDim.x + threadIdx.x;
    if (s >= NPTS) return;
    int p = g_sorted[s];
    float acc = v_lb[0];
    #pragma unroll
    for (int j = 0; j < 8; j++) {
        float w = g_nbw[j*NPTS + s];
        if (w != 0.f) acc += w * g_vout[g_nbi[j*NPTS + s]];
    }
    const float4* er4 = (const float4*)(energy + (size_t)p * CDIM);
    const float4* vw4 = (const float4*)v_lw;
    #pragma unroll 6
    for (int cb = 0; cb < 24; cb++) {
        float4 e = er4[cb], w = vw4[cb];
        acc += e.x*w.x + e.y*w.y + e.z*w.z + e.w*w.w;
    }
    g_attn[p] = acc;
}

// ======================= host orchestration =================================
extern "C" void kernel_launch(void* const* d_in, const int* in_sizes, int n_in,
                              void* d_out, int out_size) {
    const float* hidden   = (const float*)d_in[0];
    const float* query    = (const float*)d_in[1];
    const float* coords   = (const float*)d_in[2];
    const float* wq_conv  = (const float*)d_in[3];
    const float* wq_lw    = (const float*)d_in[4];
    const float* wq_lb    = (const float*)d_in[5];
    const float* wh_conv  = (const float*)d_in[6];
    const float* wh_lw    = (const float*)d_in[7];
    const float* wh_lb    = (const float*)d_in[8];
    const float* att_conv = (const float*)d_in[9];
    const float* att_lw   = (const float*)d_in[10];
    const float* att_lb   = (const float*)d_in[11];
    const float* v_conv   = (const float*)d_in[12];
    const float* v_lw     = (const float*)d_in[13];
    const float* v_lb     = (const float*)d_in[14];
    const float* upd_conv = (const float*)d_in[15];
    const float* upd_lw   = (const float*)d_in[16];
    const float* upd_lb   = (const float*)d_in[17];
    float* out = (float*)d_out;

    int *picnt;
    float *pq, *ph, *pe, *pattn;
    __half *pconv, *pconv2;
    __half *pwqB, *pwhB, *pattB, *pupdB;
    __half *pwqlB, *pwhlB, *pattlB, *pupdlB;
    __half *pA96h, *pB96h, *pA192h;
    cudaGetSymbolAddress((void**)&picnt,  g_icnt);
    cudaGetSymbolAddress((void**)&pq,     g_q);
    cudaGetSymbolAddress((void**)&ph,     g_h);
    cudaGetSymbolAddress((void**)&pe,     g_energy);
    cudaGetSymbolAddress((void**)&pattn,  g_attn);
    cudaGetSymbolAddress((void**)&pconv,  g_conv);
    cudaGetSymbolAddress((void**)&pconv2, g_conv2);
    cudaGetSymbolAddress((void**)&pwqB,   g_wqB);
    cudaGetSymbolAddress((void**)&pwhB,   g_whB);
    cudaGetSymbolAddress((void**)&pattB,  g_attB);
    cudaGetSymbolAddress((void**)&pupdB,  g_updB);
    cudaGetSymbolAddress((void**)&pwqlB,  g_wqlB);
    cudaGetSymbolAddress((void**)&pwhlB,  g_whlB);
    cudaGetSymbolAddress((void**)&pattlB, g_attlB);
    cudaGetSymbolAddress((void**)&pupdlB, g_updlB);
    cudaGetSymbolAddress((void**)&pA96h,  g_pA96_hi);
    cudaGetSymbolAddress((void**)&pB96h,  g_pB96_hi);
    cudaGetSymbolAddress((void**)&pA192h, g_pA192_hi);

    cudaFuncSetAttribute(conv_mma_k<128,2>, cudaFuncAttributeMaxDynamicSharedMemorySize, SM_TOT);
    cudaFuncSetAttribute(conv_mma_k<192,3>, cudaFuncAttributeMaxDynamicSharedMemorySize, SM_TOT);
    cudaFuncSetAttribute(lindevox_k<128,2>, cudaFuncAttributeMaxDynamicSharedMemorySize, L_TOT);
    cudaFuncSetAttribute(lindevox_k<192,3>, cudaFuncAttributeMaxDynamicSharedMemorySize, L_TOT);

    const int TB = 256;
    auto gs = [](long long n, int tb){ return (int)((n + tb - 1) / tb); };
    const int LBLK = (NPTS + 127) / 128;   // 782
    const long long ZN = 2LL*U128 + 1LL*U192;
    const long long PREP_N = ZN + 2LL*27*128*96 + 2LL*27*192*96
                           + 2LL*128*96 + 2LL*192*96 + 27*96;

    // --- shared precompute ---
    zeroi_k<<<gs(G3,TB), TB>>>(picnt, G3);
    vox_k<<<gs(NPTS,TB), TB>>>(coords);
    scan_k<<<1, 1024>>>();
    filltrilin_k<<<gs(NPTS,TB), TB>>>(coords);
    prep_all_k<<<gs(PREP_N,TB), TB>>>(wq_conv, wh_conv, att_conv, upd_conv,
                                      wq_lw, wh_lw, att_lw, upd_lw, v_conv,
                                      pwqB, pwhB, pattB, pupdB,
                                      pwqlB, pwhlB, pattlB, pupdlB,
                                      pA96h, pB96h, pA192h);

    // --- merged sconv q + sconv h ---
    gathervox_qh_k<<<gs(2LL*G3*24,TB), TB>>>(query, hidden);
    conv_mma_k<128,2><<<512, 256, SM_TOT>>>(pwqB, pA96h, pconv,
                                            pwhB, pB96h, pconv2, 256);
    lindevox_k<128,2><<<2*LBLK, 256, L_TOT>>>(
        query, nullptr, nullptr, pwqlB, wq_lb, pconv, pq,
        hidden, nullptr, nullptr, pwhlB, wh_lb, pconv2, ph, LBLK, 0);

    // --- energy = tanh(sconv([h, q])) ---
    gathervox192_k<<<gs(2LL*G3*24,TB), TB>>>(ph, pq);
    conv_mma_k<192,3><<<256, 256, SM_TOT>>>(pattB, pA192h, pconv,
                                            pattB, pA192h, pconv, 256);
    lindevox_k<192,3><<<LBLK, 256, L_TOT>>>(
        ph, pq, nullptr, pattlB, att_lb, pconv, pe,
        ph, pq, nullptr, pattlB, att_lb, pconv, pe, LBLK, 1);

    // --- attn = sconv(energy), cout=1 ---
    voxdot_k<<<G3/8, 256>>>(pe);
    stencil_k<<<gs(G3,TB), TB>>>();
    attn_k<<<gs(NPTS,TB), TB>>>(pe, v_lw, v_lb);

    // --- out = tanh(sconv([q, attn*h])) ---
    mkq_sc_k<<<gs((long long)G3*36,TB), TB>>>(ph, pattn);
    conv_mma_k<192,3><<<256, 256, SM_TOT>>>(pupdB, pA192h, pconv,
                                            pupdB, pA192h, pconv, 256);
    lindevox_k<192,3><<<LBLK, 256, L_TOT>>>(
        pq, ph, pattn, pupdlB, upd_lb, pconv, out,
        pq, ph, pattn, pupdlB, upd_lb, pconv, out, LBLK, 1);
}